// round 2
// baseline (speedup 1.0000x reference)
#include <cuda_runtime.h>
#include <math.h>

// ---------------- problem constants ----------------
namespace {
constexpr int kB  = 2;
constexpr int kS  = 2048;
constexpr int kP  = 512;
constexpr int kNL = 1536;   // latent tokens = S - P
constexpr int kD  = 1024;
constexpr int kH  = 16;
constexpr int kDH = 64;
constexpr int kID = 1024;   // H * DH
constexpr int kV  = 20000;
constexpr int kL  = 4;
constexpr int kFF = 4096;
constexpr float kScale = 0.125f;   // DH^-0.5
constexpr float kEps   = 1e-5f;
}

// ---------------- scratch (module-load allocated, legal) ----------------
__device__ float g_prefix[kB * kP * kD];
__device__ float g_lat   [kB * kNL * kD];
__device__ float g_xn    [kB * kNL * kD];
__device__ float g_cn    [kB * kP * kD];
__device__ float g_q     [kB * kNL * kID];
__device__ float g_kv    [kB * kS * 2 * kID];
__device__ float g_qkv   [kB * kNL * 3 * kID];
__device__ float g_attn  [kB * kNL * kID];
__device__ float g_ff    [kB * kNL * kFF];
__device__ float g_tmp   [kB * kNL * kD];
__device__ float g_cos   [kS * 16];
__device__ float g_sin   [kS * 16];

// ---------------- helpers ----------------
__device__ __forceinline__ float warpSum(float v) {
#pragma unroll
    for (int o = 16; o; o >>= 1) v += __shfl_xor_sync(0xffffffffu, v, o);
    return v;
}

// ---------------- embedding: token_emb[x] + pos_emb ----------------
__global__ void embed_kernel(const int* __restrict__ x,
                             const float* __restrict__ te,
                             const float* __restrict__ pe,
                             float* __restrict__ prefix,
                             float* __restrict__ lat) {
    int row = blockIdx.x;            // b*kS + s
    int b = row / kS, s = row % kS;
    int tok = x[row];
    const float* tr = te + (size_t)tok * kD;
    const float* pr = pe + (size_t)s * kD;
    float* dst = (s < kP) ? (prefix + ((size_t)b * kP + s) * kD)
                          : (lat    + ((size_t)b * kNL + (s - kP)) * kD);
    for (int i = threadIdx.x; i < kD; i += blockDim.x) dst[i] = tr[i] + pr[i];
}

// ---------------- LayerNorm over D=1024, 256 threads/row ----------------
__global__ __launch_bounds__(256) void ln_kernel(const float* __restrict__ in,
                                                 const float* __restrict__ gamma,
                                                 const float* __restrict__ beta,
                                                 float* __restrict__ out) {
    int r = blockIdx.x;
    const float* xr = in + (size_t)r * kD;
    float* o = out + (size_t)r * kD;
    int tid = threadIdx.x;
    float v[4];
    float s = 0.f;
#pragma unroll
    for (int i = 0; i < 4; i++) { v[i] = xr[tid + i * 256]; s += v[i]; }
    __shared__ float red[8];
    __shared__ float meanS, rstdS;
    s = warpSum(s);
    if ((tid & 31) == 0) red[tid >> 5] = s;
    __syncthreads();
    if (tid < 32) {
        float t = (tid < 8) ? red[tid] : 0.f;
        t = warpSum(t);
        if (tid == 0) meanS = t * (1.f / kD);
    }
    __syncthreads();
    float mean = meanS;
    float s2 = 0.f;
#pragma unroll
    for (int i = 0; i < 4; i++) { float d = v[i] - mean; s2 += d * d; }
    s2 = warpSum(s2);
    __syncthreads();
    if ((tid & 31) == 0) red[tid >> 5] = s2;
    __syncthreads();
    if (tid < 32) {
        float t = (tid < 8) ? red[tid] : 0.f;
        t = warpSum(t);
        if (tid == 0) rstdS = rsqrtf(t * (1.f / kD) + kEps);
    }
    __syncthreads();
    float rs = rstdS;
#pragma unroll
    for (int i = 0; i < 4; i++) {
        int idx = tid + i * 256;
        o[idx] = (v[i] - mean) * rs * gamma[idx] + beta[idx];
    }
}

// ---------------- RoPE cos/sin table (double trig: fast_math-proof) -------
__global__ void rope_table_kernel(float* __restrict__ ct, float* __restrict__ st) {
    int idx = blockIdx.x * blockDim.x + threadIdx.x;
    if (idx >= kS * 16) return;
    int s = idx >> 4, i = idx & 15;
    float inv = (float)(1.0 / pow(10000.0, (double)i / 16.0));
    float f = (float)s * inv;               // fp32 multiply, matches jax
    ct[idx] = (float)cos((double)f);
    st[idx] = (float)sin((double)f);
}

// ---------------- RoPE apply (first 32 dims/head), optional global scale --
__global__ void rope_kernel(float* __restrict__ buf, int rows, int rowStride,
                            int T, int posOff, float scaleAll,
                            const float* __restrict__ ct,
                            const float* __restrict__ st) {
    int idx = blockIdx.x * blockDim.x + threadIdx.x;
    if (idx >= rows * kH) return;
    int row = idx / kH, h = idx % kH;
    float* p = buf + (size_t)row * rowStride + h * kDH;
    int pos = posOff + (row % T);
    const float* cr = ct + pos * 16;
    const float* sr = st + pos * 16;
#pragma unroll
    for (int i = 0; i < 16; i++) {
        float c = cr[i], s = sr[i];
        float x1 = p[i], x2 = p[i + 16];
        p[i]      = (x1 * c - x2 * s) * scaleAll;
        p[i + 16] = (x2 * c + x1 * s) * scaleAll;
    }
    if (scaleAll != 1.f) {
#pragma unroll
        for (int i = 32; i < 64; i++) p[i] *= scaleAll;
    }
}

// ---------------- SGEMM: C(MxN) = A(MxK) @ B(KxN) [+bias][gelu][+res] -----
// Requires M % 128 == 0, K % 8 == 0, N % 4 == 0 (all true here).
__global__ __launch_bounds__(256) void sgemm_kernel(
    const float* __restrict__ A, const float* __restrict__ Bm,
    float* __restrict__ C, int M, int N, int K,
    const float* __restrict__ bias, const float* __restrict__ res, int act) {
    const int tid = threadIdx.x;
    const int m0 = blockIdx.y * 128, n0 = blockIdx.x * 128;
    __shared__ float As[8 * 132];   // transposed [k][m], padded
    __shared__ float Bs[8 * 128];   // [k][n]
    float acc[8][8] = {};
    const int aRow = tid >> 1, aCol = (tid & 1) * 4;
    const int bRow = tid >> 5, bCol = (tid & 31) * 4;
    const int tx = tid & 15, ty = tid >> 4;
    const float* Aptr = A + (size_t)(m0 + aRow) * K + aCol;
    const float* Bptr = Bm + (size_t)bRow * N + n0 + bCol;
    const bool bValid = (n0 + bCol) < N;

    for (int kt = 0; kt < K; kt += 8) {
        float4 av = *(const float4*)(Aptr + kt);
        float4 bv = make_float4(0.f, 0.f, 0.f, 0.f);
        if (bValid) bv = *(const float4*)(Bptr + (size_t)kt * N);
        As[(aCol + 0) * 132 + aRow] = av.x;
        As[(aCol + 1) * 132 + aRow] = av.y;
        As[(aCol + 2) * 132 + aRow] = av.z;
        As[(aCol + 3) * 132 + aRow] = av.w;
        *(float4*)&Bs[bRow * 128 + bCol] = bv;
        __syncthreads();
#pragma unroll
        for (int k = 0; k < 8; k++) {
            float4 a0 = *(const float4*)&As[k * 132 + ty * 8];
            float4 a1 = *(const float4*)&As[k * 132 + ty * 8 + 4];
            float4 b0 = *(const float4*)&Bs[k * 128 + tx * 8];
            float4 b1 = *(const float4*)&Bs[k * 128 + tx * 8 + 4];
            float ar[8] = {a0.x, a0.y, a0.z, a0.w, a1.x, a1.y, a1.z, a1.w};
            float br[8] = {b0.x, b0.y, b0.z, b0.w, b1.x, b1.y, b1.z, b1.w};
#pragma unroll
            for (int i = 0; i < 8; i++)
#pragma unroll
                for (int j = 0; j < 8; j++) acc[i][j] += ar[i] * br[j];
        }
        __syncthreads();
    }

#pragma unroll
    for (int i = 0; i < 8; i++) {
        int row = m0 + ty * 8 + i;
#pragma unroll
        for (int j = 0; j < 8; j++) {
            int col = n0 + tx * 8 + j;
            if (col < N) {
                float c = acc[i][j];
                if (bias) c += bias[col];
                if (act) c = 0.5f * c * (1.f + erff(c * 0.70710678118654752f));
                if (res) c += res[(size_t)row * N + col];
                C[(size_t)row * N + col] = c;
            }
        }
    }
}

// ---------------- flash attention (fp32, online softmax) ------------------
// Block: 64 queries x one head x one batch. Key tiles of 32.
// Allowed keys: j <= qi + diag. (prefix_mask in the reference is all-True and
// padded True => mathematically a no-op; intentionally NOT read to avoid any
// bool-marshalling ambiguity.)
__global__ __launch_bounds__(256) void attn_kernel(
    const float* __restrict__ qb, const float* __restrict__ kb,
    const float* __restrict__ vb, float* __restrict__ ob,
    int Tq, int Tk, int qStride, int kvStride, int diag) {
    constexpr int QLD = 65, KLD = 65, VLD = 65, SLD = 33;
    __shared__ float Qs[64 * QLD];
    __shared__ float Ks[32 * KLD];
    __shared__ float Vs[32 * VLD];
    __shared__ float Ss[64 * SLD];
    __shared__ float mrow[64], lrow[64], frow[64];

    const int tid = threadIdx.x;
    const int b = blockIdx.z, h = blockIdx.y, q0 = blockIdx.x * 64;
    const int lane = tid & 31, warp = tid >> 5;
    const int txa = tid & 7,  tya = tid >> 3;    // scores: rows 2*tya(+0..1), cols 4*txa(+0..3)
    const int txc = tid & 15, tyc = tid >> 4;    // PV: rows 4*tyc(+0..3), cols 4*txc(+0..3)

    const float* qg = qb + ((size_t)b * Tq + q0) * qStride + h * kDH;
#pragma unroll
    for (int i = 0; i < 16; i++) {
        int e = tid + i * 256;
        int r = e >> 6, c = e & 63;
        Qs[r * QLD + c] = qg[(size_t)r * qStride + c];
    }
    if (tid < 64) { mrow[tid] = -1e30f; lrow[tid] = 0.f; }
    float o[4][4] = {};

    int jmax = q0 + 63 + diag;
    int nkt = (jmax + 32) >> 5;
    int maxkt = Tk >> 5;
    if (nkt > maxkt) nkt = maxkt;
    __syncthreads();

    for (int kt = 0; kt < nkt; kt++) {
        const int k0 = kt * 32;
        const float* kg = kb + ((size_t)b * Tk + k0) * kvStride + h * kDH;
        const float* vg = vb + ((size_t)b * Tk + k0) * kvStride + h * kDH;
#pragma unroll
        for (int i = 0; i < 8; i++) {
            int e = tid + i * 256;
            int r = e >> 6, c = e & 63;
            Ks[r * KLD + c] = kg[(size_t)r * kvStride + c];
            Vs[r * VLD + c] = vg[(size_t)r * kvStride + c];
        }
        __syncthreads();

        // ---- S = Q @ K^T (64x32 tile) ----
        float sreg[2][4] = {};
#pragma unroll
        for (int kk = 0; kk < 64; kk++) {
            float a0 = Qs[(2 * tya + 0) * QLD + kk];
            float a1 = Qs[(2 * tya + 1) * QLD + kk];
            float bb0 = Ks[(4 * txa + 0) * KLD + kk];
            float bb1 = Ks[(4 * txa + 1) * KLD + kk];
            float bb2 = Ks[(4 * txa + 2) * KLD + kk];
            float bb3 = Ks[(4 * txa + 3) * KLD + kk];
            sreg[0][0] += a0 * bb0; sreg[0][1] += a0 * bb1;
            sreg[0][2] += a0 * bb2; sreg[0][3] += a0 * bb3;
            sreg[1][0] += a1 * bb0; sreg[1][1] += a1 * bb1;
            sreg[1][2] += a1 * bb2; sreg[1][3] += a1 * bb3;
        }
#pragma unroll
        for (int i = 0; i < 2; i++) {
            int qi = q0 + 2 * tya + i;
#pragma unroll
            for (int j = 0; j < 4; j++) {
                int kj = k0 + 4 * txa + j;
                float v = sreg[i][j];
                bool bad = (kj > qi + diag);
                Ss[(2 * tya + i) * SLD + (4 * txa + j)] = bad ? -1e30f : v;
            }
        }
        __syncthreads();

        // ---- online softmax per row (warp per 8 rows, lane = col) ----
        for (int rr = 0; rr < 8; rr++) {
            int row = warp * 8 + rr;
            float v = Ss[row * SLD + lane];
            float mx = v;
#pragma unroll
            for (int off = 16; off; off >>= 1)
                mx = fmaxf(mx, __shfl_xor_sync(0xffffffffu, mx, off));
            float mold = mrow[row];
            float mnew = fmaxf(mold, mx);
            float p = __expf(v - mnew);
            Ss[row * SLD + lane] = p;
            float sum = p;
#pragma unroll
            for (int off = 16; off; off >>= 1)
                sum += __shfl_xor_sync(0xffffffffu, sum, off);
            if (lane == 0) {
                float f = __expf(mold - mnew);
                frow[row] = f;
                lrow[row] = lrow[row] * f + sum;
                mrow[row] = mnew;
            }
        }
        __syncthreads();

        // ---- rescale + O += P @ V ----
#pragma unroll
        for (int i = 0; i < 4; i++) {
            float f = frow[4 * tyc + i];
#pragma unroll
            for (int j = 0; j < 4; j++) o[i][j] *= f;
        }
#pragma unroll
        for (int kk = 0; kk < 32; kk++) {
            float p0 = Ss[(4 * tyc + 0) * SLD + kk];
            float p1 = Ss[(4 * tyc + 1) * SLD + kk];
            float p2 = Ss[(4 * tyc + 2) * SLD + kk];
            float p3 = Ss[(4 * tyc + 3) * SLD + kk];
            float v0 = Vs[kk * VLD + 4 * txc + 0];
            float v1 = Vs[kk * VLD + 4 * txc + 1];
            float v2 = Vs[kk * VLD + 4 * txc + 2];
            float v3 = Vs[kk * VLD + 4 * txc + 3];
            o[0][0] += p0 * v0; o[0][1] += p0 * v1; o[0][2] += p0 * v2; o[0][3] += p0 * v3;
            o[1][0] += p1 * v0; o[1][1] += p1 * v1; o[1][2] += p1 * v2; o[1][3] += p1 * v3;
            o[2][0] += p2 * v0; o[2][1] += p2 * v1; o[2][2] += p2 * v2; o[2][3] += p2 * v3;
            o[3][0] += p3 * v0; o[3][1] += p3 * v1; o[3][2] += p3 * v2; o[3][3] += p3 * v3;
        }
        __syncthreads();
    }

#pragma unroll
    for (int i = 0; i < 4; i++) {
        int row = q0 + 4 * tyc + i;
        float inv = 1.f / lrow[4 * tyc + i];
        float4 w = make_float4(o[i][0] * inv, o[i][1] * inv,
                               o[i][2] * inv, o[i][3] * inv);
        *(float4*)(ob + ((size_t)b * Tq + row) * kID + h * kDH + 4 * txc) = w;
    }
}

// ---------------- host orchestration ----------------
static inline void run_gemm(const float* A, const float* Bm, float* C,
                            int M, int N, int K,
                            const float* bias, const float* res, int act) {
    dim3 g((N + 127) / 128, M / 128);
    sgemm_kernel<<<g, 256>>>(A, Bm, C, M, N, K, bias, res, act);
}

extern "C" void kernel_launch(void* const* d_in, const int* in_sizes, int n_in,
                              void* d_out, int out_size) {
    const int*   x           = (const int*)d_in[0];
    // d_in[1] = prefix_mask: all-True in this problem and padded True in the
    // reference => mask is a mathematical no-op; intentionally unused.
    const float* token_emb   = (const float*)d_in[2];
    const float* pos_emb     = (const float*)d_in[3];
    const float* ca_norm_s   = (const float*)d_in[4];
    const float* ca_norm_b   = (const float*)d_in[5];
    const float* ca_ctx_ns   = (const float*)d_in[6];
    const float* ca_ctx_nb   = (const float*)d_in[7];
    const float* ca_wq       = (const float*)d_in[8];
    const float* ca_wkv      = (const float*)d_in[9];
    const float* ca_wo       = (const float*)d_in[10];
    const float* ca_bo       = (const float*)d_in[11];
    const float* ca_ff_ln_s  = (const float*)d_in[12];
    const float* ca_ff_ln_b  = (const float*)d_in[13];
    const float* ca_ff_w1    = (const float*)d_in[14];
    const float* ca_ff_w2    = (const float*)d_in[15];
    const float* l_norm_s    = (const float*)d_in[16];
    const float* l_norm_b    = (const float*)d_in[17];
    const float* l_wqkv      = (const float*)d_in[18];
    const float* l_wo        = (const float*)d_in[19];
    const float* l_ff_ln_s   = (const float*)d_in[20];
    const float* l_ff_ln_b   = (const float*)d_in[21];
    const float* l_ff_w1     = (const float*)d_in[22];
    const float* l_ff_w2     = (const float*)d_in[23];
    const float* w_logits    = (const float*)d_in[24];
    float* out = (float*)d_out;

    float *prefix, *lat, *xn, *cn, *qb, *kv, *qkv, *att, *ff, *tmp, *ctab, *stab;
    cudaGetSymbolAddress((void**)&prefix, g_prefix);
    cudaGetSymbolAddress((void**)&lat,    g_lat);
    cudaGetSymbolAddress((void**)&xn,     g_xn);
    cudaGetSymbolAddress((void**)&cn,     g_cn);
    cudaGetSymbolAddress((void**)&qb,     g_q);
    cudaGetSymbolAddress((void**)&kv,     g_kv);
    cudaGetSymbolAddress((void**)&qkv,    g_qkv);
    cudaGetSymbolAddress((void**)&att,    g_attn);
    cudaGetSymbolAddress((void**)&ff,     g_ff);
    cudaGetSymbolAddress((void**)&tmp,    g_tmp);
    cudaGetSymbolAddress((void**)&ctab,   g_cos);
    cudaGetSymbolAddress((void**)&stab,   g_sin);

    // 1. embeddings + rope tables
    embed_kernel<<<kB * kS, 256>>>(x, token_emb, pos_emb, prefix, lat);
    rope_table_kernel<<<(kS * 16 + 255) / 256, 256>>>(ctab, stab);

    // 2. cross-attention block
    ln_kernel<<<kB * kNL, 256>>>(lat,    ca_norm_s,  ca_norm_b,  xn);
    ln_kernel<<<kB * kP,  256>>>(prefix, ca_ctx_ns,  ca_ctx_nb,  cn);
    run_gemm(xn, ca_wq, qb, kB * kNL, kID, kD, nullptr, nullptr, 0);
    for (int b = 0; b < kB; b++) {
        run_gemm(xn + (size_t)b * kNL * kD, ca_wkv,
                 kv + ((size_t)b * kS + kP) * 2 * kID, kNL, 2 * kID, kD,
                 nullptr, nullptr, 0);
        run_gemm(cn + (size_t)b * kP * kD, ca_wkv,
                 kv + (size_t)b * kS * 2 * kID, kP, 2 * kID, kD,
                 nullptr, nullptr, 0);
    }
    {
        int rq = kB * kNL * kH, rk = kB * kS * kH;
        rope_kernel<<<(rq + 255) / 256, 256>>>(qb, kB * kNL, kID, kNL, kP, kScale, ctab, stab);
        rope_kernel<<<(rk + 255) / 256, 256>>>(kv, kB * kS, 2 * kID, kS, 0, 1.f, ctab, stab);
    }
    attn_kernel<<<dim3(kNL / 64, kH, kB), 256>>>(qb, kv, kv + kID, att,
                                                 kNL, kS, kID, 2 * kID, kP);
    run_gemm(att, ca_wo, lat, kB * kNL, kD, kID, ca_bo, lat, 0);
    ln_kernel<<<kB * kNL, 256>>>(lat, ca_ff_ln_s, ca_ff_ln_b, tmp);
    run_gemm(tmp, ca_ff_w1, ff, kB * kNL, kFF, kD, nullptr, nullptr, 1);
    run_gemm(ff, ca_ff_w2, lat, kB * kNL, kD, kFF, nullptr, lat, 0);

    // 3. latent self-attention layers
    for (int li = 0; li < kL; li++) {
        ln_kernel<<<kB * kNL, 256>>>(lat, l_norm_s + li * kD, l_norm_b + li * kD, xn);
        run_gemm(xn, l_wqkv + (size_t)li * kD * 3 * kID, qkv,
                 kB * kNL, 3 * kID, kD, nullptr, nullptr, 0);
        int rq = kB * kNL * kH;
        rope_kernel<<<(rq + 255) / 256, 256>>>(qkv,       kB * kNL, 3 * kID, kNL, kP, kScale, ctab, stab);
        rope_kernel<<<(rq + 255) / 256, 256>>>(qkv + kID, kB * kNL, 3 * kID, kNL, kP, 1.f,    ctab, stab);
        attn_kernel<<<dim3(kNL / 64, kH, kB), 256>>>(qkv, qkv + kID, qkv + 2 * kID, att,
                                                     kNL, kNL, 3 * kID, 3 * kID, 0);
        run_gemm(att, l_wo + (size_t)li * kID * kD, lat, kB * kNL, kD, kID,
                 nullptr, lat, 0);
        ln_kernel<<<kB * kNL, 256>>>(lat, l_ff_ln_s + li * kD, l_ff_ln_b + li * kD, tmp);
        run_gemm(tmp, l_ff_w1 + (size_t)li * kD * kFF, ff, kB * kNL, kFF, kD,
                 nullptr, nullptr, 1);
        run_gemm(ff, l_ff_w2 + (size_t)li * kFF * kD, lat, kB * kNL, kD, kFF,
                 nullptr, lat, 0);
    }

    // 4. logits head
    run_gemm(lat, w_logits, out, kB * kNL, kV, kD, nullptr, nullptr, 0);
}

// round 3
// speedup vs baseline: 1.2611x; 1.2611x over previous
#include <cuda_runtime.h>
#include <math.h>
#include <stdint.h>

// ---------------- problem constants ----------------
namespace {
constexpr int kB  = 2;
constexpr int kS  = 2048;
constexpr int kP  = 512;
constexpr int kNL = 1536;   // latent tokens = S - P
constexpr int kD  = 1024;
constexpr int kH  = 16;
constexpr int kDH = 64;
constexpr int kID = 1024;   // H * DH
constexpr int kV  = 20000;
constexpr int kL  = 4;
constexpr int kFF = 4096;
constexpr float kScale = 0.125f;   // DH^-0.5
constexpr float kEps   = 1e-5f;
}

// ---------------- scratch (module-load allocated, legal) ----------------
__device__ float g_prefix[kB * kP * kD];
__device__ float g_lat   [kB * kNL * kD];
__device__ float g_xn    [kB * kNL * kD];
__device__ float g_cn    [kB * kP * kD];
__device__ float g_q     [kB * kNL * kID];
__device__ float g_kv    [kB * kS * 2 * kID];
__device__ float g_qkv   [kB * kNL * 3 * kID];
__device__ float g_attn  [kB * kNL * kID];
__device__ float g_ff    [kB * kNL * kFF];
__device__ float g_tmp   [kB * kNL * kD];
__device__ float g_cos   [kS * 16];
__device__ float g_sin   [kS * 16];

// ---------------- helpers ----------------
__device__ __forceinline__ float warpSum(float v) {
#pragma unroll
    for (int o = 16; o; o >>= 1) v += __shfl_xor_sync(0xffffffffu, v, o);
    return v;
}

__device__ __forceinline__ void splitTF32(float x, uint32_t& hi, uint32_t& lo) {
    uint32_t h;
    asm("cvt.rna.tf32.f32 %0, %1;" : "=r"(h) : "f"(x));
    float l = x - __uint_as_float(h);
    uint32_t lb;
    asm("cvt.rna.tf32.f32 %0, %1;" : "=r"(lb) : "f"(l));
    hi = h; lo = lb;
}

#define MMA_TF32(c, a, b)                                                   \
    asm volatile(                                                           \
        "mma.sync.aligned.m16n8k8.row.col.f32.tf32.tf32.f32 "               \
        "{%0,%1,%2,%3}, {%4,%5,%6,%7}, {%8,%9}, {%0,%1,%2,%3};"             \
        : "+f"((c)[0]), "+f"((c)[1]), "+f"((c)[2]), "+f"((c)[3])            \
        : "r"((a)[0]), "r"((a)[1]), "r"((a)[2]), "r"((a)[3]),               \
          "r"((b)[0]), "r"((b)[1]))

#define CP_ASYNC16(dst, src, sz)                                            \
    asm volatile("cp.async.cg.shared.global [%0], [%1], 16, %2;"            \
                 :: "r"(dst), "l"(src), "r"(sz))
#define CP_COMMIT() asm volatile("cp.async.commit_group;")
#define CP_WAIT(n)  asm volatile("cp.async.wait_group %0;" :: "n"(n))

// ---------------- embedding: token_emb[x] + pos_emb ----------------
__global__ void embed_kernel(const int* __restrict__ x,
                             const float* __restrict__ te,
                             const float* __restrict__ pe,
                             float* __restrict__ prefix,
                             float* __restrict__ lat) {
    int row = blockIdx.x;            // b*kS + s
    int b = row / kS, s = row % kS;
    int tok = x[row];
    const float* tr = te + (size_t)tok * kD;
    const float* pr = pe + (size_t)s * kD;
    float* dst = (s < kP) ? (prefix + ((size_t)b * kP + s) * kD)
                          : (lat    + ((size_t)b * kNL + (s - kP)) * kD);
    for (int i = threadIdx.x; i < kD; i += blockDim.x) dst[i] = tr[i] + pr[i];
}

// ---------------- LayerNorm over D=1024, 256 threads/row ----------------
__global__ __launch_bounds__(256) void ln_kernel(const float* __restrict__ in,
                                                 const float* __restrict__ gamma,
                                                 const float* __restrict__ beta,
                                                 float* __restrict__ out) {
    int r = blockIdx.x;
    const float* xr = in + (size_t)r * kD;
    float* o = out + (size_t)r * kD;
    int tid = threadIdx.x;
    float v[4];
    float s = 0.f;
#pragma unroll
    for (int i = 0; i < 4; i++) { v[i] = xr[tid + i * 256]; s += v[i]; }
    __shared__ float red[8];
    __shared__ float meanS, rstdS;
    s = warpSum(s);
    if ((tid & 31) == 0) red[tid >> 5] = s;
    __syncthreads();
    if (tid < 32) {
        float t = (tid < 8) ? red[tid] : 0.f;
        t = warpSum(t);
        if (tid == 0) meanS = t * (1.f / kD);
    }
    __syncthreads();
    float mean = meanS;
    float s2 = 0.f;
#pragma unroll
    for (int i = 0; i < 4; i++) { float d = v[i] - mean; s2 += d * d; }
    s2 = warpSum(s2);
    __syncthreads();
    if ((tid & 31) == 0) red[tid >> 5] = s2;
    __syncthreads();
    if (tid < 32) {
        float t = (tid < 8) ? red[tid] : 0.f;
        t = warpSum(t);
        if (tid == 0) rstdS = rsqrtf(t * (1.f / kD) + kEps);
    }
    __syncthreads();
    float rs = rstdS;
#pragma unroll
    for (int i = 0; i < 4; i++) {
        int idx = tid + i * 256;
        o[idx] = (v[i] - mean) * rs * gamma[idx] + beta[idx];
    }
}

// ---------------- RoPE cos/sin table (double trig: fast_math-proof) -------
__global__ void rope_table_kernel(float* __restrict__ ct, float* __restrict__ st) {
    int idx = blockIdx.x * blockDim.x + threadIdx.x;
    if (idx >= kS * 16) return;
    int s = idx >> 4, i = idx & 15;
    float inv = (float)(1.0 / pow(10000.0, (double)i / 16.0));
    float f = (float)s * inv;               // fp32 multiply, matches jax
    ct[idx] = (float)cos((double)f);
    st[idx] = (float)sin((double)f);
}

// ---------------- RoPE apply (first 32 dims/head), optional global scale --
__global__ void rope_kernel(float* __restrict__ buf, int rows, int rowStride,
                            int T, int posOff, float scaleAll,
                            const float* __restrict__ ct,
                            const float* __restrict__ st) {
    int idx = blockIdx.x * blockDim.x + threadIdx.x;
    if (idx >= rows * kH) return;
    int row = idx / kH, h = idx % kH;
    float* p = buf + (size_t)row * rowStride + h * kDH;
    int pos = posOff + (row % T);
    const float* cr = ct + pos * 16;
    const float* sr = st + pos * 16;
#pragma unroll
    for (int i = 0; i < 16; i++) {
        float c = cr[i], s = sr[i];
        float x1 = p[i], x2 = p[i + 16];
        p[i]      = (x1 * c - x2 * s) * scaleAll;
        p[i + 16] = (x2 * c + x1 * s) * scaleAll;
    }
    if (scaleAll != 1.f) {
#pragma unroll
        for (int i = 32; i < 64; i++) p[i] *= scaleAll;
    }
}

// ---------------- tensor-core GEMM (3xTF32): C = A @ B [+bias][gelu][+res]
// Tile 128x128, BK=16, 256 threads = 8 warps (2Mx4N), warp tile 64x32.
// Requires M % 128 == 0, K % 16 == 0, N % 4 == 0 (all true here).
namespace {
constexpr int kALd = 20;    // A smem row stride (floats)  -> conflict-free frags
constexpr int kBLd = 136;   // B smem row stride (floats)  -> conflict-free frags
}

__global__ __launch_bounds__(256, 1) void tgemm_kernel(
    const float* __restrict__ A, const float* __restrict__ Bm,
    float* __restrict__ C, int M, int N, int K,
    const float* __restrict__ bias, const float* __restrict__ res, int act) {
    __shared__ float As[2][128 * kALd];
    __shared__ float Bs[2][16 * kBLd];

    const int tid  = threadIdx.x;
    const int lane = tid & 31;
    const int warp = tid >> 5;
    const int warpM = warp >> 2;          // 0..1
    const int warpN = warp & 3;           // 0..3
    const int gid = lane >> 2;            // 0..7
    const int tig = lane & 3;             // 0..3
    const int m0 = blockIdx.y * 128, n0 = blockIdx.x * 128;

    float acc[4][4][4] = {};

    // ---- async staging ----
    auto issue = [&](int stage, int kt) {
#pragma unroll
        for (int it = 0; it < 2; it++) {
            int ch = tid + it * 256;              // A: 512 chunks of 16B
            int m = ch >> 2, kq = ch & 3;
            const float* src = A + (size_t)(m0 + m) * K + kt + kq * 4;
            uint32_t dst = (uint32_t)__cvta_generic_to_shared(
                &As[stage][m * kALd + kq * 4]);
            CP_ASYNC16(dst, src, 16);
        }
#pragma unroll
        for (int it = 0; it < 2; it++) {
            int ch = tid + it * 256;              // B: 512 chunks of 16B
            int k = ch >> 5, nq = ch & 31;
            int col = n0 + nq * 4;
            bool ok = col < N;                    // N % 4 == 0 -> no partials
            const float* src = Bm + (size_t)(kt + k) * N + (ok ? col : 0);
            uint32_t dst = (uint32_t)__cvta_generic_to_shared(
                &Bs[stage][k * kBLd + nq * 4]);
            CP_ASYNC16(dst, src, ok ? 16 : 0);
        }
    };

    auto compute = [&](int buf) {
#pragma unroll
        for (int k8 = 0; k8 < 2; k8++) {
            const int kb = k8 * 8;
            uint32_t bhi[4][2], blo[4][2];
#pragma unroll
            for (int in = 0; in < 4; in++) {
                int ncol = warpN * 32 + in * 8 + gid;
                float x0 = Bs[buf][(kb + tig) * kBLd + ncol];
                float x1 = Bs[buf][(kb + tig + 4) * kBLd + ncol];
                splitTF32(x0, bhi[in][0], blo[in][0]);
                splitTF32(x1, bhi[in][1], blo[in][1]);
            }
#pragma unroll
            for (int im = 0; im < 4; im++) {
                const int r = warpM * 64 + im * 16;
                uint32_t ahi[4], alo[4];
                splitTF32(As[buf][(r + gid) * kALd + kb + tig],         ahi[0], alo[0]);
                splitTF32(As[buf][(r + gid + 8) * kALd + kb + tig],     ahi[1], alo[1]);
                splitTF32(As[buf][(r + gid) * kALd + kb + tig + 4],     ahi[2], alo[2]);
                splitTF32(As[buf][(r + gid + 8) * kALd + kb + tig + 4], ahi[3], alo[3]);
#pragma unroll
                for (int in = 0; in < 4; in++) {
                    MMA_TF32(acc[im][in], ahi, bhi[in]);
                    MMA_TF32(acc[im][in], ahi, blo[in]);
                    MMA_TF32(acc[im][in], alo, bhi[in]);
                }
            }
        }
    };

    const int nStages = K >> 4;
    issue(0, 0);
    CP_COMMIT();
    for (int s = 0; s < nStages; s++) {
        if (s + 1 < nStages) {
            issue((s + 1) & 1, (s + 1) * 16);
            CP_COMMIT();
            CP_WAIT(1);
        } else {
            CP_WAIT(0);
        }
        __syncthreads();
        compute(s & 1);
        __syncthreads();
    }

    // ---- epilogue ----
#pragma unroll
    for (int im = 0; im < 4; im++) {
        const int row = m0 + warpM * 64 + im * 16 + gid;
#pragma unroll
        for (int in = 0; in < 4; in++) {
            const int col = n0 + warpN * 32 + in * 8 + 2 * tig;
            if (col >= N) continue;
#pragma unroll
            for (int half = 0; half < 2; half++) {
                const int rr = row + half * 8;
                float c0 = acc[im][in][half * 2 + 0];
                float c1 = acc[im][in][half * 2 + 1];
                if (bias) { c0 += bias[col]; c1 += bias[col + 1]; }
                if (act) {
                    c0 = 0.5f * c0 * (1.f + erff(c0 * 0.70710678118654752f));
                    c1 = 0.5f * c1 * (1.f + erff(c1 * 0.70710678118654752f));
                }
                if (res) {
                    const float2 rv = *(const float2*)(res + (size_t)rr * N + col);
                    c0 += rv.x; c1 += rv.y;
                }
                *(float2*)(C + (size_t)rr * N + col) = make_float2(c0, c1);
            }
        }
    }
}

// ---------------- flash attention (fp32, online softmax) ------------------
// Block: 64 queries x one head x one batch. Key tiles of 32.
// Allowed keys: j <= qi + diag. (prefix_mask all-True => no-op; not read.)
__global__ __launch_bounds__(256) void attn_kernel(
    const float* __restrict__ qb, const float* __restrict__ kb,
    const float* __restrict__ vb, float* __restrict__ ob,
    int Tq, int Tk, int qStride, int kvStride, int diag) {
    constexpr int QLD = 65, KLD = 65, VLD = 65, SLD = 33;
    __shared__ float Qs[64 * QLD];
    __shared__ float Ks[32 * KLD];
    __shared__ float Vs[32 * VLD];
    __shared__ float Ss[64 * SLD];
    __shared__ float mrow[64], lrow[64], frow[64];

    const int tid = threadIdx.x;
    const int b = blockIdx.z, h = blockIdx.y, q0 = blockIdx.x * 64;
    const int lane = tid & 31, warp = tid >> 5;
    const int txa = tid & 7,  tya = tid >> 3;
    const int txc = tid & 15, tyc = tid >> 4;

    const float* qg = qb + ((size_t)b * Tq + q0) * qStride + h * kDH;
#pragma unroll
    for (int i = 0; i < 16; i++) {
        int e = tid + i * 256;
        int r = e >> 6, c = e & 63;
        Qs[r * QLD + c] = qg[(size_t)r * qStride + c];
    }
    if (tid < 64) { mrow[tid] = -1e30f; lrow[tid] = 0.f; }
    float o[4][4] = {};

    int jmax = q0 + 63 + diag;
    int nkt = (jmax + 32) >> 5;
    int maxkt = Tk >> 5;
    if (nkt > maxkt) nkt = maxkt;
    __syncthreads();

    for (int kt = 0; kt < nkt; kt++) {
        const int k0 = kt * 32;
        const float* kg = kb + ((size_t)b * Tk + k0) * kvStride + h * kDH;
        const float* vg = vb + ((size_t)b * Tk + k0) * kvStride + h * kDH;
#pragma unroll
        for (int i = 0; i < 8; i++) {
            int e = tid + i * 256;
            int r = e >> 6, c = e & 63;
            Ks[r * KLD + c] = kg[(size_t)r * kvStride + c];
            Vs[r * VLD + c] = vg[(size_t)r * kvStride + c];
        }
        __syncthreads();

        float sreg[2][4] = {};
#pragma unroll
        for (int kk = 0; kk < 64; kk++) {
            float a0 = Qs[(2 * tya + 0) * QLD + kk];
            float a1 = Qs[(2 * tya + 1) * QLD + kk];
            float bb0 = Ks[(4 * txa + 0) * KLD + kk];
            float bb1 = Ks[(4 * txa + 1) * KLD + kk];
            float bb2 = Ks[(4 * txa + 2) * KLD + kk];
            float bb3 = Ks[(4 * txa + 3) * KLD + kk];
            sreg[0][0] += a0 * bb0; sreg[0][1] += a0 * bb1;
            sreg[0][2] += a0 * bb2; sreg[0][3] += a0 * bb3;
            sreg[1][0] += a1 * bb0; sreg[1][1] += a1 * bb1;
            sreg[1][2] += a1 * bb2; sreg[1][3] += a1 * bb3;
        }
#pragma unroll
        for (int i = 0; i < 2; i++) {
            int qi = q0 + 2 * tya + i;
#pragma unroll
            for (int j = 0; j < 4; j++) {
                int kj = k0 + 4 * txa + j;
                float v = sreg[i][j];
                bool bad = (kj > qi + diag);
                Ss[(2 * tya + i) * SLD + (4 * txa + j)] = bad ? -1e30f : v;
            }
        }
        __syncthreads();

        for (int rr = 0; rr < 8; rr++) {
            int row = warp * 8 + rr;
            float v = Ss[row * SLD + lane];
            float mx = v;
#pragma unroll
            for (int off = 16; off; off >>= 1)
                mx = fmaxf(mx, __shfl_xor_sync(0xffffffffu, mx, off));
            float mold = mrow[row];
            float mnew = fmaxf(mold, mx);
            float p = __expf(v - mnew);
            Ss[row * SLD + lane] = p;
            float sum = p;
#pragma unroll
            for (int off = 16; off; off >>= 1)
                sum += __shfl_xor_sync(0xffffffffu, sum, off);
            if (lane == 0) {
                float f = __expf(mold - mnew);
                frow[row] = f;
                lrow[row] = lrow[row] * f + sum;
                mrow[row] = mnew;
            }
        }
        __syncthreads();

#pragma unroll
        for (int i = 0; i < 4; i++) {
            float f = frow[4 * tyc + i];
#pragma unroll
            for (int j = 0; j < 4; j++) o[i][j] *= f;
        }
#pragma unroll
        for (int kk = 0; kk < 32; kk++) {
            float p0 = Ss[(4 * tyc + 0) * SLD + kk];
            float p1 = Ss[(4 * tyc + 1) * SLD + kk];
            float p2 = Ss[(4 * tyc + 2) * SLD + kk];
            float p3 = Ss[(4 * tyc + 3) * SLD + kk];
            float v0 = Vs[kk * VLD + 4 * txc + 0];
            float v1 = Vs[kk * VLD + 4 * txc + 1];
            float v2 = Vs[kk * VLD + 4 * txc + 2];
            float v3 = Vs[kk * VLD + 4 * txc + 3];
            o[0][0] += p0 * v0; o[0][1] += p0 * v1; o[0][2] += p0 * v2; o[0][3] += p0 * v3;
            o[1][0] += p1 * v0; o[1][1] += p1 * v1; o[1][2] += p1 * v2; o[1][3] += p1 * v3;
            o[2][0] += p2 * v0; o[2][1] += p2 * v1; o[2][2] += p2 * v2; o[2][3] += p2 * v3;
            o[3][0] += p3 * v0; o[3][1] += p3 * v1; o[3][2] += p3 * v2; o[3][3] += p3 * v3;
        }
        __syncthreads();
    }

#pragma unroll
    for (int i = 0; i < 4; i++) {
        int row = q0 + 4 * tyc + i;
        float inv = 1.f / lrow[4 * tyc + i];
        float4 w = make_float4(o[i][0] * inv, o[i][1] * inv,
                               o[i][2] * inv, o[i][3] * inv);
        *(float4*)(ob + ((size_t)b * Tq + row) * kID + h * kDH + 4 * txc) = w;
    }
}

// ---------------- host orchestration ----------------
static inline void run_gemm(const float* A, const float* Bm, float* C,
                            int M, int N, int K,
                            const float* bias, const float* res, int act) {
    dim3 g((N + 127) / 128, M / 128);
    tgemm_kernel<<<g, 256>>>(A, Bm, C, M, N, K, bias, res, act);
}

extern "C" void kernel_launch(void* const* d_in, const int* in_sizes, int n_in,
                              void* d_out, int out_size) {
    const int*   x           = (const int*)d_in[0];
    // d_in[1] = prefix_mask: all-True and padded True => no-op; unused.
    const float* token_emb   = (const float*)d_in[2];
    const float* pos_emb     = (const float*)d_in[3];
    const float* ca_norm_s   = (const float*)d_in[4];
    const float* ca_norm_b   = (const float*)d_in[5];
    const float* ca_ctx_ns   = (const float*)d_in[6];
    const float* ca_ctx_nb   = (const float*)d_in[7];
    const float* ca_wq       = (const float*)d_in[8];
    const float* ca_wkv      = (const float*)d_in[9];
    const float* ca_wo       = (const float*)d_in[10];
    const float* ca_bo       = (const float*)d_in[11];
    const float* ca_ff_ln_s  = (const float*)d_in[12];
    const float* ca_ff_ln_b  = (const float*)d_in[13];
    const float* ca_ff_w1    = (const float*)d_in[14];
    const float* ca_ff_w2    = (const float*)d_in[15];
    const float* l_norm_s    = (const float*)d_in[16];
    const float* l_norm_b    = (const float*)d_in[17];
    const float* l_wqkv      = (const float*)d_in[18];
    const float* l_wo        = (const float*)d_in[19];
    const float* l_ff_ln_s   = (const float*)d_in[20];
    const float* l_ff_ln_b   = (const float*)d_in[21];
    const float* l_ff_w1     = (const float*)d_in[22];
    const float* l_ff_w2     = (const float*)d_in[23];
    const float* w_logits    = (const float*)d_in[24];
    float* out = (float*)d_out;

    float *prefix, *lat, *xn, *cn, *qb, *kv, *qkv, *att, *ff, *tmp, *ctab, *stab;
    cudaGetSymbolAddress((void**)&prefix, g_prefix);
    cudaGetSymbolAddress((void**)&lat,    g_lat);
    cudaGetSymbolAddress((void**)&xn,     g_xn);
    cudaGetSymbolAddress((void**)&cn,     g_cn);
    cudaGetSymbolAddress((void**)&qb,     g_q);
    cudaGetSymbolAddress((void**)&kv,     g_kv);
    cudaGetSymbolAddress((void**)&qkv,    g_qkv);
    cudaGetSymbolAddress((void**)&att,    g_attn);
    cudaGetSymbolAddress((void**)&ff,     g_ff);
    cudaGetSymbolAddress((void**)&tmp,    g_tmp);
    cudaGetSymbolAddress((void**)&ctab,   g_cos);
    cudaGetSymbolAddress((void**)&stab,   g_sin);

    // 1. embeddings + rope tables
    embed_kernel<<<kB * kS, 256>>>(x, token_emb, pos_emb, prefix, lat);
    rope_table_kernel<<<(kS * 16 + 255) / 256, 256>>>(ctab, stab);

    // 2. cross-attention block
    ln_kernel<<<kB * kNL, 256>>>(lat,    ca_norm_s,  ca_norm_b,  xn);
    ln_kernel<<<kB * kP,  256>>>(prefix, ca_ctx_ns,  ca_ctx_nb,  cn);
    run_gemm(xn, ca_wq, qb, kB * kNL, kID, kD, nullptr, nullptr, 0);
    for (int b = 0; b < kB; b++) {
        run_gemm(xn + (size_t)b * kNL * kD, ca_wkv,
                 kv + ((size_t)b * kS + kP) * 2 * kID, kNL, 2 * kID, kD,
                 nullptr, nullptr, 0);
        run_gemm(cn + (size_t)b * kP * kD, ca_wkv,
                 kv + (size_t)b * kS * 2 * kID, kP, 2 * kID, kD,
                 nullptr, nullptr, 0);
    }
    {
        int rq = kB * kNL * kH, rk = kB * kS * kH;
        rope_kernel<<<(rq + 255) / 256, 256>>>(qb, kB * kNL, kID, kNL, kP, kScale, ctab, stab);
        rope_kernel<<<(rk + 255) / 256, 256>>>(kv, kB * kS, 2 * kID, kS, 0, 1.f, ctab, stab);
    }
    attn_kernel<<<dim3(kNL / 64, kH, kB), 256>>>(qb, kv, kv + kID, att,
                                                 kNL, kS, kID, 2 * kID, kP);
    run_gemm(att, ca_wo, lat, kB * kNL, kD, kID, ca_bo, lat, 0);
    ln_kernel<<<kB * kNL, 256>>>(lat, ca_ff_ln_s, ca_ff_ln_b, tmp);
    run_gemm(tmp, ca_ff_w1, ff, kB * kNL, kFF, kD, nullptr, nullptr, 1);
    run_gemm(ff, ca_ff_w2, lat, kB * kNL, kD, kFF, nullptr, lat, 0);

    // 3. latent self-attention layers
    for (int li = 0; li < kL; li++) {
        ln_kernel<<<kB * kNL, 256>>>(lat, l_norm_s + li * kD, l_norm_b + li * kD, xn);
        run_gemm(xn, l_wqkv + (size_t)li * kD * 3 * kID, qkv,
                 kB * kNL, 3 * kID, kD, nullptr, nullptr, 0);
        int rq = kB * kNL * kH;
        rope_kernel<<<(rq + 255) / 256, 256>>>(qkv,       kB * kNL, 3 * kID, kNL, kP, kScale, ctab, stab);
        rope_kernel<<<(rq + 255) / 256, 256>>>(qkv + kID, kB * kNL, 3 * kID, kNL, kP, 1.f,    ctab, stab);
        attn_kernel<<<dim3(kNL / 64, kH, kB), 256>>>(qkv, qkv + kID, qkv + 2 * kID, att,
                                                     kNL, kNL, 3 * kID, 3 * kID, 0);
        run_gemm(att, l_wo + (size_t)li * kID * kD, lat, kB * kNL, kD, kID,
                 nullptr, lat, 0);
        ln_kernel<<<kB * kNL, 256>>>(lat, l_ff_ln_s + li * kD, l_ff_ln_b + li * kD, tmp);
        run_gemm(tmp, l_ff_w1 + (size_t)li * kD * kFF, ff, kB * kNL, kFF, kD,
                 nullptr, nullptr, 1);
        run_gemm(ff, l_ff_w2 + (size_t)li * kFF * kD, lat, kB * kNL, kD, kFF,
                 nullptr, lat, 0);
    }

    // 4. logits head
    run_gemm(lat, w_logits, out, kB * kNL, kV, kD, nullptr, nullptr, 0);
}

// round 5
// speedup vs baseline: 1.8075x; 1.4333x over previous
#include <cuda_runtime.h>
#include <cuda_bf16.h>
#include <math.h>
#include <stdint.h>

// ---------------- problem constants ----------------
namespace {
constexpr int kB  = 2;
constexpr int kS  = 2048;
constexpr int kP  = 512;
constexpr int kNL = 1536;   // latent tokens = S - P
constexpr int kD  = 1024;
constexpr int kH  = 16;
constexpr int kDH = 64;
constexpr int kID = 1024;   // H * DH
constexpr int kV  = 20000;
constexpr int kVp = 20096;  // padded to 128
constexpr int kL  = 4;
constexpr int kFF = 4096;
constexpr float kScale = 0.125f;   // DH^-0.5
constexpr float kEps   = 1e-5f;

// weight arena offsets (transposed [N][K] layout, elements)
constexpr size_t OFF_CAWQ   = 0;                                  // 1024x1024
constexpr size_t OFF_CAWKV  = OFF_CAWQ  + 1024ull * 1024;         // 2048x1024
constexpr size_t OFF_CAWO   = OFF_CAWKV + 2048ull * 1024;         // 1024x1024
constexpr size_t OFF_CAFF1  = OFF_CAWO  + 1024ull * 1024;         // 4096x1024
constexpr size_t OFF_CAFF2  = OFF_CAFF1 + 4096ull * 1024;         // 1024x4096
constexpr size_t OFF_LQKV   = OFF_CAFF2 + 1024ull * 4096;         // 4 x 3072x1024
constexpr size_t OFF_LWO    = OFF_LQKV  + 4ull * 3072 * 1024;     // 4 x 1024x1024
constexpr size_t OFF_LFF1   = OFF_LWO   + 4ull * 1024 * 1024;     // 4 x 4096x1024
constexpr size_t OFF_LFF2   = OFF_LFF1  + 4ull * 4096 * 1024;     // 4 x 1024x4096
constexpr size_t OFF_LOGITS = OFF_LFF2  + 4ull * 1024 * 4096;     // 20096x1024
constexpr size_t W_TOTAL    = OFF_LOGITS + (size_t)kVp * 1024;

// hgemm smem: 2 stages x 4 arrays x 128 rows x 20 uint32 words
constexpr int kStageWords = 4 * 128 * 20;          // 10240
constexpr int kGemmSmem   = 2 * kStageWords * 4;   // 81920 bytes
}

// ---------------- scratch (module-load allocated, legal) ----------------
__device__ float g_prefix[kB * kP * kD];
__device__ float g_lat   [kB * kNL * kD];
__device__ float g_xn    [kB * kNL * kD];
__device__ float g_cn    [kB * kP * kD];
__device__ float g_q     [kB * kNL * kID];
__device__ float g_kv    [kB * kS * 2 * kID];
__device__ float g_qkv   [kB * kNL * 3 * kID];
__device__ float g_attn  [kB * kNL * kID];
__device__ float g_ff    [kB * kNL * kFF];
__device__ float g_tmp   [kB * kNL * kD];
__device__ float g_cos   [kS * 16];
__device__ float g_sin   [kS * 16];
__device__ __nv_bfloat16 g_whi[W_TOTAL];
__device__ __nv_bfloat16 g_wlo[W_TOTAL];
__device__ __nv_bfloat16 g_ahi[kB * kNL * kFF];   // max A = 3072x4096
__device__ __nv_bfloat16 g_alo[kB * kNL * kFF];

// ---------------- low-level helpers ----------------
__device__ __forceinline__ float warpSum(float v) {
#pragma unroll
    for (int o = 16; o; o >>= 1) v += __shfl_xor_sync(0xffffffffu, v, o);
    return v;
}

#define MMA_BF16(c, a, b)                                                   \
    asm volatile(                                                           \
        "mma.sync.aligned.m16n8k16.row.col.f32.bf16.bf16.f32 "              \
        "{%0,%1,%2,%3}, {%4,%5,%6,%7}, {%8,%9}, {%0,%1,%2,%3};"             \
        : "+f"((c)[0]), "+f"((c)[1]), "+f"((c)[2]), "+f"((c)[3])            \
        : "r"((a)[0]), "r"((a)[1]), "r"((a)[2]), "r"((a)[3]),               \
          "r"((b)[0]), "r"((b)[1]))

#define CP_ASYNC16(dst, src)                                                \
    asm volatile("cp.async.cg.shared.global [%0], [%1], 16;"                \
                 :: "r"(dst), "l"(src))
#define CP_COMMIT() asm volatile("cp.async.commit_group;")
#define CP_WAIT1()  asm volatile("cp.async.wait_group 1;")
#define CP_WAIT0()  asm volatile("cp.async.wait_group 0;")

// ---------------- embedding ----------------
__global__ void embed_kernel(const int* __restrict__ x,
                             const float* __restrict__ te,
                             const float* __restrict__ pe,
                             float* __restrict__ prefix,
                             float* __restrict__ lat) {
    int row = blockIdx.x;
    int b = row / kS, s = row % kS;
    int tok = x[row];
    const float* tr = te + (size_t)tok * kD;
    const float* pr = pe + (size_t)s * kD;
    float* dst = (s < kP) ? (prefix + ((size_t)b * kP + s) * kD)
                          : (lat    + ((size_t)b * kNL + (s - kP)) * kD);
    for (int i = threadIdx.x; i < kD; i += blockDim.x) dst[i] = tr[i] + pr[i];
}

// ---------------- LayerNorm ----------------
__global__ __launch_bounds__(256) void ln_kernel(const float* __restrict__ in,
                                                 const float* __restrict__ gamma,
                                                 const float* __restrict__ beta,
                                                 float* __restrict__ out) {
    int r = blockIdx.x;
    const float* xr = in + (size_t)r * kD;
    float* o = out + (size_t)r * kD;
    int tid = threadIdx.x;
    float v[4];
    float s = 0.f;
#pragma unroll
    for (int i = 0; i < 4; i++) { v[i] = xr[tid + i * 256]; s += v[i]; }
    __shared__ float red[8];
    __shared__ float meanS, rstdS;
    s = warpSum(s);
    if ((tid & 31) == 0) red[tid >> 5] = s;
    __syncthreads();
    if (tid < 32) {
        float t = (tid < 8) ? red[tid] : 0.f;
        t = warpSum(t);
        if (tid == 0) meanS = t * (1.f / kD);
    }
    __syncthreads();
    float mean = meanS;
    float s2 = 0.f;
#pragma unroll
    for (int i = 0; i < 4; i++) { float d = v[i] - mean; s2 += d * d; }
    s2 = warpSum(s2);
    __syncthreads();
    if ((tid & 31) == 0) red[tid >> 5] = s2;
    __syncthreads();
    if (tid < 32) {
        float t = (tid < 8) ? red[tid] : 0.f;
        t = warpSum(t);
        if (tid == 0) rstdS = rsqrtf(t * (1.f / kD) + kEps);
    }
    __syncthreads();
    float rs = rstdS;
#pragma unroll
    for (int i = 0; i < 4; i++) {
        int idx = tid + i * 256;
        o[idx] = (v[i] - mean) * rs * gamma[idx] + beta[idx];
    }
}

// ---------------- RoPE table + apply ----------------
__global__ void rope_table_kernel(float* __restrict__ ct, float* __restrict__ st) {
    int idx = blockIdx.x * blockDim.x + threadIdx.x;
    if (idx >= kS * 16) return;
    int s = idx >> 4, i = idx & 15;
    float inv = (float)(1.0 / pow(10000.0, (double)i / 16.0));
    float f = (float)s * inv;
    ct[idx] = (float)cos((double)f);
    st[idx] = (float)sin((double)f);
}

__global__ void rope_kernel(float* __restrict__ buf, int rows, int rowStride,
                            int T, int posOff, float scaleAll,
                            const float* __restrict__ ct,
                            const float* __restrict__ st) {
    int idx = blockIdx.x * blockDim.x + threadIdx.x;
    if (idx >= rows * kH) return;
    int row = idx / kH, h = idx % kH;
    float* p = buf + (size_t)row * rowStride + h * kDH;
    int pos = posOff + (row % T);
    const float* cr = ct + pos * 16;
    const float* sr = st + pos * 16;
#pragma unroll
    for (int i = 0; i < 16; i++) {
        float c = cr[i], s = sr[i];
        float x1 = p[i], x2 = p[i + 16];
        p[i]      = (x1 * c - x2 * s) * scaleAll;
        p[i + 16] = (x2 * c + x1 * s) * scaleAll;
    }
    if (scaleAll != 1.f) {
#pragma unroll
        for (int i = 32; i < 64; i++) p[i] *= scaleAll;
    }
}

// ---------------- fp32 -> bf16 hi/lo converters ----------------
__global__ void cvt_act_kernel(const float* __restrict__ in,
                               __nv_bfloat16* __restrict__ hi,
                               __nv_bfloat16* __restrict__ lo, int n) {
    int i = (blockIdx.x * blockDim.x + threadIdx.x) * 4;
    if (i >= n) return;
    float4 v = *(const float4*)(in + i);
    __nv_bfloat16 hbuf[4], lbuf[4];
#pragma unroll
    for (int j = 0; j < 4; j++) {
        float x = (&v.x)[j];
        __nv_bfloat16 h = __float2bfloat16(x);
        hbuf[j] = h;
        lbuf[j] = __float2bfloat16(x - __bfloat162float(h));
    }
    *(uint2*)(hi + i) = *(uint2*)hbuf;
    *(uint2*)(lo + i) = *(uint2*)lbuf;
}

// transpose + convert weights: W[K,N] fp32 -> Wt_hi/lo[Npad,K] bf16 (zero pad)
__global__ void cvt_wt_kernel(const float* __restrict__ W,
                              __nv_bfloat16* __restrict__ whi,
                              __nv_bfloat16* __restrict__ wlo,
                              int K, int N, int Npad) {
    __shared__ float t[32][33];
    int k0 = blockIdx.x * 32, n0 = blockIdx.y * 32;
    int tx = threadIdx.x, ty = threadIdx.y;   // 32 x 8
#pragma unroll
    for (int j = 0; j < 4; j++) {
        int k = k0 + ty + 8 * j;
        float v = (n0 + tx < N) ? W[(size_t)k * N + n0 + tx] : 0.f;
        t[ty + 8 * j][tx] = v;
    }
    __syncthreads();
#pragma unroll
    for (int j = 0; j < 4; j++) {
        int n = n0 + ty + 8 * j;
        int k = k0 + tx;
        float x = t[tx][ty + 8 * j];
        __nv_bfloat16 h = __float2bfloat16(x);
        __nv_bfloat16 l = __float2bfloat16(x - __bfloat162float(h));
        whi[(size_t)n * K + k] = h;
        wlo[(size_t)n * K + k] = l;
    }
}

// ---------------- bf16 tensor-core GEMM (3-term split) --------------------
// C[M,N] = A[M,K] @ W^T, W stored [Npad][K] bf16 hi/lo, A stored [M][K] hi/lo.
// CTA tile 128x128, BK=32, 256 threads = 8 warps (2M x 4N), warp tile 64x32.
// smem per stage (uint32 words): Ahi 2560 | Alo 2560 | Bhi 2560 | Blo 2560
// row stride = 20 words (40 bf16) -> fragment loads conflict-free.
__global__ __launch_bounds__(256, 1) void hgemm_kernel(
    const __nv_bfloat16* __restrict__ Ahi, const __nv_bfloat16* __restrict__ Alo,
    const __nv_bfloat16* __restrict__ Bhi, const __nv_bfloat16* __restrict__ Blo,
    float* __restrict__ C, int M, int N, int K,
    const float* __restrict__ bias, const float* __restrict__ res, int act) {
    extern __shared__ uint32_t sm[];
    const int tid  = threadIdx.x;
    const int lane = tid & 31;
    const int warp = tid >> 5;
    const int warpM = warp >> 2;          // 0..1
    const int warpN = warp & 3;           // 0..3
    const int gid = lane >> 2;            // 0..7
    const int tig = lane & 3;             // 0..3
    const int m0 = blockIdx.y * 128, n0 = blockIdx.x * 128;

    float acc[4][4][4] = {};

    // ---- async staging: 2048 x 16B chunks per stage, 8 per thread ----
    auto issue = [&](int stage, int kt) {
        const uint32_t base = stage * kStageWords;
#pragma unroll
        for (int i = 0; i < 8; i++) {
            int c = tid + i * 256;
            int t = c >> 9, w = c & 511;
            int row = w >> 2, ck = w & 3;
            const __nv_bfloat16* src;
            if (t == 0)      src = Ahi + (size_t)(m0 + row) * K + kt + ck * 8;
            else if (t == 1) src = Alo + (size_t)(m0 + row) * K + kt + ck * 8;
            else if (t == 2) src = Bhi + (size_t)(n0 + row) * K + kt + ck * 8;
            else             src = Blo + (size_t)(n0 + row) * K + kt + ck * 8;
            uint32_t dst = (uint32_t)__cvta_generic_to_shared(
                &sm[base + t * 2560 + row * 20 + ck * 4]);
            CP_ASYNC16(dst, src);
        }
    };

    auto compute = [&](int buf) {
        const uint32_t* SAh = sm + buf * kStageWords;
        const uint32_t* SAl = SAh + 2560;
        const uint32_t* SBh = SAl + 2560;
        const uint32_t* SBl = SBh + 2560;
#pragma unroll
        for (int ks = 0; ks < 2; ks++) {
            const int kw = ks * 8 + tig;
            uint32_t bhi[4][2], blo[4][2];
#pragma unroll
            for (int in = 0; in < 4; in++) {
                const int n = warpN * 32 + in * 8 + gid;
                bhi[in][0] = SBh[n * 20 + kw];
                bhi[in][1] = SBh[n * 20 + kw + 4];
                blo[in][0] = SBl[n * 20 + kw];
                blo[in][1] = SBl[n * 20 + kw + 4];
            }
#pragma unroll
            for (int im = 0; im < 4; im++) {
                const int r = warpM * 64 + im * 16 + gid;
                uint32_t ahi[4], alo[4];
                ahi[0] = SAh[r * 20 + kw];
                ahi[1] = SAh[(r + 8) * 20 + kw];
                ahi[2] = SAh[r * 20 + kw + 4];
                ahi[3] = SAh[(r + 8) * 20 + kw + 4];
                alo[0] = SAl[r * 20 + kw];
                alo[1] = SAl[(r + 8) * 20 + kw];
                alo[2] = SAl[r * 20 + kw + 4];
                alo[3] = SAl[(r + 8) * 20 + kw + 4];
#pragma unroll
                for (int in = 0; in < 4; in++) {
                    MMA_BF16(acc[im][in], ahi, bhi[in]);
                    MMA_BF16(acc[im][in], ahi, blo[in]);
                    MMA_BF16(acc[im][in], alo, bhi[in]);
                }
            }
        }
    };

    const int nStages = K >> 5;
    issue(0, 0);
    CP_COMMIT();
    for (int s = 0; s < nStages; s++) {
        if (s + 1 < nStages) {
            issue((s + 1) & 1, (s + 1) * 32);
            CP_COMMIT();
            CP_WAIT1();
        } else {
            CP_WAIT0();
        }
        __syncthreads();
        compute(s & 1);
        __syncthreads();
    }

    // ---- epilogue ----
#pragma unroll
    for (int im = 0; im < 4; im++) {
        const int row = m0 + warpM * 64 + im * 16 + gid;
#pragma unroll
        for (int in = 0; in < 4; in++) {
            const int col = n0 + warpN * 32 + in * 8 + 2 * tig;
            if (col >= N) continue;
#pragma unroll
            for (int half = 0; half < 2; half++) {
                const int rr = row + half * 8;
                float c0 = acc[im][in][half * 2 + 0];
                float c1 = acc[im][in][half * 2 + 1];
                if (bias) { c0 += bias[col]; c1 += bias[col + 1]; }
                if (act) {
                    c0 = 0.5f * c0 * (1.f + erff(c0 * 0.70710678118654752f));
                    c1 = 0.5f * c1 * (1.f + erff(c1 * 0.70710678118654752f));
                }
                if (res) {
                    const float2 rv = *(const float2*)(res + (size_t)rr * N + col);
                    c0 += rv.x; c1 += rv.y;
                }
                *(float2*)(C + (size_t)rr * N + col) = make_float2(c0, c1);
            }
        }
    }
}

// ---------------- flash attention (fp32, online softmax) ------------------
__global__ __launch_bounds__(256) void attn_kernel(
    const float* __restrict__ qb, const float* __restrict__ kb,
    const float* __restrict__ vb, float* __restrict__ ob,
    int Tq, int Tk, int qStride, int kvStride, int diag) {
    constexpr int QLD = 65, KLD = 65, VLD = 65, SLD = 33;
    __shared__ float Qs[64 * QLD];
    __shared__ float Ks[32 * KLD];
    __shared__ float Vs[32 * VLD];
    __shared__ float Ss[64 * SLD];
    __shared__ float mrow[64], lrow[64], frow[64];

    const int tid = threadIdx.x;
    const int b = blockIdx.z, h = blockIdx.y, q0 = blockIdx.x * 64;
    const int lane = tid & 31, warp = tid >> 5;
    const int txa = tid & 7,  tya = tid >> 3;
    const int txc = tid & 15, tyc = tid >> 4;

    const float* qg = qb + ((size_t)b * Tq + q0) * qStride + h * kDH;
#pragma unroll
    for (int i = 0; i < 16; i++) {
        int e = tid + i * 256;
        int r = e >> 6, c = e & 63;
        Qs[r * QLD + c] = qg[(size_t)r * qStride + c];
    }
    if (tid < 64) { mrow[tid] = -1e30f; lrow[tid] = 0.f; }
    float o[4][4] = {};

    int jmax = q0 + 63 + diag;
    int nkt = (jmax + 32) >> 5;
    int maxkt = Tk >> 5;
    if (nkt > maxkt) nkt = maxkt;
    __syncthreads();

    for (int kt = 0; kt < nkt; kt++) {
        const int k0 = kt * 32;
        const float* kg = kb + ((size_t)b * Tk + k0) * kvStride + h * kDH;
        const float* vg = vb + ((size_t)b * Tk + k0) * kvStride + h * kDH;
#pragma unroll
        for (int i = 0; i < 8; i++) {
            int e = tid + i * 256;
            int r = e >> 6, c = e & 63;
            Ks[r * KLD + c] = kg[(size_t)r * kvStride + c];
            Vs[r * VLD + c] = vg[(size_t)r * kvStride + c];
        }
        __syncthreads();

        float sreg[2][4] = {};
#pragma unroll
        for (int kk = 0; kk < 64; kk++) {
            float a0 = Qs[(2 * tya + 0) * QLD + kk];
            float a1 = Qs[(2 * tya + 1) * QLD + kk];
            float bb0 = Ks[(4 * txa + 0) * KLD + kk];
            float bb1 = Ks[(4 * txa + 1) * KLD + kk];
            float bb2 = Ks[(4 * txa + 2) * KLD + kk];
            float bb3 = Ks[(4 * txa + 3) * KLD + kk];
            sreg[0][0] += a0 * bb0; sreg[0][1] += a0 * bb1;
            sreg[0][2] += a0 * bb2; sreg[0][3] += a0 * bb3;
            sreg[1][0] += a1 * bb0; sreg[1][1] += a1 * bb1;
            sreg[1][2] += a1 * bb2; sreg[1][3] += a1 * bb3;
        }
#pragma unroll
        for (int i = 0; i < 2; i++) {
            int qi = q0 + 2 * tya + i;
#pragma unroll
            for (int j = 0; j < 4; j++) {
                int kj = k0 + 4 * txa + j;
                float v = sreg[i][j];
                bool bad = (kj > qi + diag);
                Ss[(2 * tya + i) * SLD + (4 * txa + j)] = bad ? -1e30f : v;
            }
        }
        __syncthreads();

        for (int rr = 0; rr < 8; rr++) {
            int row = warp * 8 + rr;
            float v = Ss[row * SLD + lane];
            float mx = v;
#pragma unroll
            for (int off = 16; off; off >>= 1)
                mx = fmaxf(mx, __shfl_xor_sync(0xffffffffu, mx, off));
            float mold = mrow[row];
            float mnew = fmaxf(mold, mx);
            float p = __expf(v - mnew);
            Ss[row * SLD + lane] = p;
            float sum = p;
#pragma unroll
            for (int off = 16; off; off >>= 1)
                sum += __shfl_xor_sync(0xffffffffu, sum, off);
            if (lane == 0) {
                float f = __expf(mold - mnew);
                frow[row] = f;
                lrow[row] = lrow[row] * f + sum;
                mrow[row] = mnew;
            }
        }
        __syncthreads();

#pragma unroll
        for (int i = 0; i < 4; i++) {
            float f = frow[4 * tyc + i];
#pragma unroll
            for (int j = 0; j < 4; j++) o[i][j] *= f;
        }
#pragma unroll
        for (int kk = 0; kk < 32; kk++) {
            float p0 = Ss[(4 * tyc + 0) * SLD + kk];
            float p1 = Ss[(4 * tyc + 1) * SLD + kk];
            float p2 = Ss[(4 * tyc + 2) * SLD + kk];
            float p3 = Ss[(4 * tyc + 3) * SLD + kk];
            float v0 = Vs[kk * VLD + 4 * txc + 0];
            float v1 = Vs[kk * VLD + 4 * txc + 1];
            float v2 = Vs[kk * VLD + 4 * txc + 2];
            float v3 = Vs[kk * VLD + 4 * txc + 3];
            o[0][0] += p0 * v0; o[0][1] += p0 * v1; o[0][2] += p0 * v2; o[0][3] += p0 * v3;
            o[1][0] += p1 * v0; o[1][1] += p1 * v1; o[1][2] += p1 * v2; o[1][3] += p1 * v3;
            o[2][0] += p2 * v0; o[2][1] += p2 * v1; o[2][2] += p2 * v2; o[2][3] += p2 * v3;
            o[3][0] += p3 * v0; o[3][1] += p3 * v1; o[3][2] += p3 * v2; o[3][3] += p3 * v3;
        }
        __syncthreads();
    }

#pragma unroll
    for (int i = 0; i < 4; i++) {
        int row = q0 + 4 * tyc + i;
        float inv = 1.f / lrow[4 * tyc + i];
        float4 w = make_float4(o[i][0] * inv, o[i][1] * inv,
                               o[i][2] * inv, o[i][3] * inv);
        *(float4*)(ob + ((size_t)b * Tq + row) * kID + h * kDH + 4 * txc) = w;
    }
}

// ---------------- host orchestration ----------------
namespace {
__nv_bfloat16 *h_whi, *h_wlo, *h_ahi, *h_alo;

inline void cvtA(const float* A, size_t n) {
    cvt_act_kernel<<<(int)((n / 4 + 255) / 256), 256>>>(A, h_ahi, h_alo, (int)n);
}

inline void gemm(size_t aOff, size_t wOff, float* C, int M, int N, int Npad,
                 int K, const float* bias, const float* res, int act) {
    dim3 g(Npad / 128, M / 128);
    hgemm_kernel<<<g, 256, kGemmSmem>>>(
        h_ahi + aOff * (size_t)K, h_alo + aOff * (size_t)K,
        h_whi + wOff, h_wlo + wOff, C, M, N, K, bias, res, act);
}
}

extern "C" void kernel_launch(void* const* d_in, const int* in_sizes, int n_in,
                              void* d_out, int out_size) {
    const int*   x           = (const int*)d_in[0];
    // d_in[1] = prefix_mask: all-True and padded True => no-op; unused.
    const float* token_emb   = (const float*)d_in[2];
    const float* pos_emb     = (const float*)d_in[3];
    const float* ca_norm_s   = (const float*)d_in[4];
    const float* ca_norm_b   = (const float*)d_in[5];
    const float* ca_ctx_ns   = (const float*)d_in[6];
    const float* ca_ctx_nb   = (const float*)d_in[7];
    const float* ca_wq       = (const float*)d_in[8];
    const float* ca_wkv      = (const float*)d_in[9];
    const float* ca_wo       = (const float*)d_in[10];
    const float* ca_bo       = (const float*)d_in[11];
    const float* ca_ff_ln_s  = (const float*)d_in[12];
    const float* ca_ff_ln_b  = (const float*)d_in[13];
    const float* ca_ff_w1    = (const float*)d_in[14];
    const float* ca_ff_w2    = (const float*)d_in[15];
    const float* l_norm_s    = (const float*)d_in[16];
    const float* l_norm_b    = (const float*)d_in[17];
    const float* l_wqkv      = (const float*)d_in[18];
    const float* l_wo        = (const float*)d_in[19];
    const float* l_ff_ln_s   = (const float*)d_in[20];
    const float* l_ff_ln_b   = (const float*)d_in[21];
    const float* l_ff_w1     = (const float*)d_in[22];
    const float* l_ff_w2     = (const float*)d_in[23];
    const float* w_logits    = (const float*)d_in[24];
    float* out = (float*)d_out;

    float *prefix, *lat, *xn, *cn, *qb, *kv, *qkv, *att, *ff, *tmp, *ctab, *stab;
    cudaGetSymbolAddress((void**)&prefix, g_prefix);
    cudaGetSymbolAddress((void**)&lat,    g_lat);
    cudaGetSymbolAddress((void**)&xn,     g_xn);
    cudaGetSymbolAddress((void**)&cn,     g_cn);
    cudaGetSymbolAddress((void**)&qb,     g_q);
    cudaGetSymbolAddress((void**)&kv,     g_kv);
    cudaGetSymbolAddress((void**)&qkv,    g_qkv);
    cudaGetSymbolAddress((void**)&att,    g_attn);
    cudaGetSymbolAddress((void**)&ff,     g_ff);
    cudaGetSymbolAddress((void**)&tmp,    g_tmp);
    cudaGetSymbolAddress((void**)&ctab,   g_cos);
    cudaGetSymbolAddress((void**)&stab,   g_sin);
    cudaGetSymbolAddress((void**)&h_whi,  g_whi);
    cudaGetSymbolAddress((void**)&h_wlo,  g_wlo);
    cudaGetSymbolAddress((void**)&h_ahi,  g_ahi);
    cudaGetSymbolAddress((void**)&h_alo,  g_alo);

    cudaFuncSetAttribute(hgemm_kernel,
                         cudaFuncAttributeMaxDynamicSharedMemorySize, kGemmSmem);

    // 0. convert + transpose all weights into bf16 hi/lo arenas
    auto cw = [&](const float* W, size_t off, int K, int N, int Npad) {
        dim3 g(K / 32, Npad / 32);
        cvt_wt_kernel<<<g, dim3(32, 8)>>>(W, h_whi + off, h_wlo + off, K, N, Npad);
    };
    cw(ca_wq,    OFF_CAWQ,  1024, 1024, 1024);
    cw(ca_wkv,   OFF_CAWKV, 1024, 2048, 2048);
    cw(ca_wo,    OFF_CAWO,  1024, 1024, 1024);
    cw(ca_ff_w1, OFF_CAFF1, 1024, 4096, 4096);
    cw(ca_ff_w2, OFF_CAFF2, 4096, 1024, 1024);
    for (int li = 0; li < kL; li++) {
        cw(l_wqkv  + (size_t)li * 1024 * 3072, OFF_LQKV + (size_t)li * 3072 * 1024, 1024, 3072, 3072);
        cw(l_wo    + (size_t)li * 1024 * 1024, OFF_LWO  + (size_t)li * 1024 * 1024, 1024, 1024, 1024);
        cw(l_ff_w1 + (size_t)li * 1024 * 4096, OFF_LFF1 + (size_t)li * 4096 * 1024, 1024, 4096, 4096);
        cw(l_ff_w2 + (size_t)li * 4096 * 1024, OFF_LFF2 + (size_t)li * 1024 * 4096, 4096, 1024, 1024);
    }
    cw(w_logits, OFF_LOGITS, 1024, kV, kVp);

    // 1. embeddings + rope tables
    embed_kernel<<<kB * kS, 256>>>(x, token_emb, pos_emb, prefix, lat);
    rope_table_kernel<<<(kS * 16 + 255) / 256, 256>>>(ctab, stab);

    // 2. cross-attention block
    ln_kernel<<<kB * kNL, 256>>>(lat,    ca_norm_s,  ca_norm_b,  xn);
    ln_kernel<<<kB * kP,  256>>>(prefix, ca_ctx_ns,  ca_ctx_nb,  cn);

    cvtA(cn, (size_t)kB * kP * kD);
    for (int b = 0; b < kB; b++)
        gemm((size_t)b * kP, OFF_CAWKV, kv + (size_t)b * kS * 2 * kID,
             kP, 2 * kID, 2 * kID, kD, nullptr, nullptr, 0);

    cvtA(xn, (size_t)kB * kNL * kD);
    gemm(0, OFF_CAWQ, qb, kB * kNL, kID, kID, kD, nullptr, nullptr, 0);
    for (int b = 0; b < kB; b++)
        gemm((size_t)b * kNL, OFF_CAWKV, kv + ((size_t)b * kS + kP) * 2 * kID,
             kNL, 2 * kID, 2 * kID, kD, nullptr, nullptr, 0);

    {
        int rq = kB * kNL * kH, rk = kB * kS * kH;
        rope_kernel<<<(rq + 255) / 256, 256>>>(qb, kB * kNL, kID, kNL, kP, kScale, ctab, stab);
        rope_kernel<<<(rk + 255) / 256, 256>>>(kv, kB * kS, 2 * kID, kS, 0, 1.f, ctab, stab);
    }
    attn_kernel<<<dim3(kNL / 64, kH, kB), 256>>>(qb, kv, kv + kID, att,
                                                 kNL, kS, kID, 2 * kID, kP);

    cvtA(att, (size_t)kB * kNL * kID);
    gemm(0, OFF_CAWO, lat, kB * kNL, kD, kD, kID, ca_bo, lat, 0);

    ln_kernel<<<kB * kNL, 256>>>(lat, ca_ff_ln_s, ca_ff_ln_b, tmp);
    cvtA(tmp, (size_t)kB * kNL * kD);
    gemm(0, OFF_CAFF1, ff, kB * kNL, kFF, kFF, kD, nullptr, nullptr, 1);
    cvtA(ff, (size_t)kB * kNL * kFF);
    gemm(0, OFF_CAFF2, lat, kB * kNL, kD, kD, kFF, nullptr, lat, 0);

    // 3. latent self-attention layers
    for (int li = 0; li < kL; li++) {
        ln_kernel<<<kB * kNL, 256>>>(lat, l_norm_s + li * kD, l_norm_b + li * kD, xn);
        cvtA(xn, (size_t)kB * kNL * kD);
        gemm(0, OFF_LQKV + (size_t)li * 3072 * 1024, qkv,
             kB * kNL, 3 * kID, 3 * kID, kD, nullptr, nullptr, 0);

        int rq = kB * kNL * kH;
        rope_kernel<<<(rq + 255) / 256, 256>>>(qkv,       kB * kNL, 3 * kID, kNL, kP, kScale, ctab, stab);
        rope_kernel<<<(rq + 255) / 256, 256>>>(qkv + kID, kB * kNL, 3 * kID, kNL, kP, 1.f,    ctab, stab);
        attn_kernel<<<dim3(kNL / 64, kH, kB), 256>>>(qkv, qkv + kID, qkv + 2 * kID, att,
                                                     kNL, kNL, 3 * kID, 3 * kID, 0);

        cvtA(att, (size_t)kB * kNL * kID);
        gemm(0, OFF_LWO + (size_t)li * 1024 * 1024, lat,
             kB * kNL, kD, kD, kID, nullptr, lat, 0);

        ln_kernel<<<kB * kNL, 256>>>(lat, l_ff_ln_s + li * kD, l_ff_ln_b + li * kD, tmp);
        cvtA(tmp, (size_t)kB * kNL * kD);
        gemm(0, OFF_LFF1 + (size_t)li * 4096 * 1024, ff,
             kB * kNL, kFF, kFF, kD, nullptr, nullptr, 1);
        cvtA(ff, (size_t)kB * kNL * kFF);
        gemm(0, OFF_LFF2 + (size_t)li * 1024 * 4096, lat,
             kB * kNL, kD, kD, kFF, nullptr, lat, 0);
    }

    // 4. logits head
    cvtA(lat, (size_t)kB * kNL * kD);
    gemm(0, OFF_LOGITS, out, kB * kNL, kV, kVp, kD, nullptr, nullptr, 0);
}

// round 6
// speedup vs baseline: 1.8774x; 1.0387x over previous
#include <cuda_runtime.h>
#include <cuda_bf16.h>
#include <math.h>
#include <stdint.h>

// ---------------- problem constants ----------------
namespace {
constexpr int kB  = 2;
constexpr int kS  = 2048;
constexpr int kP  = 512;
constexpr int kNL = 1536;   // latent tokens = S - P
constexpr int kD  = 1024;
constexpr int kH  = 16;
constexpr int kDH = 64;
constexpr int kID = 1024;   // H * DH
constexpr int kV  = 20000;
constexpr int kVp = 20096;  // padded to 128
constexpr int kL  = 4;
constexpr int kFF = 4096;
constexpr float kScale = 0.125f;   // DH^-0.5
constexpr float kEps   = 1e-5f;

// weight arena offsets (transposed [N][K] layout, elements)
constexpr size_t OFF_CAWQ   = 0;                                  // 1024x1024
constexpr size_t OFF_CAWKV  = OFF_CAWQ  + 1024ull * 1024;         // 2048x1024
constexpr size_t OFF_CAWO   = OFF_CAWKV + 2048ull * 1024;         // 1024x1024
constexpr size_t OFF_CAFF1  = OFF_CAWO  + 1024ull * 1024;         // 4096x1024
constexpr size_t OFF_CAFF2  = OFF_CAFF1 + 4096ull * 1024;         // 1024x4096
constexpr size_t OFF_LQKV   = OFF_CAFF2 + 1024ull * 4096;         // 4 x 3072x1024
constexpr size_t OFF_LWO    = OFF_LQKV  + 4ull * 3072 * 1024;     // 4 x 1024x1024
constexpr size_t OFF_LFF1   = OFF_LWO   + 4ull * 1024 * 1024;     // 4 x 4096x1024
constexpr size_t OFF_LFF2   = OFF_LFF1  + 4ull * 4096 * 1024;     // 4 x 1024x4096
constexpr size_t OFF_LOGITS = OFF_LFF2  + 4ull * 1024 * 4096;     // 20096x1024
constexpr size_t W_TOTAL    = OFF_LOGITS + (size_t)kVp * 1024;

// hgemm smem: 3 stages x 4 arrays x 128 rows x 24 uint32 words
constexpr int kRowWords   = 24;                      // 16 data + 8 pad
constexpr int kArrWords   = 128 * kRowWords;         // 3072
constexpr int kStageWords = 4 * kArrWords;           // 12288
constexpr int kGemmSmem   = 3 * kStageWords * 4;     // 147456 bytes
}

// ---------------- scratch (module-load allocated, legal) ----------------
__device__ float g_prefix[kB * kP * kD];
__device__ float g_lat   [kB * kNL * kD];
__device__ float g_xn    [kB * kNL * kD];
__device__ float g_cn    [kB * kP * kD];
__device__ float g_q     [kB * kNL * kID];
__device__ float g_kv    [kB * kS * 2 * kID];
__device__ float g_qkv   [kB * kNL * 3 * kID];
__device__ float g_attn  [kB * kNL * kID];
__device__ float g_ff    [kB * kNL * kFF];
__device__ float g_tmp   [kB * kNL * kD];
__device__ float g_cos   [kS * 16];
__device__ float g_sin   [kS * 16];
__device__ __nv_bfloat16 g_whi[W_TOTAL];
__device__ __nv_bfloat16 g_wlo[W_TOTAL];
__device__ __nv_bfloat16 g_ahi[kB * kNL * kFF];   // max A = 3072x4096
__device__ __nv_bfloat16 g_alo[kB * kNL * kFF];

// ---------------- low-level helpers ----------------
__device__ __forceinline__ float warpSum(float v) {
#pragma unroll
    for (int o = 16; o; o >>= 1) v += __shfl_xor_sync(0xffffffffu, v, o);
    return v;
}

// k-pair permutation: within each 8-word group, word w8 -> (w8&3)*2 + (w8>>2)
// so fragment word pairs (t, t+4) become adjacent (2t, 2t+1).
__device__ __forceinline__ int permWord(int w) {
    int w8 = w & 7;
    return (w & ~7) + ((w8 & 3) << 1) + (w8 >> 2);
}

#define MMA_BF16(c, a, b)                                                   \
    asm volatile(                                                           \
        "mma.sync.aligned.m16n8k16.row.col.f32.bf16.bf16.f32 "              \
        "{%0,%1,%2,%3}, {%4,%5,%6,%7}, {%8,%9}, {%0,%1,%2,%3};"             \
        : "+f"((c)[0]), "+f"((c)[1]), "+f"((c)[2]), "+f"((c)[3])            \
        : "r"((a)[0]), "r"((a)[1]), "r"((a)[2]), "r"((a)[3]),               \
          "r"((b)[0]), "r"((b)[1]))

#define CP_ASYNC16(dst, src)                                                \
    asm volatile("cp.async.cg.shared.global [%0], [%1], 16;"                \
                 :: "r"(dst), "l"(src))
#define CP_COMMIT() asm volatile("cp.async.commit_group;")
#define CP_WAIT1()  asm volatile("cp.async.wait_group 1;")

// ---------------- embedding ----------------
__global__ void embed_kernel(const int* __restrict__ x,
                             const float* __restrict__ te,
                             const float* __restrict__ pe,
                             float* __restrict__ prefix,
                             float* __restrict__ lat) {
    int row = blockIdx.x;
    int b = row / kS, s = row % kS;
    int tok = x[row];
    const float* tr = te + (size_t)tok * kD;
    const float* pr = pe + (size_t)s * kD;
    float* dst = (s < kP) ? (prefix + ((size_t)b * kP + s) * kD)
                          : (lat    + ((size_t)b * kNL + (s - kP)) * kD);
    for (int i = threadIdx.x; i < kD; i += blockDim.x) dst[i] = tr[i] + pr[i];
}

// ---------------- LayerNorm ----------------
__global__ __launch_bounds__(256) void ln_kernel(const float* __restrict__ in,
                                                 const float* __restrict__ gamma,
                                                 const float* __restrict__ beta,
                                                 float* __restrict__ out) {
    int r = blockIdx.x;
    const float* xr = in + (size_t)r * kD;
    float* o = out + (size_t)r * kD;
    int tid = threadIdx.x;
    float v[4];
    float s = 0.f;
#pragma unroll
    for (int i = 0; i < 4; i++) { v[i] = xr[tid + i * 256]; s += v[i]; }
    __shared__ float red[8];
    __shared__ float meanS, rstdS;
    s = warpSum(s);
    if ((tid & 31) == 0) red[tid >> 5] = s;
    __syncthreads();
    if (tid < 32) {
        float t = (tid < 8) ? red[tid] : 0.f;
        t = warpSum(t);
        if (tid == 0) meanS = t * (1.f / kD);
    }
    __syncthreads();
    float mean = meanS;
    float s2 = 0.f;
#pragma unroll
    for (int i = 0; i < 4; i++) { float d = v[i] - mean; s2 += d * d; }
    s2 = warpSum(s2);
    __syncthreads();
    if ((tid & 31) == 0) red[tid >> 5] = s2;
    __syncthreads();
    if (tid < 32) {
        float t = (tid < 8) ? red[tid] : 0.f;
        t = warpSum(t);
        if (tid == 0) rstdS = rsqrtf(t * (1.f / kD) + kEps);
    }
    __syncthreads();
    float rs = rstdS;
#pragma unroll
    for (int i = 0; i < 4; i++) {
        int idx = tid + i * 256;
        o[idx] = (v[i] - mean) * rs * gamma[idx] + beta[idx];
    }
}

// ---------------- RoPE table + apply ----------------
__global__ void rope_table_kernel(float* __restrict__ ct, float* __restrict__ st) {
    int idx = blockIdx.x * blockDim.x + threadIdx.x;
    if (idx >= kS * 16) return;
    int s = idx >> 4, i = idx & 15;
    float inv = (float)(1.0 / pow(10000.0, (double)i / 16.0));
    float f = (float)s * inv;
    ct[idx] = (float)cos((double)f);
    st[idx] = (float)sin((double)f);
}

__global__ void rope_kernel(float* __restrict__ buf, int rows, int rowStride,
                            int T, int posOff, float scaleAll,
                            const float* __restrict__ ct,
                            const float* __restrict__ st) {
    int idx = blockIdx.x * blockDim.x + threadIdx.x;
    if (idx >= rows * kH) return;
    int row = idx / kH, h = idx % kH;
    float* p = buf + (size_t)row * rowStride + h * kDH;
    int pos = posOff + (row % T);
    const float* cr = ct + pos * 16;
    const float* sr = st + pos * 16;
#pragma unroll
    for (int i = 0; i < 16; i++) {
        float c = cr[i], s = sr[i];
        float x1 = p[i], x2 = p[i + 16];
        p[i]      = (x1 * c - x2 * s) * scaleAll;
        p[i + 16] = (x2 * c + x1 * s) * scaleAll;
    }
    if (scaleAll != 1.f) {
#pragma unroll
        for (int i = 32; i < 64; i++) p[i] *= scaleAll;
    }
}

// ---------------- fp32 -> bf16 hi/lo converters (k-pair permuted) ---------
__global__ void cvt_act_kernel(const float* __restrict__ in,
                               __nv_bfloat16* __restrict__ hi,
                               __nv_bfloat16* __restrict__ lo, int n) {
    int w = blockIdx.x * blockDim.x + threadIdx.x;   // 2-element word index
    if (w * 2 >= n) return;
    float2 v = *(const float2*)(in + (size_t)w * 2);
    int pw = permWord(w);
    __nv_bfloat16 h0 = __float2bfloat16(v.x);
    __nv_bfloat16 l0 = __float2bfloat16(v.x - __bfloat162float(h0));
    __nv_bfloat16 h1 = __float2bfloat16(v.y);
    __nv_bfloat16 l1 = __float2bfloat16(v.y - __bfloat162float(h1));
    __nv_bfloat162 hp; hp.x = h0; hp.y = h1;
    __nv_bfloat162 lp; lp.x = l0; lp.y = l1;
    ((__nv_bfloat162*)hi)[pw] = hp;
    ((__nv_bfloat162*)lo)[pw] = lp;
}

// transpose + convert weights: W[K,N] fp32 -> Wt_hi/lo[Npad,K] bf16,
// k-pair permuted, zero padded.
__global__ void cvt_wt_kernel(const float* __restrict__ W,
                              __nv_bfloat16* __restrict__ whi,
                              __nv_bfloat16* __restrict__ wlo,
                              int K, int N, int Npad) {
    __shared__ float t[32][33];
    int k0 = blockIdx.x * 32, n0 = blockIdx.y * 32;
    int tx = threadIdx.x, ty = threadIdx.y;   // 32 x 8
#pragma unroll
    for (int j = 0; j < 4; j++) {
        int k = k0 + ty + 8 * j;
        float v = (n0 + tx < N) ? W[(size_t)k * N + n0 + tx] : 0.f;
        t[ty + 8 * j][tx] = v;
    }
    __syncthreads();
#pragma unroll
    for (int j = 0; j < 4; j++) {
        int n = n0 + ty + 8 * j;
        int k = k0 + tx;
        float x = t[tx][ty + 8 * j];
        __nv_bfloat16 h = __float2bfloat16(x);
        __nv_bfloat16 l = __float2bfloat16(x - __bfloat162float(h));
        int pk = permWord(k >> 1) * 2 + (k & 1);
        whi[(size_t)n * K + pk] = h;
        wlo[(size_t)n * K + pk] = l;
    }
}

// ---------------- bf16 tensor-core GEMM (3-term split) --------------------
// C[M,N] = A[M,K] @ W^T, W stored [Npad][K] bf16 hi/lo (k-pair permuted),
// A stored [M][K] hi/lo (k-pair permuted).
// CTA tile 128x128, BK=32, 256 threads = 8 warps (2M x 4N), warp tile 64x32.
// 3-stage cp.async ring; fragment loads are LDS.64, conflict-free at
// row stride 24 words.
__global__ __launch_bounds__(256, 1) void hgemm_kernel(
    const __nv_bfloat16* __restrict__ Ahi, const __nv_bfloat16* __restrict__ Alo,
    const __nv_bfloat16* __restrict__ Bhi, const __nv_bfloat16* __restrict__ Blo,
    float* __restrict__ C, int M, int N, int K,
    const float* __restrict__ bias, const float* __restrict__ res, int act) {
    extern __shared__ uint32_t sm[];
    const int tid  = threadIdx.x;
    const int lane = tid & 31;
    const int warp = tid >> 5;
    const int warpM = warp >> 2;          // 0..1
    const int warpN = warp & 3;           // 0..3
    const int gid = lane >> 2;            // 0..7
    const int tig = lane & 3;             // 0..3
    const int m0 = blockIdx.y * 128, n0 = blockIdx.x * 128;

    float acc[4][4][4] = {};

    // ---- async staging: 2048 x 16B chunks per stage, 8 per thread ----
    auto issue = [&](int stage, int kt) {
        const uint32_t base = stage * kStageWords;
#pragma unroll
        for (int i = 0; i < 8; i++) {
            int c = tid + i * 256;
            int t = c >> 9, w = c & 511;
            int row = w >> 2, ck = w & 3;
            const __nv_bfloat16* src;
            if (t == 0)      src = Ahi + (size_t)(m0 + row) * K + kt + ck * 8;
            else if (t == 1) src = Alo + (size_t)(m0 + row) * K + kt + ck * 8;
            else if (t == 2) src = Bhi + (size_t)(n0 + row) * K + kt + ck * 8;
            else             src = Blo + (size_t)(n0 + row) * K + kt + ck * 8;
            uint32_t dst = (uint32_t)__cvta_generic_to_shared(
                &sm[base + t * kArrWords + row * kRowWords + ck * 4]);
            CP_ASYNC16(dst, src);
        }
    };

    auto compute = [&](int buf) {
        const uint32_t* SAh = sm + buf * kStageWords;
        const uint32_t* SAl = SAh + kArrWords;
        const uint32_t* SBh = SAl + kArrWords;
        const uint32_t* SBl = SBh + kArrWords;
#pragma unroll
        for (int ks = 0; ks < 2; ks++) {
            const int kwb = ks * 8 + 2 * tig;
            uint2 bh[4], bl[4];
#pragma unroll
            for (int in = 0; in < 4; in++) {
                const int n = warpN * 32 + in * 8 + gid;
                bh[in] = *(const uint2*)&SBh[n * kRowWords + kwb];
                bl[in] = *(const uint2*)&SBl[n * kRowWords + kwb];
            }
#pragma unroll
            for (int im = 0; im < 4; im++) {
                const int r = warpM * 64 + im * 16 + gid;
                uint2 uh = *(const uint2*)&SAh[r * kRowWords + kwb];
                uint2 vh = *(const uint2*)&SAh[(r + 8) * kRowWords + kwb];
                uint2 ul = *(const uint2*)&SAl[r * kRowWords + kwb];
                uint2 vl = *(const uint2*)&SAl[(r + 8) * kRowWords + kwb];
                uint32_t ahi[4] = {uh.x, vh.x, uh.y, vh.y};
                uint32_t alo[4] = {ul.x, vl.x, ul.y, vl.y};
#pragma unroll
                for (int in = 0; in < 4; in++) {
                    uint32_t bhw[2] = {bh[in].x, bh[in].y};
                    uint32_t blw[2] = {bl[in].x, bl[in].y};
                    MMA_BF16(acc[im][in], ahi, bhw);
                    MMA_BF16(acc[im][in], ahi, blw);
                    MMA_BF16(acc[im][in], alo, bhw);
                }
            }
        }
    };

    const int nStages = K >> 5;   // K is 1024 or 4096
    issue(0, 0);
    CP_COMMIT();
    issue(1, 32);
    CP_COMMIT();
    for (int s = 0; s < nStages; s++) {
        CP_WAIT1();               // stage s resident; s+1 may be in flight
        __syncthreads();          // all warps done reading buffer (s+2)%3
        if (s + 2 < nStages) issue((s + 2) % 3, (s + 2) * 32);
        CP_COMMIT();
        compute(s % 3);
    }

    // ---- epilogue ----
#pragma unroll
    for (int im = 0; im < 4; im++) {
        const int row = m0 + warpM * 64 + im * 16 + gid;
#pragma unroll
        for (int in = 0; in < 4; in++) {
            const int col = n0 + warpN * 32 + in * 8 + 2 * tig;
            if (col >= N) continue;
#pragma unroll
            for (int half = 0; half < 2; half++) {
                const int rr = row + half * 8;
                float c0 = acc[im][in][half * 2 + 0];
                float c1 = acc[im][in][half * 2 + 1];
                if (bias) { c0 += bias[col]; c1 += bias[col + 1]; }
                if (act) {
                    c0 = 0.5f * c0 * (1.f + erff(c0 * 0.70710678118654752f));
                    c1 = 0.5f * c1 * (1.f + erff(c1 * 0.70710678118654752f));
                }
                if (res) {
                    const float2 rv = *(const float2*)(res + (size_t)rr * N + col);
                    c0 += rv.x; c1 += rv.y;
                }
                *(float2*)(C + (size_t)rr * N + col) = make_float2(c0, c1);
            }
        }
    }
}

// ---------------- flash attention (fp32, online softmax) ------------------
__global__ __launch_bounds__(256) void attn_kernel(
    const float* __restrict__ qb, const float* __restrict__ kb,
    const float* __restrict__ vb, float* __restrict__ ob,
    int Tq, int Tk, int qStride, int kvStride, int diag) {
    constexpr int QLD = 65, KLD = 65, VLD = 65, SLD = 33;
    __shared__ float Qs[64 * QLD];
    __shared__ float Ks[32 * KLD];
    __shared__ float Vs[32 * VLD];
    __shared__ float Ss[64 * SLD];
    __shared__ float mrow[64], lrow[64], frow[64];

    const int tid = threadIdx.x;
    const int b = blockIdx.z, h = blockIdx.y, q0 = blockIdx.x * 64;
    const int lane = tid & 31, warp = tid >> 5;
    const int txa = tid & 7,  tya = tid >> 3;
    const int txc = tid & 15, tyc = tid >> 4;

    const float* qg = qb + ((size_t)b * Tq + q0) * qStride + h * kDH;
#pragma unroll
    for (int i = 0; i < 16; i++) {
        int e = tid + i * 256;
        int r = e >> 6, c = e & 63;
        Qs[r * QLD + c] = qg[(size_t)r * qStride + c];
    }
    if (tid < 64) { mrow[tid] = -1e30f; lrow[tid] = 0.f; }
    float o[4][4] = {};

    int jmax = q0 + 63 + diag;
    int nkt = (jmax + 32) >> 5;
    int maxkt = Tk >> 5;
    if (nkt > maxkt) nkt = maxkt;
    __syncthreads();

    for (int kt = 0; kt < nkt; kt++) {
        const int k0 = kt * 32;
        const float* kg = kb + ((size_t)b * Tk + k0) * kvStride + h * kDH;
        const float* vg = vb + ((size_t)b * Tk + k0) * kvStride + h * kDH;
#pragma unroll
        for (int i = 0; i < 8; i++) {
            int e = tid + i * 256;
            int r = e >> 6, c = e & 63;
            Ks[r * KLD + c] = kg[(size_t)r * kvStride + c];
            Vs[r * VLD + c] = vg[(size_t)r * kvStride + c];
        }
        __syncthreads();

        float sreg[2][4] = {};
#pragma unroll
        for (int kk = 0; kk < 64; kk++) {
            float a0 = Qs[(2 * tya + 0) * QLD + kk];
            float a1 = Qs[(2 * tya + 1) * QLD + kk];
            float bb0 = Ks[(4 * txa + 0) * KLD + kk];
            float bb1 = Ks[(4 * txa + 1) * KLD + kk];
            float bb2 = Ks[(4 * txa + 2) * KLD + kk];
            float bb3 = Ks[(4 * txa + 3) * KLD + kk];
            sreg[0][0] += a0 * bb0; sreg[0][1] += a0 * bb1;
            sreg[0][2] += a0 * bb2; sreg[0][3] += a0 * bb3;
            sreg[1][0] += a1 * bb0; sreg[1][1] += a1 * bb1;
            sreg[1][2] += a1 * bb2; sreg[1][3] += a1 * bb3;
        }
#pragma unroll
        for (int i = 0; i < 2; i++) {
            int qi = q0 + 2 * tya + i;
#pragma unroll
            for (int j = 0; j < 4; j++) {
                int kj = k0 + 4 * txa + j;
                float v = sreg[i][j];
                bool bad = (kj > qi + diag);
                Ss[(2 * tya + i) * SLD + (4 * txa + j)] = bad ? -1e30f : v;
            }
        }
        __syncthreads();

        for (int rr = 0; rr < 8; rr++) {
            int row = warp * 8 + rr;
            float v = Ss[row * SLD + lane];
            float mx = v;
#pragma unroll
            for (int off = 16; off; off >>= 1)
                mx = fmaxf(mx, __shfl_xor_sync(0xffffffffu, mx, off));
            float mold = mrow[row];
            float mnew = fmaxf(mold, mx);
            float p = __expf(v - mnew);
            Ss[row * SLD + lane] = p;
            float sum = p;
#pragma unroll
            for (int off = 16; off; off >>= 1)
                sum += __shfl_xor_sync(0xffffffffu, sum, off);
            if (lane == 0) {
                float f = __expf(mold - mnew);
                frow[row] = f;
                lrow[row] = lrow[row] * f + sum;
                mrow[row] = mnew;
            }
        }
        __syncthreads();

#pragma unroll
        for (int i = 0; i < 4; i++) {
            float f = frow[4 * tyc + i];
#pragma unroll
            for (int j = 0; j < 4; j++) o[i][j] *= f;
        }
#pragma unroll
        for (int kk = 0; kk < 32; kk++) {
            float p0 = Ss[(4 * tyc + 0) * SLD + kk];
            float p1 = Ss[(4 * tyc + 1) * SLD + kk];
            float p2 = Ss[(4 * tyc + 2) * SLD + kk];
            float p3 = Ss[(4 * tyc + 3) * SLD + kk];
            float v0 = Vs[kk * VLD + 4 * txc + 0];
            float v1 = Vs[kk * VLD + 4 * txc + 1];
            float v2 = Vs[kk * VLD + 4 * txc + 2];
            float v3 = Vs[kk * VLD + 4 * txc + 3];
            o[0][0] += p0 * v0; o[0][1] += p0 * v1; o[0][2] += p0 * v2; o[0][3] += p0 * v3;
            o[1][0] += p1 * v0; o[1][1] += p1 * v1; o[1][2] += p1 * v2; o[1][3] += p1 * v3;
            o[2][0] += p2 * v0; o[2][1] += p2 * v1; o[2][2] += p2 * v2; o[2][3] += p2 * v3;
            o[3][0] += p3 * v0; o[3][1] += p3 * v1; o[3][2] += p3 * v2; o[3][3] += p3 * v3;
        }
        __syncthreads();
    }

#pragma unroll
    for (int i = 0; i < 4; i++) {
        int row = q0 + 4 * tyc + i;
        float inv = 1.f / lrow[4 * tyc + i];
        float4 w = make_float4(o[i][0] * inv, o[i][1] * inv,
                               o[i][2] * inv, o[i][3] * inv);
        *(float4*)(ob + ((size_t)b * Tq + row) * kID + h * kDH + 4 * txc) = w;
    }
}

// ---------------- host orchestration ----------------
namespace {
__nv_bfloat16 *h_whi, *h_wlo, *h_ahi, *h_alo;

inline void cvtA(const float* A, size_t n) {
    cvt_act_kernel<<<(int)((n / 2 + 255) / 256), 256>>>(A, h_ahi, h_alo, (int)n);
}

inline void gemm(size_t aOff, size_t wOff, float* C, int M, int N, int Npad,
                 int K, const float* bias, const float* res, int act) {
    dim3 g(Npad / 128, M / 128);
    hgemm_kernel<<<g, 256, kGemmSmem>>>(
        h_ahi + aOff * (size_t)K, h_alo + aOff * (size_t)K,
        h_whi + wOff, h_wlo + wOff, C, M, N, K, bias, res, act);
}
}

extern "C" void kernel_launch(void* const* d_in, const int* in_sizes, int n_in,
                              void* d_out, int out_size) {
    const int*   x           = (const int*)d_in[0];
    // d_in[1] = prefix_mask: all-True and padded True => no-op; unused.
    const float* token_emb   = (const float*)d_in[2];
    const float* pos_emb     = (const float*)d_in[3];
    const float* ca_norm_s   = (const float*)d_in[4];
    const float* ca_norm_b   = (const float*)d_in[5];
    const float* ca_ctx_ns   = (const float*)d_in[6];
    const float* ca_ctx_nb   = (const float*)d_in[7];
    const float* ca_wq       = (const float*)d_in[8];
    const float* ca_wkv      = (const float*)d_in[9];
    const float* ca_wo       = (const float*)d_in[10];
    const float* ca_bo       = (const float*)d_in[11];
    const float* ca_ff_ln_s  = (const float*)d_in[12];
    const float* ca_ff_ln_b  = (const float*)d_in[13];
    const float* ca_ff_w1    = (const float*)d_in[14];
    const float* ca_ff_w2    = (const float*)d_in[15];
    const float* l_norm_s    = (const float*)d_in[16];
    const float* l_norm_b    = (const float*)d_in[17];
    const float* l_wqkv      = (const float*)d_in[18];
    const float* l_wo        = (const float*)d_in[19];
    const float* l_ff_ln_s   = (const float*)d_in[20];
    const float* l_ff_ln_b   = (const float*)d_in[21];
    const float* l_ff_w1     = (const float*)d_in[22];
    const float* l_ff_w2     = (const float*)d_in[23];
    const float* w_logits    = (const float*)d_in[24];
    float* out = (float*)d_out;

    float *prefix, *lat, *xn, *cn, *qb, *kv, *qkv, *att, *ff, *tmp, *ctab, *stab;
    cudaGetSymbolAddress((void**)&prefix, g_prefix);
    cudaGetSymbolAddress((void**)&lat,    g_lat);
    cudaGetSymbolAddress((void**)&xn,     g_xn);
    cudaGetSymbolAddress((void**)&cn,     g_cn);
    cudaGetSymbolAddress((void**)&qb,     g_q);
    cudaGetSymbolAddress((void**)&kv,     g_kv);
    cudaGetSymbolAddress((void**)&qkv,    g_qkv);
    cudaGetSymbolAddress((void**)&att,    g_attn);
    cudaGetSymbolAddress((void**)&ff,     g_ff);
    cudaGetSymbolAddress((void**)&tmp,    g_tmp);
    cudaGetSymbolAddress((void**)&ctab,   g_cos);
    cudaGetSymbolAddress((void**)&stab,   g_sin);
    cudaGetSymbolAddress((void**)&h_whi,  g_whi);
    cudaGetSymbolAddress((void**)&h_wlo,  g_wlo);
    cudaGetSymbolAddress((void**)&h_ahi,  g_ahi);
    cudaGetSymbolAddress((void**)&h_alo,  g_alo);

    cudaFuncSetAttribute(hgemm_kernel,
                         cudaFuncAttributeMaxDynamicSharedMemorySize, kGemmSmem);

    // 0. convert + transpose all weights into bf16 hi/lo arenas
    auto cw = [&](const float* W, size_t off, int K, int N, int Npad) {
        dim3 g(K / 32, Npad / 32);
        cvt_wt_kernel<<<g, dim3(32, 8)>>>(W, h_whi + off, h_wlo + off, K, N, Npad);
    };
    cw(ca_wq,    OFF_CAWQ,  1024, 1024, 1024);
    cw(ca_wkv,   OFF_CAWKV, 1024, 2048, 2048);
    cw(ca_wo,    OFF_CAWO,  1024, 1024, 1024);
    cw(ca_ff_w1, OFF_CAFF1, 1024, 4096, 4096);
    cw(ca_ff_w2, OFF_CAFF2, 4096, 1024, 1024);
    for (int li = 0; li < kL; li++) {
        cw(l_wqkv  + (size_t)li * 1024 * 3072, OFF_LQKV + (size_t)li * 3072 * 1024, 1024, 3072, 3072);
        cw(l_wo    + (size_t)li * 1024 * 1024, OFF_LWO  + (size_t)li * 1024 * 1024, 1024, 1024, 1024);
        cw(l_ff_w1 + (size_t)li * 1024 * 4096, OFF_LFF1 + (size_t)li * 4096 * 1024, 1024, 4096, 4096);
        cw(l_ff_w2 + (size_t)li * 4096 * 1024, OFF_LFF2 + (size_t)li * 1024 * 4096, 4096, 1024, 1024);
    }
    cw(w_logits, OFF_LOGITS, 1024, kV, kVp);

    // 1. embeddings + rope tables
    embed_kernel<<<kB * kS, 256>>>(x, token_emb, pos_emb, prefix, lat);
    rope_table_kernel<<<(kS * 16 + 255) / 256, 256>>>(ctab, stab);

    // 2. cross-attention block
    ln_kernel<<<kB * kNL, 256>>>(lat,    ca_norm_s,  ca_norm_b,  xn);
    ln_kernel<<<kB * kP,  256>>>(prefix, ca_ctx_ns,  ca_ctx_nb,  cn);

    cvtA(cn, (size_t)kB * kP * kD);
    for (int b = 0; b < kB; b++)
        gemm((size_t)b * kP, OFF_CAWKV, kv + (size_t)b * kS * 2 * kID,
             kP, 2 * kID, 2 * kID, kD, nullptr, nullptr, 0);

    cvtA(xn, (size_t)kB * kNL * kD);
    gemm(0, OFF_CAWQ, qb, kB * kNL, kID, kID, kD, nullptr, nullptr, 0);
    for (int b = 0; b < kB; b++)
        gemm((size_t)b * kNL, OFF_CAWKV, kv + ((size_t)b * kS + kP) * 2 * kID,
             kNL, 2 * kID, 2 * kID, kD, nullptr, nullptr, 0);

    {
        int rq = kB * kNL * kH, rk = kB * kS * kH;
        rope_kernel<<<(rq + 255) / 256, 256>>>(qb, kB * kNL, kID, kNL, kP, kScale, ctab, stab);
        rope_kernel<<<(rk + 255) / 256, 256>>>(kv, kB * kS, 2 * kID, kS, 0, 1.f, ctab, stab);
    }
    attn_kernel<<<dim3(kNL / 64, kH, kB), 256>>>(qb, kv, kv + kID, att,
                                                 kNL, kS, kID, 2 * kID, kP);

    cvtA(att, (size_t)kB * kNL * kID);
    gemm(0, OFF_CAWO, lat, kB * kNL, kD, kD, kID, ca_bo, lat, 0);

    ln_kernel<<<kB * kNL, 256>>>(lat, ca_ff_ln_s, ca_ff_ln_b, tmp);
    cvtA(tmp, (size_t)kB * kNL * kD);
    gemm(0, OFF_CAFF1, ff, kB * kNL, kFF, kFF, kD, nullptr, nullptr, 1);
    cvtA(ff, (size_t)kB * kNL * kFF);
    gemm(0, OFF_CAFF2, lat, kB * kNL, kD, kD, kFF, nullptr, lat, 0);

    // 3. latent self-attention layers
    for (int li = 0; li < kL; li++) {
        ln_kernel<<<kB * kNL, 256>>>(lat, l_norm_s + li * kD, l_norm_b + li * kD, xn);
        cvtA(xn, (size_t)kB * kNL * kD);
        gemm(0, OFF_LQKV + (size_t)li * 3072 * 1024, qkv,
             kB * kNL, 3 * kID, 3 * kID, kD, nullptr, nullptr, 0);

        int rq = kB * kNL * kH;
        rope_kernel<<<(rq + 255) / 256, 256>>>(qkv,       kB * kNL, 3 * kID, kNL, kP, kScale, ctab, stab);
        rope_kernel<<<(rq + 255) / 256, 256>>>(qkv + kID, kB * kNL, 3 * kID, kNL, kP, 1.f,    ctab, stab);
        attn_kernel<<<dim3(kNL / 64, kH, kB), 256>>>(qkv, qkv + kID, qkv + 2 * kID, att,
                                                     kNL, kNL, 3 * kID, 3 * kID, 0);

        cvtA(att, (size_t)kB * kNL * kID);
        gemm(0, OFF_LWO + (size_t)li * 1024 * 1024, lat,
             kB * kNL, kD, kD, kID, nullptr, lat, 0);

        ln_kernel<<<kB * kNL, 256>>>(lat, l_ff_ln_s + li * kD, l_ff_ln_b + li * kD, tmp);
        cvtA(tmp, (size_t)kB * kNL * kD);
        gemm(0, OFF_LFF1 + (size_t)li * 4096 * 1024, ff,
             kB * kNL, kFF, kFF, kD, nullptr, nullptr, 1);
        cvtA(ff, (size_t)kB * kNL * kFF);
        gemm(0, OFF_LFF2 + (size_t)li * 1024 * 4096, lat,
             kB * kNL, kD, kD, kFF, nullptr, lat, 0);
    }

    // 4. logits head
    cvtA(lat, (size_t)kB * kNL * kD);
    gemm(0, OFF_LOGITS, out, kB * kNL, kV, kVp, kD, nullptr, nullptr, 0);
}

// round 7
// speedup vs baseline: 2.0152x; 1.0734x over previous
#include <cuda_runtime.h>
#include <cuda_bf16.h>
#include <math.h>
#include <stdint.h>

// ---------------- problem constants ----------------
namespace {
constexpr int kB  = 2;
constexpr int kS  = 2048;
constexpr int kP  = 512;
constexpr int kNL = 1536;   // latent tokens = S - P
constexpr int kD  = 1024;
constexpr int kH  = 16;
constexpr int kDH = 64;
constexpr int kID = 1024;   // H * DH
constexpr int kV  = 20000;
constexpr int kVp = 20096;  // padded to 128
constexpr int kL  = 4;
constexpr int kFF = 4096;
constexpr float kScale = 0.125f;   // DH^-0.5
constexpr float kEps   = 1e-5f;

// weight arena offsets (transposed [N][K] layout, elements)
constexpr size_t OFF_CAWQ   = 0;                                  // 1024x1024
constexpr size_t OFF_CAWKV  = OFF_CAWQ  + 1024ull * 1024;         // 2048x1024
constexpr size_t OFF_CAWO   = OFF_CAWKV + 2048ull * 1024;         // 1024x1024
constexpr size_t OFF_CAFF1  = OFF_CAWO  + 1024ull * 1024;         // 4096x1024
constexpr size_t OFF_CAFF2  = OFF_CAFF1 + 4096ull * 1024;         // 1024x4096
constexpr size_t OFF_LQKV   = OFF_CAFF2 + 1024ull * 4096;         // 4 x 3072x1024
constexpr size_t OFF_LWO    = OFF_LQKV  + 4ull * 3072 * 1024;     // 4 x 1024x1024
constexpr size_t OFF_LFF1   = OFF_LWO   + 4ull * 1024 * 1024;     // 4 x 4096x1024
constexpr size_t OFF_LFF2   = OFF_LFF1  + 4ull * 4096 * 1024;     // 4 x 1024x4096
constexpr size_t OFF_LOGITS = OFF_LFF2  + 4ull * 1024 * 4096;     // 20096x1024
constexpr size_t W_TOTAL    = OFF_LOGITS + (size_t)kVp * 1024;

// activation arena regions (elements)
constexpr size_t A0   = 0;                                // xn/tmp/att/lat-cvt
constexpr size_t AFF  = (size_t)kB * kNL * kD;            // GELU(ff1) output
constexpr size_t ACN  = AFF + (size_t)kB * kNL * kFF;     // cn (prefix LN)
constexpr size_t A_TOTAL = ACN + (size_t)kB * kP * kD;

// hgemm smem: 2 stages x 4 arrays x 128 rows x 24 uint32 words
constexpr int kRowWords   = 24;                      // 16 data + 8 pad
constexpr int kArrWords   = 128 * kRowWords;         // 3072
constexpr int kStageWords = 4 * kArrWords;           // 12288
constexpr int kGemmSmem   = 2 * kStageWords * 4;     // 98304 bytes
}

// ---------------- scratch (module-load allocated, legal) ----------------
__device__ float g_prefix[kB * kP * kD];
__device__ float g_lat   [kB * kNL * kD];
__device__ float g_q     [kB * kNL * kID];
__device__ float g_kv    [kB * kS * 2 * kID];
__device__ float g_qkv   [kB * kNL * 3 * kID];
__device__ float g_cos   [kS * 16];
__device__ float g_sin   [kS * 16];
__device__ __nv_bfloat16 g_whi[W_TOTAL];
__device__ __nv_bfloat16 g_wlo[W_TOTAL];
__device__ __nv_bfloat16 g_ahi[A_TOTAL];
__device__ __nv_bfloat16 g_alo[A_TOTAL];

// ---------------- low-level helpers ----------------
__device__ __forceinline__ float warpSum(float v) {
#pragma unroll
    for (int o = 16; o; o >>= 1) v += __shfl_xor_sync(0xffffffffu, v, o);
    return v;
}

// k-pair permutation: within each 8-word group, word w8 -> (w8&3)*2 + (w8>>2)
__device__ __forceinline__ int permWord(int w) {
    int w8 = w & 7;
    return (w & ~7) + ((w8 & 3) << 1) + (w8 >> 2);
}

__device__ __forceinline__ void split2(float a, float b,
                                       __nv_bfloat162& h, __nv_bfloat162& l) {
    __nv_bfloat16 h0 = __float2bfloat16(a);
    __nv_bfloat16 h1 = __float2bfloat16(b);
    h.x = h0; h.y = h1;
    l.x = __float2bfloat16(a - __bfloat162float(h0));
    l.y = __float2bfloat16(b - __bfloat162float(h1));
}

#define MMA_BF16(c, a, b)                                                   \
    asm volatile(                                                           \
        "mma.sync.aligned.m16n8k16.row.col.f32.bf16.bf16.f32 "              \
        "{%0,%1,%2,%3}, {%4,%5,%6,%7}, {%8,%9}, {%0,%1,%2,%3};"             \
        : "+f"((c)[0]), "+f"((c)[1]), "+f"((c)[2]), "+f"((c)[3])            \
        : "r"((a)[0]), "r"((a)[1]), "r"((a)[2]), "r"((a)[3]),               \
          "r"((b)[0]), "r"((b)[1]))

#define CP_ASYNC16(dst, src)                                                \
    asm volatile("cp.async.cg.shared.global [%0], [%1], 16;"                \
                 :: "r"(dst), "l"(src))
#define CP_COMMIT() asm volatile("cp.async.commit_group;")
#define CP_WAIT0()  asm volatile("cp.async.wait_group 0;")

// ---------------- embedding ----------------
__global__ void embed_kernel(const int* __restrict__ x,
                             const float* __restrict__ te,
                             const float* __restrict__ pe,
                             float* __restrict__ prefix,
                             float* __restrict__ lat) {
    int row = blockIdx.x;
    int b = row / kS, s = row % kS;
    int tok = x[row];
    const float* tr = te + (size_t)tok * kD;
    const float* pr = pe + (size_t)s * kD;
    float* dst = (s < kP) ? (prefix + ((size_t)b * kP + s) * kD)
                          : (lat    + ((size_t)b * kNL + (s - kP)) * kD);
    for (int i = threadIdx.x; i < kD; i += blockDim.x) dst[i] = tr[i] + pr[i];
}

// ---------------- LayerNorm -> split bf16 (permuted) ----------------
__global__ __launch_bounds__(256) void ln_bf16_kernel(
    const float* __restrict__ in, const float* __restrict__ gamma,
    const float* __restrict__ beta,
    __nv_bfloat16* __restrict__ hi, __nv_bfloat16* __restrict__ lo) {
    int r = blockIdx.x;
    const float* xr = in + (size_t)r * kD;
    int tid = threadIdx.x;
    float4 v4 = *(const float4*)(xr + 4 * tid);
    float v[4] = {v4.x, v4.y, v4.z, v4.w};
    float s = v[0] + v[1] + v[2] + v[3];
    __shared__ float red[8];
    __shared__ float meanS, rstdS;
    s = warpSum(s);
    if ((tid & 31) == 0) red[tid >> 5] = s;
    __syncthreads();
    if (tid < 32) {
        float t = (tid < 8) ? red[tid] : 0.f;
        t = warpSum(t);
        if (tid == 0) meanS = t * (1.f / kD);
    }
    __syncthreads();
    float mean = meanS;
    float s2 = 0.f;
#pragma unroll
    for (int i = 0; i < 4; i++) { float d = v[i] - mean; s2 += d * d; }
    s2 = warpSum(s2);
    __syncthreads();
    if ((tid & 31) == 0) red[tid >> 5] = s2;
    __syncthreads();
    if (tid < 32) {
        float t = (tid < 8) ? red[tid] : 0.f;
        t = warpSum(t);
        if (tid == 0) rstdS = rsqrtf(t * (1.f / kD) + kEps);
    }
    __syncthreads();
    float rs = rstdS;
    float4 g4 = *(const float4*)(gamma + 4 * tid);
    float4 b4 = *(const float4*)(beta + 4 * tid);
    float y0 = (v[0] - mean) * rs * g4.x + b4.x;
    float y1 = (v[1] - mean) * rs * g4.y + b4.y;
    float y2 = (v[2] - mean) * rs * g4.z + b4.z;
    float y3 = (v[3] - mean) * rs * g4.w + b4.w;
    __nv_bfloat162 h0, l0, h1, l1;
    split2(y0, y1, h0, l0);
    split2(y2, y3, h1, l1);
    size_t rowW = (size_t)r * (kD / 2);
    int w0 = 2 * tid;
    ((__nv_bfloat162*)hi)[rowW + permWord(w0)]     = h0;
    ((__nv_bfloat162*)hi)[rowW + permWord(w0 + 1)] = h1;
    ((__nv_bfloat162*)lo)[rowW + permWord(w0)]     = l0;
    ((__nv_bfloat162*)lo)[rowW + permWord(w0 + 1)] = l1;
}

// ---------------- RoPE table + apply ----------------
__global__ void rope_table_kernel(float* __restrict__ ct, float* __restrict__ st) {
    int idx = blockIdx.x * blockDim.x + threadIdx.x;
    if (idx >= kS * 16) return;
    int s = idx >> 4, i = idx & 15;
    float inv = (float)(1.0 / pow(10000.0, (double)i / 16.0));
    float f = (float)s * inv;
    ct[idx] = (float)cos((double)f);
    st[idx] = (float)sin((double)f);
}

__global__ void rope_kernel(float* __restrict__ buf, int rows, int rowStride,
                            int T, int posOff, float scaleAll,
                            const float* __restrict__ ct,
                            const float* __restrict__ st) {
    int idx = blockIdx.x * blockDim.x + threadIdx.x;
    if (idx >= rows * kH) return;
    int row = idx / kH, h = idx % kH;
    float* p = buf + (size_t)row * rowStride + h * kDH;
    int pos = posOff + (row % T);
    const float* cr = ct + pos * 16;
    const float* sr = st + pos * 16;
#pragma unroll
    for (int i = 0; i < 16; i++) {
        float c = cr[i], s = sr[i];
        float x1 = p[i], x2 = p[i + 16];
        p[i]      = (x1 * c - x2 * s) * scaleAll;
        p[i + 16] = (x2 * c + x1 * s) * scaleAll;
    }
    if (scaleAll != 1.f) {
#pragma unroll
        for (int i = 32; i < 64; i++) p[i] *= scaleAll;
    }
}

// ---------------- fp32 -> bf16 hi/lo converter (k-pair permuted) ----------
__global__ void cvt_act_kernel(const float* __restrict__ in,
                               __nv_bfloat16* __restrict__ hi,
                               __nv_bfloat16* __restrict__ lo, int n) {
    int w = blockIdx.x * blockDim.x + threadIdx.x;
    if (w * 2 >= n) return;
    float2 v = *(const float2*)(in + (size_t)w * 2);
    __nv_bfloat162 h, l;
    split2(v.x, v.y, h, l);
    int pw = permWord(w);
    ((__nv_bfloat162*)hi)[pw] = h;
    ((__nv_bfloat162*)lo)[pw] = l;
}

// transpose + convert weights: W[K,N] fp32 -> Wt_hi/lo[Npad,K] bf16,
// k-pair permuted, zero padded.
__global__ void cvt_wt_kernel(const float* __restrict__ W,
                              __nv_bfloat16* __restrict__ whi,
                              __nv_bfloat16* __restrict__ wlo,
                              int K, int N, int Npad) {
    __shared__ float t[32][33];
    int k0 = blockIdx.x * 32, n0 = blockIdx.y * 32;
    int tx = threadIdx.x, ty = threadIdx.y;   // 32 x 8
#pragma unroll
    for (int j = 0; j < 4; j++) {
        int k = k0 + ty + 8 * j;
        float v = (n0 + tx < N) ? W[(size_t)k * N + n0 + tx] : 0.f;
        t[ty + 8 * j][tx] = v;
    }
    __syncthreads();
#pragma unroll
    for (int j = 0; j < 4; j++) {
        int n = n0 + ty + 8 * j;
        int k = k0 + tx;
        float x = t[tx][ty + 8 * j];
        __nv_bfloat16 h = __float2bfloat16(x);
        __nv_bfloat16 l = __float2bfloat16(x - __bfloat162float(h));
        int pk = permWord(k >> 1) * 2 + (k & 1);
        whi[(size_t)n * K + pk] = h;
        wlo[(size_t)n * K + pk] = l;
    }
}

// ---------------- bf16 tensor-core GEMM (3-term split) --------------------
// C[M,N] = A[M,K] @ W^T. Optional fp32 C and/or split-bf16 (Chi/Clo) output.
// CTA tile 128x128, BK=32, 8 warps (2M x 4N), 2-stage ring, 2 CTAs/SM.
__global__ __launch_bounds__(256, 2) void hgemm_kernel(
    const __nv_bfloat16* __restrict__ Ahi, const __nv_bfloat16* __restrict__ Alo,
    const __nv_bfloat16* __restrict__ Bhi, const __nv_bfloat16* __restrict__ Blo,
    float* __restrict__ C,
    __nv_bfloat16* __restrict__ Chi, __nv_bfloat16* __restrict__ Clo,
    int M, int N, int K,
    const float* __restrict__ bias, const float* __restrict__ res, int act) {
    extern __shared__ uint32_t sm[];
    const int tid  = threadIdx.x;
    const int lane = tid & 31;
    const int warp = tid >> 5;
    const int warpM = warp >> 2;
    const int warpN = warp & 3;
    const int gid = lane >> 2;
    const int tig = lane & 3;
    const int m0 = blockIdx.y * 128, n0 = blockIdx.x * 128;

    float acc[4][4][4] = {};

    auto issue = [&](int stage, int kt) {
        const uint32_t base = stage * kStageWords;
#pragma unroll
        for (int i = 0; i < 8; i++) {
            int c = tid + i * 256;
            int t = c >> 9, w = c & 511;
            int row = w >> 2, ck = w & 3;
            const __nv_bfloat16* src;
            if (t == 0)      src = Ahi + (size_t)(m0 + row) * K + kt + ck * 8;
            else if (t == 1) src = Alo + (size_t)(m0 + row) * K + kt + ck * 8;
            else if (t == 2) src = Bhi + (size_t)(n0 + row) * K + kt + ck * 8;
            else             src = Blo + (size_t)(n0 + row) * K + kt + ck * 8;
            uint32_t dst = (uint32_t)__cvta_generic_to_shared(
                &sm[base + t * kArrWords + row * kRowWords + ck * 4]);
            CP_ASYNC16(dst, src);
        }
    };

    auto compute = [&](int buf) {
        const uint32_t* SAh = sm + buf * kStageWords;
        const uint32_t* SAl = SAh + kArrWords;
        const uint32_t* SBh = SAl + kArrWords;
        const uint32_t* SBl = SBh + kArrWords;
#pragma unroll
        for (int ks = 0; ks < 2; ks++) {
            const int kwb = ks * 8 + 2 * tig;
            uint2 bh[4], bl[4];
#pragma unroll
            for (int in = 0; in < 4; in++) {
                const int n = warpN * 32 + in * 8 + gid;
                bh[in] = *(const uint2*)&SBh[n * kRowWords + kwb];
                bl[in] = *(const uint2*)&SBl[n * kRowWords + kwb];
            }
#pragma unroll
            for (int im = 0; im < 4; im++) {
                const int r = warpM * 64 + im * 16 + gid;
                uint2 uh = *(const uint2*)&SAh[r * kRowWords + kwb];
                uint2 vh = *(const uint2*)&SAh[(r + 8) * kRowWords + kwb];
                uint2 ul = *(const uint2*)&SAl[r * kRowWords + kwb];
                uint2 vl = *(const uint2*)&SAl[(r + 8) * kRowWords + kwb];
                uint32_t ahi[4] = {uh.x, vh.x, uh.y, vh.y};
                uint32_t alo[4] = {ul.x, vl.x, ul.y, vl.y};
#pragma unroll
                for (int in = 0; in < 4; in++) {
                    uint32_t bhw[2] = {bh[in].x, bh[in].y};
                    uint32_t blw[2] = {bl[in].x, bl[in].y};
                    MMA_BF16(acc[im][in], ahi, bhw);
                    MMA_BF16(acc[im][in], ahi, blw);
                    MMA_BF16(acc[im][in], alo, bhw);
                }
            }
        }
    };

    const int nStages = K >> 5;
    issue(0, 0);
    CP_COMMIT();
    for (int s = 0; s < nStages; s++) {
        CP_WAIT0();
        __syncthreads();
        if (s + 1 < nStages) { issue((s + 1) & 1, (s + 1) * 32); CP_COMMIT(); }
        compute(s & 1);
    }

    // ---- epilogue ----
#pragma unroll
    for (int im = 0; im < 4; im++) {
        const int row = m0 + warpM * 64 + im * 16 + gid;
#pragma unroll
        for (int in = 0; in < 4; in++) {
            const int col = n0 + warpN * 32 + in * 8 + 2 * tig;
            if (col >= N) continue;
#pragma unroll
            for (int half = 0; half < 2; half++) {
                const int rr = row + half * 8;
                float c0 = acc[im][in][half * 2 + 0];
                float c1 = acc[im][in][half * 2 + 1];
                if (bias) { c0 += bias[col]; c1 += bias[col + 1]; }
                if (act) {
                    c0 = 0.5f * c0 * (1.f + erff(c0 * 0.70710678118654752f));
                    c1 = 0.5f * c1 * (1.f + erff(c1 * 0.70710678118654752f));
                }
                if (res) {
                    const float2 rv = *(const float2*)(res + (size_t)rr * N + col);
                    c0 += rv.x; c1 += rv.y;
                }
                if (C)
                    *(float2*)(C + (size_t)rr * N + col) = make_float2(c0, c1);
                if (Chi) {
                    __nv_bfloat162 h, l;
                    split2(c0, c1, h, l);
                    size_t rowW = (size_t)rr * (N >> 1);
                    int pw = permWord(col >> 1);
                    ((__nv_bfloat162*)Chi)[rowW + pw] = h;
                    ((__nv_bfloat162*)Clo)[rowW + pw] = l;
                }
            }
        }
    }
}

// ---------------- flash attention (fp32), split-bf16 output ---------------
__global__ __launch_bounds__(256) void attn_kernel(
    const float* __restrict__ qb, const float* __restrict__ kb,
    const float* __restrict__ vb,
    __nv_bfloat16* __restrict__ ohi, __nv_bfloat16* __restrict__ olo,
    int Tq, int Tk, int qStride, int kvStride, int diag) {
    constexpr int QLD = 65, KLD = 65, VLD = 65, SLD = 33;
    __shared__ float Qs[64 * QLD];
    __shared__ float Ks[32 * KLD];
    __shared__ float Vs[32 * VLD];
    __shared__ float Ss[64 * SLD];
    __shared__ float mrow[64], lrow[64], frow[64];

    const int tid = threadIdx.x;
    const int b = blockIdx.z, h = blockIdx.y, q0 = blockIdx.x * 64;
    const int lane = tid & 31, warp = tid >> 5;
    const int txa = tid & 7,  tya = tid >> 3;
    const int txc = tid & 15, tyc = tid >> 4;

    const float* qg = qb + ((size_t)b * Tq + q0) * qStride + h * kDH;
#pragma unroll
    for (int i = 0; i < 16; i++) {
        int e = tid + i * 256;
        int r = e >> 6, c = e & 63;
        Qs[r * QLD + c] = qg[(size_t)r * qStride + c];
    }
    if (tid < 64) { mrow[tid] = -1e30f; lrow[tid] = 0.f; }
    float o[4][4] = {};

    int jmax = q0 + 63 + diag;
    int nkt = (jmax + 32) >> 5;
    int maxkt = Tk >> 5;
    if (nkt > maxkt) nkt = maxkt;
    __syncthreads();

    for (int kt = 0; kt < nkt; kt++) {
        const int k0 = kt * 32;
        const float* kg = kb + ((size_t)b * Tk + k0) * kvStride + h * kDH;
        const float* vg = vb + ((size_t)b * Tk + k0) * kvStride + h * kDH;
#pragma unroll
        for (int i = 0; i < 8; i++) {
            int e = tid + i * 256;
            int r = e >> 6, c = e & 63;
            Ks[r * KLD + c] = kg[(size_t)r * kvStride + c];
            Vs[r * VLD + c] = vg[(size_t)r * kvStride + c];
        }
        __syncthreads();

        float sreg[2][4] = {};
#pragma unroll
        for (int kk = 0; kk < 64; kk++) {
            float a0 = Qs[(2 * tya + 0) * QLD + kk];
            float a1 = Qs[(2 * tya + 1) * QLD + kk];
            float bb0 = Ks[(4 * txa + 0) * KLD + kk];
            float bb1 = Ks[(4 * txa + 1) * KLD + kk];
            float bb2 = Ks[(4 * txa + 2) * KLD + kk];
            float bb3 = Ks[(4 * txa + 3) * KLD + kk];
            sreg[0][0] += a0 * bb0; sreg[0][1] += a0 * bb1;
            sreg[0][2] += a0 * bb2; sreg[0][3] += a0 * bb3;
            sreg[1][0] += a1 * bb0; sreg[1][1] += a1 * bb1;
            sreg[1][2] += a1 * bb2; sreg[1][3] += a1 * bb3;
        }
#pragma unroll
        for (int i = 0; i < 2; i++) {
            int qi = q0 + 2 * tya + i;
#pragma unroll
            for (int j = 0; j < 4; j++) {
                int kj = k0 + 4 * txa + j;
                float v = sreg[i][j];
                bool bad = (kj > qi + diag);
                Ss[(2 * tya + i) * SLD + (4 * txa + j)] = bad ? -1e30f : v;
            }
        }
        __syncthreads();

        for (int rr = 0; rr < 8; rr++) {
            int row = warp * 8 + rr;
            float v = Ss[row * SLD + lane];
            float mx = v;
#pragma unroll
            for (int off = 16; off; off >>= 1)
                mx = fmaxf(mx, __shfl_xor_sync(0xffffffffu, mx, off));
            float mold = mrow[row];
            float mnew = fmaxf(mold, mx);
            float p = __expf(v - mnew);
            Ss[row * SLD + lane] = p;
            float sum = p;
#pragma unroll
            for (int off = 16; off; off >>= 1)
                sum += __shfl_xor_sync(0xffffffffu, sum, off);
            if (lane == 0) {
                float f = __expf(mold - mnew);
                frow[row] = f;
                lrow[row] = lrow[row] * f + sum;
                mrow[row] = mnew;
            }
        }
        __syncthreads();

#pragma unroll
        for (int i = 0; i < 4; i++) {
            float f = frow[4 * tyc + i];
#pragma unroll
            for (int j = 0; j < 4; j++) o[i][j] *= f;
        }
#pragma unroll
        for (int kk = 0; kk < 32; kk++) {
            float p0 = Ss[(4 * tyc + 0) * SLD + kk];
            float p1 = Ss[(4 * tyc + 1) * SLD + kk];
            float p2 = Ss[(4 * tyc + 2) * SLD + kk];
            float p3 = Ss[(4 * tyc + 3) * SLD + kk];
            float v0 = Vs[kk * VLD + 4 * txc + 0];
            float v1 = Vs[kk * VLD + 4 * txc + 1];
            float v2 = Vs[kk * VLD + 4 * txc + 2];
            float v3 = Vs[kk * VLD + 4 * txc + 3];
            o[0][0] += p0 * v0; o[0][1] += p0 * v1; o[0][2] += p0 * v2; o[0][3] += p0 * v3;
            o[1][0] += p1 * v0; o[1][1] += p1 * v1; o[1][2] += p1 * v2; o[1][3] += p1 * v3;
            o[2][0] += p2 * v0; o[2][1] += p2 * v1; o[2][2] += p2 * v2; o[2][3] += p2 * v3;
            o[3][0] += p3 * v0; o[3][1] += p3 * v1; o[3][2] += p3 * v2; o[3][3] += p3 * v3;
        }
        __syncthreads();
    }

#pragma unroll
    for (int i = 0; i < 4; i++) {
        int row = q0 + 4 * tyc + i;
        float inv = 1.f / lrow[4 * tyc + i];
        float y0 = o[i][0] * inv, y1 = o[i][1] * inv;
        float y2 = o[i][2] * inv, y3 = o[i][3] * inv;
        __nv_bfloat162 h0, l0, h1, l1;
        split2(y0, y1, h0, l0);
        split2(y2, y3, h1, l1);
        size_t rowW = (size_t)((size_t)b * Tq + row) * (kID / 2);
        int w0 = (h * kDH + 4 * txc) >> 1;
        ((__nv_bfloat162*)ohi)[rowW + permWord(w0)]     = h0;
        ((__nv_bfloat162*)ohi)[rowW + permWord(w0 + 1)] = h1;
        ((__nv_bfloat162*)olo)[rowW + permWord(w0)]     = l0;
        ((__nv_bfloat162*)olo)[rowW + permWord(w0 + 1)] = l1;
    }
}

// ---------------- host orchestration ----------------
namespace {
__nv_bfloat16 *h_whi, *h_wlo, *h_ahi, *h_alo;

inline void gemm(size_t aOff, size_t wOff, float* C,
                 __nv_bfloat16* chi, __nv_bfloat16* clo,
                 int M, int N, int Npad, int K,
                 const float* bias, const float* res, int act) {
    dim3 g(Npad / 128, M / 128);
    hgemm_kernel<<<g, 256, kGemmSmem>>>(
        h_ahi + aOff, h_alo + aOff, h_whi + wOff, h_wlo + wOff,
        C, chi, clo, M, N, K, bias, res, act);
}
}

extern "C" void kernel_launch(void* const* d_in, const int* in_sizes, int n_in,
                              void* d_out, int out_size) {
    const int*   x           = (const int*)d_in[0];
    // d_in[1] = prefix_mask: all-True and padded True => no-op; unused.
    const float* token_emb   = (const float*)d_in[2];
    const float* pos_emb     = (const float*)d_in[3];
    const float* ca_norm_s   = (const float*)d_in[4];
    const float* ca_norm_b   = (const float*)d_in[5];
    const float* ca_ctx_ns   = (const float*)d_in[6];
    const float* ca_ctx_nb   = (const float*)d_in[7];
    const float* ca_wq       = (const float*)d_in[8];
    const float* ca_wkv      = (const float*)d_in[9];
    const float* ca_wo       = (const float*)d_in[10];
    const float* ca_bo       = (const float*)d_in[11];
    const float* ca_ff_ln_s  = (const float*)d_in[12];
    const float* ca_ff_ln_b  = (const float*)d_in[13];
    const float* ca_ff_w1    = (const float*)d_in[14];
    const float* ca_ff_w2    = (const float*)d_in[15];
    const float* l_norm_s    = (const float*)d_in[16];
    const float* l_norm_b    = (const float*)d_in[17];
    const float* l_wqkv      = (const float*)d_in[18];
    const float* l_wo        = (const float*)d_in[19];
    const float* l_ff_ln_s   = (const float*)d_in[20];
    const float* l_ff_ln_b   = (const float*)d_in[21];
    const float* l_ff_w1     = (const float*)d_in[22];
    const float* l_ff_w2     = (const float*)d_in[23];
    const float* w_logits    = (const float*)d_in[24];
    float* out = (float*)d_out;

    float *prefix, *lat, *qb, *kv, *qkv, *ctab, *stab;
    cudaGetSymbolAddress((void**)&prefix, g_prefix);
    cudaGetSymbolAddress((void**)&lat,    g_lat);
    cudaGetSymbolAddress((void**)&qb,     g_q);
    cudaGetSymbolAddress((void**)&kv,     g_kv);
    cudaGetSymbolAddress((void**)&qkv,    g_qkv);
    cudaGetSymbolAddress((void**)&ctab,   g_cos);
    cudaGetSymbolAddress((void**)&stab,   g_sin);
    cudaGetSymbolAddress((void**)&h_whi,  g_whi);
    cudaGetSymbolAddress((void**)&h_wlo,  g_wlo);
    cudaGetSymbolAddress((void**)&h_ahi,  g_ahi);
    cudaGetSymbolAddress((void**)&h_alo,  g_alo);

    cudaFuncSetAttribute(hgemm_kernel,
                         cudaFuncAttributeMaxDynamicSharedMemorySize, kGemmSmem);

    // 0. convert + transpose all weights into bf16 hi/lo arenas
    auto cw = [&](const float* W, size_t off, int K, int N, int Npad) {
        dim3 g(K / 32, Npad / 32);
        cvt_wt_kernel<<<g, dim3(32, 8)>>>(W, h_whi + off, h_wlo + off, K, N, Npad);
    };
    cw(ca_wq,    OFF_CAWQ,  1024, 1024, 1024);
    cw(ca_wkv,   OFF_CAWKV, 1024, 2048, 2048);
    cw(ca_wo,    OFF_CAWO,  1024, 1024, 1024);
    cw(ca_ff_w1, OFF_CAFF1, 1024, 4096, 4096);
    cw(ca_ff_w2, OFF_CAFF2, 4096, 1024, 1024);
    for (int li = 0; li < kL; li++) {
        cw(l_wqkv  + (size_t)li * 1024 * 3072, OFF_LQKV + (size_t)li * 3072 * 1024, 1024, 3072, 3072);
        cw(l_wo    + (size_t)li * 1024 * 1024, OFF_LWO  + (size_t)li * 1024 * 1024, 1024, 1024, 1024);
        cw(l_ff_w1 + (size_t)li * 1024 * 4096, OFF_LFF1 + (size_t)li * 4096 * 1024, 1024, 4096, 4096);
        cw(l_ff_w2 + (size_t)li * 4096 * 1024, OFF_LFF2 + (size_t)li * 1024 * 4096, 4096, 1024, 1024);
    }
    cw(w_logits, OFF_LOGITS, 1024, kV, kVp);

    // 1. embeddings + rope tables
    embed_kernel<<<kB * kS, 256>>>(x, token_emb, pos_emb, prefix, lat);
    rope_table_kernel<<<(kS * 16 + 255) / 256, 256>>>(ctab, stab);

    // 2. cross-attention block
    ln_bf16_kernel<<<kB * kNL, 256>>>(lat,    ca_norm_s, ca_norm_b,
                                      h_ahi + A0,  h_alo + A0);
    ln_bf16_kernel<<<kB * kP,  256>>>(prefix, ca_ctx_ns, ca_ctx_nb,
                                      h_ahi + ACN, h_alo + ACN);

    for (int b = 0; b < kB; b++)
        gemm(ACN + (size_t)b * kP * kD, OFF_CAWKV,
             kv + (size_t)b * kS * 2 * kID, nullptr, nullptr,
             kP, 2 * kID, 2 * kID, kD, nullptr, nullptr, 0);
    gemm(A0, OFF_CAWQ, qb, nullptr, nullptr,
         kB * kNL, kID, kID, kD, nullptr, nullptr, 0);
    for (int b = 0; b < kB; b++)
        gemm(A0 + (size_t)b * kNL * kD, OFF_CAWKV,
             kv + ((size_t)b * kS + kP) * 2 * kID, nullptr, nullptr,
             kNL, 2 * kID, 2 * kID, kD, nullptr, nullptr, 0);

    {
        int rq = kB * kNL * kH, rk = kB * kS * kH;
        rope_kernel<<<(rq + 255) / 256, 256>>>(qb, kB * kNL, kID, kNL, kP, kScale, ctab, stab);
        rope_kernel<<<(rk + 255) / 256, 256>>>(kv, kB * kS, 2 * kID, kS, 0, 1.f, ctab, stab);
    }
    attn_kernel<<<dim3(kNL / 64, kH, kB), 256>>>(qb, kv, kv + kID,
                                                 h_ahi + A0, h_alo + A0,
                                                 kNL, kS, kID, 2 * kID, kP);

    gemm(A0, OFF_CAWO, lat, nullptr, nullptr,
         kB * kNL, kD, kD, kID, ca_bo, lat, 0);

    ln_bf16_kernel<<<kB * kNL, 256>>>(lat, ca_ff_ln_s, ca_ff_ln_b,
                                      h_ahi + A0, h_alo + A0);
    gemm(A0, OFF_CAFF1, nullptr, h_ahi + AFF, h_alo + AFF,
         kB * kNL, kFF, kFF, kD, nullptr, nullptr, 1);
    gemm(AFF, OFF_CAFF2, lat, nullptr, nullptr,
         kB * kNL, kD, kD, kFF, nullptr, lat, 0);

    // 3. latent self-attention layers
    for (int li = 0; li < kL; li++) {
        ln_bf16_kernel<<<kB * kNL, 256>>>(lat, l_norm_s + li * kD,
                                          l_norm_b + li * kD,
                                          h_ahi + A0, h_alo + A0);
        gemm(A0, OFF_LQKV + (size_t)li * 3072 * 1024, qkv, nullptr, nullptr,
             kB * kNL, 3 * kID, 3 * kID, kD, nullptr, nullptr, 0);

        int rq = kB * kNL * kH;
        rope_kernel<<<(rq + 255) / 256, 256>>>(qkv,       kB * kNL, 3 * kID, kNL, kP, kScale, ctab, stab);
        rope_kernel<<<(rq + 255) / 256, 256>>>(qkv + kID, kB * kNL, 3 * kID, kNL, kP, 1.f,    ctab, stab);
        attn_kernel<<<dim3(kNL / 64, kH, kB), 256>>>(qkv, qkv + kID, qkv + 2 * kID,
                                                     h_ahi + A0, h_alo + A0,
                                                     kNL, kNL, 3 * kID, 3 * kID, 0);

        gemm(A0, OFF_LWO + (size_t)li * 1024 * 1024, lat, nullptr, nullptr,
             kB * kNL, kD, kD, kID, nullptr, lat, 0);

        ln_bf16_kernel<<<kB * kNL, 256>>>(lat, l_ff_ln_s + li * kD,
                                          l_ff_ln_b + li * kD,
                                          h_ahi + A0, h_alo + A0);
        gemm(A0, OFF_LFF1 + (size_t)li * 4096 * 1024, nullptr,
             h_ahi + AFF, h_alo + AFF,
             kB * kNL, kFF, kFF, kD, nullptr, nullptr, 1);
        gemm(AFF, OFF_LFF2 + (size_t)li * 1024 * 4096, lat, nullptr, nullptr,
             kB * kNL, kD, kD, kFF, nullptr, lat, 0);
    }

    // 4. logits head
    {
        size_t n = (size_t)kB * kNL * kD;
        cvt_act_kernel<<<(int)((n / 2 + 255) / 256), 256>>>(
            lat, h_ahi + A0, h_alo + A0, (int)n);
    }
    gemm(A0, OFF_LOGITS, out, nullptr, nullptr,
         kB * kNL, kV, kVp, kD, nullptr, nullptr, 0);
}

// round 8
// speedup vs baseline: 2.7375x; 1.3584x over previous
#include <cuda_runtime.h>
#include <cuda_bf16.h>
#include <math.h>
#include <stdint.h>

// ---------------- problem constants ----------------
namespace {
constexpr int kB  = 2;
constexpr int kS  = 2048;
constexpr int kP  = 512;
constexpr int kNL = 1536;   // latent tokens = S - P
constexpr int kD  = 1024;
constexpr int kH  = 16;
constexpr int kDH = 64;
constexpr int kID = 1024;   // H * DH
constexpr int kV  = 20000;
constexpr int kVp = 20096;  // padded to 128
constexpr int kL  = 4;
constexpr int kFF = 4096;
constexpr float kScale = 0.125f;   // DH^-0.5
constexpr float kEps   = 1e-5f;

// weight arena offsets (transposed [N][K] layout, elements)
constexpr size_t OFF_CAWQ   = 0;                                  // 1024x1024
constexpr size_t OFF_CAWKV  = OFF_CAWQ  + 1024ull * 1024;         // 2048x1024
constexpr size_t OFF_CAWO   = OFF_CAWKV + 2048ull * 1024;         // 1024x1024
constexpr size_t OFF_CAFF1  = OFF_CAWO  + 1024ull * 1024;         // 4096x1024
constexpr size_t OFF_CAFF2  = OFF_CAFF1 + 4096ull * 1024;         // 1024x4096
constexpr size_t OFF_LQKV   = OFF_CAFF2 + 1024ull * 4096;         // 4 x 3072x1024
constexpr size_t OFF_LWO    = OFF_LQKV  + 4ull * 3072 * 1024;     // 4 x 1024x1024
constexpr size_t OFF_LFF1   = OFF_LWO   + 4ull * 1024 * 1024;     // 4 x 4096x1024
constexpr size_t OFF_LFF2   = OFF_LFF1  + 4ull * 4096 * 1024;     // 4 x 1024x4096
constexpr size_t OFF_LOGITS = OFF_LFF2  + 4ull * 1024 * 4096;     // 20096x1024
constexpr size_t W_TOTAL    = OFF_LOGITS + (size_t)kVp * 1024;

// activation arena regions (elements)
constexpr size_t A0   = 0;                                // xn/tmp/att/lat-cvt
constexpr size_t AFF  = (size_t)kB * kNL * kD;            // GELU(ff1) output
constexpr size_t ACN  = AFF + (size_t)kB * kNL * kFF;     // cn (prefix LN)
constexpr size_t A_TOTAL = ACN + (size_t)kB * kP * kD;

// hgemm smem: 2 stages x 4 arrays x 128 rows x 24 uint32 words
constexpr int kRowWords   = 24;                      // 16 data + 8 pad
constexpr int kArrWords   = 128 * kRowWords;         // 3072
constexpr int kStageWords = 4 * kArrWords;           // 12288
constexpr int kGemmSmem   = 2 * kStageWords * 4;     // 98304 bytes

// attention smem layout (uint32 word offsets)
constexpr int AQH = 0;                // Q hi  64 x 36
constexpr int AQL = AQH + 64 * 36;
constexpr int AKH = AQL + 64 * 36;    // K hi  64 x 36
constexpr int AKL = AKH + 64 * 36;
constexpr int AVH = AKL + 64 * 36;    // V hi  32 kpairs x 72
constexpr int AVL = AVH + 32 * 72;
constexpr int APH = AVL + 32 * 72;    // P hi  64 x 36
constexpr int APL = APH + 64 * 36;
constexpr int AMR = APL + 64 * 36;    // mrow[64] (float)
constexpr int ALR = AMR + 64;         // lrow[64]
constexpr int AMX = ALR + 64;         // smMax[64][2]
constexpr int ASM = AMX + 128;        // smSum[64][2]
constexpr int kAttnWords = ASM + 128; // 18816
constexpr int kAttnSmem  = kAttnWords * 4;  // 75264 bytes
}

// ---------------- scratch (module-load allocated, legal) ----------------
__device__ float g_prefix[kB * kP * kD];
__device__ float g_lat   [kB * kNL * kD];
__device__ float g_q     [kB * kNL * kID];
__device__ float g_kv    [kB * kS * 2 * kID];
__device__ float g_qkv   [kB * kNL * 3 * kID];
__device__ float g_cos   [kS * 16];
__device__ float g_sin   [kS * 16];
__device__ __nv_bfloat16 g_whi[W_TOTAL];
__device__ __nv_bfloat16 g_wlo[W_TOTAL];
__device__ __nv_bfloat16 g_ahi[A_TOTAL];
__device__ __nv_bfloat16 g_alo[A_TOTAL];

// ---------------- low-level helpers ----------------
__device__ __forceinline__ float warpSum(float v) {
#pragma unroll
    for (int o = 16; o; o >>= 1) v += __shfl_xor_sync(0xffffffffu, v, o);
    return v;
}

// k-pair permutation: within each 8-word group, word w8 -> (w8&3)*2 + (w8>>2)
__device__ __forceinline__ int permWord(int w) {
    int w8 = w & 7;
    return (w & ~7) + ((w8 & 3) << 1) + (w8 >> 2);
}

__device__ __forceinline__ void split2(float a, float b,
                                       __nv_bfloat162& h, __nv_bfloat162& l) {
    __nv_bfloat16 h0 = __float2bfloat16(a);
    __nv_bfloat16 h1 = __float2bfloat16(b);
    h.x = h0; h.y = h1;
    l.x = __float2bfloat16(a - __bfloat162float(h0));
    l.y = __float2bfloat16(b - __bfloat162float(h1));
}

__device__ __forceinline__ void pack2(float a, float b,
                                      uint32_t& hw, uint32_t& lw) {
    __nv_bfloat162 h, l;
    split2(a, b, h, l);
    hw = *reinterpret_cast<uint32_t*>(&h);
    lw = *reinterpret_cast<uint32_t*>(&l);
}

#define MMA_BF16(c, a, b)                                                   \
    asm volatile(                                                           \
        "mma.sync.aligned.m16n8k16.row.col.f32.bf16.bf16.f32 "              \
        "{%0,%1,%2,%3}, {%4,%5,%6,%7}, {%8,%9}, {%0,%1,%2,%3};"             \
        : "+f"((c)[0]), "+f"((c)[1]), "+f"((c)[2]), "+f"((c)[3])            \
        : "r"((a)[0]), "r"((a)[1]), "r"((a)[2]), "r"((a)[3]),               \
          "r"((b)[0]), "r"((b)[1]))

#define CP_ASYNC16(dst, src)                                                \
    asm volatile("cp.async.cg.shared.global [%0], [%1], 16;"                \
                 :: "r"(dst), "l"(src))
#define CP_COMMIT() asm volatile("cp.async.commit_group;")
#define CP_WAIT0()  asm volatile("cp.async.wait_group 0;")

// ---------------- embedding ----------------
__global__ void embed_kernel(const int* __restrict__ x,
                             const float* __restrict__ te,
                             const float* __restrict__ pe,
                             float* __restrict__ prefix,
                             float* __restrict__ lat) {
    int row = blockIdx.x;
    int b = row / kS, s = row % kS;
    int tok = x[row];
    const float* tr = te + (size_t)tok * kD;
    const float* pr = pe + (size_t)s * kD;
    float* dst = (s < kP) ? (prefix + ((size_t)b * kP + s) * kD)
                          : (lat    + ((size_t)b * kNL + (s - kP)) * kD);
    for (int i = threadIdx.x; i < kD; i += blockDim.x) dst[i] = tr[i] + pr[i];
}

// ---------------- LayerNorm -> split bf16 (permuted) ----------------
__global__ __launch_bounds__(256) void ln_bf16_kernel(
    const float* __restrict__ in, const float* __restrict__ gamma,
    const float* __restrict__ beta,
    __nv_bfloat16* __restrict__ hi, __nv_bfloat16* __restrict__ lo) {
    int r = blockIdx.x;
    const float* xr = in + (size_t)r * kD;
    int tid = threadIdx.x;
    float4 v4 = *(const float4*)(xr + 4 * tid);
    float v[4] = {v4.x, v4.y, v4.z, v4.w};
    float s = v[0] + v[1] + v[2] + v[3];
    __shared__ float red[8];
    __shared__ float meanS, rstdS;
    s = warpSum(s);
    if ((tid & 31) == 0) red[tid >> 5] = s;
    __syncthreads();
    if (tid < 32) {
        float t = (tid < 8) ? red[tid] : 0.f;
        t = warpSum(t);
        if (tid == 0) meanS = t * (1.f / kD);
    }
    __syncthreads();
    float mean = meanS;
    float s2 = 0.f;
#pragma unroll
    for (int i = 0; i < 4; i++) { float d = v[i] - mean; s2 += d * d; }
    s2 = warpSum(s2);
    __syncthreads();
    if ((tid & 31) == 0) red[tid >> 5] = s2;
    __syncthreads();
    if (tid < 32) {
        float t = (tid < 8) ? red[tid] : 0.f;
        t = warpSum(t);
        if (tid == 0) rstdS = rsqrtf(t * (1.f / kD) + kEps);
    }
    __syncthreads();
    float rs = rstdS;
    float4 g4 = *(const float4*)(gamma + 4 * tid);
    float4 b4 = *(const float4*)(beta + 4 * tid);
    float y0 = (v[0] - mean) * rs * g4.x + b4.x;
    float y1 = (v[1] - mean) * rs * g4.y + b4.y;
    float y2 = (v[2] - mean) * rs * g4.z + b4.z;
    float y3 = (v[3] - mean) * rs * g4.w + b4.w;
    __nv_bfloat162 h0, l0, h1, l1;
    split2(y0, y1, h0, l0);
    split2(y2, y3, h1, l1);
    size_t rowW = (size_t)r * (kD / 2);
    int w0 = 2 * tid;
    ((__nv_bfloat162*)hi)[rowW + permWord(w0)]     = h0;
    ((__nv_bfloat162*)hi)[rowW + permWord(w0 + 1)] = h1;
    ((__nv_bfloat162*)lo)[rowW + permWord(w0)]     = l0;
    ((__nv_bfloat162*)lo)[rowW + permWord(w0 + 1)] = l1;
}

// ---------------- RoPE table + apply ----------------
__global__ void rope_table_kernel(float* __restrict__ ct, float* __restrict__ st) {
    int idx = blockIdx.x * blockDim.x + threadIdx.x;
    if (idx >= kS * 16) return;
    int s = idx >> 4, i = idx & 15;
    float inv = (float)(1.0 / pow(10000.0, (double)i / 16.0));
    float f = (float)s * inv;
    ct[idx] = (float)cos((double)f);
    st[idx] = (float)sin((double)f);
}

__global__ void rope_kernel(float* __restrict__ buf, int rows, int rowStride,
                            int T, int posOff, float scaleAll,
                            const float* __restrict__ ct,
                            const float* __restrict__ st) {
    int idx = blockIdx.x * blockDim.x + threadIdx.x;
    if (idx >= rows * kH) return;
    int row = idx / kH, h = idx % kH;
    float* p = buf + (size_t)row * rowStride + h * kDH;
    int pos = posOff + (row % T);
    const float* cr = ct + pos * 16;
    const float* sr = st + pos * 16;
#pragma unroll
    for (int i = 0; i < 16; i++) {
        float c = cr[i], s = sr[i];
        float x1 = p[i], x2 = p[i + 16];
        p[i]      = (x1 * c - x2 * s) * scaleAll;
        p[i + 16] = (x2 * c + x1 * s) * scaleAll;
    }
    if (scaleAll != 1.f) {
#pragma unroll
        for (int i = 32; i < 64; i++) p[i] *= scaleAll;
    }
}

// ---------------- fp32 -> bf16 hi/lo converter (k-pair permuted) ----------
__global__ void cvt_act_kernel(const float* __restrict__ in,
                               __nv_bfloat16* __restrict__ hi,
                               __nv_bfloat16* __restrict__ lo, int n) {
    int w = blockIdx.x * blockDim.x + threadIdx.x;
    if (w * 2 >= n) return;
    float2 v = *(const float2*)(in + (size_t)w * 2);
    __nv_bfloat162 h, l;
    split2(v.x, v.y, h, l);
    int pw = permWord(w);
    ((__nv_bfloat162*)hi)[pw] = h;
    ((__nv_bfloat162*)lo)[pw] = l;
}

// transpose + convert weights: W[K,N] fp32 -> Wt_hi/lo[Npad,K] bf16,
// k-pair permuted, zero padded.
__global__ void cvt_wt_kernel(const float* __restrict__ W,
                              __nv_bfloat16* __restrict__ whi,
                              __nv_bfloat16* __restrict__ wlo,
                              int K, int N, int Npad) {
    __shared__ float t[32][33];
    int k0 = blockIdx.x * 32, n0 = blockIdx.y * 32;
    int tx = threadIdx.x, ty = threadIdx.y;   // 32 x 8
#pragma unroll
    for (int j = 0; j < 4; j++) {
        int k = k0 + ty + 8 * j;
        float v = (n0 + tx < N) ? W[(size_t)k * N + n0 + tx] : 0.f;
        t[ty + 8 * j][tx] = v;
    }
    __syncthreads();
#pragma unroll
    for (int j = 0; j < 4; j++) {
        int n = n0 + ty + 8 * j;
        int k = k0 + tx;
        float x = t[tx][ty + 8 * j];
        __nv_bfloat16 h = __float2bfloat16(x);
        __nv_bfloat16 l = __float2bfloat16(x - __bfloat162float(h));
        int pk = permWord(k >> 1) * 2 + (k & 1);
        whi[(size_t)n * K + pk] = h;
        wlo[(size_t)n * K + pk] = l;
    }
}

// ---------------- bf16 tensor-core GEMM (3-term split) --------------------
__global__ __launch_bounds__(256, 2) void hgemm_kernel(
    const __nv_bfloat16* __restrict__ Ahi, const __nv_bfloat16* __restrict__ Alo,
    const __nv_bfloat16* __restrict__ Bhi, const __nv_bfloat16* __restrict__ Blo,
    float* __restrict__ C,
    __nv_bfloat16* __restrict__ Chi, __nv_bfloat16* __restrict__ Clo,
    int M, int N, int K,
    const float* __restrict__ bias, const float* __restrict__ res, int act) {
    extern __shared__ uint32_t sm[];
    const int tid  = threadIdx.x;
    const int lane = tid & 31;
    const int warp = tid >> 5;
    const int warpM = warp >> 2;
    const int warpN = warp & 3;
    const int gid = lane >> 2;
    const int tig = lane & 3;
    const int m0 = blockIdx.y * 128, n0 = blockIdx.x * 128;

    float acc[4][4][4] = {};

    auto issue = [&](int stage, int kt) {
        const uint32_t base = stage * kStageWords;
#pragma unroll
        for (int i = 0; i < 8; i++) {
            int c = tid + i * 256;
            int t = c >> 9, w = c & 511;
            int row = w >> 2, ck = w & 3;
            const __nv_bfloat16* src;
            if (t == 0)      src = Ahi + (size_t)(m0 + row) * K + kt + ck * 8;
            else if (t == 1) src = Alo + (size_t)(m0 + row) * K + kt + ck * 8;
            else if (t == 2) src = Bhi + (size_t)(n0 + row) * K + kt + ck * 8;
            else             src = Blo + (size_t)(n0 + row) * K + kt + ck * 8;
            uint32_t dst = (uint32_t)__cvta_generic_to_shared(
                &sm[base + t * kArrWords + row * kRowWords + ck * 4]);
            CP_ASYNC16(dst, src);
        }
    };

    auto compute = [&](int buf) {
        const uint32_t* SAh = sm + buf * kStageWords;
        const uint32_t* SAl = SAh + kArrWords;
        const uint32_t* SBh = SAl + kArrWords;
        const uint32_t* SBl = SBh + kArrWords;
#pragma unroll
        for (int ks = 0; ks < 2; ks++) {
            const int kwb = ks * 8 + 2 * tig;
            uint2 bh[4], bl[4];
#pragma unroll
            for (int in = 0; in < 4; in++) {
                const int n = warpN * 32 + in * 8 + gid;
                bh[in] = *(const uint2*)&SBh[n * kRowWords + kwb];
                bl[in] = *(const uint2*)&SBl[n * kRowWords + kwb];
            }
#pragma unroll
            for (int im = 0; im < 4; im++) {
                const int r = warpM * 64 + im * 16 + gid;
                uint2 uh = *(const uint2*)&SAh[r * kRowWords + kwb];
                uint2 vh = *(const uint2*)&SAh[(r + 8) * kRowWords + kwb];
                uint2 ul = *(const uint2*)&SAl[r * kRowWords + kwb];
                uint2 vl = *(const uint2*)&SAl[(r + 8) * kRowWords + kwb];
                uint32_t ahi[4] = {uh.x, vh.x, uh.y, vh.y};
                uint32_t alo[4] = {ul.x, vl.x, ul.y, vl.y};
#pragma unroll
                for (int in = 0; in < 4; in++) {
                    uint32_t bhw[2] = {bh[in].x, bh[in].y};
                    uint32_t blw[2] = {bl[in].x, bl[in].y};
                    MMA_BF16(acc[im][in], ahi, bhw);
                    MMA_BF16(acc[im][in], ahi, blw);
                    MMA_BF16(acc[im][in], alo, bhw);
                }
            }
        }
    };

    const int nStages = K >> 5;
    issue(0, 0);
    CP_COMMIT();
    for (int s = 0; s < nStages; s++) {
        CP_WAIT0();
        __syncthreads();
        if (s + 1 < nStages) { issue((s + 1) & 1, (s + 1) * 32); CP_COMMIT(); }
        compute(s & 1);
    }

    // ---- epilogue ----
#pragma unroll
    for (int im = 0; im < 4; im++) {
        const int row = m0 + warpM * 64 + im * 16 + gid;
#pragma unroll
        for (int in = 0; in < 4; in++) {
            const int col = n0 + warpN * 32 + in * 8 + 2 * tig;
            if (col >= N) continue;
#pragma unroll
            for (int half = 0; half < 2; half++) {
                const int rr = row + half * 8;
                float c0 = acc[im][in][half * 2 + 0];
                float c1 = acc[im][in][half * 2 + 1];
                if (bias) { c0 += bias[col]; c1 += bias[col + 1]; }
                if (act) {
                    c0 = 0.5f * c0 * (1.f + erff(c0 * 0.70710678118654752f));
                    c1 = 0.5f * c1 * (1.f + erff(c1 * 0.70710678118654752f));
                }
                if (res) {
                    const float2 rv = *(const float2*)(res + (size_t)rr * N + col);
                    c0 += rv.x; c1 += rv.y;
                }
                if (C)
                    *(float2*)(C + (size_t)rr * N + col) = make_float2(c0, c1);
                if (Chi) {
                    __nv_bfloat162 h, l;
                    split2(c0, c1, h, l);
                    size_t rowW = (size_t)rr * (N >> 1);
                    int pw = permWord(col >> 1);
                    ((__nv_bfloat162*)Chi)[rowW + pw] = h;
                    ((__nv_bfloat162*)Clo)[rowW + pw] = l;
                }
            }
        }
    }
}

// ---------------- flash attention on tensor cores (bf16 3-term split) -----
// CTA: 64 q x 1 head x 1 batch; k-tiles of 64. 8 warps: warpQ=warp>>1 (16q
// band), warpK=warp&1 (32-wide k band for QK, 32-wide d band for PV).
// Q/K stored [row][cpair] packed words, LD=36; V pair-packed along k,
// [kpair][d] LD=72; P [q][kpair] LD=36. All fragment LDS conflict-free.
__global__ __launch_bounds__(256, 2) void attn_kernel(
    const float* __restrict__ qb, const float* __restrict__ kb,
    const float* __restrict__ vb,
    __nv_bfloat16* __restrict__ ohi, __nv_bfloat16* __restrict__ olo,
    int Tq, int Tk, int qStride, int kvStride, int diag) {
    extern __shared__ uint32_t sa[];
    float* sf = (float*)sa;
    const int tid = threadIdx.x;
    const int lane = tid & 31, warp = tid >> 5;
    const int g = lane >> 2, tg = lane & 3;
    const int warpQ = warp >> 1, warpK = warp & 1;
    const int q0 = blockIdx.x * 64, h = blockIdx.y, b = blockIdx.z;
    const int q0w = warpQ * 16;

    // stage Q (64 x 64 fp32 -> split packed)
    {
        const float* qg = qb + ((size_t)b * Tq + q0) * qStride + h * kDH;
#pragma unroll
        for (int i = 0; i < 4; i++) {
            int ch = tid + i * 256;
            int row = ch >> 4, c4 = (ch & 15) * 4;
            float4 v = *(const float4*)(qg + (size_t)row * qStride + c4);
            uint32_t h0, l0, h1, l1;
            pack2(v.x, v.y, h0, l0);
            pack2(v.z, v.w, h1, l1);
            *(uint2*)&sa[AQH + row * 36 + (c4 >> 1)] = make_uint2(h0, h1);
            *(uint2*)&sa[AQL + row * 36 + (c4 >> 1)] = make_uint2(l0, l1);
        }
    }
    if (tid < 64) { sf[AMR + tid] = -1e30f; sf[ALR + tid] = 0.f; }

    float O[4][4] = {};
    int jmax = q0 + 63 + diag;
    int nkt = (jmax + 64) >> 6;
    int maxkt = Tk >> 6;
    if (nkt > maxkt) nkt = maxkt;

    const int r0i = q0w + g, r1i = r0i + 8;

    for (int kt = 0; kt < nkt; kt++) {
        const int k0 = kt * 64;
        const float* kg = kb + ((size_t)b * Tk + k0) * kvStride + h * kDH;
        const float* vg = vb + ((size_t)b * Tk + k0) * kvStride + h * kDH;
        // stage K
#pragma unroll
        for (int i = 0; i < 4; i++) {
            int ch = tid + i * 256;
            int row = ch >> 4, c4 = (ch & 15) * 4;
            float4 v = *(const float4*)(kg + (size_t)row * kvStride + c4);
            uint32_t h0, l0, h1, l1;
            pack2(v.x, v.y, h0, l0);
            pack2(v.z, v.w, h1, l1);
            *(uint2*)&sa[AKH + row * 36 + (c4 >> 1)] = make_uint2(h0, h1);
            *(uint2*)&sa[AKL + row * 36 + (c4 >> 1)] = make_uint2(l0, l1);
        }
        // stage V (pair-pack along k)
#pragma unroll
        for (int i = 0; i < 2; i++) {
            int ch = tid + i * 256;
            int k2 = ch >> 4, d4 = (ch & 15) * 4;
            const float* p0 = vg + (size_t)(2 * k2) * kvStride + d4;
            float4 r0 = *(const float4*)p0;
            float4 r1 = *(const float4*)(p0 + kvStride);
            uint32_t hw0, lw0, hw1, lw1, hw2, lw2, hw3, lw3;
            pack2(r0.x, r1.x, hw0, lw0);
            pack2(r0.y, r1.y, hw1, lw1);
            pack2(r0.z, r1.z, hw2, lw2);
            pack2(r0.w, r1.w, hw3, lw3);
            *(uint4*)&sa[AVH + k2 * 72 + d4] = make_uint4(hw0, hw1, hw2, hw3);
            *(uint4*)&sa[AVL + k2 * 72 + d4] = make_uint4(lw0, lw1, lw2, lw3);
        }
        __syncthreads();   // A: staging complete

        // ---- S = Q @ K^T ----
        float s[4][4];
#pragma unroll
        for (int nt = 0; nt < 4; nt++)
#pragma unroll
            for (int j = 0; j < 4; j++) s[nt][j] = 0.f;
#pragma unroll
        for (int ck = 0; ck < 4; ck++) {
            const int ac = ck * 8 + tg;
            uint32_t ahi[4] = {
                sa[AQH + r0i * 36 + ac], sa[AQH + r1i * 36 + ac],
                sa[AQH + r0i * 36 + ac + 4], sa[AQH + r1i * 36 + ac + 4]};
            uint32_t alo[4] = {
                sa[AQL + r0i * 36 + ac], sa[AQL + r1i * 36 + ac],
                sa[AQL + r0i * 36 + ac + 4], sa[AQL + r1i * 36 + ac + 4]};
#pragma unroll
            for (int nt = 0; nt < 4; nt++) {
                const int key = warpK * 32 + nt * 8 + g;
                uint32_t bhi[2] = {sa[AKH + key * 36 + ac],
                                   sa[AKH + key * 36 + ac + 4]};
                uint32_t blo[2] = {sa[AKL + key * 36 + ac],
                                   sa[AKL + key * 36 + ac + 4]};
                MMA_BF16(s[nt], ahi, bhi);
                MMA_BF16(s[nt], ahi, blo);
                MMA_BF16(s[nt], alo, bhi);
            }
        }
        // ---- causal mask ----
        if (k0 + 63 > q0 + diag) {
            int qr0 = q0 + r0i + diag;
            int qr1 = qr0 + 8;
#pragma unroll
            for (int nt = 0; nt < 4; nt++) {
                int cb = k0 + warpK * 32 + nt * 8 + 2 * tg;
                if (cb > qr0)     s[nt][0] = -1e30f;
                if (cb + 1 > qr0) s[nt][1] = -1e30f;
                if (cb > qr1)     s[nt][2] = -1e30f;
                if (cb + 1 > qr1) s[nt][3] = -1e30f;
            }
        }
        // ---- row max (quad butterfly + cross-warp via smem) ----
        float mx0 = -1e30f, mx1 = -1e30f;
#pragma unroll
        for (int nt = 0; nt < 4; nt++) {
            mx0 = fmaxf(mx0, fmaxf(s[nt][0], s[nt][1]));
            mx1 = fmaxf(mx1, fmaxf(s[nt][2], s[nt][3]));
        }
        mx0 = fmaxf(mx0, __shfl_xor_sync(0xffffffffu, mx0, 1));
        mx0 = fmaxf(mx0, __shfl_xor_sync(0xffffffffu, mx0, 2));
        mx1 = fmaxf(mx1, __shfl_xor_sync(0xffffffffu, mx1, 1));
        mx1 = fmaxf(mx1, __shfl_xor_sync(0xffffffffu, mx1, 2));
        if (tg == 0) {
            sf[AMX + r0i * 2 + warpK] = mx0;
            sf[AMX + r1i * 2 + warpK] = mx1;
        }
        __syncthreads();   // B: maxes visible

        float mold0 = sf[AMR + r0i], mold1 = sf[AMR + r1i];
        float lold0 = sf[ALR + r0i], lold1 = sf[ALR + r1i];
        float mnew0 = fmaxf(mold0, fmaxf(sf[AMX + r0i * 2], sf[AMX + r0i * 2 + 1]));
        float mnew1 = fmaxf(mold1, fmaxf(sf[AMX + r1i * 2], sf[AMX + r1i * 2 + 1]));
        float f0 = __expf(mold0 - mnew0);
        float f1 = __expf(mold1 - mnew1);
        float sum0 = 0.f, sum1 = 0.f;
#pragma unroll
        for (int nt = 0; nt < 4; nt++) {
            float p00 = __expf(s[nt][0] - mnew0);
            float p01 = __expf(s[nt][1] - mnew0);
            float p10 = __expf(s[nt][2] - mnew1);
            float p11 = __expf(s[nt][3] - mnew1);
            sum0 += p00 + p01; sum1 += p10 + p11;
            uint32_t hw, lw;
            const int pc = warpK * 16 + nt * 4 + tg;
            pack2(p00, p01, hw, lw);
            sa[APH + r0i * 36 + pc] = hw; sa[APL + r0i * 36 + pc] = lw;
            pack2(p10, p11, hw, lw);
            sa[APH + r1i * 36 + pc] = hw; sa[APL + r1i * 36 + pc] = lw;
        }
        sum0 += __shfl_xor_sync(0xffffffffu, sum0, 1);
        sum0 += __shfl_xor_sync(0xffffffffu, sum0, 2);
        sum1 += __shfl_xor_sync(0xffffffffu, sum1, 1);
        sum1 += __shfl_xor_sync(0xffffffffu, sum1, 2);
        if (tg == 0) {
            sf[ASM + r0i * 2 + warpK] = sum0;
            sf[ASM + r1i * 2 + warpK] = sum1;
        }
        __syncthreads();  // C: P + sums visible

        // ---- rescale O, then O += P @ V ----
#pragma unroll
        for (int nt = 0; nt < 4; nt++) {
            O[nt][0] *= f0; O[nt][1] *= f0;
            O[nt][2] *= f1; O[nt][3] *= f1;
        }
#pragma unroll
        for (int kk = 0; kk < 4; kk++) {
            const int pc = kk * 8 + tg;
            uint32_t ahi[4] = {
                sa[APH + r0i * 36 + pc], sa[APH + r1i * 36 + pc],
                sa[APH + r0i * 36 + pc + 4], sa[APH + r1i * 36 + pc + 4]};
            uint32_t alo[4] = {
                sa[APL + r0i * 36 + pc], sa[APL + r1i * 36 + pc],
                sa[APL + r0i * 36 + pc + 4], sa[APL + r1i * 36 + pc + 4]};
#pragma unroll
            for (int nt = 0; nt < 4; nt++) {
                const int d0 = warpK * 32 + nt * 8 + g;
                uint32_t bhi[2] = {sa[AVH + (kk * 8 + tg) * 72 + d0],
                                   sa[AVH + (kk * 8 + 4 + tg) * 72 + d0]};
                uint32_t blo[2] = {sa[AVL + (kk * 8 + tg) * 72 + d0],
                                   sa[AVL + (kk * 8 + 4 + tg) * 72 + d0]};
                MMA_BF16(O[nt], ahi, bhi);
                MMA_BF16(O[nt], ahi, blo);
                MMA_BF16(O[nt], alo, bhi);
            }
        }
        // ---- state update (one warp per q band) ----
        if (warpK == 0 && tg == 0) {
            sf[AMR + r0i] = mnew0;
            sf[AMR + r1i] = mnew1;
            sf[ALR + r0i] = lold0 * f0 + sf[ASM + r0i * 2] + sf[ASM + r0i * 2 + 1];
            sf[ALR + r1i] = lold1 * f1 + sf[ASM + r1i * 2] + sf[ASM + r1i * 2 + 1];
        }
        __syncthreads();  // D: state final; K/V/P safe to overwrite
    }

    // ---- write output (split bf16, permuted, GEMM-ready) ----
    float inv0 = 1.f / sf[ALR + r0i];
    float inv1 = 1.f / sf[ALR + r1i];
    size_t rowW0 = ((size_t)b * Tq + q0 + r0i) * (kID / 2);
    size_t rowW1 = ((size_t)b * Tq + q0 + r1i) * (kID / 2);
#pragma unroll
    for (int nt = 0; nt < 4; nt++) {
        int col = h * kDH + warpK * 32 + nt * 8 + 2 * tg;
        int w0 = col >> 1;
        uint32_t hw, lw;
        pack2(O[nt][0] * inv0, O[nt][1] * inv0, hw, lw);
        ((uint32_t*)ohi)[rowW0 + permWord(w0)] = hw;
        ((uint32_t*)olo)[rowW0 + permWord(w0)] = lw;
        pack2(O[nt][2] * inv1, O[nt][3] * inv1, hw, lw);
        ((uint32_t*)ohi)[rowW1 + permWord(w0)] = hw;
        ((uint32_t*)olo)[rowW1 + permWord(w0)] = lw;
    }
}

// ---------------- host orchestration ----------------
namespace {
__nv_bfloat16 *h_whi, *h_wlo, *h_ahi, *h_alo;

inline void gemm(size_t aOff, size_t wOff, float* C,
                 __nv_bfloat16* chi, __nv_bfloat16* clo,
                 int M, int N, int Npad, int K,
                 const float* bias, const float* res, int act) {
    dim3 g(Npad / 128, M / 128);
    hgemm_kernel<<<g, 256, kGemmSmem>>>(
        h_ahi + aOff, h_alo + aOff, h_whi + wOff, h_wlo + wOff,
        C, chi, clo, M, N, K, bias, res, act);
}
}

extern "C" void kernel_launch(void* const* d_in, const int* in_sizes, int n_in,
                              void* d_out, int out_size) {
    const int*   x           = (const int*)d_in[0];
    // d_in[1] = prefix_mask: all-True and padded True => no-op; unused.
    const float* token_emb   = (const float*)d_in[2];
    const float* pos_emb     = (const float*)d_in[3];
    const float* ca_norm_s   = (const float*)d_in[4];
    const float* ca_norm_b   = (const float*)d_in[5];
    const float* ca_ctx_ns   = (const float*)d_in[6];
    const float* ca_ctx_nb   = (const float*)d_in[7];
    const float* ca_wq       = (const float*)d_in[8];
    const float* ca_wkv      = (const float*)d_in[9];
    const float* ca_wo       = (const float*)d_in[10];
    const float* ca_bo       = (const float*)d_in[11];
    const float* ca_ff_ln_s  = (const float*)d_in[12];
    const float* ca_ff_ln_b  = (const float*)d_in[13];
    const float* ca_ff_w1    = (const float*)d_in[14];
    const float* ca_ff_w2    = (const float*)d_in[15];
    const float* l_norm_s    = (const float*)d_in[16];
    const float* l_norm_b    = (const float*)d_in[17];
    const float* l_wqkv      = (const float*)d_in[18];
    const float* l_wo        = (const float*)d_in[19];
    const float* l_ff_ln_s   = (const float*)d_in[20];
    const float* l_ff_ln_b   = (const float*)d_in[21];
    const float* l_ff_w1     = (const float*)d_in[22];
    const float* l_ff_w2     = (const float*)d_in[23];
    const float* w_logits    = (const float*)d_in[24];
    float* out = (float*)d_out;

    float *prefix, *lat, *qb, *kv, *qkv, *ctab, *stab;
    cudaGetSymbolAddress((void**)&prefix, g_prefix);
    cudaGetSymbolAddress((void**)&lat,    g_lat);
    cudaGetSymbolAddress((void**)&qb,     g_q);
    cudaGetSymbolAddress((void**)&kv,     g_kv);
    cudaGetSymbolAddress((void**)&qkv,    g_qkv);
    cudaGetSymbolAddress((void**)&ctab,   g_cos);
    cudaGetSymbolAddress((void**)&stab,   g_sin);
    cudaGetSymbolAddress((void**)&h_whi,  g_whi);
    cudaGetSymbolAddress((void**)&h_wlo,  g_wlo);
    cudaGetSymbolAddress((void**)&h_ahi,  g_ahi);
    cudaGetSymbolAddress((void**)&h_alo,  g_alo);

    cudaFuncSetAttribute(hgemm_kernel,
                         cudaFuncAttributeMaxDynamicSharedMemorySize, kGemmSmem);
    cudaFuncSetAttribute(attn_kernel,
                         cudaFuncAttributeMaxDynamicSharedMemorySize, kAttnSmem);

    // 0. convert + transpose all weights into bf16 hi/lo arenas
    auto cw = [&](const float* W, size_t off, int K, int N, int Npad) {
        dim3 g(K / 32, Npad / 32);
        cvt_wt_kernel<<<g, dim3(32, 8)>>>(W, h_whi + off, h_wlo + off, K, N, Npad);
    };
    cw(ca_wq,    OFF_CAWQ,  1024, 1024, 1024);
    cw(ca_wkv,   OFF_CAWKV, 1024, 2048, 2048);
    cw(ca_wo,    OFF_CAWO,  1024, 1024, 1024);
    cw(ca_ff_w1, OFF_CAFF1, 1024, 4096, 4096);
    cw(ca_ff_w2, OFF_CAFF2, 4096, 1024, 1024);
    for (int li = 0; li < kL; li++) {
        cw(l_wqkv  + (size_t)li * 1024 * 3072, OFF_LQKV + (size_t)li * 3072 * 1024, 1024, 3072, 3072);
        cw(l_wo    + (size_t)li * 1024 * 1024, OFF_LWO  + (size_t)li * 1024 * 1024, 1024, 1024, 1024);
        cw(l_ff_w1 + (size_t)li * 1024 * 4096, OFF_LFF1 + (size_t)li * 4096 * 1024, 1024, 4096, 4096);
        cw(l_ff_w2 + (size_t)li * 4096 * 1024, OFF_LFF2 + (size_t)li * 1024 * 4096, 4096, 1024, 1024);
    }
    cw(w_logits, OFF_LOGITS, 1024, kV, kVp);

    // 1. embeddings + rope tables
    embed_kernel<<<kB * kS, 256>>>(x, token_emb, pos_emb, prefix, lat);
    rope_table_kernel<<<(kS * 16 + 255) / 256, 256>>>(ctab, stab);

    // 2. cross-attention block
    ln_bf16_kernel<<<kB * kNL, 256>>>(lat,    ca_norm_s, ca_norm_b,
                                      h_ahi + A0,  h_alo + A0);
    ln_bf16_kernel<<<kB * kP,  256>>>(prefix, ca_ctx_ns, ca_ctx_nb,
                                      h_ahi + ACN, h_alo + ACN);

    for (int b = 0; b < kB; b++)
        gemm(ACN + (size_t)b * kP * kD, OFF_CAWKV,
             kv + (size_t)b * kS * 2 * kID, nullptr, nullptr,
             kP, 2 * kID, 2 * kID, kD, nullptr, nullptr, 0);
    gemm(A0, OFF_CAWQ, qb, nullptr, nullptr,
         kB * kNL, kID, kID, kD, nullptr, nullptr, 0);
    for (int b = 0; b < kB; b++)
        gemm(A0 + (size_t)b * kNL * kD, OFF_CAWKV,
             kv + ((size_t)b * kS + kP) * 2 * kID, nullptr, nullptr,
             kNL, 2 * kID, 2 * kID, kD, nullptr, nullptr, 0);

    {
        int rq = kB * kNL * kH, rk = kB * kS * kH;
        rope_kernel<<<(rq + 255) / 256, 256>>>(qb, kB * kNL, kID, kNL, kP, kScale, ctab, stab);
        rope_kernel<<<(rk + 255) / 256, 256>>>(kv, kB * kS, 2 * kID, kS, 0, 1.f, ctab, stab);
    }
    attn_kernel<<<dim3(kNL / 64, kH, kB), 256, kAttnSmem>>>(
        qb, kv, kv + kID, h_ahi + A0, h_alo + A0, kNL, kS, kID, 2 * kID, kP);

    gemm(A0, OFF_CAWO, lat, nullptr, nullptr,
         kB * kNL, kD, kD, kID, ca_bo, lat, 0);

    ln_bf16_kernel<<<kB * kNL, 256>>>(lat, ca_ff_ln_s, ca_ff_ln_b,
                                      h_ahi + A0, h_alo + A0);
    gemm(A0, OFF_CAFF1, nullptr, h_ahi + AFF, h_alo + AFF,
         kB * kNL, kFF, kFF, kD, nullptr, nullptr, 1);
    gemm(AFF, OFF_CAFF2, lat, nullptr, nullptr,
         kB * kNL, kD, kD, kFF, nullptr, lat, 0);

    // 3. latent self-attention layers
    for (int li = 0; li < kL; li++) {
        ln_bf16_kernel<<<kB * kNL, 256>>>(lat, l_norm_s + li * kD,
                                          l_norm_b + li * kD,
                                          h_ahi + A0, h_alo + A0);
        gemm(A0, OFF_LQKV + (size_t)li * 3072 * 1024, qkv, nullptr, nullptr,
             kB * kNL, 3 * kID, 3 * kID, kD, nullptr, nullptr, 0);

        int rq = kB * kNL * kH;
        rope_kernel<<<(rq + 255) / 256, 256>>>(qkv,       kB * kNL, 3 * kID, kNL, kP, kScale, ctab, stab);
        rope_kernel<<<(rq + 255) / 256, 256>>>(qkv + kID, kB * kNL, 3 * kID, kNL, kP, 1.f,    ctab, stab);
        attn_kernel<<<dim3(kNL / 64, kH, kB), 256, kAttnSmem>>>(
            qkv, qkv + kID, qkv + 2 * kID, h_ahi + A0, h_alo + A0,
            kNL, kNL, 3 * kID, 3 * kID, 0);

        gemm(A0, OFF_LWO + (size_t)li * 1024 * 1024, lat, nullptr, nullptr,
             kB * kNL, kD, kD, kID, nullptr, lat, 0);

        ln_bf16_kernel<<<kB * kNL, 256>>>(lat, l_ff_ln_s + li * kD,
                                          l_ff_ln_b + li * kD,
                                          h_ahi + A0, h_alo + A0);
        gemm(A0, OFF_LFF1 + (size_t)li * 4096 * 1024, nullptr,
             h_ahi + AFF, h_alo + AFF,
             kB * kNL, kFF, kFF, kD, nullptr, nullptr, 1);
        gemm(AFF, OFF_LFF2 + (size_t)li * 1024 * 4096, lat, nullptr, nullptr,
             kB * kNL, kD, kD, kFF, nullptr, lat, 0);
    }

    // 4. logits head
    {
        size_t n = (size_t)kB * kNL * kD;
        cvt_act_kernel<<<(int)((n / 2 + 255) / 256), 256>>>(
            lat, h_ahi + A0, h_alo + A0, (int)n);
    }
    gemm(A0, OFF_LOGITS, out, nullptr, nullptr,
         kB * kNL, kV, kVp, kD, nullptr, nullptr, 0);
}

// round 9
// speedup vs baseline: 2.8718x; 1.0491x over previous
#include <cuda_runtime.h>
#include <cuda_bf16.h>
#include <math.h>
#include <stdint.h>

// ---------------- problem constants ----------------
namespace {
constexpr int kB  = 2;
constexpr int kS  = 2048;
constexpr int kP  = 512;
constexpr int kNL = 1536;   // latent tokens = S - P
constexpr int kD  = 1024;
constexpr int kH  = 16;
constexpr int kDH = 64;
constexpr int kID = 1024;   // H * DH
constexpr int kV  = 20000;
constexpr int kVp = 20096;  // padded to 128
constexpr int kL  = 4;
constexpr int kFF = 4096;
constexpr float kScale = 0.125f;   // DH^-0.5
constexpr float kEps   = 1e-5f;

// weight arena offsets (transposed [N][K] layout, elements)
constexpr size_t OFF_CAWQ   = 0;                                  // 1024x1024
constexpr size_t OFF_CAWKV  = OFF_CAWQ  + 1024ull * 1024;         // 2048x1024
constexpr size_t OFF_CAWO   = OFF_CAWKV + 2048ull * 1024;         // 1024x1024
constexpr size_t OFF_CAFF1  = OFF_CAWO  + 1024ull * 1024;         // 4096x1024
constexpr size_t OFF_CAFF2  = OFF_CAFF1 + 4096ull * 1024;         // 1024x4096
constexpr size_t OFF_LQKV   = OFF_CAFF2 + 1024ull * 4096;         // 4 x 3072x1024
constexpr size_t OFF_LWO    = OFF_LQKV  + 4ull * 3072 * 1024;     // 4 x 1024x1024
constexpr size_t OFF_LFF1   = OFF_LWO   + 4ull * 1024 * 1024;     // 4 x 4096x1024
constexpr size_t OFF_LFF2   = OFF_LFF1  + 4ull * 4096 * 1024;     // 4 x 1024x4096
constexpr size_t OFF_LOGITS = OFF_LFF2  + 4ull * 1024 * 4096;     // 20096x1024
constexpr size_t W_TOTAL    = OFF_LOGITS + (size_t)kVp * 1024;

// activation arena regions (elements)
constexpr size_t A0   = 0;                                // xn/tmp/att/lat-cvt
constexpr size_t AFF  = (size_t)kB * kNL * kD;            // GELU(ff1) output
constexpr size_t ACN  = AFF + (size_t)kB * kNL * kFF;     // cn (prefix LN)
constexpr size_t A_TOTAL = ACN + (size_t)kB * kP * kD;

// hgemm smem: 2 stages x 4 arrays x 128 rows x 24 uint32 words
constexpr int kRowWords   = 24;                      // 16 data + 8 pad
constexpr int kArrWords   = 128 * kRowWords;         // 3072
constexpr int kStageWords = 4 * kArrWords;           // 12288
constexpr int kGemmSmem   = 2 * kStageWords * 4;     // 98304 bytes

// attention smem layout (uint32 word offsets)
constexpr int AQH = 0;                // Q hi  64 x 36
constexpr int AQL = AQH + 64 * 36;
constexpr int AKH = AQL + 64 * 36;    // K hi  64 x 36
constexpr int AKL = AKH + 64 * 36;
constexpr int AVH = AKL + 64 * 36;    // V hi  32 kpairs x 72
constexpr int AVL = AVH + 32 * 72;
constexpr int APH = AVL + 32 * 72;    // P hi  64 x 36
constexpr int APL = APH + 64 * 36;
constexpr int AMR = APL + 64 * 36;    // mrow[64] (float)
constexpr int ALR = AMR + 64;         // lrow[64]
constexpr int AMX = ALR + 64;         // smMax[64][2]
constexpr int ASM = AMX + 128;        // smSum[64][2]
constexpr int kAttnWords = ASM + 128; // 18816
constexpr int kAttnSmem  = kAttnWords * 4;  // 75264 bytes
}

// ---------------- scratch (module-load allocated, legal) ----------------
__device__ float g_prefix[kB * kP * kD];
__device__ float g_lat   [kB * kNL * kD];
__device__ float g_q     [kB * kNL * kID];
__device__ float g_kv    [kB * kS * 2 * kID];
__device__ float g_qkv   [kB * kNL * 3 * kID];
__device__ float g_cos   [kS * 16];
__device__ float g_sin   [kS * 16];
__device__ __nv_bfloat16 g_whi[W_TOTAL];
__device__ __nv_bfloat16 g_wlo[W_TOTAL];
__device__ __nv_bfloat16 g_ahi[A_TOTAL];
__device__ __nv_bfloat16 g_alo[A_TOTAL];
// attention operand buffers (split bf16, fragment-pair packed)
__device__ __nv_bfloat16 g_qhi[kB * kNL * kID];
__device__ __nv_bfloat16 g_qlo[kB * kNL * kID];
__device__ __nv_bfloat16 g_khi[kB * kS * kID];
__device__ __nv_bfloat16 g_klo[kB * kS * kID];
__device__ uint32_t g_vph[(size_t)kB * kH * (kS / 2) * 64];
__device__ uint32_t g_vpl[(size_t)kB * kH * (kS / 2) * 64];

// ---------------- low-level helpers ----------------
__device__ __forceinline__ float warpSum(float v) {
#pragma unroll
    for (int o = 16; o; o >>= 1) v += __shfl_xor_sync(0xffffffffu, v, o);
    return v;
}

// k-pair permutation: within each 8-word group, word w8 -> (w8&3)*2 + (w8>>2)
__device__ __forceinline__ int permWord(int w) {
    int w8 = w & 7;
    return (w & ~7) + ((w8 & 3) << 1) + (w8 >> 2);
}

__device__ __forceinline__ void split2(float a, float b,
                                       __nv_bfloat162& h, __nv_bfloat162& l) {
    __nv_bfloat16 h0 = __float2bfloat16(a);
    __nv_bfloat16 h1 = __float2bfloat16(b);
    h.x = h0; h.y = h1;
    l.x = __float2bfloat16(a - __bfloat162float(h0));
    l.y = __float2bfloat16(b - __bfloat162float(h1));
}

__device__ __forceinline__ void pack2(float a, float b,
                                      uint32_t& hw, uint32_t& lw) {
    __nv_bfloat162 h, l;
    split2(a, b, h, l);
    hw = *reinterpret_cast<uint32_t*>(&h);
    lw = *reinterpret_cast<uint32_t*>(&l);
}

#define MMA_BF16(c, a, b)                                                   \
    asm volatile(                                                           \
        "mma.sync.aligned.m16n8k16.row.col.f32.bf16.bf16.f32 "              \
        "{%0,%1,%2,%3}, {%4,%5,%6,%7}, {%8,%9}, {%0,%1,%2,%3};"             \
        : "+f"((c)[0]), "+f"((c)[1]), "+f"((c)[2]), "+f"((c)[3])            \
        : "r"((a)[0]), "r"((a)[1]), "r"((a)[2]), "r"((a)[3]),               \
          "r"((b)[0]), "r"((b)[1]))

#define CP_ASYNC16(dst, src)                                                \
    asm volatile("cp.async.cg.shared.global [%0], [%1], 16;"                \
                 :: "r"(dst), "l"(src))
#define CP_COMMIT() asm volatile("cp.async.commit_group;")
#define CP_WAIT0()  asm volatile("cp.async.wait_group 0;")

// ---------------- embedding ----------------
__global__ void embed_kernel(const int* __restrict__ x,
                             const float* __restrict__ te,
                             const float* __restrict__ pe,
                             float* __restrict__ prefix,
                             float* __restrict__ lat) {
    int row = blockIdx.x;
    int b = row / kS, s = row % kS;
    int tok = x[row];
    const float* tr = te + (size_t)tok * kD;
    const float* pr = pe + (size_t)s * kD;
    float* dst = (s < kP) ? (prefix + ((size_t)b * kP + s) * kD)
                          : (lat    + ((size_t)b * kNL + (s - kP)) * kD);
    for (int i = threadIdx.x; i < kD; i += blockDim.x) dst[i] = tr[i] + pr[i];
}

// ---------------- LayerNorm -> split bf16 (permuted) ----------------
__global__ __launch_bounds__(256) void ln_bf16_kernel(
    const float* __restrict__ in, const float* __restrict__ gamma,
    const float* __restrict__ beta,
    __nv_bfloat16* __restrict__ hi, __nv_bfloat16* __restrict__ lo) {
    int r = blockIdx.x;
    const float* xr = in + (size_t)r * kD;
    int tid = threadIdx.x;
    float4 v4 = *(const float4*)(xr + 4 * tid);
    float v[4] = {v4.x, v4.y, v4.z, v4.w};
    float s = v[0] + v[1] + v[2] + v[3];
    __shared__ float red[8];
    __shared__ float meanS, rstdS;
    s = warpSum(s);
    if ((tid & 31) == 0) red[tid >> 5] = s;
    __syncthreads();
    if (tid < 32) {
        float t = (tid < 8) ? red[tid] : 0.f;
        t = warpSum(t);
        if (tid == 0) meanS = t * (1.f / kD);
    }
    __syncthreads();
    float mean = meanS;
    float s2 = 0.f;
#pragma unroll
    for (int i = 0; i < 4; i++) { float d = v[i] - mean; s2 += d * d; }
    s2 = warpSum(s2);
    __syncthreads();
    if ((tid & 31) == 0) red[tid >> 5] = s2;
    __syncthreads();
    if (tid < 32) {
        float t = (tid < 8) ? red[tid] : 0.f;
        t = warpSum(t);
        if (tid == 0) rstdS = rsqrtf(t * (1.f / kD) + kEps);
    }
    __syncthreads();
    float rs = rstdS;
    float4 g4 = *(const float4*)(gamma + 4 * tid);
    float4 b4 = *(const float4*)(beta + 4 * tid);
    float y0 = (v[0] - mean) * rs * g4.x + b4.x;
    float y1 = (v[1] - mean) * rs * g4.y + b4.y;
    float y2 = (v[2] - mean) * rs * g4.z + b4.z;
    float y3 = (v[3] - mean) * rs * g4.w + b4.w;
    __nv_bfloat162 h0, l0, h1, l1;
    split2(y0, y1, h0, l0);
    split2(y2, y3, h1, l1);
    size_t rowW = (size_t)r * (kD / 2);
    int w0 = 2 * tid;
    ((__nv_bfloat162*)hi)[rowW + permWord(w0)]     = h0;
    ((__nv_bfloat162*)hi)[rowW + permWord(w0 + 1)] = h1;
    ((__nv_bfloat162*)lo)[rowW + permWord(w0)]     = l0;
    ((__nv_bfloat162*)lo)[rowW + permWord(w0 + 1)] = l1;
}

// ---------------- RoPE table ----------------
__global__ void rope_table_kernel(float* __restrict__ ct, float* __restrict__ st) {
    int idx = blockIdx.x * blockDim.x + threadIdx.x;
    if (idx >= kS * 16) return;
    int s = idx >> 4, i = idx & 15;
    float inv = (float)(1.0 / pow(10000.0, (double)i / 16.0));
    float f = (float)s * inv;
    ct[idx] = (float)cos((double)f);
    st[idx] = (float)sin((double)f);
}

// ---------------- RoPE + scale + split-bf16, fragment-pair packed ---------
// in: fp32 [row][rowStride], head slice at h*64. out: [row][kID] hi/lo bf16,
// word w = pair (2w, 2w+1) — attention fragment layout.
__global__ void rope_cvt_kernel(const float* __restrict__ in, int rows,
                                int rowStride, int T, int posOff,
                                float scaleAll,
                                const float* __restrict__ ct,
                                const float* __restrict__ st,
                                __nv_bfloat16* __restrict__ hi,
                                __nv_bfloat16* __restrict__ lo) {
    int idx = blockIdx.x * blockDim.x + threadIdx.x;
    if (idx >= rows * kH) return;
    int row = idx / kH, h = idx % kH;
    const float* p = in + (size_t)row * rowStride + h * kDH;
    int pos = posOff + (row % T);
    const float* cr = ct + pos * 16;
    const float* sr = st + pos * 16;
    float v[64];
#pragma unroll
    for (int i = 0; i < 16; i++) {
        float4 q = *(const float4*)(p + 4 * i);
        v[4 * i] = q.x; v[4 * i + 1] = q.y; v[4 * i + 2] = q.z; v[4 * i + 3] = q.w;
    }
#pragma unroll
    for (int i = 0; i < 16; i++) {
        float c = cr[i], s = sr[i];
        float x1 = v[i], x2 = v[i + 16];
        v[i]      = (x1 * c - x2 * s) * scaleAll;
        v[i + 16] = (x2 * c + x1 * s) * scaleAll;
    }
#pragma unroll
    for (int i = 32; i < 64; i++) v[i] *= scaleAll;
    uint32_t hw[32], lw[32];
#pragma unroll
    for (int w = 0; w < 32; w++) pack2(v[2 * w], v[2 * w + 1], hw[w], lw[w]);
    uint32_t* ho = (uint32_t*)(hi + (size_t)row * kID + h * kDH);
    uint32_t* loo = (uint32_t*)(lo + (size_t)row * kID + h * kDH);
#pragma unroll
    for (int w = 0; w < 32; w += 4) {
        *(uint4*)(ho + w) = make_uint4(hw[w], hw[w + 1], hw[w + 2], hw[w + 3]);
        *(uint4*)(loo + w) = make_uint4(lw[w], lw[w + 1], lw[w + 2], lw[w + 3]);
    }
}

// ---------------- V pair-pack: fp32 -> split bf16 [b][h][k2][d] words ------
__global__ void vpack_kernel(const float* __restrict__ vin, int Tk,
                             int rowStride,
                             uint32_t* __restrict__ vph,
                             uint32_t* __restrict__ vpl) {
    int idx = blockIdx.x * blockDim.x + threadIdx.x;
    int tk2 = Tk >> 1;
    int total = kB * kH * tk2 * 16;
    if (idx >= total) return;
    int d4 = (idx & 15) * 4;
    int k2 = (idx >> 4) % tk2;
    int bh = idx / (16 * tk2);
    int b = bh / kH, h = bh % kH;
    const float* p0 = vin + ((size_t)b * Tk + 2 * k2) * rowStride + h * kDH + d4;
    float4 r0 = *(const float4*)p0;
    float4 r1 = *(const float4*)(p0 + rowStride);
    uint32_t h0, l0, h1, l1, h2, l2, h3, l3;
    pack2(r0.x, r1.x, h0, l0);
    pack2(r0.y, r1.y, h1, l1);
    pack2(r0.z, r1.z, h2, l2);
    pack2(r0.w, r1.w, h3, l3);
    size_t base = (((size_t)b * kH + h) * tk2 + k2) * 64 + d4;
    *(uint4*)(vph + base) = make_uint4(h0, h1, h2, h3);
    *(uint4*)(vpl + base) = make_uint4(l0, l1, l2, l3);
}

// ---------------- fp32 -> bf16 hi/lo converter (k-pair permuted) ----------
__global__ void cvt_act_kernel(const float* __restrict__ in,
                               __nv_bfloat16* __restrict__ hi,
                               __nv_bfloat16* __restrict__ lo, int n) {
    int w = blockIdx.x * blockDim.x + threadIdx.x;
    if (w * 2 >= n) return;
    float2 v = *(const float2*)(in + (size_t)w * 2);
    __nv_bfloat162 h, l;
    split2(v.x, v.y, h, l);
    int pw = permWord(w);
    ((__nv_bfloat162*)hi)[pw] = h;
    ((__nv_bfloat162*)lo)[pw] = l;
}

// transpose + convert weights: W[K,N] fp32 -> Wt_hi/lo[Npad,K] bf16,
// k-pair permuted, zero padded.
__global__ void cvt_wt_kernel(const float* __restrict__ W,
                              __nv_bfloat16* __restrict__ whi,
                              __nv_bfloat16* __restrict__ wlo,
                              int K, int N, int Npad) {
    __shared__ float t[32][33];
    int k0 = blockIdx.x * 32, n0 = blockIdx.y * 32;
    int tx = threadIdx.x, ty = threadIdx.y;   // 32 x 8
#pragma unroll
    for (int j = 0; j < 4; j++) {
        int k = k0 + ty + 8 * j;
        float v = (n0 + tx < N) ? W[(size_t)k * N + n0 + tx] : 0.f;
        t[ty + 8 * j][tx] = v;
    }
    __syncthreads();
#pragma unroll
    for (int j = 0; j < 4; j++) {
        int n = n0 + ty + 8 * j;
        int k = k0 + tx;
        float x = t[tx][ty + 8 * j];
        __nv_bfloat16 h = __float2bfloat16(x);
        __nv_bfloat16 l = __float2bfloat16(x - __bfloat162float(h));
        int pk = permWord(k >> 1) * 2 + (k & 1);
        whi[(size_t)n * K + pk] = h;
        wlo[(size_t)n * K + pk] = l;
    }
}

// ---------------- bf16 tensor-core GEMM (3-term split) --------------------
__global__ __launch_bounds__(256, 2) void hgemm_kernel(
    const __nv_bfloat16* __restrict__ Ahi, const __nv_bfloat16* __restrict__ Alo,
    const __nv_bfloat16* __restrict__ Bhi, const __nv_bfloat16* __restrict__ Blo,
    float* __restrict__ C,
    __nv_bfloat16* __restrict__ Chi, __nv_bfloat16* __restrict__ Clo,
    int M, int N, int K,
    const float* __restrict__ bias, const float* __restrict__ res, int act) {
    extern __shared__ uint32_t sm[];
    const int tid  = threadIdx.x;
    const int lane = tid & 31;
    const int warp = tid >> 5;
    const int warpM = warp >> 2;
    const int warpN = warp & 3;
    const int gid = lane >> 2;
    const int tig = lane & 3;
    const int m0 = blockIdx.y * 128, n0 = blockIdx.x * 128;

    float acc[4][4][4] = {};

    auto issue = [&](int stage, int kt) {
        const uint32_t base = stage * kStageWords;
#pragma unroll
        for (int i = 0; i < 8; i++) {
            int c = tid + i * 256;
            int t = c >> 9, w = c & 511;
            int row = w >> 2, ck = w & 3;
            const __nv_bfloat16* src;
            if (t == 0)      src = Ahi + (size_t)(m0 + row) * K + kt + ck * 8;
            else if (t == 1) src = Alo + (size_t)(m0 + row) * K + kt + ck * 8;
            else if (t == 2) src = Bhi + (size_t)(n0 + row) * K + kt + ck * 8;
            else             src = Blo + (size_t)(n0 + row) * K + kt + ck * 8;
            uint32_t dst = (uint32_t)__cvta_generic_to_shared(
                &sm[base + t * kArrWords + row * kRowWords + ck * 4]);
            CP_ASYNC16(dst, src);
        }
    };

    auto compute = [&](int buf) {
        const uint32_t* SAh = sm + buf * kStageWords;
        const uint32_t* SAl = SAh + kArrWords;
        const uint32_t* SBh = SAl + kArrWords;
        const uint32_t* SBl = SBh + kArrWords;
#pragma unroll
        for (int ks = 0; ks < 2; ks++) {
            const int kwb = ks * 8 + 2 * tig;
            uint2 bh[4], bl[4];
#pragma unroll
            for (int in = 0; in < 4; in++) {
                const int n = warpN * 32 + in * 8 + gid;
                bh[in] = *(const uint2*)&SBh[n * kRowWords + kwb];
                bl[in] = *(const uint2*)&SBl[n * kRowWords + kwb];
            }
#pragma unroll
            for (int im = 0; im < 4; im++) {
                const int r = warpM * 64 + im * 16 + gid;
                uint2 uh = *(const uint2*)&SAh[r * kRowWords + kwb];
                uint2 vh = *(const uint2*)&SAh[(r + 8) * kRowWords + kwb];
                uint2 ul = *(const uint2*)&SAl[r * kRowWords + kwb];
                uint2 vl = *(const uint2*)&SAl[(r + 8) * kRowWords + kwb];
                uint32_t ahi[4] = {uh.x, vh.x, uh.y, vh.y};
                uint32_t alo[4] = {ul.x, vl.x, ul.y, vl.y};
#pragma unroll
                for (int in = 0; in < 4; in++) {
                    uint32_t bhw[2] = {bh[in].x, bh[in].y};
                    uint32_t blw[2] = {bl[in].x, bl[in].y};
                    MMA_BF16(acc[im][in], ahi, bhw);
                    MMA_BF16(acc[im][in], ahi, blw);
                    MMA_BF16(acc[im][in], alo, bhw);
                }
            }
        }
    };

    const int nStages = K >> 5;
    issue(0, 0);
    CP_COMMIT();
    for (int s = 0; s < nStages; s++) {
        CP_WAIT0();
        __syncthreads();
        if (s + 1 < nStages) { issue((s + 1) & 1, (s + 1) * 32); CP_COMMIT(); }
        compute(s & 1);
    }

    // ---- epilogue ----
#pragma unroll
    for (int im = 0; im < 4; im++) {
        const int row = m0 + warpM * 64 + im * 16 + gid;
#pragma unroll
        for (int in = 0; in < 4; in++) {
            const int col = n0 + warpN * 32 + in * 8 + 2 * tig;
            if (col >= N) continue;
#pragma unroll
            for (int half = 0; half < 2; half++) {
                const int rr = row + half * 8;
                float c0 = acc[im][in][half * 2 + 0];
                float c1 = acc[im][in][half * 2 + 1];
                if (bias) { c0 += bias[col]; c1 += bias[col + 1]; }
                if (act) {
                    c0 = 0.5f * c0 * (1.f + erff(c0 * 0.70710678118654752f));
                    c1 = 0.5f * c1 * (1.f + erff(c1 * 0.70710678118654752f));
                }
                if (res) {
                    const float2 rv = *(const float2*)(res + (size_t)rr * N + col);
                    c0 += rv.x; c1 += rv.y;
                }
                if (C)
                    *(float2*)(C + (size_t)rr * N + col) = make_float2(c0, c1);
                if (Chi) {
                    __nv_bfloat162 h, l;
                    split2(c0, c1, h, l);
                    size_t rowW = (size_t)rr * (N >> 1);
                    int pw = permWord(col >> 1);
                    ((__nv_bfloat162*)Chi)[rowW + pw] = h;
                    ((__nv_bfloat162*)Clo)[rowW + pw] = l;
                }
            }
        }
    }
}

// ---------------- flash attention on tensor cores (bf16 3-term split) -----
// Inputs preconverted: Q/K split bf16 [token][kID]; V pair-packed
// [b][h][k2][64] words. Staging is pure cp.async.
__global__ __launch_bounds__(256, 2) void attn_kernel(
    const __nv_bfloat16* __restrict__ qhi, const __nv_bfloat16* __restrict__ qlo,
    const __nv_bfloat16* __restrict__ khi, const __nv_bfloat16* __restrict__ klo,
    const uint32_t* __restrict__ vph, const uint32_t* __restrict__ vpl,
    __nv_bfloat16* __restrict__ ohi, __nv_bfloat16* __restrict__ olo,
    int Tq, int Tk, int diag) {
    extern __shared__ uint32_t sa[];
    float* sf = (float*)sa;
    const int tid = threadIdx.x;
    const int lane = tid & 31, warp = tid >> 5;
    const int g = lane >> 2, tg = lane & 3;
    const int warpQ = warp >> 1, warpK = warp & 1;
    const int q0 = blockIdx.x * 64, h = blockIdx.y, b = blockIdx.z;
    const int q0w = warpQ * 16;

    // stage Q via cp.async (64 rows x 8 chunks x 2 arrays)
    {
        const __nv_bfloat16* qh = qhi + ((size_t)(b * Tq + q0)) * kID + h * kDH;
        const __nv_bfloat16* ql = qlo + ((size_t)(b * Tq + q0)) * kID + h * kDH;
#pragma unroll
        for (int i = 0; i < 4; i++) {
            int ch = tid + i * 256;
            int arr = ch >> 9, w = ch & 511;
            int row = w >> 3, ck = w & 7;
            const __nv_bfloat16* src = (arr ? ql : qh) + (size_t)row * kID + ck * 8;
            uint32_t dst = (uint32_t)__cvta_generic_to_shared(
                &sa[(arr ? AQL : AQH) + row * 36 + ck * 4]);
            CP_ASYNC16(dst, src);
        }
        CP_COMMIT();
    }
    if (tid < 64) { sf[AMR + tid] = -1e30f; sf[ALR + tid] = 0.f; }

    float O[4][4] = {};
    int jmax = q0 + 63 + diag;
    int nkt = (jmax + 64) >> 6;
    int maxkt = Tk >> 6;
    if (nkt > maxkt) nkt = maxkt;

    const int r0i = q0w + g, r1i = r0i + 8;
    const int tk2 = Tk >> 1;
    const uint32_t* vhB = vph + ((size_t)b * kH + h) * tk2 * 64;
    const uint32_t* vlB = vpl + ((size_t)b * kH + h) * tk2 * 64;

    for (int kt = 0; kt < nkt; kt++) {
        const int k0 = kt * 64;
        // stage K (64 rows x 8 chunks x 2) + V (32 rows x 16 chunks x 2)
        {
            const __nv_bfloat16* kh = khi + ((size_t)(b * Tk + k0)) * kID + h * kDH;
            const __nv_bfloat16* kl = klo + ((size_t)(b * Tk + k0)) * kID + h * kDH;
#pragma unroll
            for (int i = 0; i < 4; i++) {
                int ch = tid + i * 256;
                int arr = ch >> 9, w = ch & 511;
                int row = w >> 3, ck = w & 7;
                const __nv_bfloat16* src = (arr ? kl : kh) + (size_t)row * kID + ck * 8;
                uint32_t dst = (uint32_t)__cvta_generic_to_shared(
                    &sa[(arr ? AKL : AKH) + row * 36 + ck * 4]);
                CP_ASYNC16(dst, src);
            }
            const uint32_t* vh = vhB + (size_t)(k0 >> 1) * 64;
            const uint32_t* vl = vlB + (size_t)(k0 >> 1) * 64;
#pragma unroll
            for (int i = 0; i < 4; i++) {
                int ch = tid + i * 256;
                int arr = ch >> 9, w = ch & 511;
                int k2 = w >> 4, ck = w & 15;
                const uint32_t* src = (arr ? vl : vh) + k2 * 64 + ck * 4;
                uint32_t dst = (uint32_t)__cvta_generic_to_shared(
                    &sa[(arr ? AVL : AVH) + k2 * 72 + ck * 4]);
                CP_ASYNC16(dst, src);
            }
            CP_COMMIT();
        }
        CP_WAIT0();
        __syncthreads();   // A: staging complete

        // ---- S = Q @ K^T ----
        float s[4][4];
#pragma unroll
        for (int nt = 0; nt < 4; nt++)
#pragma unroll
            for (int j = 0; j < 4; j++) s[nt][j] = 0.f;
#pragma unroll
        for (int ck = 0; ck < 4; ck++) {
            const int ac = ck * 8 + tg;
            uint32_t ahi[4] = {
                sa[AQH + r0i * 36 + ac], sa[AQH + r1i * 36 + ac],
                sa[AQH + r0i * 36 + ac + 4], sa[AQH + r1i * 36 + ac + 4]};
            uint32_t alo[4] = {
                sa[AQL + r0i * 36 + ac], sa[AQL + r1i * 36 + ac],
                sa[AQL + r0i * 36 + ac + 4], sa[AQL + r1i * 36 + ac + 4]};
#pragma unroll
            for (int nt = 0; nt < 4; nt++) {
                const int key = warpK * 32 + nt * 8 + g;
                uint32_t bhi[2] = {sa[AKH + key * 36 + ac],
                                   sa[AKH + key * 36 + ac + 4]};
                uint32_t blo[2] = {sa[AKL + key * 36 + ac],
                                   sa[AKL + key * 36 + ac + 4]};
                MMA_BF16(s[nt], ahi, bhi);
                MMA_BF16(s[nt], ahi, blo);
                MMA_BF16(s[nt], alo, bhi);
            }
        }
        // ---- causal mask ----
        if (k0 + 63 > q0 + diag) {
            int qr0 = q0 + r0i + diag;
            int qr1 = qr0 + 8;
#pragma unroll
            for (int nt = 0; nt < 4; nt++) {
                int cb = k0 + warpK * 32 + nt * 8 + 2 * tg;
                if (cb > qr0)     s[nt][0] = -1e30f;
                if (cb + 1 > qr0) s[nt][1] = -1e30f;
                if (cb > qr1)     s[nt][2] = -1e30f;
                if (cb + 1 > qr1) s[nt][3] = -1e30f;
            }
        }
        // ---- row max ----
        float mx0 = -1e30f, mx1 = -1e30f;
#pragma unroll
        for (int nt = 0; nt < 4; nt++) {
            mx0 = fmaxf(mx0, fmaxf(s[nt][0], s[nt][1]));
            mx1 = fmaxf(mx1, fmaxf(s[nt][2], s[nt][3]));
        }
        mx0 = fmaxf(mx0, __shfl_xor_sync(0xffffffffu, mx0, 1));
        mx0 = fmaxf(mx0, __shfl_xor_sync(0xffffffffu, mx0, 2));
        mx1 = fmaxf(mx1, __shfl_xor_sync(0xffffffffu, mx1, 1));
        mx1 = fmaxf(mx1, __shfl_xor_sync(0xffffffffu, mx1, 2));
        if (tg == 0) {
            sf[AMX + r0i * 2 + warpK] = mx0;
            sf[AMX + r1i * 2 + warpK] = mx1;
        }
        __syncthreads();   // B: maxes visible

        float mold0 = sf[AMR + r0i], mold1 = sf[AMR + r1i];
        float lold0 = sf[ALR + r0i], lold1 = sf[ALR + r1i];
        float mnew0 = fmaxf(mold0, fmaxf(sf[AMX + r0i * 2], sf[AMX + r0i * 2 + 1]));
        float mnew1 = fmaxf(mold1, fmaxf(sf[AMX + r1i * 2], sf[AMX + r1i * 2 + 1]));
        float f0 = __expf(mold0 - mnew0);
        float f1 = __expf(mold1 - mnew1);
        float sum0 = 0.f, sum1 = 0.f;
#pragma unroll
        for (int nt = 0; nt < 4; nt++) {
            float p00 = __expf(s[nt][0] - mnew0);
            float p01 = __expf(s[nt][1] - mnew0);
            float p10 = __expf(s[nt][2] - mnew1);
            float p11 = __expf(s[nt][3] - mnew1);
            sum0 += p00 + p01; sum1 += p10 + p11;
            uint32_t hw, lw;
            const int pc = warpK * 16 + nt * 4 + tg;
            pack2(p00, p01, hw, lw);
            sa[APH + r0i * 36 + pc] = hw; sa[APL + r0i * 36 + pc] = lw;
            pack2(p10, p11, hw, lw);
            sa[APH + r1i * 36 + pc] = hw; sa[APL + r1i * 36 + pc] = lw;
        }
        sum0 += __shfl_xor_sync(0xffffffffu, sum0, 1);
        sum0 += __shfl_xor_sync(0xffffffffu, sum0, 2);
        sum1 += __shfl_xor_sync(0xffffffffu, sum1, 1);
        sum1 += __shfl_xor_sync(0xffffffffu, sum1, 2);
        if (tg == 0) {
            sf[ASM + r0i * 2 + warpK] = sum0;
            sf[ASM + r1i * 2 + warpK] = sum1;
        }
        __syncthreads();  // C: P + sums visible

        // ---- rescale O, then O += P @ V ----
#pragma unroll
        for (int nt = 0; nt < 4; nt++) {
            O[nt][0] *= f0; O[nt][1] *= f0;
            O[nt][2] *= f1; O[nt][3] *= f1;
        }
#pragma unroll
        for (int kk = 0; kk < 4; kk++) {
            const int pc = kk * 8 + tg;
            uint32_t ahi[4] = {
                sa[APH + r0i * 36 + pc], sa[APH + r1i * 36 + pc],
                sa[APH + r0i * 36 + pc + 4], sa[APH + r1i * 36 + pc + 4]};
            uint32_t alo[4] = {
                sa[APL + r0i * 36 + pc], sa[APL + r1i * 36 + pc],
                sa[APL + r0i * 36 + pc + 4], sa[APL + r1i * 36 + pc + 4]};
#pragma unroll
            for (int nt = 0; nt < 4; nt++) {
                const int d0 = warpK * 32 + nt * 8 + g;
                uint32_t bhi[2] = {sa[AVH + (kk * 8 + tg) * 72 + d0],
                                   sa[AVH + (kk * 8 + 4 + tg) * 72 + d0]};
                uint32_t blo[2] = {sa[AVL + (kk * 8 + tg) * 72 + d0],
                                   sa[AVL + (kk * 8 + 4 + tg) * 72 + d0]};
                MMA_BF16(O[nt], ahi, bhi);
                MMA_BF16(O[nt], ahi, blo);
                MMA_BF16(O[nt], alo, bhi);
            }
        }
        // ---- state update ----
        if (warpK == 0 && tg == 0) {
            sf[AMR + r0i] = mnew0;
            sf[AMR + r1i] = mnew1;
            sf[ALR + r0i] = lold0 * f0 + sf[ASM + r0i * 2] + sf[ASM + r0i * 2 + 1];
            sf[ALR + r1i] = lold1 * f1 + sf[ASM + r1i * 2] + sf[ASM + r1i * 2 + 1];
        }
        __syncthreads();  // D: state final; K/V/P safe to overwrite
    }

    // ---- write output (split bf16, permuted, GEMM-ready) ----
    float inv0 = 1.f / sf[ALR + r0i];
    float inv1 = 1.f / sf[ALR + r1i];
    size_t rowW0 = ((size_t)b * Tq + q0 + r0i) * (kID / 2);
    size_t rowW1 = ((size_t)b * Tq + q0 + r1i) * (kID / 2);
#pragma unroll
    for (int nt = 0; nt < 4; nt++) {
        int col = h * kDH + warpK * 32 + nt * 8 + 2 * tg;
        int w0 = col >> 1;
        uint32_t hw, lw;
        pack2(O[nt][0] * inv0, O[nt][1] * inv0, hw, lw);
        ((uint32_t*)ohi)[rowW0 + permWord(w0)] = hw;
        ((uint32_t*)olo)[rowW0 + permWord(w0)] = lw;
        pack2(O[nt][2] * inv1, O[nt][3] * inv1, hw, lw);
        ((uint32_t*)ohi)[rowW1 + permWord(w0)] = hw;
        ((uint32_t*)olo)[rowW1 + permWord(w0)] = lw;
    }
}

// ---------------- host orchestration ----------------
namespace {
__nv_bfloat16 *h_whi, *h_wlo, *h_ahi, *h_alo;
__nv_bfloat16 *h_qhi, *h_qlo, *h_khi, *h_klo;
uint32_t *h_vph, *h_vpl;

inline void gemm(size_t aOff, size_t wOff, float* C,
                 __nv_bfloat16* chi, __nv_bfloat16* clo,
                 int M, int N, int Npad, int K,
                 const float* bias, const float* res, int act) {
    dim3 g(Npad / 128, M / 128);
    hgemm_kernel<<<g, 256, kGemmSmem>>>(
        h_ahi + aOff, h_alo + aOff, h_whi + wOff, h_wlo + wOff,
        C, chi, clo, M, N, K, bias, res, act);
}
}

extern "C" void kernel_launch(void* const* d_in, const int* in_sizes, int n_in,
                              void* d_out, int out_size) {
    const int*   x           = (const int*)d_in[0];
    // d_in[1] = prefix_mask: all-True and padded True => no-op; unused.
    const float* token_emb   = (const float*)d_in[2];
    const float* pos_emb     = (const float*)d_in[3];
    const float* ca_norm_s   = (const float*)d_in[4];
    const float* ca_norm_b   = (const float*)d_in[5];
    const float* ca_ctx_ns   = (const float*)d_in[6];
    const float* ca_ctx_nb   = (const float*)d_in[7];
    const float* ca_wq       = (const float*)d_in[8];
    const float* ca_wkv      = (const float*)d_in[9];
    const float* ca_wo       = (const float*)d_in[10];
    const float* ca_bo       = (const float*)d_in[11];
    const float* ca_ff_ln_s  = (const float*)d_in[12];
    const float* ca_ff_ln_b  = (const float*)d_in[13];
    const float* ca_ff_w1    = (const float*)d_in[14];
    const float* ca_ff_w2    = (const float*)d_in[15];
    const float* l_norm_s    = (const float*)d_in[16];
    const float* l_norm_b    = (const float*)d_in[17];
    const float* l_wqkv      = (const float*)d_in[18];
    const float* l_wo        = (const float*)d_in[19];
    const float* l_ff_ln_s   = (const float*)d_in[20];
    const float* l_ff_ln_b   = (const float*)d_in[21];
    const float* l_ff_w1     = (const float*)d_in[22];
    const float* l_ff_w2     = (const float*)d_in[23];
    const float* w_logits    = (const float*)d_in[24];
    float* out = (float*)d_out;

    float *prefix, *lat, *qb, *kv, *qkv, *ctab, *stab;
    cudaGetSymbolAddress((void**)&prefix, g_prefix);
    cudaGetSymbolAddress((void**)&lat,    g_lat);
    cudaGetSymbolAddress((void**)&qb,     g_q);
    cudaGetSymbolAddress((void**)&kv,     g_kv);
    cudaGetSymbolAddress((void**)&qkv,    g_qkv);
    cudaGetSymbolAddress((void**)&ctab,   g_cos);
    cudaGetSymbolAddress((void**)&stab,   g_sin);
    cudaGetSymbolAddress((void**)&h_whi,  g_whi);
    cudaGetSymbolAddress((void**)&h_wlo,  g_wlo);
    cudaGetSymbolAddress((void**)&h_ahi,  g_ahi);
    cudaGetSymbolAddress((void**)&h_alo,  g_alo);
    cudaGetSymbolAddress((void**)&h_qhi,  g_qhi);
    cudaGetSymbolAddress((void**)&h_qlo,  g_qlo);
    cudaGetSymbolAddress((void**)&h_khi,  g_khi);
    cudaGetSymbolAddress((void**)&h_klo,  g_klo);
    cudaGetSymbolAddress((void**)&h_vph,  g_vph);
    cudaGetSymbolAddress((void**)&h_vpl,  g_vpl);

    cudaFuncSetAttribute(hgemm_kernel,
                         cudaFuncAttributeMaxDynamicSharedMemorySize, kGemmSmem);
    cudaFuncSetAttribute(attn_kernel,
                         cudaFuncAttributeMaxDynamicSharedMemorySize, kAttnSmem);

    // 0. convert + transpose all weights into bf16 hi/lo arenas
    auto cw = [&](const float* W, size_t off, int K, int N, int Npad) {
        dim3 g(K / 32, Npad / 32);
        cvt_wt_kernel<<<g, dim3(32, 8)>>>(W, h_whi + off, h_wlo + off, K, N, Npad);
    };
    cw(ca_wq,    OFF_CAWQ,  1024, 1024, 1024);
    cw(ca_wkv,   OFF_CAWKV, 1024, 2048, 2048);
    cw(ca_wo,    OFF_CAWO,  1024, 1024, 1024);
    cw(ca_ff_w1, OFF_CAFF1, 1024, 4096, 4096);
    cw(ca_ff_w2, OFF_CAFF2, 4096, 1024, 1024);
    for (int li = 0; li < kL; li++) {
        cw(l_wqkv  + (size_t)li * 1024 * 3072, OFF_LQKV + (size_t)li * 3072 * 1024, 1024, 3072, 3072);
        cw(l_wo    + (size_t)li * 1024 * 1024, OFF_LWO  + (size_t)li * 1024 * 1024, 1024, 1024, 1024);
        cw(l_ff_w1 + (size_t)li * 1024 * 4096, OFF_LFF1 + (size_t)li * 4096 * 1024, 1024, 4096, 4096);
        cw(l_ff_w2 + (size_t)li * 4096 * 1024, OFF_LFF2 + (size_t)li * 1024 * 4096, 4096, 1024, 1024);
    }
    cw(w_logits, OFF_LOGITS, 1024, kV, kVp);

    // 1. embeddings + rope tables
    embed_kernel<<<kB * kS, 256>>>(x, token_emb, pos_emb, prefix, lat);
    rope_table_kernel<<<(kS * 16 + 255) / 256, 256>>>(ctab, stab);

    // 2. cross-attention block
    ln_bf16_kernel<<<kB * kNL, 256>>>(lat,    ca_norm_s, ca_norm_b,
                                      h_ahi + A0,  h_alo + A0);
    ln_bf16_kernel<<<kB * kP,  256>>>(prefix, ca_ctx_ns, ca_ctx_nb,
                                      h_ahi + ACN, h_alo + ACN);

    for (int b = 0; b < kB; b++)
        gemm(ACN + (size_t)b * kP * kD, OFF_CAWKV,
             kv + (size_t)b * kS * 2 * kID, nullptr, nullptr,
             kP, 2 * kID, 2 * kID, kD, nullptr, nullptr, 0);
    gemm(A0, OFF_CAWQ, qb, nullptr, nullptr,
         kB * kNL, kID, kID, kD, nullptr, nullptr, 0);
    for (int b = 0; b < kB; b++)
        gemm(A0 + (size_t)b * kNL * kD, OFF_CAWKV,
             kv + ((size_t)b * kS + kP) * 2 * kID, nullptr, nullptr,
             kNL, 2 * kID, 2 * kID, kD, nullptr, nullptr, 0);

    {
        int rq = kB * kNL * kH, rk = kB * kS * kH;
        rope_cvt_kernel<<<(rq + 255) / 256, 256>>>(
            qb, kB * kNL, kID, kNL, kP, kScale, ctab, stab, h_qhi, h_qlo);
        rope_cvt_kernel<<<(rk + 255) / 256, 256>>>(
            kv, kB * kS, 2 * kID, kS, 0, 1.f, ctab, stab, h_khi, h_klo);
        int vt = kB * kH * (kS / 2) * 16;
        vpack_kernel<<<(vt + 255) / 256, 256>>>(kv + kID, kS, 2 * kID,
                                                h_vph, h_vpl);
    }
    attn_kernel<<<dim3(kNL / 64, kH, kB), 256, kAttnSmem>>>(
        h_qhi, h_qlo, h_khi, h_klo, h_vph, h_vpl,
        h_ahi + A0, h_alo + A0, kNL, kS, kP);

    gemm(A0, OFF_CAWO, lat, nullptr, nullptr,
         kB * kNL, kD, kD, kID, ca_bo, lat, 0);

    ln_bf16_kernel<<<kB * kNL, 256>>>(lat, ca_ff_ln_s, ca_ff_ln_b,
                                      h_ahi + A0, h_alo + A0);
    gemm(A0, OFF_CAFF1, nullptr, h_ahi + AFF, h_alo + AFF,
         kB * kNL, kFF, kFF, kD, nullptr, nullptr, 1);
    gemm(AFF, OFF_CAFF2, lat, nullptr, nullptr,
         kB * kNL, kD, kD, kFF, nullptr, lat, 0);

    // 3. latent self-attention layers
    for (int li = 0; li < kL; li++) {
        ln_bf16_kernel<<<kB * kNL, 256>>>(lat, l_norm_s + li * kD,
                                          l_norm_b + li * kD,
                                          h_ahi + A0, h_alo + A0);
        gemm(A0, OFF_LQKV + (size_t)li * 3072 * 1024, qkv, nullptr, nullptr,
             kB * kNL, 3 * kID, 3 * kID, kD, nullptr, nullptr, 0);

        int rq = kB * kNL * kH;
        rope_cvt_kernel<<<(rq + 255) / 256, 256>>>(
            qkv, kB * kNL, 3 * kID, kNL, kP, kScale, ctab, stab, h_qhi, h_qlo);
        rope_cvt_kernel<<<(rq + 255) / 256, 256>>>(
            qkv + kID, kB * kNL, 3 * kID, kNL, kP, 1.f, ctab, stab, h_khi, h_klo);
        int vt = kB * kH * (kNL / 2) * 16;
        vpack_kernel<<<(vt + 255) / 256, 256>>>(qkv + 2 * kID, kNL, 3 * kID,
                                                h_vph, h_vpl);
        attn_kernel<<<dim3(kNL / 64, kH, kB), 256, kAttnSmem>>>(
            h_qhi, h_qlo, h_khi, h_klo, h_vph, h_vpl,
            h_ahi + A0, h_alo + A0, kNL, kNL, 0);

        gemm(A0, OFF_LWO + (size_t)li * 1024 * 1024, lat, nullptr, nullptr,
             kB * kNL, kD, kD, kID, nullptr, lat, 0);

        ln_bf16_kernel<<<kB * kNL, 256>>>(lat, l_ff_ln_s + li * kD,
                                          l_ff_ln_b + li * kD,
                                          h_ahi + A0, h_alo + A0);
        gemm(A0, OFF_LFF1 + (size_t)li * 4096 * 1024, nullptr,
             h_ahi + AFF, h_alo + AFF,
             kB * kNL, kFF, kFF, kD, nullptr, nullptr, 1);
        gemm(AFF, OFF_LFF2 + (size_t)li * 1024 * 4096, lat, nullptr, nullptr,
             kB * kNL, kD, kD, kFF, nullptr, lat, 0);
    }

    // 4. logits head
    {
        size_t n = (size_t)kB * kNL * kD;
        cvt_act_kernel<<<(int)((n / 2 + 255) / 256), 256>>>(
            lat, h_ahi + A0, h_alo + A0, (int)n);
    }
    gemm(A0, OFF_LOGITS, out, nullptr, nullptr,
         kB * kNL, kV, kVp, kD, nullptr, nullptr, 0);
}

// round 11
// speedup vs baseline: 2.8969x; 1.0087x over previous
#include <cuda_runtime.h>
#include <cuda_bf16.h>
#include <math.h>
#include <stdint.h>

// ---------------- problem constants ----------------
namespace {
constexpr int kB  = 2;
constexpr int kS  = 2048;
constexpr int kP  = 512;
constexpr int kNL = 1536;   // latent tokens = S - P
constexpr int kD  = 1024;
constexpr int kH  = 16;
constexpr int kDH = 64;
constexpr int kID = 1024;   // H * DH
constexpr int kV  = 20000;
constexpr int kVp = 20096;  // padded to 128
constexpr int kL  = 4;
constexpr int kFF = 4096;
constexpr float kScale = 0.125f;   // DH^-0.5
constexpr float kEps   = 1e-5f;

// weight arena offsets (transposed [N][K] layout, elements)
constexpr size_t OFF_CAWQ   = 0;                                  // 1024x1024
constexpr size_t OFF_CAWKV  = OFF_CAWQ  + 1024ull * 1024;         // 2048x1024
constexpr size_t OFF_CAWO   = OFF_CAWKV + 2048ull * 1024;         // 1024x1024
constexpr size_t OFF_CAFF1  = OFF_CAWO  + 1024ull * 1024;         // 4096x1024
constexpr size_t OFF_CAFF2  = OFF_CAFF1 + 4096ull * 1024;         // 1024x4096
constexpr size_t OFF_LQKV   = OFF_CAFF2 + 1024ull * 4096;         // 4 x 3072x1024
constexpr size_t OFF_LWO    = OFF_LQKV  + 4ull * 3072 * 1024;     // 4 x 1024x1024
constexpr size_t OFF_LFF1   = OFF_LWO   + 4ull * 1024 * 1024;     // 4 x 4096x1024
constexpr size_t OFF_LFF2   = OFF_LFF1  + 4ull * 4096 * 1024;     // 4 x 1024x4096
constexpr size_t OFF_LOGITS = OFF_LFF2  + 4ull * 1024 * 4096;     // 20096x1024
constexpr size_t W_TOTAL    = OFF_LOGITS + (size_t)kVp * 1024;

// activation arena regions (elements)
constexpr size_t A0   = 0;                                // xn/tmp/att/lat-cvt
constexpr size_t AFF  = (size_t)kB * kNL * kD;            // GELU(ff1) output
constexpr size_t ACN  = AFF + (size_t)kB * kNL * kFF;     // cn (prefix LN)
constexpr size_t A_TOTAL = ACN + (size_t)kB * kP * kD;

// hgemm smem: 2 stages x 4 arrays x 128 rows x 24 uint32 words
constexpr int kRowWords   = 24;                      // 16 data + 8 pad
constexpr int kArrWords   = 128 * kRowWords;         // 3072
constexpr int kStageWords = 4 * kArrWords;           // 12288
constexpr int kGemmSmem   = 2 * kStageWords * 4;     // 98304 bytes

// attention smem layout (uint32 word offsets)
constexpr int AQH = 0;                // Q hi  64 x 36
constexpr int AQL = AQH + 64 * 36;
constexpr int AKH = AQL + 64 * 36;    // K hi  64 x 36
constexpr int AKL = AKH + 64 * 36;
constexpr int AVH = AKL + 64 * 36;    // V hi  32 kpairs x 72
constexpr int AVL = AVH + 32 * 72;
constexpr int APH = AVL + 32 * 72;    // P hi  64 x 36
constexpr int APL = APH + 64 * 36;
constexpr int AMR = APL + 64 * 36;    // mrow[64] (float)
constexpr int ALR = AMR + 64;         // lrow[64]
constexpr int AMX = ALR + 64;         // smMax[64][2]
constexpr int ASM = AMX + 128;        // smSum[64][2]
constexpr int kAttnWords = ASM + 128; // 18816
constexpr int kAttnSmem  = kAttnWords * 4;  // 75264 bytes
}

// ---------------- scratch (module-load allocated, legal) ----------------
__device__ float g_prefix[kB * kP * kD];
__device__ float g_lat   [kB * kNL * kD];
__device__ float g_q     [kB * kNL * kID];
__device__ float g_kv    [kB * kS * 2 * kID];
__device__ float g_qkv   [kB * kNL * 3 * kID];
__device__ float g_cos   [kS * 16];
__device__ float g_sin   [kS * 16];
__device__ __nv_bfloat16 g_whi[W_TOTAL];
__device__ __nv_bfloat16 g_wlo[W_TOTAL];
__device__ __nv_bfloat16 g_ahi[A_TOTAL];
__device__ __nv_bfloat16 g_alo[A_TOTAL];
// attention operand buffers (split bf16, fragment-pair packed)
__device__ __nv_bfloat16 g_qhi[kB * kNL * kID];
__device__ __nv_bfloat16 g_qlo[kB * kNL * kID];
__device__ __nv_bfloat16 g_khi[kB * kS * kID];
__device__ __nv_bfloat16 g_klo[kB * kS * kID];
__device__ uint32_t g_vph[(size_t)kB * kH * (kS / 2) * 64];
__device__ uint32_t g_vpl[(size_t)kB * kH * (kS / 2) * 64];

// ---------------- low-level helpers ----------------
__device__ __forceinline__ float warpSum(float v) {
#pragma unroll
    for (int o = 16; o; o >>= 1) v += __shfl_xor_sync(0xffffffffu, v, o);
    return v;
}

// k-pair permutation: within each 8-word group, word w8 -> (w8&3)*2 + (w8>>2)
__device__ __forceinline__ int permWord(int w) {
    int w8 = w & 7;
    return (w & ~7) + ((w8 & 3) << 1) + (w8 >> 2);
}

__device__ __forceinline__ void split2(float a, float b,
                                       __nv_bfloat162& h, __nv_bfloat162& l) {
    __nv_bfloat16 h0 = __float2bfloat16(a);
    __nv_bfloat16 h1 = __float2bfloat16(b);
    h.x = h0; h.y = h1;
    l.x = __float2bfloat16(a - __bfloat162float(h0));
    l.y = __float2bfloat16(b - __bfloat162float(h1));
}

__device__ __forceinline__ void pack2(float a, float b,
                                      uint32_t& hw, uint32_t& lw) {
    __nv_bfloat162 h, l;
    split2(a, b, h, l);
    hw = *reinterpret_cast<uint32_t*>(&h);
    lw = *reinterpret_cast<uint32_t*>(&l);
}

#define MMA_BF16(c, a, b)                                                   \
    asm volatile(                                                           \
        "mma.sync.aligned.m16n8k16.row.col.f32.bf16.bf16.f32 "              \
        "{%0,%1,%2,%3}, {%4,%5,%6,%7}, {%8,%9}, {%0,%1,%2,%3};"             \
        : "+f"((c)[0]), "+f"((c)[1]), "+f"((c)[2]), "+f"((c)[3])            \
        : "r"((a)[0]), "r"((a)[1]), "r"((a)[2]), "r"((a)[3]),               \
          "r"((b)[0]), "r"((b)[1]))

#define CP_ASYNC16(dst, src)                                                \
    asm volatile("cp.async.cg.shared.global [%0], [%1], 16;"                \
                 :: "r"(dst), "l"(src))
#define CP_COMMIT() asm volatile("cp.async.commit_group;")
#define CP_WAIT0()  asm volatile("cp.async.wait_group 0;")

// ---------------- embedding ----------------
__global__ void embed_kernel(const int* __restrict__ x,
                             const float* __restrict__ te,
                             const float* __restrict__ pe,
                             float* __restrict__ prefix,
                             float* __restrict__ lat) {
    int row = blockIdx.x;
    int b = row / kS, s = row % kS;
    int tok = x[row];
    const float* tr = te + (size_t)tok * kD;
    const float* pr = pe + (size_t)s * kD;
    float* dst = (s < kP) ? (prefix + ((size_t)b * kP + s) * kD)
                          : (lat    + ((size_t)b * kNL + (s - kP)) * kD);
    for (int i = threadIdx.x; i < kD; i += blockDim.x) dst[i] = tr[i] + pr[i];
}

// ---------------- LayerNorm -> split bf16 (permuted) ----------------
__global__ __launch_bounds__(256) void ln_bf16_kernel(
    const float* __restrict__ in, const float* __restrict__ gamma,
    const float* __restrict__ beta,
    __nv_bfloat16* __restrict__ hi, __nv_bfloat16* __restrict__ lo) {
    int r = blockIdx.x;
    const float* xr = in + (size_t)r * kD;
    int tid = threadIdx.x;
    float4 v4 = *(const float4*)(xr + 4 * tid);
    float v[4] = {v4.x, v4.y, v4.z, v4.w};
    float s = v[0] + v[1] + v[2] + v[3];
    __shared__ float red[8];
    __shared__ float meanS, rstdS;
    s = warpSum(s);
    if ((tid & 31) == 0) red[tid >> 5] = s;
    __syncthreads();
    if (tid < 32) {
        float t = (tid < 8) ? red[tid] : 0.f;
        t = warpSum(t);
        if (tid == 0) meanS = t * (1.f / kD);
    }
    __syncthreads();
    float mean = meanS;
    float s2 = 0.f;
#pragma unroll
    for (int i = 0; i < 4; i++) { float d = v[i] - mean; s2 += d * d; }
    s2 = warpSum(s2);
    __syncthreads();
    if ((tid & 31) == 0) red[tid >> 5] = s2;
    __syncthreads();
    if (tid < 32) {
        float t = (tid < 8) ? red[tid] : 0.f;
        t = warpSum(t);
        if (tid == 0) rstdS = rsqrtf(t * (1.f / kD) + kEps);
    }
    __syncthreads();
    float rs = rstdS;
    float4 g4 = *(const float4*)(gamma + 4 * tid);
    float4 b4 = *(const float4*)(beta + 4 * tid);
    float y0 = (v[0] - mean) * rs * g4.x + b4.x;
    float y1 = (v[1] - mean) * rs * g4.y + b4.y;
    float y2 = (v[2] - mean) * rs * g4.z + b4.z;
    float y3 = (v[3] - mean) * rs * g4.w + b4.w;
    __nv_bfloat162 h0, l0, h1, l1;
    split2(y0, y1, h0, l0);
    split2(y2, y3, h1, l1);
    size_t rowW = (size_t)r * (kD / 2);
    int w0 = 2 * tid;
    ((__nv_bfloat162*)hi)[rowW + permWord(w0)]     = h0;
    ((__nv_bfloat162*)hi)[rowW + permWord(w0 + 1)] = h1;
    ((__nv_bfloat162*)lo)[rowW + permWord(w0)]     = l0;
    ((__nv_bfloat162*)lo)[rowW + permWord(w0 + 1)] = l1;
}

// ---------------- RoPE table ----------------
__global__ void rope_table_kernel(float* __restrict__ ct, float* __restrict__ st) {
    int idx = blockIdx.x * blockDim.x + threadIdx.x;
    if (idx >= kS * 16) return;
    int s = idx >> 4, i = idx & 15;
    float inv = (float)(1.0 / pow(10000.0, (double)i / 16.0));
    float f = (float)s * inv;
    ct[idx] = (float)cos((double)f);
    st[idx] = (float)sin((double)f);
}

// ---------------- RoPE + scale + split-bf16 (warp per row-head) -----------
// Lane l owns output word l (values 2l, 2l+1). Rotation partner via shfl.
// Fully coalesced 128B reads/writes per warp.
__global__ __launch_bounds__(256) void rope_cvt_kernel(
    const float* __restrict__ in, int rows, int rowStride, int T, int posOff,
    float scaleAll, const float* __restrict__ ct, const float* __restrict__ st,
    __nv_bfloat16* __restrict__ hi, __nv_bfloat16* __restrict__ lo) {
    int warp = threadIdx.x >> 5, lane = threadIdx.x & 31;
    int idx = blockIdx.x * 8 + warp;
    if (idx >= rows * kH) return;
    int row = idx / kH, h = idx % kH;
    const float* p = in + (size_t)row * rowStride + h * kDH;
    int pos = posOff + (row % T);
    float2 v = *(const float2*)(p + 2 * lane);
    float ox = __shfl_xor_sync(0xffffffffu, v.x, 8);
    float oy = __shfl_xor_sync(0xffffffffu, v.y, 8);
    float y0, y1;
    if (lane < 8) {
        float c0 = ct[pos * 16 + 2 * lane],     s0 = st[pos * 16 + 2 * lane];
        float c1 = ct[pos * 16 + 2 * lane + 1], s1 = st[pos * 16 + 2 * lane + 1];
        y0 = v.x * c0 - ox * s0;
        y1 = v.y * c1 - oy * s1;
    } else if (lane < 16) {
        int i = 2 * lane - 16;
        float c0 = ct[pos * 16 + i],     s0 = st[pos * 16 + i];
        float c1 = ct[pos * 16 + i + 1], s1 = st[pos * 16 + i + 1];
        y0 = v.x * c0 + ox * s0;
        y1 = v.y * c1 + oy * s1;
    } else {
        y0 = v.x; y1 = v.y;
    }
    y0 *= scaleAll; y1 *= scaleAll;
    uint32_t hw, lw;
    pack2(y0, y1, hw, lw);
    size_t w = (size_t)row * (kID / 2) + h * 32 + lane;
    ((uint32_t*)hi)[w] = hw;
    ((uint32_t*)lo)[w] = lw;
}

// ---------------- V pair-pack: fp32 -> split bf16 [b][h][k2][d] words ------
__global__ void vpack_kernel(const float* __restrict__ vin, int Tk,
                             int rowStride,
                             uint32_t* __restrict__ vph,
                             uint32_t* __restrict__ vpl) {
    int idx = blockIdx.x * blockDim.x + threadIdx.x;
    int tk2 = Tk >> 1;
    int total = kB * kH * tk2 * 16;
    if (idx >= total) return;
    int d4 = (idx & 15) * 4;
    int k2 = (idx >> 4) % tk2;
    int bh = idx / (16 * tk2);
    int b = bh / kH, h = bh % kH;
    const float* p0 = vin + ((size_t)b * Tk + 2 * k2) * rowStride + h * kDH + d4;
    float4 r0 = *(const float4*)p0;
    float4 r1 = *(const float4*)(p0 + rowStride);
    uint32_t h0, l0, h1, l1, h2, l2, h3, l3;
    pack2(r0.x, r1.x, h0, l0);
    pack2(r0.y, r1.y, h1, l1);
    pack2(r0.z, r1.z, h2, l2);
    pack2(r0.w, r1.w, h3, l3);
    size_t base = (((size_t)b * kH + h) * tk2 + k2) * 64 + d4;
    *(uint4*)(vph + base) = make_uint4(h0, h1, h2, h3);
    *(uint4*)(vpl + base) = make_uint4(l0, l1, l2, l3);
}

// ---------------- fp32 -> bf16 hi/lo converter (k-pair permuted) ----------
__global__ void cvt_act_kernel(const float* __restrict__ in,
                               __nv_bfloat16* __restrict__ hi,
                               __nv_bfloat16* __restrict__ lo, int n) {
    int w = blockIdx.x * blockDim.x + threadIdx.x;
    if (w * 2 >= n) return;
    float2 v = *(const float2*)(in + (size_t)w * 2);
    __nv_bfloat162 h, l;
    split2(v.x, v.y, h, l);
    int pw = permWord(w);
    ((__nv_bfloat162*)hi)[pw] = h;
    ((__nv_bfloat162*)lo)[pw] = l;
}

// transpose + convert weights: W[K,N] fp32 -> Wt_hi/lo[Npad,K] bf16,
// k-pair permuted, zero padded. Tile 64(k) x 32(n); whole-word writes.
// Store loop: 32 n-rows per tile, 4 per thread (j < 4). Each thread owns
// k-pair word (k0/2 + tx).
__global__ void cvt_wt_kernel(const float* __restrict__ W,
                              __nv_bfloat16* __restrict__ whi,
                              __nv_bfloat16* __restrict__ wlo,
                              int K, int N, int Npad) {
    __shared__ float t[64][33];
    int k0 = blockIdx.x * 64, n0 = blockIdx.y * 32;
    int tx = threadIdx.x, ty = threadIdx.y;   // 32 x 8
    bool nOK = (n0 + tx) < N;
#pragma unroll
    for (int j = 0; j < 8; j++) {
        int k = k0 + ty + 8 * j;
        float v = nOK ? W[(size_t)k * N + n0 + tx] : 0.f;
        t[ty + 8 * j][tx] = v;
    }
    __syncthreads();
    uint32_t* wh = (uint32_t*)whi;
    uint32_t* wl = (uint32_t*)wlo;
    int pw = permWord((k0 >> 1) + tx);
#pragma unroll
    for (int j = 0; j < 4; j++) {
        int nl = ty + 8 * j;                 // 0..31 (tile-local n)
        int n = n0 + nl;
        float a = t[2 * tx][nl];
        float b = t[2 * tx + 1][nl];
        uint32_t hw, lw;
        pack2(a, b, hw, lw);
        size_t rowW = (size_t)n * (K >> 1);
        wh[rowW + pw] = hw;
        wl[rowW + pw] = lw;
    }
}

// ---------------- bf16 tensor-core GEMM (3-term split) --------------------
__global__ __launch_bounds__(256, 2) void hgemm_kernel(
    const __nv_bfloat16* __restrict__ Ahi, const __nv_bfloat16* __restrict__ Alo,
    const __nv_bfloat16* __restrict__ Bhi, const __nv_bfloat16* __restrict__ Blo,
    float* __restrict__ C,
    __nv_bfloat16* __restrict__ Chi, __nv_bfloat16* __restrict__ Clo,
    int M, int N, int K,
    const float* __restrict__ bias, const float* __restrict__ res, int act) {
    extern __shared__ uint32_t sm[];
    const int tid  = threadIdx.x;
    const int lane = tid & 31;
    const int warp = tid >> 5;
    const int warpM = warp >> 2;
    const int warpN = warp & 3;
    const int gid = lane >> 2;
    const int tig = lane & 3;
    const int m0 = blockIdx.y * 128, n0 = blockIdx.x * 128;

    float acc[4][4][4] = {};

    auto issue = [&](int stage, int kt) {
        const uint32_t base = stage * kStageWords;
#pragma unroll
        for (int i = 0; i < 8; i++) {
            int c = tid + i * 256;
            int t = c >> 9, w = c & 511;
            int row = w >> 2, ck = w & 3;
            const __nv_bfloat16* src;
            if (t == 0)      src = Ahi + (size_t)(m0 + row) * K + kt + ck * 8;
            else if (t == 1) src = Alo + (size_t)(m0 + row) * K + kt + ck * 8;
            else if (t == 2) src = Bhi + (size_t)(n0 + row) * K + kt + ck * 8;
            else             src = Blo + (size_t)(n0 + row) * K + kt + ck * 8;
            uint32_t dst = (uint32_t)__cvta_generic_to_shared(
                &sm[base + t * kArrWords + row * kRowWords + ck * 4]);
            CP_ASYNC16(dst, src);
        }
    };

    auto compute = [&](int buf) {
        const uint32_t* SAh = sm + buf * kStageWords;
        const uint32_t* SAl = SAh + kArrWords;
        const uint32_t* SBh = SAl + kArrWords;
        const uint32_t* SBl = SBh + kArrWords;
#pragma unroll
        for (int ks = 0; ks < 2; ks++) {
            const int kwb = ks * 8 + 2 * tig;
            uint2 bh[4], bl[4];
#pragma unroll
            for (int in = 0; in < 4; in++) {
                const int n = warpN * 32 + in * 8 + gid;
                bh[in] = *(const uint2*)&SBh[n * kRowWords + kwb];
                bl[in] = *(const uint2*)&SBl[n * kRowWords + kwb];
            }
#pragma unroll
            for (int im = 0; im < 4; im++) {
                const int r = warpM * 64 + im * 16 + gid;
                uint2 uh = *(const uint2*)&SAh[r * kRowWords + kwb];
                uint2 vh = *(const uint2*)&SAh[(r + 8) * kRowWords + kwb];
                uint2 ul = *(const uint2*)&SAl[r * kRowWords + kwb];
                uint2 vl = *(const uint2*)&SAl[(r + 8) * kRowWords + kwb];
                uint32_t ahi[4] = {uh.x, vh.x, uh.y, vh.y};
                uint32_t alo[4] = {ul.x, vl.x, ul.y, vl.y};
#pragma unroll
                for (int in = 0; in < 4; in++) {
                    uint32_t bhw[2] = {bh[in].x, bh[in].y};
                    uint32_t blw[2] = {bl[in].x, bl[in].y};
                    MMA_BF16(acc[im][in], ahi, bhw);
                    MMA_BF16(acc[im][in], ahi, blw);
                    MMA_BF16(acc[im][in], alo, bhw);
                }
            }
        }
    };

    const int nStages = K >> 5;
    issue(0, 0);
    CP_COMMIT();
    for (int s = 0; s < nStages; s++) {
        CP_WAIT0();
        __syncthreads();
        if (s + 1 < nStages) { issue((s + 1) & 1, (s + 1) * 32); CP_COMMIT(); }
        compute(s & 1);
    }

    // ---- epilogue ----
#pragma unroll
    for (int im = 0; im < 4; im++) {
        const int row = m0 + warpM * 64 + im * 16 + gid;
#pragma unroll
        for (int in = 0; in < 4; in++) {
            const int col = n0 + warpN * 32 + in * 8 + 2 * tig;
            if (col >= N) continue;
#pragma unroll
            for (int half = 0; half < 2; half++) {
                const int rr = row + half * 8;
                float c0 = acc[im][in][half * 2 + 0];
                float c1 = acc[im][in][half * 2 + 1];
                if (bias) { c0 += bias[col]; c1 += bias[col + 1]; }
                if (act) {
                    c0 = 0.5f * c0 * (1.f + erff(c0 * 0.70710678118654752f));
                    c1 = 0.5f * c1 * (1.f + erff(c1 * 0.70710678118654752f));
                }
                if (res) {
                    const float2 rv = *(const float2*)(res + (size_t)rr * N + col);
                    c0 += rv.x; c1 += rv.y;
                }
                if (C)
                    *(float2*)(C + (size_t)rr * N + col) = make_float2(c0, c1);
                if (Chi) {
                    __nv_bfloat162 h, l;
                    split2(c0, c1, h, l);
                    size_t rowW = (size_t)rr * (N >> 1);
                    int pw = permWord(col >> 1);
                    ((__nv_bfloat162*)Chi)[rowW + pw] = h;
                    ((__nv_bfloat162*)Clo)[rowW + pw] = l;
                }
            }
        }
    }
}

// ---------------- flash attention on tensor cores (bf16 3-term split) -----
__global__ __launch_bounds__(256, 2) void attn_kernel(
    const __nv_bfloat16* __restrict__ qhi, const __nv_bfloat16* __restrict__ qlo,
    const __nv_bfloat16* __restrict__ khi, const __nv_bfloat16* __restrict__ klo,
    const uint32_t* __restrict__ vph, const uint32_t* __restrict__ vpl,
    __nv_bfloat16* __restrict__ ohi, __nv_bfloat16* __restrict__ olo,
    int Tq, int Tk, int diag) {
    extern __shared__ uint32_t sa[];
    float* sf = (float*)sa;
    const int tid = threadIdx.x;
    const int lane = tid & 31, warp = tid >> 5;
    const int g = lane >> 2, tg = lane & 3;
    const int warpQ = warp >> 1, warpK = warp & 1;
    const int q0 = blockIdx.x * 64, h = blockIdx.y, b = blockIdx.z;
    const int q0w = warpQ * 16;

    // stage Q via cp.async
    {
        const __nv_bfloat16* qh = qhi + ((size_t)(b * Tq + q0)) * kID + h * kDH;
        const __nv_bfloat16* ql = qlo + ((size_t)(b * Tq + q0)) * kID + h * kDH;
#pragma unroll
        for (int i = 0; i < 4; i++) {
            int ch = tid + i * 256;
            int arr = ch >> 9, w = ch & 511;
            int row = w >> 3, ck = w & 7;
            const __nv_bfloat16* src = (arr ? ql : qh) + (size_t)row * kID + ck * 8;
            uint32_t dst = (uint32_t)__cvta_generic_to_shared(
                &sa[(arr ? AQL : AQH) + row * 36 + ck * 4]);
            CP_ASYNC16(dst, src);
        }
        CP_COMMIT();
    }
    if (tid < 64) { sf[AMR + tid] = -1e30f; sf[ALR + tid] = 0.f; }

    float O[4][4] = {};
    int jmax = q0 + 63 + diag;
    int nkt = (jmax + 64) >> 6;
    int maxkt = Tk >> 6;
    if (nkt > maxkt) nkt = maxkt;

    const int r0i = q0w + g, r1i = r0i + 8;
    const int tk2 = Tk >> 1;
    const uint32_t* vhB = vph + ((size_t)b * kH + h) * tk2 * 64;
    const uint32_t* vlB = vpl + ((size_t)b * kH + h) * tk2 * 64;

    for (int kt = 0; kt < nkt; kt++) {
        const int k0 = kt * 64;
        {
            const __nv_bfloat16* kh = khi + ((size_t)(b * Tk + k0)) * kID + h * kDH;
            const __nv_bfloat16* kl = klo + ((size_t)(b * Tk + k0)) * kID + h * kDH;
#pragma unroll
            for (int i = 0; i < 4; i++) {
                int ch = tid + i * 256;
                int arr = ch >> 9, w = ch & 511;
                int row = w >> 3, ck = w & 7;
                const __nv_bfloat16* src = (arr ? kl : kh) + (size_t)row * kID + ck * 8;
                uint32_t dst = (uint32_t)__cvta_generic_to_shared(
                    &sa[(arr ? AKL : AKH) + row * 36 + ck * 4]);
                CP_ASYNC16(dst, src);
            }
            const uint32_t* vh = vhB + (size_t)(k0 >> 1) * 64;
            const uint32_t* vl = vlB + (size_t)(k0 >> 1) * 64;
#pragma unroll
            for (int i = 0; i < 4; i++) {
                int ch = tid + i * 256;
                int arr = ch >> 9, w = ch & 511;
                int k2 = w >> 4, ck = w & 15;
                const uint32_t* src = (arr ? vl : vh) + k2 * 64 + ck * 4;
                uint32_t dst = (uint32_t)__cvta_generic_to_shared(
                    &sa[(arr ? AVL : AVH) + k2 * 72 + ck * 4]);
                CP_ASYNC16(dst, src);
            }
            CP_COMMIT();
        }
        CP_WAIT0();
        __syncthreads();   // A: staging complete

        // ---- S = Q @ K^T ----
        float s[4][4];
#pragma unroll
        for (int nt = 0; nt < 4; nt++)
#pragma unroll
            for (int j = 0; j < 4; j++) s[nt][j] = 0.f;
#pragma unroll
        for (int ck = 0; ck < 4; ck++) {
            const int ac = ck * 8 + tg;
            uint32_t ahi[4] = {
                sa[AQH + r0i * 36 + ac], sa[AQH + r1i * 36 + ac],
                sa[AQH + r0i * 36 + ac + 4], sa[AQH + r1i * 36 + ac + 4]};
            uint32_t alo[4] = {
                sa[AQL + r0i * 36 + ac], sa[AQL + r1i * 36 + ac],
                sa[AQL + r0i * 36 + ac + 4], sa[AQL + r1i * 36 + ac + 4]};
#pragma unroll
            for (int nt = 0; nt < 4; nt++) {
                const int key = warpK * 32 + nt * 8 + g;
                uint32_t bhi[2] = {sa[AKH + key * 36 + ac],
                                   sa[AKH + key * 36 + ac + 4]};
                uint32_t blo[2] = {sa[AKL + key * 36 + ac],
                                   sa[AKL + key * 36 + ac + 4]};
                MMA_BF16(s[nt], ahi, bhi);
                MMA_BF16(s[nt], ahi, blo);
                MMA_BF16(s[nt], alo, bhi);
            }
        }
        // ---- causal mask ----
        if (k0 + 63 > q0 + diag) {
            int qr0 = q0 + r0i + diag;
            int qr1 = qr0 + 8;
#pragma unroll
            for (int nt = 0; nt < 4; nt++) {
                int cb = k0 + warpK * 32 + nt * 8 + 2 * tg;
                if (cb > qr0)     s[nt][0] = -1e30f;
                if (cb + 1 > qr0) s[nt][1] = -1e30f;
                if (cb > qr1)     s[nt][2] = -1e30f;
                if (cb + 1 > qr1) s[nt][3] = -1e30f;
            }
        }
        // ---- row max ----
        float mx0 = -1e30f, mx1 = -1e30f;
#pragma unroll
        for (int nt = 0; nt < 4; nt++) {
            mx0 = fmaxf(mx0, fmaxf(s[nt][0], s[nt][1]));
            mx1 = fmaxf(mx1, fmaxf(s[nt][2], s[nt][3]));
        }
        mx0 = fmaxf(mx0, __shfl_xor_sync(0xffffffffu, mx0, 1));
        mx0 = fmaxf(mx0, __shfl_xor_sync(0xffffffffu, mx0, 2));
        mx1 = fmaxf(mx1, __shfl_xor_sync(0xffffffffu, mx1, 1));
        mx1 = fmaxf(mx1, __shfl_xor_sync(0xffffffffu, mx1, 2));
        if (tg == 0) {
            sf[AMX + r0i * 2 + warpK] = mx0;
            sf[AMX + r1i * 2 + warpK] = mx1;
        }
        __syncthreads();   // B: maxes visible

        float mold0 = sf[AMR + r0i], mold1 = sf[AMR + r1i];
        float lold0 = sf[ALR + r0i], lold1 = sf[ALR + r1i];
        float mnew0 = fmaxf(mold0, fmaxf(sf[AMX + r0i * 2], sf[AMX + r0i * 2 + 1]));
        float mnew1 = fmaxf(mold1, fmaxf(sf[AMX + r1i * 2], sf[AMX + r1i * 2 + 1]));
        float f0 = __expf(mold0 - mnew0);
        float f1 = __expf(mold1 - mnew1);
        float sum0 = 0.f, sum1 = 0.f;
#pragma unroll
        for (int nt = 0; nt < 4; nt++) {
            float p00 = __expf(s[nt][0] - mnew0);
            float p01 = __expf(s[nt][1] - mnew0);
            float p10 = __expf(s[nt][2] - mnew1);
            float p11 = __expf(s[nt][3] - mnew1);
            sum0 += p00 + p01; sum1 += p10 + p11;
            uint32_t hw, lw;
            const int pc = warpK * 16 + nt * 4 + tg;
            pack2(p00, p01, hw, lw);
            sa[APH + r0i * 36 + pc] = hw; sa[APL + r0i * 36 + pc] = lw;
            pack2(p10, p11, hw, lw);
            sa[APH + r1i * 36 + pc] = hw; sa[APL + r1i * 36 + pc] = lw;
        }
        sum0 += __shfl_xor_sync(0xffffffffu, sum0, 1);
        sum0 += __shfl_xor_sync(0xffffffffu, sum0, 2);
        sum1 += __shfl_xor_sync(0xffffffffu, sum1, 1);
        sum1 += __shfl_xor_sync(0xffffffffu, sum1, 2);
        if (tg == 0) {
            sf[ASM + r0i * 2 + warpK] = sum0;
            sf[ASM + r1i * 2 + warpK] = sum1;
        }
        __syncthreads();  // C: P + sums visible

        // ---- rescale O, then O += P @ V ----
#pragma unroll
        for (int nt = 0; nt < 4; nt++) {
            O[nt][0] *= f0; O[nt][1] *= f0;
            O[nt][2] *= f1; O[nt][3] *= f1;
        }
#pragma unroll
        for (int kk = 0; kk < 4; kk++) {
            const int pc = kk * 8 + tg;
            uint32_t ahi[4] = {
                sa[APH + r0i * 36 + pc], sa[APH + r1i * 36 + pc],
                sa[APH + r0i * 36 + pc + 4], sa[APH + r1i * 36 + pc + 4]};
            uint32_t alo[4] = {
                sa[APL + r0i * 36 + pc], sa[APL + r1i * 36 + pc],
                sa[APL + r0i * 36 + pc + 4], sa[APL + r1i * 36 + pc + 4]};
#pragma unroll
            for (int nt = 0; nt < 4; nt++) {
                const int d0 = warpK * 32 + nt * 8 + g;
                uint32_t bhi[2] = {sa[AVH + (kk * 8 + tg) * 72 + d0],
                                   sa[AVH + (kk * 8 + 4 + tg) * 72 + d0]};
                uint32_t blo[2] = {sa[AVL + (kk * 8 + tg) * 72 + d0],
                                   sa[AVL + (kk * 8 + 4 + tg) * 72 + d0]};
                MMA_BF16(O[nt], ahi, bhi);
                MMA_BF16(O[nt], ahi, blo);
                MMA_BF16(O[nt], alo, bhi);
            }
        }
        // ---- state update ----
        if (warpK == 0 && tg == 0) {
            sf[AMR + r0i] = mnew0;
            sf[AMR + r1i] = mnew1;
            sf[ALR + r0i] = lold0 * f0 + sf[ASM + r0i * 2] + sf[ASM + r0i * 2 + 1];
            sf[ALR + r1i] = lold1 * f1 + sf[ASM + r1i * 2] + sf[ASM + r1i * 2 + 1];
        }
        __syncthreads();  // D: state final; K/V/P safe to overwrite
    }

    // ---- write output (split bf16, permuted, GEMM-ready) ----
    float inv0 = 1.f / sf[ALR + r0i];
    float inv1 = 1.f / sf[ALR + r1i];
    size_t rowW0 = ((size_t)b * Tq + q0 + r0i) * (kID / 2);
    size_t rowW1 = ((size_t)b * Tq + q0 + r1i) * (kID / 2);
#pragma unroll
    for (int nt = 0; nt < 4; nt++) {
        int col = h * kDH + warpK * 32 + nt * 8 + 2 * tg;
        int w0 = col >> 1;
        uint32_t hw, lw;
        pack2(O[nt][0] * inv0, O[nt][1] * inv0, hw, lw);
        ((uint32_t*)ohi)[rowW0 + permWord(w0)] = hw;
        ((uint32_t*)olo)[rowW0 + permWord(w0)] = lw;
        pack2(O[nt][2] * inv1, O[nt][3] * inv1, hw, lw);
        ((uint32_t*)ohi)[rowW1 + permWord(w0)] = hw;
        ((uint32_t*)olo)[rowW1 + permWord(w0)] = lw;
    }
}

// ---------------- host orchestration ----------------
namespace {
__nv_bfloat16 *h_whi, *h_wlo, *h_ahi, *h_alo;
__nv_bfloat16 *h_qhi, *h_qlo, *h_khi, *h_klo;
uint32_t *h_vph, *h_vpl;

inline void gemm(size_t aOff, size_t wOff, float* C,
                 __nv_bfloat16* chi, __nv_bfloat16* clo,
                 int M, int N, int Npad, int K,
                 const float* bias, const float* res, int act) {
    dim3 g(Npad / 128, M / 128);
    hgemm_kernel<<<g, 256, kGemmSmem>>>(
        h_ahi + aOff, h_alo + aOff, h_whi + wOff, h_wlo + wOff,
        C, chi, clo, M, N, K, bias, res, act);
}
}

extern "C" void kernel_launch(void* const* d_in, const int* in_sizes, int n_in,
                              void* d_out, int out_size) {
    const int*   x           = (const int*)d_in[0];
    // d_in[1] = prefix_mask: all-True and padded True => no-op; unused.
    const float* token_emb   = (const float*)d_in[2];
    const float* pos_emb     = (const float*)d_in[3];
    const float* ca_norm_s   = (const float*)d_in[4];
    const float* ca_norm_b   = (const float*)d_in[5];
    const float* ca_ctx_ns   = (const float*)d_in[6];
    const float* ca_ctx_nb   = (const float*)d_in[7];
    const float* ca_wq       = (const float*)d_in[8];
    const float* ca_wkv      = (const float*)d_in[9];
    const float* ca_wo       = (const float*)d_in[10];
    const float* ca_bo       = (const float*)d_in[11];
    const float* ca_ff_ln_s  = (const float*)d_in[12];
    const float* ca_ff_ln_b  = (const float*)d_in[13];
    const float* ca_ff_w1    = (const float*)d_in[14];
    const float* ca_ff_w2    = (const float*)d_in[15];
    const float* l_norm_s    = (const float*)d_in[16];
    const float* l_norm_b    = (const float*)d_in[17];
    const float* l_wqkv      = (const float*)d_in[18];
    const float* l_wo        = (const float*)d_in[19];
    const float* l_ff_ln_s   = (const float*)d_in[20];
    const float* l_ff_ln_b   = (const float*)d_in[21];
    const float* l_ff_w1     = (const float*)d_in[22];
    const float* l_ff_w2     = (const float*)d_in[23];
    const float* w_logits    = (const float*)d_in[24];
    float* out = (float*)d_out;

    float *prefix, *lat, *qb, *kv, *qkv, *ctab, *stab;
    cudaGetSymbolAddress((void**)&prefix, g_prefix);
    cudaGetSymbolAddress((void**)&lat,    g_lat);
    cudaGetSymbolAddress((void**)&qb,     g_q);
    cudaGetSymbolAddress((void**)&kv,     g_kv);
    cudaGetSymbolAddress((void**)&qkv,    g_qkv);
    cudaGetSymbolAddress((void**)&ctab,   g_cos);
    cudaGetSymbolAddress((void**)&stab,   g_sin);
    cudaGetSymbolAddress((void**)&h_whi,  g_whi);
    cudaGetSymbolAddress((void**)&h_wlo,  g_wlo);
    cudaGetSymbolAddress((void**)&h_ahi,  g_ahi);
    cudaGetSymbolAddress((void**)&h_alo,  g_alo);
    cudaGetSymbolAddress((void**)&h_qhi,  g_qhi);
    cudaGetSymbolAddress((void**)&h_qlo,  g_qlo);
    cudaGetSymbolAddress((void**)&h_khi,  g_khi);
    cudaGetSymbolAddress((void**)&h_klo,  g_klo);
    cudaGetSymbolAddress((void**)&h_vph,  g_vph);
    cudaGetSymbolAddress((void**)&h_vpl,  g_vpl);

    cudaFuncSetAttribute(hgemm_kernel,
                         cudaFuncAttributeMaxDynamicSharedMemorySize, kGemmSmem);
    cudaFuncSetAttribute(attn_kernel,
                         cudaFuncAttributeMaxDynamicSharedMemorySize, kAttnSmem);

    auto cw = [&](const float* W, size_t off, int K, int N, int Npad) {
        dim3 g(K / 64, Npad / 32);
        cvt_wt_kernel<<<g, dim3(32, 8)>>>(W, h_whi + off, h_wlo + off, K, N, Npad);
    };

    // Launch order chosen so launch #6 (ncu -s 5 -c 1) is hgemm_kernel.
    cw(ca_wq, OFF_CAWQ, 1024, 1024, 1024);                       // 1
    embed_kernel<<<kB * kS, 256>>>(x, token_emb, pos_emb, prefix, lat);   // 2
    rope_table_kernel<<<(kS * 16 + 255) / 256, 256>>>(ctab, stab);        // 3
    ln_bf16_kernel<<<kB * kNL, 256>>>(lat,    ca_norm_s, ca_norm_b,
                                      h_ahi + A0,  h_alo + A0);           // 4
    ln_bf16_kernel<<<kB * kP,  256>>>(prefix, ca_ctx_ns, ca_ctx_nb,
                                      h_ahi + ACN, h_alo + ACN);          // 5
    gemm(A0, OFF_CAWQ, qb, nullptr, nullptr,
         kB * kNL, kID, kID, kD, nullptr, nullptr, 0);                    // 6 (profiled)

    // remaining weight conversions
    cw(ca_wkv,   OFF_CAWKV, 1024, 2048, 2048);
    cw(ca_wo,    OFF_CAWO,  1024, 1024, 1024);
    cw(ca_ff_w1, OFF_CAFF1, 1024, 4096, 4096);
    cw(ca_ff_w2, OFF_CAFF2, 4096, 1024, 1024);
    for (int li = 0; li < kL; li++) {
        cw(l_wqkv  + (size_t)li * 1024 * 3072, OFF_LQKV + (size_t)li * 3072 * 1024, 1024, 3072, 3072);
        cw(l_wo    + (size_t)li * 1024 * 1024, OFF_LWO  + (size_t)li * 1024 * 1024, 1024, 1024, 1024);
        cw(l_ff_w1 + (size_t)li * 1024 * 4096, OFF_LFF1 + (size_t)li * 4096 * 1024, 1024, 4096, 4096);
        cw(l_ff_w2 + (size_t)li * 4096 * 1024, OFF_LFF2 + (size_t)li * 1024 * 4096, 4096, 1024, 1024);
    }
    cw(w_logits, OFF_LOGITS, 1024, kV, kVp);

    // 2. cross-attention block (continued)
    for (int b = 0; b < kB; b++)
        gemm(ACN + (size_t)b * kP * kD, OFF_CAWKV,
             kv + (size_t)b * kS * 2 * kID, nullptr, nullptr,
             kP, 2 * kID, 2 * kID, kD, nullptr, nullptr, 0);
    for (int b = 0; b < kB; b++)
        gemm(A0 + (size_t)b * kNL * kD, OFF_CAWKV,
             kv + ((size_t)b * kS + kP) * 2 * kID, nullptr, nullptr,
             kNL, 2 * kID, 2 * kID, kD, nullptr, nullptr, 0);

    {
        int rq = kB * kNL * kH, rk = kB * kS * kH;
        rope_cvt_kernel<<<(rq + 7) / 8, 256>>>(
            qb, kB * kNL, kID, kNL, kP, kScale, ctab, stab, h_qhi, h_qlo);
        rope_cvt_kernel<<<(rk + 7) / 8, 256>>>(
            kv, kB * kS, 2 * kID, kS, 0, 1.f, ctab, stab, h_khi, h_klo);
        int vt = kB * kH * (kS / 2) * 16;
        vpack_kernel<<<(vt + 255) / 256, 256>>>(kv + kID, kS, 2 * kID,
                                                h_vph, h_vpl);
    }
    attn_kernel<<<dim3(kNL / 64, kH, kB), 256, kAttnSmem>>>(
        h_qhi, h_qlo, h_khi, h_klo, h_vph, h_vpl,
        h_ahi + A0, h_alo + A0, kNL, kS, kP);

    gemm(A0, OFF_CAWO, lat, nullptr, nullptr,
         kB * kNL, kD, kD, kID, ca_bo, lat, 0);

    ln_bf16_kernel<<<kB * kNL, 256>>>(lat, ca_ff_ln_s, ca_ff_ln_b,
                                      h_ahi + A0, h_alo + A0);
    gemm(A0, OFF_CAFF1, nullptr, h_ahi + AFF, h_alo + AFF,
         kB * kNL, kFF, kFF, kD, nullptr, nullptr, 1);
    gemm(AFF, OFF_CAFF2, lat, nullptr, nullptr,
         kB * kNL, kD, kD, kFF, nullptr, lat, 0);

    // 3. latent self-attention layers
    for (int li = 0; li < kL; li++) {
        ln_bf16_kernel<<<kB * kNL, 256>>>(lat, l_norm_s + li * kD,
                                          l_norm_b + li * kD,
                                          h_ahi + A0, h_alo + A0);
        gemm(A0, OFF_LQKV + (size_t)li * 3072 * 1024, qkv, nullptr, nullptr,
             kB * kNL, 3 * kID, 3 * kID, kD, nullptr, nullptr, 0);

        int rq = kB * kNL * kH;
        rope_cvt_kernel<<<(rq + 7) / 8, 256>>>(
            qkv, kB * kNL, 3 * kID, kNL, kP, kScale, ctab, stab, h_qhi, h_qlo);
        rope_cvt_kernel<<<(rq + 7) / 8, 256>>>(
            qkv + kID, kB * kNL, 3 * kID, kNL, kP, 1.f, ctab, stab, h_khi, h_klo);
        int vt = kB * kH * (kNL / 2) * 16;
        vpack_kernel<<<(vt + 255) / 256, 256>>>(qkv + 2 * kID, kNL, 3 * kID,
                                                h_vph, h_vpl);
        attn_kernel<<<dim3(kNL / 64, kH, kB), 256, kAttnSmem>>>(
            h_qhi, h_qlo, h_khi, h_klo, h_vph, h_vpl,
            h_ahi + A0, h_alo + A0, kNL, kNL, 0);

        gemm(A0, OFF_LWO + (size_t)li * 1024 * 1024, lat, nullptr, nullptr,
             kB * kNL, kD, kD, kID, nullptr, lat, 0);

        ln_bf16_kernel<<<kB * kNL, 256>>>(lat, l_ff_ln_s + li * kD,
                                          l_ff_ln_b + li * kD,
                                          h_ahi + A0, h_alo + A0);
        gemm(A0, OFF_LFF1 + (size_t)li * 4096 * 1024, nullptr,
             h_ahi + AFF, h_alo + AFF,
             kB * kNL, kFF, kFF, kD, nullptr, nullptr, 1);
        gemm(AFF, OFF_LFF2 + (size_t)li * 1024 * 4096, lat, nullptr, nullptr,
             kB * kNL, kD, kD, kFF, nullptr, lat, 0);
    }

    // 4. logits head
    {
        size_t n = (size_t)kB * kNL * kD;
        cvt_act_kernel<<<(int)((n / 2 + 255) / 256), 256>>>(
            lat, h_ahi + A0, h_alo + A0, (int)n);
    }
    gemm(A0, OFF_LOGITS, out, nullptr, nullptr,
         kB * kNL, kV, kVp, kD, nullptr, nullptr, 0);
}

// round 12
// speedup vs baseline: 3.2242x; 1.1130x over previous
#include <cuda_runtime.h>
#include <cuda_bf16.h>
#include <math.h>
#include <stdint.h>

// ---------------- problem constants ----------------
namespace {
constexpr int kB  = 2;
constexpr int kS  = 2048;
constexpr int kP  = 512;
constexpr int kNL = 1536;   // latent tokens = S - P
constexpr int kD  = 1024;
constexpr int kH  = 16;
constexpr int kDH = 64;
constexpr int kID = 1024;   // H * DH
constexpr int kV  = 20000;
constexpr int kVp = 20096;  // padded to 128
constexpr int kL  = 4;
constexpr int kFF = 4096;
constexpr float kScale = 0.125f;   // DH^-0.5
constexpr float kEps   = 1e-5f;

// weight arena offsets (transposed [N][K] layout, elements)
constexpr size_t OFF_CAWQ   = 0;                                  // 1024x1024
constexpr size_t OFF_CAWKV  = OFF_CAWQ  + 1024ull * 1024;         // 2048x1024
constexpr size_t OFF_CAWO   = OFF_CAWKV + 2048ull * 1024;         // 1024x1024
constexpr size_t OFF_CAFF1  = OFF_CAWO  + 1024ull * 1024;         // 4096x1024
constexpr size_t OFF_CAFF2  = OFF_CAFF1 + 4096ull * 1024;         // 1024x4096
constexpr size_t OFF_LQKV   = OFF_CAFF2 + 1024ull * 4096;         // 4 x 3072x1024
constexpr size_t OFF_LWO    = OFF_LQKV  + 4ull * 3072 * 1024;     // 4 x 1024x1024
constexpr size_t OFF_LFF1   = OFF_LWO   + 4ull * 1024 * 1024;     // 4 x 4096x1024
constexpr size_t OFF_LFF2   = OFF_LFF1  + 4ull * 4096 * 1024;     // 4 x 1024x4096
constexpr size_t OFF_LOGITS = OFF_LFF2  + 4ull * 1024 * 4096;     // 20096x1024
constexpr size_t W_TOTAL    = OFF_LOGITS + (size_t)kVp * 1024;

// activation arena regions (elements)
constexpr size_t A0   = 0;                                // xn/tmp/att/lat-cvt
constexpr size_t AFF  = (size_t)kB * kNL * kD;            // GELU(ff1) output
constexpr size_t ACN  = AFF + (size_t)kB * kNL * kFF;     // cn (prefix LN)
constexpr size_t A_TOTAL = ACN + (size_t)kB * kP * kD;

// hgemm smem: 2 stages x 4 arrays x 128 rows x 24 uint32 words
constexpr int kRowWords   = 24;                      // 16 data + 8 pad
constexpr int kArrWords   = 128 * kRowWords;         // 3072
constexpr int kStageWords = 4 * kArrWords;           // 12288
constexpr int kGemmSmem   = 2 * kStageWords * 4;     // 98304 bytes

// attention smem layout (uint32 word offsets)
constexpr int AQH = 0;                // Q hi  64 x 36
constexpr int AQL = AQH + 64 * 36;
constexpr int AKH = AQL + 64 * 36;    // K hi  64 x 36
constexpr int AKL = AKH + 64 * 36;
constexpr int AVH = AKL + 64 * 36;    // V hi  32 kpairs x 72
constexpr int AVL = AVH + 32 * 72;
constexpr int APH = AVL + 32 * 72;    // P hi  64 x 36
constexpr int APL = APH + 64 * 36;
constexpr int AMR = APL + 64 * 36;    // mrow[64] (float)
constexpr int ALR = AMR + 64;         // lrow[64]
constexpr int AMX = ALR + 64;         // smMax[64][2]
constexpr int ASM = AMX + 128;        // smSum[64][2]
constexpr int kAttnWords = ASM + 128; // 18816
constexpr int kAttnSmem  = kAttnWords * 4;  // 75264 bytes

constexpr int kFF2N = 3072 * 1024;    // FF2 output elements
}

// ---------------- scratch (module-load allocated, legal) ----------------
__device__ float g_prefix[kB * kP * kD];
__device__ float g_lat   [kB * kNL * kD];
__device__ float g_q     [kB * kNL * kID];
__device__ float g_kv    [kB * kS * 2 * kID];
__device__ float g_qkv   [kB * kNL * 3 * kID];
__device__ float g_cos   [kS * 16];
__device__ float g_sin   [kS * 16];
__device__ float g_part  [3ull * kFF2N];             // split-K partials
__device__ __nv_bfloat16 g_whi[W_TOTAL];
__device__ __nv_bfloat16 g_wlo[W_TOTAL];
__device__ __nv_bfloat16 g_ahi[A_TOTAL];
__device__ __nv_bfloat16 g_alo[A_TOTAL];
// attention operand buffers (split bf16, fragment-pair packed)
__device__ __nv_bfloat16 g_qhi[kB * kNL * kID];
__device__ __nv_bfloat16 g_qlo[kB * kNL * kID];
__device__ __nv_bfloat16 g_khi[kB * kS * kID];
__device__ __nv_bfloat16 g_klo[kB * kS * kID];
__device__ uint32_t g_vph[(size_t)kB * kH * (kS / 2) * 64];
__device__ uint32_t g_vpl[(size_t)kB * kH * (kS / 2) * 64];

// ---------------- low-level helpers ----------------
__device__ __forceinline__ float warpSum(float v) {
#pragma unroll
    for (int o = 16; o; o >>= 1) v += __shfl_xor_sync(0xffffffffu, v, o);
    return v;
}

// k-pair permutation: within each 8-word group, word w8 -> (w8&3)*2 + (w8>>2)
__device__ __forceinline__ int permWord(int w) {
    int w8 = w & 7;
    return (w & ~7) + ((w8 & 3) << 1) + (w8 >> 2);
}

__device__ __forceinline__ void split2(float a, float b,
                                       __nv_bfloat162& h, __nv_bfloat162& l) {
    __nv_bfloat16 h0 = __float2bfloat16(a);
    __nv_bfloat16 h1 = __float2bfloat16(b);
    h.x = h0; h.y = h1;
    l.x = __float2bfloat16(a - __bfloat162float(h0));
    l.y = __float2bfloat16(b - __bfloat162float(h1));
}

__device__ __forceinline__ void pack2(float a, float b,
                                      uint32_t& hw, uint32_t& lw) {
    __nv_bfloat162 h, l;
    split2(a, b, h, l);
    hw = *reinterpret_cast<uint32_t*>(&h);
    lw = *reinterpret_cast<uint32_t*>(&l);
}

#define MMA_BF16(c, a, b)                                                   \
    asm volatile(                                                           \
        "mma.sync.aligned.m16n8k16.row.col.f32.bf16.bf16.f32 "              \
        "{%0,%1,%2,%3}, {%4,%5,%6,%7}, {%8,%9}, {%0,%1,%2,%3};"             \
        : "+f"((c)[0]), "+f"((c)[1]), "+f"((c)[2]), "+f"((c)[3])            \
        : "r"((a)[0]), "r"((a)[1]), "r"((a)[2]), "r"((a)[3]),               \
          "r"((b)[0]), "r"((b)[1]))

#define CP_ASYNC16(dst, src)                                                \
    asm volatile("cp.async.cg.shared.global [%0], [%1], 16;"                \
                 :: "r"(dst), "l"(src))
#define CP_COMMIT() asm volatile("cp.async.commit_group;")
#define CP_WAIT0()  asm volatile("cp.async.wait_group 0;")

// ---------------- embedding ----------------
__global__ void embed_kernel(const int* __restrict__ x,
                             const float* __restrict__ te,
                             const float* __restrict__ pe,
                             float* __restrict__ prefix,
                             float* __restrict__ lat) {
    int row = blockIdx.x;
    int b = row / kS, s = row % kS;
    int tok = x[row];
    const float* tr = te + (size_t)tok * kD;
    const float* pr = pe + (size_t)s * kD;
    float* dst = (s < kP) ? (prefix + ((size_t)b * kP + s) * kD)
                          : (lat    + ((size_t)b * kNL + (s - kP)) * kD);
    for (int i = threadIdx.x; i < kD; i += blockDim.x) dst[i] = tr[i] + pr[i];
}

// ---------------- LayerNorm -> split bf16 (permuted) ----------------
__global__ __launch_bounds__(256) void ln_bf16_kernel(
    const float* __restrict__ in, const float* __restrict__ gamma,
    const float* __restrict__ beta,
    __nv_bfloat16* __restrict__ hi, __nv_bfloat16* __restrict__ lo) {
    int r = blockIdx.x;
    const float* xr = in + (size_t)r * kD;
    int tid = threadIdx.x;
    float4 v4 = *(const float4*)(xr + 4 * tid);
    float v[4] = {v4.x, v4.y, v4.z, v4.w};
    float s = v[0] + v[1] + v[2] + v[3];
    __shared__ float red[8];
    __shared__ float meanS, rstdS;
    s = warpSum(s);
    if ((tid & 31) == 0) red[tid >> 5] = s;
    __syncthreads();
    if (tid < 32) {
        float t = (tid < 8) ? red[tid] : 0.f;
        t = warpSum(t);
        if (tid == 0) meanS = t * (1.f / kD);
    }
    __syncthreads();
    float mean = meanS;
    float s2 = 0.f;
#pragma unroll
    for (int i = 0; i < 4; i++) { float d = v[i] - mean; s2 += d * d; }
    s2 = warpSum(s2);
    __syncthreads();
    if ((tid & 31) == 0) red[tid >> 5] = s2;
    __syncthreads();
    if (tid < 32) {
        float t = (tid < 8) ? red[tid] : 0.f;
        t = warpSum(t);
        if (tid == 0) rstdS = rsqrtf(t * (1.f / kD) + kEps);
    }
    __syncthreads();
    float rs = rstdS;
    float4 g4 = *(const float4*)(gamma + 4 * tid);
    float4 b4 = *(const float4*)(beta + 4 * tid);
    float y0 = (v[0] - mean) * rs * g4.x + b4.x;
    float y1 = (v[1] - mean) * rs * g4.y + b4.y;
    float y2 = (v[2] - mean) * rs * g4.z + b4.z;
    float y3 = (v[3] - mean) * rs * g4.w + b4.w;
    __nv_bfloat162 h0, l0, h1, l1;
    split2(y0, y1, h0, l0);
    split2(y2, y3, h1, l1);
    size_t rowW = (size_t)r * (kD / 2);
    int w0 = 2 * tid;
    ((__nv_bfloat162*)hi)[rowW + permWord(w0)]     = h0;
    ((__nv_bfloat162*)hi)[rowW + permWord(w0 + 1)] = h1;
    ((__nv_bfloat162*)lo)[rowW + permWord(w0)]     = l0;
    ((__nv_bfloat162*)lo)[rowW + permWord(w0 + 1)] = l1;
}

// ---------------- RoPE table ----------------
__global__ void rope_table_kernel(float* __restrict__ ct, float* __restrict__ st) {
    int idx = blockIdx.x * blockDim.x + threadIdx.x;
    if (idx >= kS * 16) return;
    int s = idx >> 4, i = idx & 15;
    float inv = (float)(1.0 / pow(10000.0, (double)i / 16.0));
    float f = (float)s * inv;
    ct[idx] = (float)cos((double)f);
    st[idx] = (float)sin((double)f);
}

// ---------------- warp rope helper: lane owns word (2l, 2l+1) -------------
__device__ __forceinline__ void ropeWord(const float* __restrict__ p, int pos,
                                         float scaleAll, int lane,
                                         const float* __restrict__ ct,
                                         const float* __restrict__ st,
                                         uint32_t& hw, uint32_t& lw) {
    float2 v = *(const float2*)(p + 2 * lane);
    float ox = __shfl_xor_sync(0xffffffffu, v.x, 8);
    float oy = __shfl_xor_sync(0xffffffffu, v.y, 8);
    float y0, y1;
    if (lane < 8) {
        float c0 = ct[pos * 16 + 2 * lane],     s0 = st[pos * 16 + 2 * lane];
        float c1 = ct[pos * 16 + 2 * lane + 1], s1 = st[pos * 16 + 2 * lane + 1];
        y0 = v.x * c0 - ox * s0;
        y1 = v.y * c1 - oy * s1;
    } else if (lane < 16) {
        int i = 2 * lane - 16;
        float c0 = ct[pos * 16 + i],     s0 = st[pos * 16 + i];
        float c1 = ct[pos * 16 + i + 1], s1 = st[pos * 16 + i + 1];
        y0 = v.x * c0 + ox * s0;
        y1 = v.y * c1 + oy * s1;
    } else {
        y0 = v.x; y1 = v.y;
    }
    pack2(y0 * scaleAll, y1 * scaleAll, hw, lw);
}

// ---------------- fused Q-rope + K-rope + V-pack (warp per row-head) ------
__global__ __launch_bounds__(256) void qkvprep_kernel(
    const float* __restrict__ qsrc, int qRows, int qStride, int qT, int qPos,
    const float* __restrict__ ksrc, const float* __restrict__ vsrc,
    int kvRows, int kvStride, int kT, int kPos,
    const float* __restrict__ ct, const float* __restrict__ st,
    __nv_bfloat16* __restrict__ qhi, __nv_bfloat16* __restrict__ qlo,
    __nv_bfloat16* __restrict__ khi, __nv_bfloat16* __restrict__ klo,
    uint32_t* __restrict__ vph, uint32_t* __restrict__ vpl) {
    int warp = threadIdx.x >> 5, lane = threadIdx.x & 31;
    int idx = blockIdx.x * 8 + warp;
    if (idx >= kvRows * kH) return;
    int row = idx / kH, h = idx % kH;
    uint32_t hw, lw;
    // K rope (scale 1)
    {
        const float* p = ksrc + (size_t)row * kvStride + h * kDH;
        ropeWord(p, kPos + (row % kT), 1.f, lane, ct, st, hw, lw);
        size_t w = (size_t)row * (kID / 2) + h * 32 + lane;
        ((uint32_t*)khi)[w] = hw;
        ((uint32_t*)klo)[w] = lw;
    }
    // V pack (even rows handle the pair)
    if (!(row & 1)) {
        const float* p0 = vsrc + (size_t)row * kvStride + h * kDH;
        const float* p1 = p0 + kvStride;
        int b = row / kT;
        int k2 = (row % kT) >> 1;
        size_t base = (((size_t)b * kH + h) * (kT >> 1) + k2) * 64;
        pack2(p0[lane], p1[lane], hw, lw);
        vph[base + lane] = hw;
        vpl[base + lane] = lw;
        pack2(p0[lane + 32], p1[lane + 32], hw, lw);
        vph[base + lane + 32] = hw;
        vpl[base + lane + 32] = lw;
    }
    // Q rope (scale kScale)
    if (row < qRows) {
        const float* p = qsrc + (size_t)row * qStride + h * kDH;
        ropeWord(p, qPos + (row % qT), kScale, lane, ct, st, hw, lw);
        size_t w = (size_t)row * (kID / 2) + h * 32 + lane;
        ((uint32_t*)qhi)[w] = hw;
        ((uint32_t*)qlo)[w] = lw;
    }
}

// ---------------- fp32 -> bf16 hi/lo converter (k-pair permuted) ----------
__global__ void cvt_act_kernel(const float* __restrict__ in,
                               __nv_bfloat16* __restrict__ hi,
                               __nv_bfloat16* __restrict__ lo, int n) {
    int w = blockIdx.x * blockDim.x + threadIdx.x;
    if (w * 2 >= n) return;
    float2 v = *(const float2*)(in + (size_t)w * 2);
    __nv_bfloat162 h, l;
    split2(v.x, v.y, h, l);
    int pw = permWord(w);
    ((__nv_bfloat162*)hi)[pw] = h;
    ((__nv_bfloat162*)lo)[pw] = l;
}

// transpose + convert weights: W[K,N] fp32 -> Wt_hi/lo[Npad,K] bf16,
// k-pair permuted, zero padded. Tile 64(k) x 32(n); whole-word writes.
// blockIdx.z = layer (batched conversion).
__global__ void cvt_wt_kernel(const float* __restrict__ W,
                              __nv_bfloat16* __restrict__ whi,
                              __nv_bfloat16* __restrict__ wlo,
                              int K, int N, int Npad,
                              size_t srcStride, size_t dstStride) {
    __shared__ float t[64][33];
    const float* Wz = W + (size_t)blockIdx.z * srcStride;
    int k0 = blockIdx.x * 64, n0 = blockIdx.y * 32;
    int tx = threadIdx.x, ty = threadIdx.y;   // 32 x 8
    bool nOK = (n0 + tx) < N;
#pragma unroll
    for (int j = 0; j < 8; j++) {
        int k = k0 + ty + 8 * j;
        float v = nOK ? Wz[(size_t)k * N + n0 + tx] : 0.f;
        t[ty + 8 * j][tx] = v;
    }
    __syncthreads();
    uint32_t* wh = (uint32_t*)(whi + (size_t)blockIdx.z * dstStride);
    uint32_t* wl = (uint32_t*)(wlo + (size_t)blockIdx.z * dstStride);
    int pw = permWord((k0 >> 1) + tx);
#pragma unroll
    for (int j = 0; j < 4; j++) {
        int nl = ty + 8 * j;                 // 0..31 (tile-local n)
        int n = n0 + nl;
        float a = t[2 * tx][nl];
        float b = t[2 * tx + 1][nl];
        uint32_t hw, lw;
        pack2(a, b, hw, lw);
        size_t rowW = (size_t)n * (K >> 1);
        wh[rowW + pw] = hw;
        wl[rowW + pw] = lw;
    }
}

// ---------------- split-K partial reduce: out = p0+p1+p2 + res ------------
__global__ void reduce3_kernel(const float* __restrict__ p,
                               const float* __restrict__ res,
                               float* __restrict__ out, int n) {
    int i = (blockIdx.x * blockDim.x + threadIdx.x) * 4;
    if (i >= n) return;
    float4 a = *(const float4*)(p + i);
    float4 b = *(const float4*)(p + n + i);
    float4 c = *(const float4*)(p + 2 * (size_t)n + i);
    float4 r = *(const float4*)(res + i);
    float4 o;
    o.x = a.x + b.x + c.x + r.x;
    o.y = a.y + b.y + c.y + r.y;
    o.z = a.z + b.z + c.z + r.z;
    o.w = a.w + b.w + c.w + r.w;
    *(float4*)(out + i) = o;
}

// ---------------- bf16 tensor-core GEMM (3-term split) --------------------
// blockIdx.z = split-K slice when nSplit > 1 (raw fp32 partial output).
__global__ __launch_bounds__(256, 2) void hgemm_kernel(
    const __nv_bfloat16* __restrict__ Ahi, const __nv_bfloat16* __restrict__ Alo,
    const __nv_bfloat16* __restrict__ Bhi, const __nv_bfloat16* __restrict__ Blo,
    float* __restrict__ C,
    __nv_bfloat16* __restrict__ Chi, __nv_bfloat16* __restrict__ Clo,
    int M, int N, int K,
    const float* __restrict__ bias, const float* __restrict__ res, int act,
    int nSplit) {
    extern __shared__ uint32_t sm[];
    const int tid  = threadIdx.x;
    const int lane = tid & 31;
    const int warp = tid >> 5;
    const int warpM = warp >> 2;
    const int warpN = warp & 3;
    const int gid = lane >> 2;
    const int tig = lane & 3;
    const int m0 = blockIdx.y * 128, n0 = blockIdx.x * 128;

    float acc[4][4][4] = {};

    auto issue = [&](int stage, int kt) {
        const uint32_t base = stage * kStageWords;
#pragma unroll
        for (int i = 0; i < 8; i++) {
            int c = tid + i * 256;
            int t = c >> 9, w = c & 511;
            int row = w >> 2, ck = w & 3;
            const __nv_bfloat16* src;
            if (t == 0)      src = Ahi + (size_t)(m0 + row) * K + kt + ck * 8;
            else if (t == 1) src = Alo + (size_t)(m0 + row) * K + kt + ck * 8;
            else if (t == 2) src = Bhi + (size_t)(n0 + row) * K + kt + ck * 8;
            else             src = Blo + (size_t)(n0 + row) * K + kt + ck * 8;
            uint32_t dst = (uint32_t)__cvta_generic_to_shared(
                &sm[base + t * kArrWords + row * kRowWords + ck * 4]);
            CP_ASYNC16(dst, src);
        }
    };

    auto compute = [&](int buf) {
        const uint32_t* SAh = sm + buf * kStageWords;
        const uint32_t* SAl = SAh + kArrWords;
        const uint32_t* SBh = SAl + kArrWords;
        const uint32_t* SBl = SBh + kArrWords;
#pragma unroll
        for (int ks = 0; ks < 2; ks++) {
            const int kwb = ks * 8 + 2 * tig;
            uint2 bh[4], bl[4];
#pragma unroll
            for (int in = 0; in < 4; in++) {
                const int n = warpN * 32 + in * 8 + gid;
                bh[in] = *(const uint2*)&SBh[n * kRowWords + kwb];
                bl[in] = *(const uint2*)&SBl[n * kRowWords + kwb];
            }
#pragma unroll
            for (int im = 0; im < 4; im++) {
                const int r = warpM * 64 + im * 16 + gid;
                uint2 uh = *(const uint2*)&SAh[r * kRowWords + kwb];
                uint2 vh = *(const uint2*)&SAh[(r + 8) * kRowWords + kwb];
                uint2 ul = *(const uint2*)&SAl[r * kRowWords + kwb];
                uint2 vl = *(const uint2*)&SAl[(r + 8) * kRowWords + kwb];
                uint32_t ahi[4] = {uh.x, vh.x, uh.y, vh.y};
                uint32_t alo[4] = {ul.x, vl.x, ul.y, vl.y};
#pragma unroll
                for (int in = 0; in < 4; in++) {
                    uint32_t bhw[2] = {bh[in].x, bh[in].y};
                    uint32_t blw[2] = {bl[in].x, bl[in].y};
                    MMA_BF16(acc[im][in], ahi, bhw);
                    MMA_BF16(acc[im][in], ahi, blw);
                    MMA_BF16(acc[im][in], alo, bhw);
                }
            }
        }
    };

    const int totalStages = K >> 5;
    const int per = (totalStages + nSplit - 1) / nSplit;
    const int s0 = blockIdx.z * per;
    int s1 = s0 + per;
    if (s1 > totalStages) s1 = totalStages;

    issue(0, s0 * 32);
    CP_COMMIT();
    for (int s = s0; s < s1; s++) {
        CP_WAIT0();
        __syncthreads();
        if (s + 1 < s1) { issue((s + 1 - s0) & 1, (s + 1) * 32); CP_COMMIT(); }
        compute((s - s0) & 1);
    }

    // ---- epilogue ----
    float* Cz = C;
    const bool partial = (nSplit > 1);
    if (partial) Cz = C + (size_t)blockIdx.z * M * N;
#pragma unroll
    for (int im = 0; im < 4; im++) {
        const int row = m0 + warpM * 64 + im * 16 + gid;
#pragma unroll
        for (int in = 0; in < 4; in++) {
            const int col = n0 + warpN * 32 + in * 8 + 2 * tig;
            if (col >= N) continue;
#pragma unroll
            for (int half = 0; half < 2; half++) {
                const int rr = row + half * 8;
                float c0 = acc[im][in][half * 2 + 0];
                float c1 = acc[im][in][half * 2 + 1];
                if (partial) {
                    *(float2*)(Cz + (size_t)rr * N + col) = make_float2(c0, c1);
                    continue;
                }
                if (bias) { c0 += bias[col]; c1 += bias[col + 1]; }
                if (act) {
                    c0 = 0.5f * c0 * (1.f + erff(c0 * 0.70710678118654752f));
                    c1 = 0.5f * c1 * (1.f + erff(c1 * 0.70710678118654752f));
                }
                if (res) {
                    const float2 rv = *(const float2*)(res + (size_t)rr * N + col);
                    c0 += rv.x; c1 += rv.y;
                }
                if (C)
                    *(float2*)(C + (size_t)rr * N + col) = make_float2(c0, c1);
                if (Chi) {
                    __nv_bfloat162 h, l;
                    split2(c0, c1, h, l);
                    size_t rowW = (size_t)rr * (N >> 1);
                    int pw = permWord(col >> 1);
                    ((__nv_bfloat162*)Chi)[rowW + pw] = h;
                    ((__nv_bfloat162*)Clo)[rowW + pw] = l;
                }
            }
        }
    }
}

// ---------------- flash attention on tensor cores (bf16 3-term split) -----
__global__ __launch_bounds__(256, 2) void attn_kernel(
    const __nv_bfloat16* __restrict__ qhi, const __nv_bfloat16* __restrict__ qlo,
    const __nv_bfloat16* __restrict__ khi, const __nv_bfloat16* __restrict__ klo,
    const uint32_t* __restrict__ vph, const uint32_t* __restrict__ vpl,
    __nv_bfloat16* __restrict__ ohi, __nv_bfloat16* __restrict__ olo,
    int Tq, int Tk, int diag) {
    extern __shared__ uint32_t sa[];
    float* sf = (float*)sa;
    const int tid = threadIdx.x;
    const int lane = tid & 31, warp = tid >> 5;
    const int g = lane >> 2, tg = lane & 3;
    const int warpQ = warp >> 1, warpK = warp & 1;
    const int q0 = blockIdx.x * 64, h = blockIdx.y, b = blockIdx.z;
    const int q0w = warpQ * 16;

    // stage Q via cp.async
    {
        const __nv_bfloat16* qh = qhi + ((size_t)(b * Tq + q0)) * kID + h * kDH;
        const __nv_bfloat16* ql = qlo + ((size_t)(b * Tq + q0)) * kID + h * kDH;
#pragma unroll
        for (int i = 0; i < 4; i++) {
            int ch = tid + i * 256;
            int arr = ch >> 9, w = ch & 511;
            int row = w >> 3, ck = w & 7;
            const __nv_bfloat16* src = (arr ? ql : qh) + (size_t)row * kID + ck * 8;
            uint32_t dst = (uint32_t)__cvta_generic_to_shared(
                &sa[(arr ? AQL : AQH) + row * 36 + ck * 4]);
            CP_ASYNC16(dst, src);
        }
        CP_COMMIT();
    }
    if (tid < 64) { sf[AMR + tid] = -1e30f; sf[ALR + tid] = 0.f; }

    float O[4][4] = {};
    int jmax = q0 + 63 + diag;
    int nkt = (jmax + 64) >> 6;
    int maxkt = Tk >> 6;
    if (nkt > maxkt) nkt = maxkt;

    const int r0i = q0w + g, r1i = r0i + 8;
    const int tk2 = Tk >> 1;
    const uint32_t* vhB = vph + ((size_t)b * kH + h) * tk2 * 64;
    const uint32_t* vlB = vpl + ((size_t)b * kH + h) * tk2 * 64;

    for (int kt = 0; kt < nkt; kt++) {
        const int k0 = kt * 64;
        {
            const __nv_bfloat16* kh = khi + ((size_t)(b * Tk + k0)) * kID + h * kDH;
            const __nv_bfloat16* kl = klo + ((size_t)(b * Tk + k0)) * kID + h * kDH;
#pragma unroll
            for (int i = 0; i < 4; i++) {
                int ch = tid + i * 256;
                int arr = ch >> 9, w = ch & 511;
                int row = w >> 3, ck = w & 7;
                const __nv_bfloat16* src = (arr ? kl : kh) + (size_t)row * kID + ck * 8;
                uint32_t dst = (uint32_t)__cvta_generic_to_shared(
                    &sa[(arr ? AKL : AKH) + row * 36 + ck * 4]);
                CP_ASYNC16(dst, src);
            }
            const uint32_t* vh = vhB + (size_t)(k0 >> 1) * 64;
            const uint32_t* vl = vlB + (size_t)(k0 >> 1) * 64;
#pragma unroll
            for (int i = 0; i < 4; i++) {
                int ch = tid + i * 256;
                int arr = ch >> 9, w = ch & 511;
                int k2 = w >> 4, ck = w & 15;
                const uint32_t* src = (arr ? vl : vh) + k2 * 64 + ck * 4;
                uint32_t dst = (uint32_t)__cvta_generic_to_shared(
                    &sa[(arr ? AVL : AVH) + k2 * 72 + ck * 4]);
                CP_ASYNC16(dst, src);
            }
            CP_COMMIT();
        }
        CP_WAIT0();
        __syncthreads();   // A: staging complete

        // ---- S = Q @ K^T ----
        float s[4][4];
#pragma unroll
        for (int nt = 0; nt < 4; nt++)
#pragma unroll
            for (int j = 0; j < 4; j++) s[nt][j] = 0.f;
#pragma unroll
        for (int ck = 0; ck < 4; ck++) {
            const int ac = ck * 8 + tg;
            uint32_t ahi[4] = {
                sa[AQH + r0i * 36 + ac], sa[AQH + r1i * 36 + ac],
                sa[AQH + r0i * 36 + ac + 4], sa[AQH + r1i * 36 + ac + 4]};
            uint32_t alo[4] = {
                sa[AQL + r0i * 36 + ac], sa[AQL + r1i * 36 + ac],
                sa[AQL + r0i * 36 + ac + 4], sa[AQL + r1i * 36 + ac + 4]};
#pragma unroll
            for (int nt = 0; nt < 4; nt++) {
                const int key = warpK * 32 + nt * 8 + g;
                uint32_t bhi[2] = {sa[AKH + key * 36 + ac],
                                   sa[AKH + key * 36 + ac + 4]};
                uint32_t blo[2] = {sa[AKL + key * 36 + ac],
                                   sa[AKL + key * 36 + ac + 4]};
                MMA_BF16(s[nt], ahi, bhi);
                MMA_BF16(s[nt], ahi, blo);
                MMA_BF16(s[nt], alo, bhi);
            }
        }
        // ---- causal mask ----
        if (k0 + 63 > q0 + diag) {
            int qr0 = q0 + r0i + diag;
            int qr1 = qr0 + 8;
#pragma unroll
            for (int nt = 0; nt < 4; nt++) {
                int cb = k0 + warpK * 32 + nt * 8 + 2 * tg;
                if (cb > qr0)     s[nt][0] = -1e30f;
                if (cb + 1 > qr0) s[nt][1] = -1e30f;
                if (cb > qr1)     s[nt][2] = -1e30f;
                if (cb + 1 > qr1) s[nt][3] = -1e30f;
            }
        }
        // ---- row max ----
        float mx0 = -1e30f, mx1 = -1e30f;
#pragma unroll
        for (int nt = 0; nt < 4; nt++) {
            mx0 = fmaxf(mx0, fmaxf(s[nt][0], s[nt][1]));
            mx1 = fmaxf(mx1, fmaxf(s[nt][2], s[nt][3]));
        }
        mx0 = fmaxf(mx0, __shfl_xor_sync(0xffffffffu, mx0, 1));
        mx0 = fmaxf(mx0, __shfl_xor_sync(0xffffffffu, mx0, 2));
        mx1 = fmaxf(mx1, __shfl_xor_sync(0xffffffffu, mx1, 1));
        mx1 = fmaxf(mx1, __shfl_xor_sync(0xffffffffu, mx1, 2));
        if (tg == 0) {
            sf[AMX + r0i * 2 + warpK] = mx0;
            sf[AMX + r1i * 2 + warpK] = mx1;
        }
        __syncthreads();   // B: maxes visible

        float mold0 = sf[AMR + r0i], mold1 = sf[AMR + r1i];
        float lold0 = sf[ALR + r0i], lold1 = sf[ALR + r1i];
        float mnew0 = fmaxf(mold0, fmaxf(sf[AMX + r0i * 2], sf[AMX + r0i * 2 + 1]));
        float mnew1 = fmaxf(mold1, fmaxf(sf[AMX + r1i * 2], sf[AMX + r1i * 2 + 1]));
        float f0 = __expf(mold0 - mnew0);
        float f1 = __expf(mold1 - mnew1);
        float sum0 = 0.f, sum1 = 0.f;
#pragma unroll
        for (int nt = 0; nt < 4; nt++) {
            float p00 = __expf(s[nt][0] - mnew0);
            float p01 = __expf(s[nt][1] - mnew0);
            float p10 = __expf(s[nt][2] - mnew1);
            float p11 = __expf(s[nt][3] - mnew1);
            sum0 += p00 + p01; sum1 += p10 + p11;
            uint32_t hw, lw;
            const int pc = warpK * 16 + nt * 4 + tg;
            pack2(p00, p01, hw, lw);
            sa[APH + r0i * 36 + pc] = hw; sa[APL + r0i * 36 + pc] = lw;
            pack2(p10, p11, hw, lw);
            sa[APH + r1i * 36 + pc] = hw; sa[APL + r1i * 36 + pc] = lw;
        }
        sum0 += __shfl_xor_sync(0xffffffffu, sum0, 1);
        sum0 += __shfl_xor_sync(0xffffffffu, sum0, 2);
        sum1 += __shfl_xor_sync(0xffffffffu, sum1, 1);
        sum1 += __shfl_xor_sync(0xffffffffu, sum1, 2);
        if (tg == 0) {
            sf[ASM + r0i * 2 + warpK] = sum0;
            sf[ASM + r1i * 2 + warpK] = sum1;
        }
        __syncthreads();  // C: P + sums visible

        // ---- rescale O, then O += P @ V ----
#pragma unroll
        for (int nt = 0; nt < 4; nt++) {
            O[nt][0] *= f0; O[nt][1] *= f0;
            O[nt][2] *= f1; O[nt][3] *= f1;
        }
#pragma unroll
        for (int kk = 0; kk < 4; kk++) {
            const int pc = kk * 8 + tg;
            uint32_t ahi[4] = {
                sa[APH + r0i * 36 + pc], sa[APH + r1i * 36 + pc],
                sa[APH + r0i * 36 + pc + 4], sa[APH + r1i * 36 + pc + 4]};
            uint32_t alo[4] = {
                sa[APL + r0i * 36 + pc], sa[APL + r1i * 36 + pc],
                sa[APL + r0i * 36 + pc + 4], sa[APL + r1i * 36 + pc + 4]};
#pragma unroll
            for (int nt = 0; nt < 4; nt++) {
                const int d0 = warpK * 32 + nt * 8 + g;
                uint32_t bhi[2] = {sa[AVH + (kk * 8 + tg) * 72 + d0],
                                   sa[AVH + (kk * 8 + 4 + tg) * 72 + d0]};
                uint32_t blo[2] = {sa[AVL + (kk * 8 + tg) * 72 + d0],
                                   sa[AVL + (kk * 8 + 4 + tg) * 72 + d0]};
                MMA_BF16(O[nt], ahi, bhi);
                MMA_BF16(O[nt], ahi, blo);
                MMA_BF16(O[nt], alo, bhi);
            }
        }
        // ---- state update ----
        if (warpK == 0 && tg == 0) {
            sf[AMR + r0i] = mnew0;
            sf[AMR + r1i] = mnew1;
            sf[ALR + r0i] = lold0 * f0 + sf[ASM + r0i * 2] + sf[ASM + r0i * 2 + 1];
            sf[ALR + r1i] = lold1 * f1 + sf[ASM + r1i * 2] + sf[ASM + r1i * 2 + 1];
        }
        __syncthreads();  // D: state final; K/V/P safe to overwrite
    }

    // ---- write output (split bf16, permuted, GEMM-ready) ----
    float inv0 = 1.f / sf[ALR + r0i];
    float inv1 = 1.f / sf[ALR + r1i];
    size_t rowW0 = ((size_t)b * Tq + q0 + r0i) * (kID / 2);
    size_t rowW1 = ((size_t)b * Tq + q0 + r1i) * (kID / 2);
#pragma unroll
    for (int nt = 0; nt < 4; nt++) {
        int col = h * kDH + warpK * 32 + nt * 8 + 2 * tg;
        int w0 = col >> 1;
        uint32_t hw, lw;
        pack2(O[nt][0] * inv0, O[nt][1] * inv0, hw, lw);
        ((uint32_t*)ohi)[rowW0 + permWord(w0)] = hw;
        ((uint32_t*)olo)[rowW0 + permWord(w0)] = lw;
        pack2(O[nt][2] * inv1, O[nt][3] * inv1, hw, lw);
        ((uint32_t*)ohi)[rowW1 + permWord(w0)] = hw;
        ((uint32_t*)olo)[rowW1 + permWord(w0)] = lw;
    }
}

// ---------------- host orchestration ----------------
namespace {
__nv_bfloat16 *h_whi, *h_wlo, *h_ahi, *h_alo;
__nv_bfloat16 *h_qhi, *h_qlo, *h_khi, *h_klo;
uint32_t *h_vph, *h_vpl;
float *h_part;

inline void gemm(size_t aOff, size_t wOff, float* C,
                 __nv_bfloat16* chi, __nv_bfloat16* clo,
                 int M, int N, int Npad, int K,
                 const float* bias, const float* res, int act,
                 int nSplit = 1) {
    dim3 g(Npad / 128, M / 128, nSplit);
    hgemm_kernel<<<g, 256, kGemmSmem>>>(
        h_ahi + aOff, h_alo + aOff, h_whi + wOff, h_wlo + wOff,
        C, chi, clo, M, N, K, bias, res, act, nSplit);
}
}

extern "C" void kernel_launch(void* const* d_in, const int* in_sizes, int n_in,
                              void* d_out, int out_size) {
    const int*   x           = (const int*)d_in[0];
    // d_in[1] = prefix_mask: all-True and padded True => no-op; unused.
    const float* token_emb   = (const float*)d_in[2];
    const float* pos_emb     = (const float*)d_in[3];
    const float* ca_norm_s   = (const float*)d_in[4];
    const float* ca_norm_b   = (const float*)d_in[5];
    const float* ca_ctx_ns   = (const float*)d_in[6];
    const float* ca_ctx_nb   = (const float*)d_in[7];
    const float* ca_wq       = (const float*)d_in[8];
    const float* ca_wkv      = (const float*)d_in[9];
    const float* ca_wo       = (const float*)d_in[10];
    const float* ca_bo       = (const float*)d_in[11];
    const float* ca_ff_ln_s  = (const float*)d_in[12];
    const float* ca_ff_ln_b  = (const float*)d_in[13];
    const float* ca_ff_w1    = (const float*)d_in[14];
    const float* ca_ff_w2    = (const float*)d_in[15];
    const float* l_norm_s    = (const float*)d_in[16];
    const float* l_norm_b    = (const float*)d_in[17];
    const float* l_wqkv      = (const float*)d_in[18];
    const float* l_wo        = (const float*)d_in[19];
    const float* l_ff_ln_s   = (const float*)d_in[20];
    const float* l_ff_ln_b   = (const float*)d_in[21];
    const float* l_ff_w1     = (const float*)d_in[22];
    const float* l_ff_w2     = (const float*)d_in[23];
    const float* w_logits    = (const float*)d_in[24];
    float* out = (float*)d_out;

    float *prefix, *lat, *qb, *kv, *qkv, *ctab, *stab;
    cudaGetSymbolAddress((void**)&prefix, g_prefix);
    cudaGetSymbolAddress((void**)&lat,    g_lat);
    cudaGetSymbolAddress((void**)&qb,     g_q);
    cudaGetSymbolAddress((void**)&kv,     g_kv);
    cudaGetSymbolAddress((void**)&qkv,    g_qkv);
    cudaGetSymbolAddress((void**)&ctab,   g_cos);
    cudaGetSymbolAddress((void**)&stab,   g_sin);
    cudaGetSymbolAddress((void**)&h_whi,  g_whi);
    cudaGetSymbolAddress((void**)&h_wlo,  g_wlo);
    cudaGetSymbolAddress((void**)&h_ahi,  g_ahi);
    cudaGetSymbolAddress((void**)&h_alo,  g_alo);
    cudaGetSymbolAddress((void**)&h_qhi,  g_qhi);
    cudaGetSymbolAddress((void**)&h_qlo,  g_qlo);
    cudaGetSymbolAddress((void**)&h_khi,  g_khi);
    cudaGetSymbolAddress((void**)&h_klo,  g_klo);
    cudaGetSymbolAddress((void**)&h_vph,  g_vph);
    cudaGetSymbolAddress((void**)&h_vpl,  g_vpl);
    cudaGetSymbolAddress((void**)&h_part, g_part);

    cudaFuncSetAttribute(hgemm_kernel,
                         cudaFuncAttributeMaxDynamicSharedMemorySize, kGemmSmem);
    cudaFuncSetAttribute(attn_kernel,
                         cudaFuncAttributeMaxDynamicSharedMemorySize, kAttnSmem);

    auto cw = [&](const float* W, size_t off, int K, int N, int Npad,
                  int layers, size_t srcStride, size_t dstStride) {
        dim3 g(K / 64, Npad / 32, layers);
        cvt_wt_kernel<<<g, dim3(32, 8)>>>(W, h_whi + off, h_wlo + off,
                                          K, N, Npad, srcStride, dstStride);
    };

    // weight conversions (batched across layers where possible)
    cw(ca_wq,    OFF_CAWQ,  1024, 1024, 1024, 1, 0, 0);
    cw(ca_wkv,   OFF_CAWKV, 1024, 2048, 2048, 1, 0, 0);
    cw(ca_wo,    OFF_CAWO,  1024, 1024, 1024, 1, 0, 0);
    cw(ca_ff_w1, OFF_CAFF1, 1024, 4096, 4096, 1, 0, 0);
    cw(ca_ff_w2, OFF_CAFF2, 4096, 1024, 1024, 1, 0, 0);
    cw(l_wqkv,   OFF_LQKV,  1024, 3072, 3072, kL, 1024ull * 3072, 3072ull * 1024);
    cw(l_wo,     OFF_LWO,   1024, 1024, 1024, kL, 1024ull * 1024, 1024ull * 1024);
    cw(l_ff_w1,  OFF_LFF1,  1024, 4096, 4096, kL, 1024ull * 4096, 4096ull * 1024);
    cw(l_ff_w2,  OFF_LFF2,  4096, 1024, 1024, kL, 4096ull * 1024, 1024ull * 4096);
    cw(w_logits, OFF_LOGITS, 1024, kV, kVp, 1, 0, 0);

    // embeddings + rope tables
    embed_kernel<<<kB * kS, 256>>>(x, token_emb, pos_emb, prefix, lat);
    rope_table_kernel<<<(kS * 16 + 255) / 256, 256>>>(ctab, stab);

    // 2. cross-attention block
    ln_bf16_kernel<<<kB * kNL, 256>>>(lat,    ca_norm_s, ca_norm_b,
                                      h_ahi + A0,  h_alo + A0);
    ln_bf16_kernel<<<kB * kP,  256>>>(prefix, ca_ctx_ns, ca_ctx_nb,
                                      h_ahi + ACN, h_alo + ACN);
    gemm(A0, OFF_CAWQ, qb, nullptr, nullptr,
         kB * kNL, kID, kID, kD, nullptr, nullptr, 0);
    for (int b = 0; b < kB; b++)
        gemm(ACN + (size_t)b * kP * kD, OFF_CAWKV,
             kv + (size_t)b * kS * 2 * kID, nullptr, nullptr,
             kP, 2 * kID, 2 * kID, kD, nullptr, nullptr, 0);
    for (int b = 0; b < kB; b++)
        gemm(A0 + (size_t)b * kNL * kD, OFF_CAWKV,
             kv + ((size_t)b * kS + kP) * 2 * kID, nullptr, nullptr,
             kNL, 2 * kID, 2 * kID, kD, nullptr, nullptr, 0);

    {
        int warps = kB * kS * kH;        // kv rows dominate
        qkvprep_kernel<<<(warps + 7) / 8, 256>>>(
            qb, kB * kNL, kID, kNL, kP,
            kv, kv + kID, kB * kS, 2 * kID, kS, 0,
            ctab, stab, h_qhi, h_qlo, h_khi, h_klo, h_vph, h_vpl);
    }
    attn_kernel<<<dim3(kNL / 64, kH, kB), 256, kAttnSmem>>>(
        h_qhi, h_qlo, h_khi, h_klo, h_vph, h_vpl,
        h_ahi + A0, h_alo + A0, kNL, kS, kP);

    gemm(A0, OFF_CAWO, lat, nullptr, nullptr,
         kB * kNL, kD, kD, kID, ca_bo, lat, 0);

    ln_bf16_kernel<<<kB * kNL, 256>>>(lat, ca_ff_ln_s, ca_ff_ln_b,
                                      h_ahi + A0, h_alo + A0);
    gemm(A0, OFF_CAFF1, nullptr, h_ahi + AFF, h_alo + AFF,
         kB * kNL, kFF, kFF, kD, nullptr, nullptr, 1);
    gemm(AFF, OFF_CAFF2, h_part, nullptr, nullptr,
         kB * kNL, kD, kD, kFF, nullptr, nullptr, 0, 3);
    reduce3_kernel<<<kFF2N / 1024, 256>>>(h_part, lat, lat, kFF2N);

    // 3. latent self-attention layers
    for (int li = 0; li < kL; li++) {
        ln_bf16_kernel<<<kB * kNL, 256>>>(lat, l_norm_s + li * kD,
                                          l_norm_b + li * kD,
                                          h_ahi + A0, h_alo + A0);
        gemm(A0, OFF_LQKV + (size_t)li * 3072 * 1024, qkv, nullptr, nullptr,
             kB * kNL, 3 * kID, 3 * kID, kD, nullptr, nullptr, 0);

        int warps = kB * kNL * kH;
        qkvprep_kernel<<<(warps + 7) / 8, 256>>>(
            qkv, kB * kNL, 3 * kID, kNL, kP,
            qkv + kID, qkv + 2 * kID, kB * kNL, 3 * kID, kNL, kP,
            ctab, stab, h_qhi, h_qlo, h_khi, h_klo, h_vph, h_vpl);
        attn_kernel<<<dim3(kNL / 64, kH, kB), 256, kAttnSmem>>>(
            h_qhi, h_qlo, h_khi, h_klo, h_vph, h_vpl,
            h_ahi + A0, h_alo + A0, kNL, kNL, 0);

        gemm(A0, OFF_LWO + (size_t)li * 1024 * 1024, lat, nullptr, nullptr,
             kB * kNL, kD, kD, kID, nullptr, lat, 0);

        ln_bf16_kernel<<<kB * kNL, 256>>>(lat, l_ff_ln_s + li * kD,
                                          l_ff_ln_b + li * kD,
                                          h_ahi + A0, h_alo + A0);
        gemm(A0, OFF_LFF1 + (size_t)li * 4096 * 1024, nullptr,
             h_ahi + AFF, h_alo + AFF,
             kB * kNL, kFF, kFF, kD, nullptr, nullptr, 1);
        gemm(AFF, OFF_LFF2 + (size_t)li * 1024 * 4096, h_part, nullptr, nullptr,
             kB * kNL, kD, kD, kFF, nullptr, nullptr, 0, 3);
        reduce3_kernel<<<kFF2N / 1024, 256>>>(h_part, lat, lat, kFF2N);
    }

    // 4. logits head
    {
        size_t n = (size_t)kB * kNL * kD;
        cvt_act_kernel<<<(int)((n / 2 + 255) / 256), 256>>>(
            lat, h_ahi + A0, h_alo + A0, (int)n);
    }
    gemm(A0, OFF_LOGITS, out, nullptr, nullptr,
         kB * kNL, kV, kVp, kD, nullptr, nullptr, 0);
}

// round 13
// speedup vs baseline: 3.3772x; 1.0474x over previous
#include <cuda_runtime.h>
#include <cuda_bf16.h>
#include <math.h>
#include <stdint.h>

// ---------------- problem constants ----------------
namespace {
constexpr int kB  = 2;
constexpr int kS  = 2048;
constexpr int kP  = 512;
constexpr int kNL = 1536;   // latent tokens = S - P
constexpr int kD  = 1024;
constexpr int kH  = 16;
constexpr int kDH = 64;
constexpr int kID = 1024;   // H * DH
constexpr int kV  = 20000;
constexpr int kVp = 20096;  // padded to 128
constexpr int kL  = 4;
constexpr int kFF = 4096;
constexpr float kScale = 0.125f;   // DH^-0.5
constexpr float kEps   = 1e-5f;

// weight arena offsets (transposed [N][K] layout, elements)
// NOTE: CAWQ rows [0,1024) and CAWKV rows [1024,3072) are adjacent, forming a
// combined 3072-row [q|k|v] projection used as ONE GEMM.
constexpr size_t OFF_CAWQ   = 0;                                  // 1024x1024
constexpr size_t OFF_CAWKV  = OFF_CAWQ  + 1024ull * 1024;         // 2048x1024
constexpr size_t OFF_CAWO   = OFF_CAWKV + 2048ull * 1024;         // 1024x1024
constexpr size_t OFF_CAFF1  = OFF_CAWO  + 1024ull * 1024;         // 4096x1024
constexpr size_t OFF_CAFF2  = OFF_CAFF1 + 4096ull * 1024;         // 1024x4096
constexpr size_t OFF_LQKV   = OFF_CAFF2 + 1024ull * 4096;         // 4 x 3072x1024
constexpr size_t OFF_LWO    = OFF_LQKV  + 4ull * 3072 * 1024;     // 4 x 1024x1024
constexpr size_t OFF_LFF1   = OFF_LWO   + 4ull * 1024 * 1024;     // 4 x 4096x1024
constexpr size_t OFF_LFF2   = OFF_LFF1  + 4ull * 4096 * 1024;     // 4 x 1024x4096
constexpr size_t OFF_LOGITS = OFF_LFF2  + 4ull * 1024 * 4096;     // 20096x1024
constexpr size_t W_TOTAL    = OFF_LOGITS + (size_t)kVp * 1024;

// activation arena regions (elements)
constexpr size_t A0   = 0;                                // xn/tmp/att/lat-cvt
constexpr size_t AFF  = (size_t)kB * kNL * kD;            // GELU(ff1) output
constexpr size_t ACN  = AFF + (size_t)kB * kNL * kFF;     // cn (prefix LN)
constexpr size_t A_TOTAL = ACN + (size_t)kB * kP * kD;

// hgemm smem: 2 stages x 4 arrays x 128 rows x 24 uint32 words
constexpr int kRowWords   = 24;                      // 16 data + 8 pad
constexpr int kArrWords   = 128 * kRowWords;         // 3072
constexpr int kStageWords = 4 * kArrWords;           // 12288
constexpr int kGemmSmem   = 2 * kStageWords * 4;     // 98304 bytes

// attention smem layout (uint32 word offsets)
constexpr int AQH = 0;                // Q hi  64 x 36
constexpr int AQL = AQH + 64 * 36;
constexpr int AKH = AQL + 64 * 36;    // K hi  64 x 36
constexpr int AKL = AKH + 64 * 36;
constexpr int AVH = AKL + 64 * 36;    // V hi  32 kpairs x 72
constexpr int AVL = AVH + 32 * 72;
constexpr int APH = AVL + 32 * 72;    // P hi  64 x 36
constexpr int APL = APH + 64 * 36;
constexpr int AMR = APL + 64 * 36;    // mrow[64] (float)
constexpr int ALR = AMR + 64;         // lrow[64]
constexpr int AMX = ALR + 64;         // smMax[64][2]
constexpr int ASM = AMX + 128;        // smSum[64][2]
constexpr int kAttnWords = ASM + 128; // 18816
constexpr int kAttnSmem  = kAttnWords * 4;  // 75264 bytes

constexpr int kFF2N = 3072 * 1024;    // split-K output elements (max)
}

// ---------------- scratch (module-load allocated, legal) ----------------
__device__ float g_prefix[kB * kP * kD];
__device__ float g_lat   [kB * kNL * kD];
__device__ float g_pkv   [kB * kP * 2 * kID];        // prefix [k|v] projection
__device__ float g_qkv   [kB * kNL * 3 * kID];
__device__ float g_cos   [kS * 16];
__device__ float g_sin   [kS * 16];
__device__ float g_part  [3ull * kFF2N];             // split-K partials
__device__ __nv_bfloat16 g_whi[W_TOTAL];
__device__ __nv_bfloat16 g_wlo[W_TOTAL];
__device__ __nv_bfloat16 g_ahi[A_TOTAL];
__device__ __nv_bfloat16 g_alo[A_TOTAL];
// attention operand buffers (split bf16, fragment-pair packed)
__device__ __nv_bfloat16 g_qhi[kB * kNL * kID];
__device__ __nv_bfloat16 g_qlo[kB * kNL * kID];
__device__ __nv_bfloat16 g_khi[kB * kS * kID];
__device__ __nv_bfloat16 g_klo[kB * kS * kID];
__device__ uint32_t g_vph[(size_t)kB * kH * (kS / 2) * 64];
__device__ uint32_t g_vpl[(size_t)kB * kH * (kS / 2) * 64];

// ---------------- low-level helpers ----------------
__device__ __forceinline__ float warpSum(float v) {
#pragma unroll
    for (int o = 16; o; o >>= 1) v += __shfl_xor_sync(0xffffffffu, v, o);
    return v;
}

// k-pair permutation: within each 8-word group, word w8 -> (w8&3)*2 + (w8>>2)
__device__ __forceinline__ int permWord(int w) {
    int w8 = w & 7;
    return (w & ~7) + ((w8 & 3) << 1) + (w8 >> 2);
}

__device__ __forceinline__ void split2(float a, float b,
                                       __nv_bfloat162& h, __nv_bfloat162& l) {
    __nv_bfloat16 h0 = __float2bfloat16(a);
    __nv_bfloat16 h1 = __float2bfloat16(b);
    h.x = h0; h.y = h1;
    l.x = __float2bfloat16(a - __bfloat162float(h0));
    l.y = __float2bfloat16(b - __bfloat162float(h1));
}

__device__ __forceinline__ void pack2(float a, float b,
                                      uint32_t& hw, uint32_t& lw) {
    __nv_bfloat162 h, l;
    split2(a, b, h, l);
    hw = *reinterpret_cast<uint32_t*>(&h);
    lw = *reinterpret_cast<uint32_t*>(&l);
}

#define MMA_BF16(c, a, b)                                                   \
    asm volatile(                                                           \
        "mma.sync.aligned.m16n8k16.row.col.f32.bf16.bf16.f32 "              \
        "{%0,%1,%2,%3}, {%4,%5,%6,%7}, {%8,%9}, {%0,%1,%2,%3};"             \
        : "+f"((c)[0]), "+f"((c)[1]), "+f"((c)[2]), "+f"((c)[3])            \
        : "r"((a)[0]), "r"((a)[1]), "r"((a)[2]), "r"((a)[3]),               \
          "r"((b)[0]), "r"((b)[1]))

#define CP_ASYNC16(dst, src)                                                \
    asm volatile("cp.async.cg.shared.global [%0], [%1], 16;"                \
                 :: "r"(dst), "l"(src))
#define CP_COMMIT() asm volatile("cp.async.commit_group;")
#define CP_WAIT0()  asm volatile("cp.async.wait_group 0;")

// ---------------- embedding ----------------
__global__ void embed_kernel(const int* __restrict__ x,
                             const float* __restrict__ te,
                             const float* __restrict__ pe,
                             float* __restrict__ prefix,
                             float* __restrict__ lat) {
    int row = blockIdx.x;
    int b = row / kS, s = row % kS;
    int tok = x[row];
    const float* tr = te + (size_t)tok * kD;
    const float* pr = pe + (size_t)s * kD;
    float* dst = (s < kP) ? (prefix + ((size_t)b * kP + s) * kD)
                          : (lat    + ((size_t)b * kNL + (s - kP)) * kD);
    for (int i = threadIdx.x; i < kD; i += blockDim.x) dst[i] = tr[i] + pr[i];
}

// ---------------- LayerNorm -> split bf16 (permuted) ----------------
__global__ __launch_bounds__(256) void ln_bf16_kernel(
    const float* __restrict__ in, const float* __restrict__ gamma,
    const float* __restrict__ beta,
    __nv_bfloat16* __restrict__ hi, __nv_bfloat16* __restrict__ lo) {
    int r = blockIdx.x;
    const float* xr = in + (size_t)r * kD;
    int tid = threadIdx.x;
    float4 v4 = *(const float4*)(xr + 4 * tid);
    float v[4] = {v4.x, v4.y, v4.z, v4.w};
    float s = v[0] + v[1] + v[2] + v[3];
    __shared__ float red[8];
    __shared__ float meanS, rstdS;
    s = warpSum(s);
    if ((tid & 31) == 0) red[tid >> 5] = s;
    __syncthreads();
    if (tid < 32) {
        float t = (tid < 8) ? red[tid] : 0.f;
        t = warpSum(t);
        if (tid == 0) meanS = t * (1.f / kD);
    }
    __syncthreads();
    float mean = meanS;
    float s2 = 0.f;
#pragma unroll
    for (int i = 0; i < 4; i++) { float d = v[i] - mean; s2 += d * d; }
    s2 = warpSum(s2);
    __syncthreads();
    if ((tid & 31) == 0) red[tid >> 5] = s2;
    __syncthreads();
    if (tid < 32) {
        float t = (tid < 8) ? red[tid] : 0.f;
        t = warpSum(t);
        if (tid == 0) rstdS = rsqrtf(t * (1.f / kD) + kEps);
    }
    __syncthreads();
    float rs = rstdS;
    float4 g4 = *(const float4*)(gamma + 4 * tid);
    float4 b4 = *(const float4*)(beta + 4 * tid);
    float y0 = (v[0] - mean) * rs * g4.x + b4.x;
    float y1 = (v[1] - mean) * rs * g4.y + b4.y;
    float y2 = (v[2] - mean) * rs * g4.z + b4.z;
    float y3 = (v[3] - mean) * rs * g4.w + b4.w;
    __nv_bfloat162 h0, l0, h1, l1;
    split2(y0, y1, h0, l0);
    split2(y2, y3, h1, l1);
    size_t rowW = (size_t)r * (kD / 2);
    int w0 = 2 * tid;
    ((__nv_bfloat162*)hi)[rowW + permWord(w0)]     = h0;
    ((__nv_bfloat162*)hi)[rowW + permWord(w0 + 1)] = h1;
    ((__nv_bfloat162*)lo)[rowW + permWord(w0)]     = l0;
    ((__nv_bfloat162*)lo)[rowW + permWord(w0 + 1)] = l1;
}

// ---------------- RoPE table ----------------
__global__ void rope_table_kernel(float* __restrict__ ct, float* __restrict__ st) {
    int idx = blockIdx.x * blockDim.x + threadIdx.x;
    if (idx >= kS * 16) return;
    int s = idx >> 4, i = idx & 15;
    float inv = (float)(1.0 / pow(10000.0, (double)i / 16.0));
    float f = (float)s * inv;
    ct[idx] = (float)cos((double)f);
    st[idx] = (float)sin((double)f);
}

// ---------------- warp rope helper: lane owns word (2l, 2l+1) -------------
__device__ __forceinline__ void ropeWord(const float* __restrict__ p, int pos,
                                         float scaleAll, int lane,
                                         const float* __restrict__ ct,
                                         const float* __restrict__ st,
                                         uint32_t& hw, uint32_t& lw) {
    float2 v = *(const float2*)(p + 2 * lane);
    float ox = __shfl_xor_sync(0xffffffffu, v.x, 8);
    float oy = __shfl_xor_sync(0xffffffffu, v.y, 8);
    float y0, y1;
    if (lane < 8) {
        float c0 = ct[pos * 16 + 2 * lane],     s0 = st[pos * 16 + 2 * lane];
        float c1 = ct[pos * 16 + 2 * lane + 1], s1 = st[pos * 16 + 2 * lane + 1];
        y0 = v.x * c0 - ox * s0;
        y1 = v.y * c1 - oy * s1;
    } else if (lane < 16) {
        int i = 2 * lane - 16;
        float c0 = ct[pos * 16 + i],     s0 = st[pos * 16 + i];
        float c1 = ct[pos * 16 + i + 1], s1 = st[pos * 16 + i + 1];
        y0 = v.x * c0 + ox * s0;
        y1 = v.y * c1 + oy * s1;
    } else {
        y0 = v.x; y1 = v.y;
    }
    pack2(y0 * scaleAll, y1 * scaleAll, hw, lw);
}

// ---------------- fused Q-rope + K-rope + V-pack (warp per row-head) ------
// K/V output token index = kOutOff + (row % kT), sequence length kSeqOut.
// qRows may be 0 (prefix-only call).
__global__ __launch_bounds__(256) void qkvprep_kernel(
    const float* __restrict__ qsrc, int qRows, int qStride, int qT, int qPos,
    const float* __restrict__ ksrc, const float* __restrict__ vsrc,
    int kvRows, int kvStride, int kT, int kPos, int kSeqOut, int kOutOff,
    const float* __restrict__ ct, const float* __restrict__ st,
    __nv_bfloat16* __restrict__ qhi, __nv_bfloat16* __restrict__ qlo,
    __nv_bfloat16* __restrict__ khi, __nv_bfloat16* __restrict__ klo,
    uint32_t* __restrict__ vph, uint32_t* __restrict__ vpl) {
    int warp = threadIdx.x >> 5, lane = threadIdx.x & 31;
    int idx = blockIdx.x * 8 + warp;
    if (idx >= kvRows * kH) return;
    int row = idx / kH, h = idx % kH;
    int b = row / kT, tloc = row % kT;
    int token = kOutOff + tloc;
    uint32_t hw, lw;
    // K rope (scale 1)
    {
        const float* p = ksrc + (size_t)row * kvStride + h * kDH;
        ropeWord(p, kPos + tloc, 1.f, lane, ct, st, hw, lw);
        size_t w = ((size_t)b * kSeqOut + token) * (kID / 2) + h * 32 + lane;
        ((uint32_t*)khi)[w] = hw;
        ((uint32_t*)klo)[w] = lw;
    }
    // V pack (even local rows handle the pair; kOutOff and kT are even)
    if (!(tloc & 1)) {
        const float* p0 = vsrc + (size_t)row * kvStride + h * kDH;
        const float* p1 = p0 + kvStride;
        int k2 = token >> 1;
        size_t base = (((size_t)b * kH + h) * (kSeqOut >> 1) + k2) * 64;
        pack2(p0[lane], p1[lane], hw, lw);
        vph[base + lane] = hw;
        vpl[base + lane] = lw;
        pack2(p0[lane + 32], p1[lane + 32], hw, lw);
        vph[base + lane + 32] = hw;
        vpl[base + lane + 32] = lw;
    }
    // Q rope (scale kScale)
    if (row < qRows) {
        const float* p = qsrc + (size_t)row * qStride + h * kDH;
        ropeWord(p, qPos + (row % qT), kScale, lane, ct, st, hw, lw);
        size_t w = (size_t)row * (kID / 2) + h * 32 + lane;
        ((uint32_t*)qhi)[w] = hw;
        ((uint32_t*)qlo)[w] = lw;
    }
}

// ---------------- fp32 -> bf16 hi/lo converter (k-pair permuted) ----------
__global__ void cvt_act_kernel(const float* __restrict__ in,
                               __nv_bfloat16* __restrict__ hi,
                               __nv_bfloat16* __restrict__ lo, int n) {
    int w = blockIdx.x * blockDim.x + threadIdx.x;
    if (w * 2 >= n) return;
    float2 v = *(const float2*)(in + (size_t)w * 2);
    __nv_bfloat162 h, l;
    split2(v.x, v.y, h, l);
    int pw = permWord(w);
    ((__nv_bfloat162*)hi)[pw] = h;
    ((__nv_bfloat162*)lo)[pw] = l;
}

// transpose + convert weights: W[K,N] fp32 -> Wt_hi/lo[Npad,K] bf16,
// k-pair permuted, zero padded. Tile 64(k) x 32(n); whole-word writes.
// blockIdx.z = layer (batched conversion).
__global__ void cvt_wt_kernel(const float* __restrict__ W,
                              __nv_bfloat16* __restrict__ whi,
                              __nv_bfloat16* __restrict__ wlo,
                              int K, int N, int Npad,
                              size_t srcStride, size_t dstStride) {
    __shared__ float t[64][33];
    const float* Wz = W + (size_t)blockIdx.z * srcStride;
    int k0 = blockIdx.x * 64, n0 = blockIdx.y * 32;
    int tx = threadIdx.x, ty = threadIdx.y;   // 32 x 8
    bool nOK = (n0 + tx) < N;
#pragma unroll
    for (int j = 0; j < 8; j++) {
        int k = k0 + ty + 8 * j;
        float v = nOK ? Wz[(size_t)k * N + n0 + tx] : 0.f;
        t[ty + 8 * j][tx] = v;
    }
    __syncthreads();
    uint32_t* wh = (uint32_t*)(whi + (size_t)blockIdx.z * dstStride);
    uint32_t* wl = (uint32_t*)(wlo + (size_t)blockIdx.z * dstStride);
    int pw = permWord((k0 >> 1) + tx);
#pragma unroll
    for (int j = 0; j < 4; j++) {
        int nl = ty + 8 * j;                 // 0..31 (tile-local n)
        int n = n0 + nl;
        float a = t[2 * tx][nl];
        float b = t[2 * tx + 1][nl];
        uint32_t hw, lw;
        pack2(a, b, hw, lw);
        size_t rowW = (size_t)n * (K >> 1);
        wh[rowW + pw] = hw;
        wl[rowW + pw] = lw;
    }
}

// ---------------- split-K reduce: out = p0+p1+p2 [+bias] [+res] -----------
__global__ void reduce3_kernel(const float* __restrict__ p,
                               const float* __restrict__ bias,
                               const float* __restrict__ res,
                               float* __restrict__ out, int n, int N) {
    int i = (blockIdx.x * blockDim.x + threadIdx.x) * 4;
    if (i >= n) return;
    float4 a = *(const float4*)(p + i);
    float4 b = *(const float4*)(p + n + i);
    float4 c = *(const float4*)(p + 2 * (size_t)n + i);
    float4 o;
    o.x = a.x + b.x + c.x;
    o.y = a.y + b.y + c.y;
    o.z = a.z + b.z + c.z;
    o.w = a.w + b.w + c.w;
    if (bias) {
        const float4 bv = *(const float4*)(bias + (i & (N - 1)));
        o.x += bv.x; o.y += bv.y; o.z += bv.z; o.w += bv.w;
    }
    if (res) {
        const float4 r = *(const float4*)(res + i);
        o.x += r.x; o.y += r.y; o.z += r.z; o.w += r.w;
    }
    *(float4*)(out + i) = o;
}

// ---------------- bf16 tensor-core GEMM (3-term split) --------------------
// blockIdx.z = split-K slice when nSplit > 1 (raw fp32 partial output).
__global__ __launch_bounds__(256, 2) void hgemm_kernel(
    const __nv_bfloat16* __restrict__ Ahi, const __nv_bfloat16* __restrict__ Alo,
    const __nv_bfloat16* __restrict__ Bhi, const __nv_bfloat16* __restrict__ Blo,
    float* __restrict__ C,
    __nv_bfloat16* __restrict__ Chi, __nv_bfloat16* __restrict__ Clo,
    int M, int N, int K,
    const float* __restrict__ bias, const float* __restrict__ res, int act,
    int nSplit) {
    extern __shared__ uint32_t sm[];
    const int tid  = threadIdx.x;
    const int lane = tid & 31;
    const int warp = tid >> 5;
    const int warpM = warp >> 2;
    const int warpN = warp & 3;
    const int gid = lane >> 2;
    const int tig = lane & 3;
    const int m0 = blockIdx.y * 128, n0 = blockIdx.x * 128;

    float acc[4][4][4] = {};

    auto issue = [&](int stage, int kt) {
        const uint32_t base = stage * kStageWords;
#pragma unroll
        for (int i = 0; i < 8; i++) {
            int c = tid + i * 256;
            int t = c >> 9, w = c & 511;
            int row = w >> 2, ck = w & 3;
            const __nv_bfloat16* src;
            if (t == 0)      src = Ahi + (size_t)(m0 + row) * K + kt + ck * 8;
            else if (t == 1) src = Alo + (size_t)(m0 + row) * K + kt + ck * 8;
            else if (t == 2) src = Bhi + (size_t)(n0 + row) * K + kt + ck * 8;
            else             src = Blo + (size_t)(n0 + row) * K + kt + ck * 8;
            uint32_t dst = (uint32_t)__cvta_generic_to_shared(
                &sm[base + t * kArrWords + row * kRowWords + ck * 4]);
            CP_ASYNC16(dst, src);
        }
    };

    auto compute = [&](int buf) {
        const uint32_t* SAh = sm + buf * kStageWords;
        const uint32_t* SAl = SAh + kArrWords;
        const uint32_t* SBh = SAl + kArrWords;
        const uint32_t* SBl = SBh + kArrWords;
#pragma unroll
        for (int ks = 0; ks < 2; ks++) {
            const int kwb = ks * 8 + 2 * tig;
            uint2 bh[4], bl[4];
#pragma unroll
            for (int in = 0; in < 4; in++) {
                const int n = warpN * 32 + in * 8 + gid;
                bh[in] = *(const uint2*)&SBh[n * kRowWords + kwb];
                bl[in] = *(const uint2*)&SBl[n * kRowWords + kwb];
            }
#pragma unroll
            for (int im = 0; im < 4; im++) {
                const int r = warpM * 64 + im * 16 + gid;
                uint2 uh = *(const uint2*)&SAh[r * kRowWords + kwb];
                uint2 vh = *(const uint2*)&SAh[(r + 8) * kRowWords + kwb];
                uint2 ul = *(const uint2*)&SAl[r * kRowWords + kwb];
                uint2 vl = *(const uint2*)&SAl[(r + 8) * kRowWords + kwb];
                uint32_t ahi[4] = {uh.x, vh.x, uh.y, vh.y};
                uint32_t alo[4] = {ul.x, vl.x, ul.y, vl.y};
#pragma unroll
                for (int in = 0; in < 4; in++) {
                    uint32_t bhw[2] = {bh[in].x, bh[in].y};
                    uint32_t blw[2] = {bl[in].x, bl[in].y};
                    MMA_BF16(acc[im][in], ahi, bhw);
                    MMA_BF16(acc[im][in], ahi, blw);
                    MMA_BF16(acc[im][in], alo, bhw);
                }
            }
        }
    };

    const int totalStages = K >> 5;
    const int per = (totalStages + nSplit - 1) / nSplit;
    const int s0 = blockIdx.z * per;
    int s1 = s0 + per;
    if (s1 > totalStages) s1 = totalStages;

    issue(0, s0 * 32);
    CP_COMMIT();
    for (int s = s0; s < s1; s++) {
        CP_WAIT0();
        __syncthreads();
        if (s + 1 < s1) { issue((s + 1 - s0) & 1, (s + 1) * 32); CP_COMMIT(); }
        compute((s - s0) & 1);
    }

    // ---- epilogue ----
    float* Cz = C;
    const bool partial = (nSplit > 1);
    if (partial) Cz = C + (size_t)blockIdx.z * M * N;
#pragma unroll
    for (int im = 0; im < 4; im++) {
        const int row = m0 + warpM * 64 + im * 16 + gid;
#pragma unroll
        for (int in = 0; in < 4; in++) {
            const int col = n0 + warpN * 32 + in * 8 + 2 * tig;
            if (col >= N) continue;
#pragma unroll
            for (int half = 0; half < 2; half++) {
                const int rr = row + half * 8;
                float c0 = acc[im][in][half * 2 + 0];
                float c1 = acc[im][in][half * 2 + 1];
                if (partial) {
                    *(float2*)(Cz + (size_t)rr * N + col) = make_float2(c0, c1);
                    continue;
                }
                if (bias) { c0 += bias[col]; c1 += bias[col + 1]; }
                if (act) {
                    c0 = 0.5f * c0 * (1.f + erff(c0 * 0.70710678118654752f));
                    c1 = 0.5f * c1 * (1.f + erff(c1 * 0.70710678118654752f));
                }
                if (res) {
                    const float2 rv = *(const float2*)(res + (size_t)rr * N + col);
                    c0 += rv.x; c1 += rv.y;
                }
                if (C)
                    *(float2*)(C + (size_t)rr * N + col) = make_float2(c0, c1);
                if (Chi) {
                    __nv_bfloat162 h, l;
                    split2(c0, c1, h, l);
                    size_t rowW = (size_t)rr * (N >> 1);
                    int pw = permWord(col >> 1);
                    ((__nv_bfloat162*)Chi)[rowW + pw] = h;
                    ((__nv_bfloat162*)Clo)[rowW + pw] = l;
                }
            }
        }
    }
}

// ---------------- flash attention on tensor cores (bf16 3-term split) -----
// Longest-first scheduling: q-blocks processed in reverse order.
__global__ __launch_bounds__(256, 2) void attn_kernel(
    const __nv_bfloat16* __restrict__ qhi, const __nv_bfloat16* __restrict__ qlo,
    const __nv_bfloat16* __restrict__ khi, const __nv_bfloat16* __restrict__ klo,
    const uint32_t* __restrict__ vph, const uint32_t* __restrict__ vpl,
    __nv_bfloat16* __restrict__ ohi, __nv_bfloat16* __restrict__ olo,
    int Tq, int Tk, int diag) {
    extern __shared__ uint32_t sa[];
    float* sf = (float*)sa;
    const int tid = threadIdx.x;
    const int lane = tid & 31, warp = tid >> 5;
    const int g = lane >> 2, tg = lane & 3;
    const int warpQ = warp >> 1, warpK = warp & 1;
    const int q0 = (gridDim.x - 1 - blockIdx.x) * 64;
    const int h = blockIdx.y, b = blockIdx.z;
    const int q0w = warpQ * 16;

    // stage Q via cp.async
    {
        const __nv_bfloat16* qh = qhi + ((size_t)(b * Tq + q0)) * kID + h * kDH;
        const __nv_bfloat16* ql = qlo + ((size_t)(b * Tq + q0)) * kID + h * kDH;
#pragma unroll
        for (int i = 0; i < 4; i++) {
            int ch = tid + i * 256;
            int arr = ch >> 9, w = ch & 511;
            int row = w >> 3, ck = w & 7;
            const __nv_bfloat16* src = (arr ? ql : qh) + (size_t)row * kID + ck * 8;
            uint32_t dst = (uint32_t)__cvta_generic_to_shared(
                &sa[(arr ? AQL : AQH) + row * 36 + ck * 4]);
            CP_ASYNC16(dst, src);
        }
        CP_COMMIT();
    }
    if (tid < 64) { sf[AMR + tid] = -1e30f; sf[ALR + tid] = 0.f; }

    float O[4][4] = {};
    int jmax = q0 + 63 + diag;
    int nkt = (jmax + 64) >> 6;
    int maxkt = Tk >> 6;
    if (nkt > maxkt) nkt = maxkt;

    const int r0i = q0w + g, r1i = r0i + 8;
    const int tk2 = Tk >> 1;
    const uint32_t* vhB = vph + ((size_t)b * kH + h) * tk2 * 64;
    const uint32_t* vlB = vpl + ((size_t)b * kH + h) * tk2 * 64;

    for (int kt = 0; kt < nkt; kt++) {
        const int k0 = kt * 64;
        {
            const __nv_bfloat16* kh = khi + ((size_t)(b * Tk + k0)) * kID + h * kDH;
            const __nv_bfloat16* kl = klo + ((size_t)(b * Tk + k0)) * kID + h * kDH;
#pragma unroll
            for (int i = 0; i < 4; i++) {
                int ch = tid + i * 256;
                int arr = ch >> 9, w = ch & 511;
                int row = w >> 3, ck = w & 7;
                const __nv_bfloat16* src = (arr ? kl : kh) + (size_t)row * kID + ck * 8;
                uint32_t dst = (uint32_t)__cvta_generic_to_shared(
                    &sa[(arr ? AKL : AKH) + row * 36 + ck * 4]);
                CP_ASYNC16(dst, src);
            }
            const uint32_t* vh = vhB + (size_t)(k0 >> 1) * 64;
            const uint32_t* vl = vlB + (size_t)(k0 >> 1) * 64;
#pragma unroll
            for (int i = 0; i < 4; i++) {
                int ch = tid + i * 256;
                int arr = ch >> 9, w = ch & 511;
                int k2 = w >> 4, ck = w & 15;
                const uint32_t* src = (arr ? vl : vh) + k2 * 64 + ck * 4;
                uint32_t dst = (uint32_t)__cvta_generic_to_shared(
                    &sa[(arr ? AVL : AVH) + k2 * 72 + ck * 4]);
                CP_ASYNC16(dst, src);
            }
            CP_COMMIT();
        }
        CP_WAIT0();
        __syncthreads();   // A: staging complete

        // ---- S = Q @ K^T ----
        float s[4][4];
#pragma unroll
        for (int nt = 0; nt < 4; nt++)
#pragma unroll
            for (int j = 0; j < 4; j++) s[nt][j] = 0.f;
#pragma unroll
        for (int ck = 0; ck < 4; ck++) {
            const int ac = ck * 8 + tg;
            uint32_t ahi[4] = {
                sa[AQH + r0i * 36 + ac], sa[AQH + r1i * 36 + ac],
                sa[AQH + r0i * 36 + ac + 4], sa[AQH + r1i * 36 + ac + 4]};
            uint32_t alo[4] = {
                sa[AQL + r0i * 36 + ac], sa[AQL + r1i * 36 + ac],
                sa[AQL + r0i * 36 + ac + 4], sa[AQL + r1i * 36 + ac + 4]};
#pragma unroll
            for (int nt = 0; nt < 4; nt++) {
                const int key = warpK * 32 + nt * 8 + g;
                uint32_t bhi[2] = {sa[AKH + key * 36 + ac],
                                   sa[AKH + key * 36 + ac + 4]};
                uint32_t blo[2] = {sa[AKL + key * 36 + ac],
                                   sa[AKL + key * 36 + ac + 4]};
                MMA_BF16(s[nt], ahi, bhi);
                MMA_BF16(s[nt], ahi, blo);
                MMA_BF16(s[nt], alo, bhi);
            }
        }
        // ---- causal mask ----
        if (k0 + 63 > q0 + diag) {
            int qr0 = q0 + r0i + diag;
            int qr1 = qr0 + 8;
#pragma unroll
            for (int nt = 0; nt < 4; nt++) {
                int cb = k0 + warpK * 32 + nt * 8 + 2 * tg;
                if (cb > qr0)     s[nt][0] = -1e30f;
                if (cb + 1 > qr0) s[nt][1] = -1e30f;
                if (cb > qr1)     s[nt][2] = -1e30f;
                if (cb + 1 > qr1) s[nt][3] = -1e30f;
            }
        }
        // ---- row max ----
        float mx0 = -1e30f, mx1 = -1e30f;
#pragma unroll
        for (int nt = 0; nt < 4; nt++) {
            mx0 = fmaxf(mx0, fmaxf(s[nt][0], s[nt][1]));
            mx1 = fmaxf(mx1, fmaxf(s[nt][2], s[nt][3]));
        }
        mx0 = fmaxf(mx0, __shfl_xor_sync(0xffffffffu, mx0, 1));
        mx0 = fmaxf(mx0, __shfl_xor_sync(0xffffffffu, mx0, 2));
        mx1 = fmaxf(mx1, __shfl_xor_sync(0xffffffffu, mx1, 1));
        mx1 = fmaxf(mx1, __shfl_xor_sync(0xffffffffu, mx1, 2));
        if (tg == 0) {
            sf[AMX + r0i * 2 + warpK] = mx0;
            sf[AMX + r1i * 2 + warpK] = mx1;
        }
        __syncthreads();   // B: maxes visible

        float mold0 = sf[AMR + r0i], mold1 = sf[AMR + r1i];
        float lold0 = sf[ALR + r0i], lold1 = sf[ALR + r1i];
        float mnew0 = fmaxf(mold0, fmaxf(sf[AMX + r0i * 2], sf[AMX + r0i * 2 + 1]));
        float mnew1 = fmaxf(mold1, fmaxf(sf[AMX + r1i * 2], sf[AMX + r1i * 2 + 1]));
        float f0 = __expf(mold0 - mnew0);
        float f1 = __expf(mold1 - mnew1);
        float sum0 = 0.f, sum1 = 0.f;
#pragma unroll
        for (int nt = 0; nt < 4; nt++) {
            float p00 = __expf(s[nt][0] - mnew0);
            float p01 = __expf(s[nt][1] - mnew0);
            float p10 = __expf(s[nt][2] - mnew1);
            float p11 = __expf(s[nt][3] - mnew1);
            sum0 += p00 + p01; sum1 += p10 + p11;
            uint32_t hw, lw;
            const int pc = warpK * 16 + nt * 4 + tg;
            pack2(p00, p01, hw, lw);
            sa[APH + r0i * 36 + pc] = hw; sa[APL + r0i * 36 + pc] = lw;
            pack2(p10, p11, hw, lw);
            sa[APH + r1i * 36 + pc] = hw; sa[APL + r1i * 36 + pc] = lw;
        }
        sum0 += __shfl_xor_sync(0xffffffffu, sum0, 1);
        sum0 += __shfl_xor_sync(0xffffffffu, sum0, 2);
        sum1 += __shfl_xor_sync(0xffffffffu, sum1, 1);
        sum1 += __shfl_xor_sync(0xffffffffu, sum1, 2);
        if (tg == 0) {
            sf[ASM + r0i * 2 + warpK] = sum0;
            sf[ASM + r1i * 2 + warpK] = sum1;
        }
        __syncthreads();  // C: P + sums visible

        // ---- rescale O, then O += P @ V ----
#pragma unroll
        for (int nt = 0; nt < 4; nt++) {
            O[nt][0] *= f0; O[nt][1] *= f0;
            O[nt][2] *= f1; O[nt][3] *= f1;
        }
#pragma unroll
        for (int kk = 0; kk < 4; kk++) {
            const int pc = kk * 8 + tg;
            uint32_t ahi[4] = {
                sa[APH + r0i * 36 + pc], sa[APH + r1i * 36 + pc],
                sa[APH + r0i * 36 + pc + 4], sa[APH + r1i * 36 + pc + 4]};
            uint32_t alo[4] = {
                sa[APL + r0i * 36 + pc], sa[APL + r1i * 36 + pc],
                sa[APL + r0i * 36 + pc + 4], sa[APL + r1i * 36 + pc + 4]};
#pragma unroll
            for (int nt = 0; nt < 4; nt++) {
                const int d0 = warpK * 32 + nt * 8 + g;
                uint32_t bhi[2] = {sa[AVH + (kk * 8 + tg) * 72 + d0],
                                   sa[AVH + (kk * 8 + 4 + tg) * 72 + d0]};
                uint32_t blo[2] = {sa[AVL + (kk * 8 + tg) * 72 + d0],
                                   sa[AVL + (kk * 8 + 4 + tg) * 72 + d0]};
                MMA_BF16(O[nt], ahi, bhi);
                MMA_BF16(O[nt], ahi, blo);
                MMA_BF16(O[nt], alo, bhi);
            }
        }
        // ---- state update ----
        if (warpK == 0 && tg == 0) {
            sf[AMR + r0i] = mnew0;
            sf[AMR + r1i] = mnew1;
            sf[ALR + r0i] = lold0 * f0 + sf[ASM + r0i * 2] + sf[ASM + r0i * 2 + 1];
            sf[ALR + r1i] = lold1 * f1 + sf[ASM + r1i * 2] + sf[ASM + r1i * 2 + 1];
        }
        __syncthreads();  // D: state final; K/V/P safe to overwrite
    }

    // ---- write output (split bf16, permuted, GEMM-ready) ----
    float inv0 = 1.f / sf[ALR + r0i];
    float inv1 = 1.f / sf[ALR + r1i];
    size_t rowW0 = ((size_t)b * Tq + q0 + r0i) * (kID / 2);
    size_t rowW1 = ((size_t)b * Tq + q0 + r1i) * (kID / 2);
#pragma unroll
    for (int nt = 0; nt < 4; nt++) {
        int col = h * kDH + warpK * 32 + nt * 8 + 2 * tg;
        int w0 = col >> 1;
        uint32_t hw, lw;
        pack2(O[nt][0] * inv0, O[nt][1] * inv0, hw, lw);
        ((uint32_t*)ohi)[rowW0 + permWord(w0)] = hw;
        ((uint32_t*)olo)[rowW0 + permWord(w0)] = lw;
        pack2(O[nt][2] * inv1, O[nt][3] * inv1, hw, lw);
        ((uint32_t*)ohi)[rowW1 + permWord(w0)] = hw;
        ((uint32_t*)olo)[rowW1 + permWord(w0)] = lw;
    }
}

// ---------------- host orchestration ----------------
namespace {
__nv_bfloat16 *h_whi, *h_wlo, *h_ahi, *h_alo;
__nv_bfloat16 *h_qhi, *h_qlo, *h_khi, *h_klo;
uint32_t *h_vph, *h_vpl;
float *h_part;

inline void gemm(size_t aOff, size_t wOff, float* C,
                 __nv_bfloat16* chi, __nv_bfloat16* clo,
                 int M, int N, int Npad, int K,
                 const float* bias, const float* res, int act,
                 int nSplit = 1) {
    dim3 g(Npad / 128, M / 128, nSplit);
    hgemm_kernel<<<g, 256, kGemmSmem>>>(
        h_ahi + aOff, h_alo + aOff, h_whi + wOff, h_wlo + wOff,
        C, chi, clo, M, N, K, bias, res, act, nSplit);
}
}

extern "C" void kernel_launch(void* const* d_in, const int* in_sizes, int n_in,
                              void* d_out, int out_size) {
    const int*   x           = (const int*)d_in[0];
    // d_in[1] = prefix_mask: all-True and padded True => no-op; unused.
    const float* token_emb   = (const float*)d_in[2];
    const float* pos_emb     = (const float*)d_in[3];
    const float* ca_norm_s   = (const float*)d_in[4];
    const float* ca_norm_b   = (const float*)d_in[5];
    const float* ca_ctx_ns   = (const float*)d_in[6];
    const float* ca_ctx_nb   = (const float*)d_in[7];
    const float* ca_wq       = (const float*)d_in[8];
    const float* ca_wkv      = (const float*)d_in[9];
    const float* ca_wo       = (const float*)d_in[10];
    const float* ca_bo       = (const float*)d_in[11];
    const float* ca_ff_ln_s  = (const float*)d_in[12];
    const float* ca_ff_ln_b  = (const float*)d_in[13];
    const float* ca_ff_w1    = (const float*)d_in[14];
    const float* ca_ff_w2    = (const float*)d_in[15];
    const float* l_norm_s    = (const float*)d_in[16];
    const float* l_norm_b    = (const float*)d_in[17];
    const float* l_wqkv      = (const float*)d_in[18];
    const float* l_wo        = (const float*)d_in[19];
    const float* l_ff_ln_s   = (const float*)d_in[20];
    const float* l_ff_ln_b   = (const float*)d_in[21];
    const float* l_ff_w1     = (const float*)d_in[22];
    const float* l_ff_w2     = (const float*)d_in[23];
    const float* w_logits    = (const float*)d_in[24];
    float* out = (float*)d_out;

    float *prefix, *lat, *pkv, *qkv, *ctab, *stab;
    cudaGetSymbolAddress((void**)&prefix, g_prefix);
    cudaGetSymbolAddress((void**)&lat,    g_lat);
    cudaGetSymbolAddress((void**)&pkv,    g_pkv);
    cudaGetSymbolAddress((void**)&qkv,    g_qkv);
    cudaGetSymbolAddress((void**)&ctab,   g_cos);
    cudaGetSymbolAddress((void**)&stab,   g_sin);
    cudaGetSymbolAddress((void**)&h_whi,  g_whi);
    cudaGetSymbolAddress((void**)&h_wlo,  g_wlo);
    cudaGetSymbolAddress((void**)&h_ahi,  g_ahi);
    cudaGetSymbolAddress((void**)&h_alo,  g_alo);
    cudaGetSymbolAddress((void**)&h_qhi,  g_qhi);
    cudaGetSymbolAddress((void**)&h_qlo,  g_qlo);
    cudaGetSymbolAddress((void**)&h_khi,  g_khi);
    cudaGetSymbolAddress((void**)&h_klo,  g_klo);
    cudaGetSymbolAddress((void**)&h_vph,  g_vph);
    cudaGetSymbolAddress((void**)&h_vpl,  g_vpl);
    cudaGetSymbolAddress((void**)&h_part, g_part);

    cudaFuncSetAttribute(hgemm_kernel,
                         cudaFuncAttributeMaxDynamicSharedMemorySize, kGemmSmem);
    cudaFuncSetAttribute(attn_kernel,
                         cudaFuncAttributeMaxDynamicSharedMemorySize, kAttnSmem);

    auto cw = [&](const float* W, size_t off, int K, int N, int Npad,
                  int layers, size_t srcStride, size_t dstStride) {
        dim3 g(K / 64, Npad / 32, layers);
        cvt_wt_kernel<<<g, dim3(32, 8)>>>(W, h_whi + off, h_wlo + off,
                                          K, N, Npad, srcStride, dstStride);
    };

    // weight conversions (batched across layers where possible)
    cw(ca_wq,    OFF_CAWQ,  1024, 1024, 1024, 1, 0, 0);
    cw(ca_wkv,   OFF_CAWKV, 1024, 2048, 2048, 1, 0, 0);
    cw(ca_wo,    OFF_CAWO,  1024, 1024, 1024, 1, 0, 0);
    cw(ca_ff_w1, OFF_CAFF1, 1024, 4096, 4096, 1, 0, 0);
    cw(ca_ff_w2, OFF_CAFF2, 4096, 1024, 1024, 1, 0, 0);
    cw(l_wqkv,   OFF_LQKV,  1024, 3072, 3072, kL, 1024ull * 3072, 3072ull * 1024);
    cw(l_wo,     OFF_LWO,   1024, 1024, 1024, kL, 1024ull * 1024, 1024ull * 1024);
    cw(l_ff_w1,  OFF_LFF1,  1024, 4096, 4096, kL, 1024ull * 4096, 4096ull * 1024);
    cw(l_ff_w2,  OFF_LFF2,  4096, 1024, 1024, kL, 4096ull * 1024, 1024ull * 4096);
    cw(w_logits, OFF_LOGITS, 1024, kV, kVp, 1, 0, 0);

    // embeddings + rope tables
    embed_kernel<<<kB * kS, 256>>>(x, token_emb, pos_emb, prefix, lat);
    rope_table_kernel<<<(kS * 16 + 255) / 256, 256>>>(ctab, stab);

    // 2. cross-attention block
    ln_bf16_kernel<<<kB * kNL, 256>>>(lat,    ca_norm_s, ca_norm_b,
                                      h_ahi + A0,  h_alo + A0);
    ln_bf16_kernel<<<kB * kP,  256>>>(prefix, ca_ctx_ns, ca_ctx_nb,
                                      h_ahi + ACN, h_alo + ACN);
    // combined [q|k|v] projection for latents (wq/wkv rows are adjacent)
    gemm(A0, OFF_CAWQ, qkv, nullptr, nullptr,
         kB * kNL, 3 * kID, 3 * kID, kD, nullptr, nullptr, 0);
    // prefix [k|v] projection, both batches in one launch (cn contiguous)
    gemm(ACN, OFF_CAWKV, pkv, nullptr, nullptr,
         kB * kP, 2 * kID, 2 * kID, kD, nullptr, nullptr, 0);

    {
        // latent q + latent kv -> tokens [kP, kS)
        int warps = kB * kNL * kH;
        qkvprep_kernel<<<(warps + 7) / 8, 256>>>(
            qkv, kB * kNL, 3 * kID, kNL, kP,
            qkv + kID, qkv + 2 * kID, kB * kNL, 3 * kID, kNL, kP, kS, kP,
            ctab, stab, h_qhi, h_qlo, h_khi, h_klo, h_vph, h_vpl);
        // prefix kv -> tokens [0, kP)
        warps = kB * kP * kH;
        qkvprep_kernel<<<(warps + 7) / 8, 256>>>(
            nullptr, 0, 0, 1, 0,
            pkv, pkv + kID, kB * kP, 2 * kID, kP, 0, kS, 0,
            ctab, stab, h_qhi, h_qlo, h_khi, h_klo, h_vph, h_vpl);
    }
    attn_kernel<<<dim3(kNL / 64, kH, kB), 256, kAttnSmem>>>(
        h_qhi, h_qlo, h_khi, h_klo, h_vph, h_vpl,
        h_ahi + A0, h_alo + A0, kNL, kS, kP);

    gemm(A0, OFF_CAWO, h_part, nullptr, nullptr,
         kB * kNL, kD, kD, kID, nullptr, nullptr, 0, 3);
    reduce3_kernel<<<kFF2N / 1024, 256>>>(h_part, ca_bo, lat, lat, kFF2N, kD);

    ln_bf16_kernel<<<kB * kNL, 256>>>(lat, ca_ff_ln_s, ca_ff_ln_b,
                                      h_ahi + A0, h_alo + A0);
    gemm(A0, OFF_CAFF1, nullptr, h_ahi + AFF, h_alo + AFF,
         kB * kNL, kFF, kFF, kD, nullptr, nullptr, 1);
    gemm(AFF, OFF_CAFF2, h_part, nullptr, nullptr,
         kB * kNL, kD, kD, kFF, nullptr, nullptr, 0, 3);
    reduce3_kernel<<<kFF2N / 1024, 256>>>(h_part, nullptr, lat, lat, kFF2N, kD);

    // 3. latent self-attention layers
    for (int li = 0; li < kL; li++) {
        ln_bf16_kernel<<<kB * kNL, 256>>>(lat, l_norm_s + li * kD,
                                          l_norm_b + li * kD,
                                          h_ahi + A0, h_alo + A0);
        gemm(A0, OFF_LQKV + (size_t)li * 3072 * 1024, qkv, nullptr, nullptr,
             kB * kNL, 3 * kID, 3 * kID, kD, nullptr, nullptr, 0);

        int warps = kB * kNL * kH;
        qkvprep_kernel<<<(warps + 7) / 8, 256>>>(
            qkv, kB * kNL, 3 * kID, kNL, kP,
            qkv + kID, qkv + 2 * kID, kB * kNL, 3 * kID, kNL, kP, kNL, 0,
            ctab, stab, h_qhi, h_qlo, h_khi, h_klo, h_vph, h_vpl);
        attn_kernel<<<dim3(kNL / 64, kH, kB), 256, kAttnSmem>>>(
            h_qhi, h_qlo, h_khi, h_klo, h_vph, h_vpl,
            h_ahi + A0, h_alo + A0, kNL, kNL, 0);

        gemm(A0, OFF_LWO + (size_t)li * 1024 * 1024, h_part, nullptr, nullptr,
             kB * kNL, kD, kD, kID, nullptr, nullptr, 0, 3);
        reduce3_kernel<<<kFF2N / 1024, 256>>>(h_part, nullptr, lat, lat,
                                              kFF2N, kD);

        ln_bf16_kernel<<<kB * kNL, 256>>>(lat, l_ff_ln_s + li * kD,
                                          l_ff_ln_b + li * kD,
                                          h_ahi + A0, h_alo + A0);
        gemm(A0, OFF_LFF1 + (size_t)li * 4096 * 1024, nullptr,
             h_ahi + AFF, h_alo + AFF,
             kB * kNL, kFF, kFF, kD, nullptr, nullptr, 1);
        gemm(AFF, OFF_LFF2 + (size_t)li * 1024 * 4096, h_part, nullptr, nullptr,
             kB * kNL, kD, kD, kFF, nullptr, nullptr, 0, 3);
        reduce3_kernel<<<kFF2N / 1024, 256>>>(h_part, nullptr, lat, lat,
                                              kFF2N, kD);
    }

    // 4. logits head
    {
        size_t n = (size_t)kB * kNL * kD;
        cvt_act_kernel<<<(int)((n / 2 + 255) / 256), 256>>>(
            lat, h_ahi + A0, h_alo + A0, (int)n);
    }
    gemm(A0, OFF_LOGITS, out, nullptr, nullptr,
         kB * kNL, kV, kVp, kD, nullptr, nullptr, 0);
}

// round 14
// speedup vs baseline: 3.4239x; 1.0138x over previous
#include <cuda_runtime.h>
#include <cuda_bf16.h>
#include <math.h>
#include <stdint.h>

// ---------------- problem constants ----------------
namespace {
constexpr int kB  = 2;
constexpr int kS  = 2048;
constexpr int kP  = 512;
constexpr int kNL = 1536;   // latent tokens = S - P
constexpr int kD  = 1024;
constexpr int kH  = 16;
constexpr int kDH = 64;
constexpr int kID = 1024;   // H * DH
constexpr int kV  = 20000;
constexpr int kVp = 20096;  // padded to 128
constexpr int kL  = 4;
constexpr int kFF = 4096;
constexpr float kScale = 0.125f;   // DH^-0.5
constexpr float kEps   = 1e-5f;

// weight arena offsets (transposed [N][K] layout, elements)
// CAWQ rows [0,1024) and CAWKV rows [1024,3072) are adjacent -> one [q|k|v].
constexpr size_t OFF_CAWQ   = 0;                                  // 1024x1024
constexpr size_t OFF_CAWKV  = OFF_CAWQ  + 1024ull * 1024;         // 2048x1024
constexpr size_t OFF_CAWO   = OFF_CAWKV + 2048ull * 1024;         // 1024x1024
constexpr size_t OFF_CAFF1  = OFF_CAWO  + 1024ull * 1024;         // 4096x1024
constexpr size_t OFF_CAFF2  = OFF_CAFF1 + 4096ull * 1024;         // 1024x4096
constexpr size_t OFF_LQKV   = OFF_CAFF2 + 1024ull * 4096;         // 4 x 3072x1024
constexpr size_t OFF_LWO    = OFF_LQKV  + 4ull * 3072 * 1024;     // 4 x 1024x1024
constexpr size_t OFF_LFF1   = OFF_LWO   + 4ull * 1024 * 1024;     // 4 x 4096x1024
constexpr size_t OFF_LFF2   = OFF_LFF1  + 4ull * 4096 * 1024;     // 4 x 1024x4096
constexpr size_t OFF_LOGITS = OFF_LFF2  + 4ull * 1024 * 4096;     // 20096x1024
constexpr size_t W_TOTAL    = OFF_LOGITS + (size_t)kVp * 1024;

// activation arena regions (elements)
constexpr size_t A0   = 0;                                // xn/tmp/att/lat-cvt
constexpr size_t AFF  = (size_t)kB * kNL * kD;            // GELU(ff1) output
constexpr size_t ACN  = AFF + (size_t)kB * kNL * kFF;     // cn (prefix LN)
constexpr size_t A_TOTAL = ACN + (size_t)kB * kP * kD;

// hgemm smem: 2 stages x 4 arrays x 128 rows x 24 uint32 words
constexpr int kRowWords   = 24;
constexpr int kArrWords   = 128 * kRowWords;         // 3072
constexpr int kStageWords = 4 * kArrWords;           // 12288
constexpr int kGemmSmem   = 2 * kStageWords * 4;     // 98304 bytes

// attention smem layout (uint32 word offsets)
constexpr int AQH = 0;
constexpr int AQL = AQH + 64 * 36;
constexpr int AKH = AQL + 64 * 36;
constexpr int AKL = AKH + 64 * 36;
constexpr int AVH = AKL + 64 * 36;
constexpr int AVL = AVH + 32 * 72;
constexpr int APH = AVL + 32 * 72;
constexpr int APL = APH + 64 * 36;
constexpr int AMR = APL + 64 * 36;
constexpr int ALR = AMR + 64;
constexpr int AMX = ALR + 64;
constexpr int ASM = AMX + 128;
constexpr int kAttnWords = ASM + 128;
constexpr int kAttnSmem  = kAttnWords * 4;  // 75264 bytes

constexpr int kFF2N = 3072 * 1024;    // split-K output elements (rows*kD)
}

// ---------------- scratch (module-load allocated, legal) ----------------
__device__ float g_prefix[kB * kP * kD];
__device__ float g_lat   [kB * kNL * kD];
__device__ float g_pkv   [kB * kP * 2 * kID];
__device__ float g_qkv   [kB * kNL * 3 * kID];
__device__ float g_cos   [kS * 16];
__device__ float g_sin   [kS * 16];
__device__ float g_part  [3ull * kFF2N];
__device__ __nv_bfloat16 g_whi[W_TOTAL];
__device__ __nv_bfloat16 g_wlo[W_TOTAL];
__device__ __nv_bfloat16 g_ahi[A_TOTAL];
__device__ __nv_bfloat16 g_alo[A_TOTAL];
__device__ __nv_bfloat16 g_qhi[kB * kNL * kID];
__device__ __nv_bfloat16 g_qlo[kB * kNL * kID];
__device__ __nv_bfloat16 g_khi[kB * kS * kID];
__device__ __nv_bfloat16 g_klo[kB * kS * kID];
__device__ uint32_t g_vph[(size_t)kB * kH * (kS / 2) * 64];
__device__ uint32_t g_vpl[(size_t)kB * kH * (kS / 2) * 64];

// ---------------- low-level helpers ----------------
__device__ __forceinline__ float warpSum(float v) {
#pragma unroll
    for (int o = 16; o; o >>= 1) v += __shfl_xor_sync(0xffffffffu, v, o);
    return v;
}

__device__ __forceinline__ int permWord(int w) {
    int w8 = w & 7;
    return (w & ~7) + ((w8 & 3) << 1) + (w8 >> 2);
}

__device__ __forceinline__ void split2(float a, float b,
                                       __nv_bfloat162& h, __nv_bfloat162& l) {
    __nv_bfloat16 h0 = __float2bfloat16(a);
    __nv_bfloat16 h1 = __float2bfloat16(b);
    h.x = h0; h.y = h1;
    l.x = __float2bfloat16(a - __bfloat162float(h0));
    l.y = __float2bfloat16(b - __bfloat162float(h1));
}

__device__ __forceinline__ void pack2(float a, float b,
                                      uint32_t& hw, uint32_t& lw) {
    __nv_bfloat162 h, l;
    split2(a, b, h, l);
    hw = *reinterpret_cast<uint32_t*>(&h);
    lw = *reinterpret_cast<uint32_t*>(&l);
}

#define MMA_BF16(c, a, b)                                                   \
    asm volatile(                                                           \
        "mma.sync.aligned.m16n8k16.row.col.f32.bf16.bf16.f32 "              \
        "{%0,%1,%2,%3}, {%4,%5,%6,%7}, {%8,%9}, {%0,%1,%2,%3};"             \
        : "+f"((c)[0]), "+f"((c)[1]), "+f"((c)[2]), "+f"((c)[3])            \
        : "r"((a)[0]), "r"((a)[1]), "r"((a)[2]), "r"((a)[3]),               \
          "r"((b)[0]), "r"((b)[1]))

#define CP_ASYNC16(dst, src)                                                \
    asm volatile("cp.async.cg.shared.global [%0], [%1], 16;"                \
                 :: "r"(dst), "l"(src))
#define CP_COMMIT() asm volatile("cp.async.commit_group;")
#define CP_WAIT0()  asm volatile("cp.async.wait_group 0;")

// ---------------- embedding ----------------
__global__ void embed_kernel(const int* __restrict__ x,
                             const float* __restrict__ te,
                             const float* __restrict__ pe,
                             float* __restrict__ prefix,
                             float* __restrict__ lat) {
    int row = blockIdx.x;
    int b = row / kS, s = row % kS;
    int tok = x[row];
    const float* tr = te + (size_t)tok * kD;
    const float* pr = pe + (size_t)s * kD;
    float* dst = (s < kP) ? (prefix + ((size_t)b * kP + s) * kD)
                          : (lat    + ((size_t)b * kNL + (s - kP)) * kD);
    for (int i = threadIdx.x; i < kD; i += blockDim.x) dst[i] = tr[i] + pr[i];
}

// ---------------- LN core: given per-thread v[4], produce outputs ---------
__device__ __forceinline__ void lnTail(float v[4], int tid, int r,
                                       const float* __restrict__ gamma,
                                       const float* __restrict__ beta,
                                       __nv_bfloat16* __restrict__ hi,
                                       __nv_bfloat16* __restrict__ lo) {
    __shared__ float red[8];
    __shared__ float meanS, rstdS;
    float s = v[0] + v[1] + v[2] + v[3];
    s = warpSum(s);
    if ((tid & 31) == 0) red[tid >> 5] = s;
    __syncthreads();
    if (tid < 32) {
        float t = (tid < 8) ? red[tid] : 0.f;
        t = warpSum(t);
        if (tid == 0) meanS = t * (1.f / kD);
    }
    __syncthreads();
    float mean = meanS;
    float s2 = 0.f;
#pragma unroll
    for (int i = 0; i < 4; i++) { float d = v[i] - mean; s2 += d * d; }
    s2 = warpSum(s2);
    __syncthreads();
    if ((tid & 31) == 0) red[tid >> 5] = s2;
    __syncthreads();
    if (tid < 32) {
        float t = (tid < 8) ? red[tid] : 0.f;
        t = warpSum(t);
        if (tid == 0) rstdS = rsqrtf(t * (1.f / kD) + kEps);
    }
    __syncthreads();
    float rs = rstdS;
    float4 g4 = *(const float4*)(gamma + 4 * tid);
    float4 b4 = *(const float4*)(beta + 4 * tid);
    float y0 = (v[0] - mean) * rs * g4.x + b4.x;
    float y1 = (v[1] - mean) * rs * g4.y + b4.y;
    float y2 = (v[2] - mean) * rs * g4.z + b4.z;
    float y3 = (v[3] - mean) * rs * g4.w + b4.w;
    __nv_bfloat162 h0, l0, h1, l1;
    split2(y0, y1, h0, l0);
    split2(y2, y3, h1, l1);
    size_t rowW = (size_t)r * (kD / 2);
    int w0 = 2 * tid;
    ((__nv_bfloat162*)hi)[rowW + permWord(w0)]     = h0;
    ((__nv_bfloat162*)hi)[rowW + permWord(w0 + 1)] = h1;
    ((__nv_bfloat162*)lo)[rowW + permWord(w0)]     = l0;
    ((__nv_bfloat162*)lo)[rowW + permWord(w0 + 1)] = l1;
}

// ---------------- LayerNorm -> split bf16 (standalone) ----------------
__global__ __launch_bounds__(256) void ln_bf16_kernel(
    const float* __restrict__ in, const float* __restrict__ gamma,
    const float* __restrict__ beta,
    __nv_bfloat16* __restrict__ hi, __nv_bfloat16* __restrict__ lo) {
    int r = blockIdx.x;
    int tid = threadIdx.x;
    float4 v4 = *(const float4*)(in + (size_t)r * kD + 4 * tid);
    float v[4] = {v4.x, v4.y, v4.z, v4.w};
    lnTail(v, tid, r, gamma, beta, hi, lo);
}

// ---------------- fused split-K reduce + residual + LN -> split bf16 ------
// v = p0+p1+p2 [+bias] + res; writes latOut (new residual) AND LN outputs.
__global__ __launch_bounds__(256) void lnred_bf16_kernel(
    const float* __restrict__ p, const float* __restrict__ bias,
    const float* __restrict__ res,
    const float* __restrict__ gamma, const float* __restrict__ beta,
    float* __restrict__ latOut,
    __nv_bfloat16* __restrict__ hi, __nv_bfloat16* __restrict__ lo) {
    int r = blockIdx.x;
    int tid = threadIdx.x;
    size_t off = (size_t)r * kD + 4 * tid;
    float4 a = *(const float4*)(p + off);
    float4 b = *(const float4*)(p + kFF2N + off);
    float4 c = *(const float4*)(p + 2 * (size_t)kFF2N + off);
    float4 rr = *(const float4*)(res + off);
    float v[4] = {a.x + b.x + c.x + rr.x, a.y + b.y + c.y + rr.y,
                  a.z + b.z + c.z + rr.z, a.w + b.w + c.w + rr.w};
    if (bias) {
        float4 bv = *(const float4*)(bias + 4 * tid);
        v[0] += bv.x; v[1] += bv.y; v[2] += bv.z; v[3] += bv.w;
    }
    *(float4*)(latOut + off) = make_float4(v[0], v[1], v[2], v[3]);
    lnTail(v, tid, r, gamma, beta, hi, lo);
}

// ---------------- fused split-K reduce + residual -> split bf16 -----------
// (last FF2: feeds logits GEMM only; no fp32 lat write needed)
__global__ void redcvt_kernel(const float* __restrict__ p,
                              const float* __restrict__ res,
                              __nv_bfloat16* __restrict__ hi,
                              __nv_bfloat16* __restrict__ lo) {
    int w = blockIdx.x * blockDim.x + threadIdx.x;   // word index
    size_t i = (size_t)w * 2;
    if (i >= kFF2N) return;
    float2 a = *(const float2*)(p + i);
    float2 b = *(const float2*)(p + kFF2N + i);
    float2 c = *(const float2*)(p + 2 * (size_t)kFF2N + i);
    float2 r = *(const float2*)(res + i);
    float x = a.x + b.x + c.x + r.x;
    float y = a.y + b.y + c.y + r.y;
    uint32_t hw, lw;
    pack2(x, y, hw, lw);
    int pw = permWord(w);
    ((uint32_t*)hi)[pw] = hw;
    ((uint32_t*)lo)[pw] = lw;
}

// ---------------- RoPE table ----------------
__global__ void rope_table_kernel(float* __restrict__ ct, float* __restrict__ st) {
    int idx = blockIdx.x * blockDim.x + threadIdx.x;
    if (idx >= kS * 16) return;
    int s = idx >> 4, i = idx & 15;
    float inv = (float)(1.0 / pow(10000.0, (double)i / 16.0));
    float f = (float)s * inv;
    ct[idx] = (float)cos((double)f);
    st[idx] = (float)sin((double)f);
}

// ---------------- warp rope helper ----------------
__device__ __forceinline__ void ropeWord(const float* __restrict__ p, int pos,
                                         float scaleAll, int lane,
                                         const float* __restrict__ ct,
                                         const float* __restrict__ st,
                                         uint32_t& hw, uint32_t& lw) {
    float2 v = *(const float2*)(p + 2 * lane);
    float ox = __shfl_xor_sync(0xffffffffu, v.x, 8);
    float oy = __shfl_xor_sync(0xffffffffu, v.y, 8);
    float y0, y1;
    if (lane < 8) {
        float c0 = ct[pos * 16 + 2 * lane],     s0 = st[pos * 16 + 2 * lane];
        float c1 = ct[pos * 16 + 2 * lane + 1], s1 = st[pos * 16 + 2 * lane + 1];
        y0 = v.x * c0 - ox * s0;
        y1 = v.y * c1 - oy * s1;
    } else if (lane < 16) {
        int i = 2 * lane - 16;
        float c0 = ct[pos * 16 + i],     s0 = st[pos * 16 + i];
        float c1 = ct[pos * 16 + i + 1], s1 = st[pos * 16 + i + 1];
        y0 = v.x * c0 + ox * s0;
        y1 = v.y * c1 + oy * s1;
    } else {
        y0 = v.x; y1 = v.y;
    }
    pack2(y0 * scaleAll, y1 * scaleAll, hw, lw);
}

// ---------------- fused Q-rope + K-rope + V-pack ----------------
__global__ __launch_bounds__(256) void qkvprep_kernel(
    const float* __restrict__ qsrc, int qRows, int qStride, int qT, int qPos,
    const float* __restrict__ ksrc, const float* __restrict__ vsrc,
    int kvRows, int kvStride, int kT, int kPos, int kSeqOut, int kOutOff,
    const float* __restrict__ ct, const float* __restrict__ st,
    __nv_bfloat16* __restrict__ qhi, __nv_bfloat16* __restrict__ qlo,
    __nv_bfloat16* __restrict__ khi, __nv_bfloat16* __restrict__ klo,
    uint32_t* __restrict__ vph, uint32_t* __restrict__ vpl) {
    int warp = threadIdx.x >> 5, lane = threadIdx.x & 31;
    int idx = blockIdx.x * 8 + warp;
    if (idx >= kvRows * kH) return;
    int row = idx / kH, h = idx % kH;
    int b = row / kT, tloc = row % kT;
    int token = kOutOff + tloc;
    uint32_t hw, lw;
    {
        const float* p = ksrc + (size_t)row * kvStride + h * kDH;
        ropeWord(p, kPos + tloc, 1.f, lane, ct, st, hw, lw);
        size_t w = ((size_t)b * kSeqOut + token) * (kID / 2) + h * 32 + lane;
        ((uint32_t*)khi)[w] = hw;
        ((uint32_t*)klo)[w] = lw;
    }
    if (!(tloc & 1)) {
        const float* p0 = vsrc + (size_t)row * kvStride + h * kDH;
        const float* p1 = p0 + kvStride;
        int k2 = token >> 1;
        size_t base = (((size_t)b * kH + h) * (kSeqOut >> 1) + k2) * 64;
        pack2(p0[lane], p1[lane], hw, lw);
        vph[base + lane] = hw;
        vpl[base + lane] = lw;
        pack2(p0[lane + 32], p1[lane + 32], hw, lw);
        vph[base + lane + 32] = hw;
        vpl[base + lane + 32] = lw;
    }
    if (row < qRows) {
        const float* p = qsrc + (size_t)row * qStride + h * kDH;
        ropeWord(p, qPos + (row % qT), kScale, lane, ct, st, hw, lw);
        size_t w = (size_t)row * (kID / 2) + h * 32 + lane;
        ((uint32_t*)qhi)[w] = hw;
        ((uint32_t*)qlo)[w] = lw;
    }
}

// transpose + convert weights, 64(k) x 64(n) tiles, word-granular writes.
__global__ void cvt_wt_kernel(const float* __restrict__ W,
                              __nv_bfloat16* __restrict__ whi,
                              __nv_bfloat16* __restrict__ wlo,
                              int K, int N, int Npad,
                              size_t srcStride, size_t dstStride) {
    __shared__ float t[64][65];
    const float* Wz = W + (size_t)blockIdx.z * srcStride;
    int k0 = blockIdx.x * 64, n0 = blockIdx.y * 64;
    int tx = threadIdx.x, ty = threadIdx.y;   // 32 x 8
    bool n0OK = (n0 + tx) < N;
    bool n1OK = (n0 + tx + 32) < N;
#pragma unroll
    for (int j = 0; j < 8; j++) {
        int k = k0 + ty + 8 * j;
        t[ty + 8 * j][tx]      = n0OK ? Wz[(size_t)k * N + n0 + tx] : 0.f;
        t[ty + 8 * j][tx + 32] = n1OK ? Wz[(size_t)k * N + n0 + tx + 32] : 0.f;
    }
    __syncthreads();
    uint32_t* wh = (uint32_t*)(whi + (size_t)blockIdx.z * dstStride);
    uint32_t* wl = (uint32_t*)(wlo + (size_t)blockIdx.z * dstStride);
    int pw = permWord((k0 >> 1) + tx);
#pragma unroll
    for (int j = 0; j < 8; j++) {
        int nl = ty + 8 * j;                 // 0..63 (tile-local n)
        int n = n0 + nl;
        float a = t[2 * tx][nl];
        float b = t[2 * tx + 1][nl];
        uint32_t hw, lw;
        pack2(a, b, hw, lw);
        size_t rowW = (size_t)n * (K >> 1);
        wh[rowW + pw] = hw;
        wl[rowW + pw] = lw;
    }
}

// ---------------- fp32 -> bf16 hi/lo converter (k-pair permuted) ----------
__global__ void cvt_act_kernel(const float* __restrict__ in,
                               __nv_bfloat16* __restrict__ hi,
                               __nv_bfloat16* __restrict__ lo, int n) {
    int w = blockIdx.x * blockDim.x + threadIdx.x;
    if (w * 2 >= n) return;
    float2 v = *(const float2*)(in + (size_t)w * 2);
    __nv_bfloat162 h, l;
    split2(v.x, v.y, h, l);
    int pw = permWord(w);
    ((__nv_bfloat162*)hi)[pw] = h;
    ((__nv_bfloat162*)lo)[pw] = l;
}

// ---------------- bf16 tensor-core GEMM (3-term split) --------------------
__global__ __launch_bounds__(256, 2) void hgemm_kernel(
    const __nv_bfloat16* __restrict__ Ahi, const __nv_bfloat16* __restrict__ Alo,
    const __nv_bfloat16* __restrict__ Bhi, const __nv_bfloat16* __restrict__ Blo,
    float* __restrict__ C,
    __nv_bfloat16* __restrict__ Chi, __nv_bfloat16* __restrict__ Clo,
    int M, int N, int K,
    const float* __restrict__ bias, const float* __restrict__ res, int act,
    int nSplit) {
    extern __shared__ uint32_t sm[];
    const int tid  = threadIdx.x;
    const int lane = tid & 31;
    const int warp = tid >> 5;
    const int warpM = warp >> 2;
    const int warpN = warp & 3;
    const int gid = lane >> 2;
    const int tig = lane & 3;
    const int m0 = blockIdx.y * 128, n0 = blockIdx.x * 128;

    float acc[4][4][4] = {};

    auto issue = [&](int stage, int kt) {
        const uint32_t base = stage * kStageWords;
#pragma unroll
        for (int i = 0; i < 8; i++) {
            int c = tid + i * 256;
            int t = c >> 9, w = c & 511;
            int row = w >> 2, ck = w & 3;
            const __nv_bfloat16* src;
            if (t == 0)      src = Ahi + (size_t)(m0 + row) * K + kt + ck * 8;
            else if (t == 1) src = Alo + (size_t)(m0 + row) * K + kt + ck * 8;
            else if (t == 2) src = Bhi + (size_t)(n0 + row) * K + kt + ck * 8;
            else             src = Blo + (size_t)(n0 + row) * K + kt + ck * 8;
            uint32_t dst = (uint32_t)__cvta_generic_to_shared(
                &sm[base + t * kArrWords + row * kRowWords + ck * 4]);
            CP_ASYNC16(dst, src);
        }
    };

    auto compute = [&](int buf) {
        const uint32_t* SAh = sm + buf * kStageWords;
        const uint32_t* SAl = SAh + kArrWords;
        const uint32_t* SBh = SAl + kArrWords;
        const uint32_t* SBl = SBh + kArrWords;
#pragma unroll
        for (int ks = 0; ks < 2; ks++) {
            const int kwb = ks * 8 + 2 * tig;
            uint2 bh[4], bl[4];
#pragma unroll
            for (int in = 0; in < 4; in++) {
                const int n = warpN * 32 + in * 8 + gid;
                bh[in] = *(const uint2*)&SBh[n * kRowWords + kwb];
                bl[in] = *(const uint2*)&SBl[n * kRowWords + kwb];
            }
#pragma unroll
            for (int im = 0; im < 4; im++) {
                const int r = warpM * 64 + im * 16 + gid;
                uint2 uh = *(const uint2*)&SAh[r * kRowWords + kwb];
                uint2 vh = *(const uint2*)&SAh[(r + 8) * kRowWords + kwb];
                uint2 ul = *(const uint2*)&SAl[r * kRowWords + kwb];
                uint2 vl = *(const uint2*)&SAl[(r + 8) * kRowWords + kwb];
                uint32_t ahi[4] = {uh.x, vh.x, uh.y, vh.y};
                uint32_t alo[4] = {ul.x, vl.x, ul.y, vl.y};
#pragma unroll
                for (int in = 0; in < 4; in++) {
                    uint32_t bhw[2] = {bh[in].x, bh[in].y};
                    uint32_t blw[2] = {bl[in].x, bl[in].y};
                    MMA_BF16(acc[im][in], ahi, bhw);
                    MMA_BF16(acc[im][in], ahi, blw);
                    MMA_BF16(acc[im][in], alo, bhw);
                }
            }
        }
    };

    const int totalStages = K >> 5;
    const int per = (totalStages + nSplit - 1) / nSplit;
    const int s0 = blockIdx.z * per;
    int s1 = s0 + per;
    if (s1 > totalStages) s1 = totalStages;

    issue(0, s0 * 32);
    CP_COMMIT();
    for (int s = s0; s < s1; s++) {
        CP_WAIT0();
        __syncthreads();
        if (s + 1 < s1) { issue((s + 1 - s0) & 1, (s + 1) * 32); CP_COMMIT(); }
        compute((s - s0) & 1);
    }

    // ---- epilogue ----
    float* Cz = C;
    const bool partial = (nSplit > 1);
    if (partial) Cz = C + (size_t)blockIdx.z * M * N;
#pragma unroll
    for (int im = 0; im < 4; im++) {
        const int row = m0 + warpM * 64 + im * 16 + gid;
#pragma unroll
        for (int in = 0; in < 4; in++) {
            const int col = n0 + warpN * 32 + in * 8 + 2 * tig;
            if (col >= N) continue;
#pragma unroll
            for (int half = 0; half < 2; half++) {
                const int rr = row + half * 8;
                float c0 = acc[im][in][half * 2 + 0];
                float c1 = acc[im][in][half * 2 + 1];
                if (partial) {
                    *(float2*)(Cz + (size_t)rr * N + col) = make_float2(c0, c1);
                    continue;
                }
                if (bias) { c0 += bias[col]; c1 += bias[col + 1]; }
                if (act) {
                    c0 = 0.5f * c0 * (1.f + erff(c0 * 0.70710678118654752f));
                    c1 = 0.5f * c1 * (1.f + erff(c1 * 0.70710678118654752f));
                }
                if (res) {
                    const float2 rv = *(const float2*)(res + (size_t)rr * N + col);
                    c0 += rv.x; c1 += rv.y;
                }
                if (C)
                    *(float2*)(C + (size_t)rr * N + col) = make_float2(c0, c1);
                if (Chi) {
                    __nv_bfloat162 h, l;
                    split2(c0, c1, h, l);
                    size_t rowW = (size_t)rr * (N >> 1);
                    int pw = permWord(col >> 1);
                    ((__nv_bfloat162*)Chi)[rowW + pw] = h;
                    ((__nv_bfloat162*)Clo)[rowW + pw] = l;
                }
            }
        }
    }
}

// ---------------- flash attention on tensor cores (bf16 3-term split) -----
__global__ __launch_bounds__(256, 2) void attn_kernel(
    const __nv_bfloat16* __restrict__ qhi, const __nv_bfloat16* __restrict__ qlo,
    const __nv_bfloat16* __restrict__ khi, const __nv_bfloat16* __restrict__ klo,
    const uint32_t* __restrict__ vph, const uint32_t* __restrict__ vpl,
    __nv_bfloat16* __restrict__ ohi, __nv_bfloat16* __restrict__ olo,
    int Tq, int Tk, int diag) {
    extern __shared__ uint32_t sa[];
    float* sf = (float*)sa;
    const int tid = threadIdx.x;
    const int lane = tid & 31, warp = tid >> 5;
    const int g = lane >> 2, tg = lane & 3;
    const int warpQ = warp >> 1, warpK = warp & 1;
    const int q0 = (gridDim.x - 1 - blockIdx.x) * 64;
    const int h = blockIdx.y, b = blockIdx.z;
    const int q0w = warpQ * 16;

    {
        const __nv_bfloat16* qh = qhi + ((size_t)(b * Tq + q0)) * kID + h * kDH;
        const __nv_bfloat16* ql = qlo + ((size_t)(b * Tq + q0)) * kID + h * kDH;
#pragma unroll
        for (int i = 0; i < 4; i++) {
            int ch = tid + i * 256;
            int arr = ch >> 9, w = ch & 511;
            int row = w >> 3, ck = w & 7;
            const __nv_bfloat16* src = (arr ? ql : qh) + (size_t)row * kID + ck * 8;
            uint32_t dst = (uint32_t)__cvta_generic_to_shared(
                &sa[(arr ? AQL : AQH) + row * 36 + ck * 4]);
            CP_ASYNC16(dst, src);
        }
        CP_COMMIT();
    }
    if (tid < 64) { sf[AMR + tid] = -1e30f; sf[ALR + tid] = 0.f; }

    float O[4][4] = {};
    int jmax = q0 + 63 + diag;
    int nkt = (jmax + 64) >> 6;
    int maxkt = Tk >> 6;
    if (nkt > maxkt) nkt = maxkt;

    const int r0i = q0w + g, r1i = r0i + 8;
    const int tk2 = Tk >> 1;
    const uint32_t* vhB = vph + ((size_t)b * kH + h) * tk2 * 64;
    const uint32_t* vlB = vpl + ((size_t)b * kH + h) * tk2 * 64;

    for (int kt = 0; kt < nkt; kt++) {
        const int k0 = kt * 64;
        {
            const __nv_bfloat16* kh = khi + ((size_t)(b * Tk + k0)) * kID + h * kDH;
            const __nv_bfloat16* kl = klo + ((size_t)(b * Tk + k0)) * kID + h * kDH;
#pragma unroll
            for (int i = 0; i < 4; i++) {
                int ch = tid + i * 256;
                int arr = ch >> 9, w = ch & 511;
                int row = w >> 3, ck = w & 7;
                const __nv_bfloat16* src = (arr ? kl : kh) + (size_t)row * kID + ck * 8;
                uint32_t dst = (uint32_t)__cvta_generic_to_shared(
                    &sa[(arr ? AKL : AKH) + row * 36 + ck * 4]);
                CP_ASYNC16(dst, src);
            }
            const uint32_t* vh = vhB + (size_t)(k0 >> 1) * 64;
            const uint32_t* vl = vlB + (size_t)(k0 >> 1) * 64;
#pragma unroll
            for (int i = 0; i < 4; i++) {
                int ch = tid + i * 256;
                int arr = ch >> 9, w = ch & 511;
                int k2 = w >> 4, ck = w & 15;
                const uint32_t* src = (arr ? vl : vh) + k2 * 64 + ck * 4;
                uint32_t dst = (uint32_t)__cvta_generic_to_shared(
                    &sa[(arr ? AVL : AVH) + k2 * 72 + ck * 4]);
                CP_ASYNC16(dst, src);
            }
            CP_COMMIT();
        }
        CP_WAIT0();
        __syncthreads();

        float s[4][4];
#pragma unroll
        for (int nt = 0; nt < 4; nt++)
#pragma unroll
            for (int j = 0; j < 4; j++) s[nt][j] = 0.f;
#pragma unroll
        for (int ck = 0; ck < 4; ck++) {
            const int ac = ck * 8 + tg;
            uint32_t ahi[4] = {
                sa[AQH + r0i * 36 + ac], sa[AQH + r1i * 36 + ac],
                sa[AQH + r0i * 36 + ac + 4], sa[AQH + r1i * 36 + ac + 4]};
            uint32_t alo[4] = {
                sa[AQL + r0i * 36 + ac], sa[AQL + r1i * 36 + ac],
                sa[AQL + r0i * 36 + ac + 4], sa[AQL + r1i * 36 + ac + 4]};
#pragma unroll
            for (int nt = 0; nt < 4; nt++) {
                const int key = warpK * 32 + nt * 8 + g;
                uint32_t bhi[2] = {sa[AKH + key * 36 + ac],
                                   sa[AKH + key * 36 + ac + 4]};
                uint32_t blo[2] = {sa[AKL + key * 36 + ac],
                                   sa[AKL + key * 36 + ac + 4]};
                MMA_BF16(s[nt], ahi, bhi);
                MMA_BF16(s[nt], ahi, blo);
                MMA_BF16(s[nt], alo, bhi);
            }
        }
        if (k0 + 63 > q0 + diag) {
            int qr0 = q0 + r0i + diag;
            int qr1 = qr0 + 8;
#pragma unroll
            for (int nt = 0; nt < 4; nt++) {
                int cb = k0 + warpK * 32 + nt * 8 + 2 * tg;
                if (cb > qr0)     s[nt][0] = -1e30f;
                if (cb + 1 > qr0) s[nt][1] = -1e30f;
                if (cb > qr1)     s[nt][2] = -1e30f;
                if (cb + 1 > qr1) s[nt][3] = -1e30f;
            }
        }
        float mx0 = -1e30f, mx1 = -1e30f;
#pragma unroll
        for (int nt = 0; nt < 4; nt++) {
            mx0 = fmaxf(mx0, fmaxf(s[nt][0], s[nt][1]));
            mx1 = fmaxf(mx1, fmaxf(s[nt][2], s[nt][3]));
        }
        mx0 = fmaxf(mx0, __shfl_xor_sync(0xffffffffu, mx0, 1));
        mx0 = fmaxf(mx0, __shfl_xor_sync(0xffffffffu, mx0, 2));
        mx1 = fmaxf(mx1, __shfl_xor_sync(0xffffffffu, mx1, 1));
        mx1 = fmaxf(mx1, __shfl_xor_sync(0xffffffffu, mx1, 2));
        if (tg == 0) {
            sf[AMX + r0i * 2 + warpK] = mx0;
            sf[AMX + r1i * 2 + warpK] = mx1;
        }
        __syncthreads();

        float mold0 = sf[AMR + r0i], mold1 = sf[AMR + r1i];
        float lold0 = sf[ALR + r0i], lold1 = sf[ALR + r1i];
        float mnew0 = fmaxf(mold0, fmaxf(sf[AMX + r0i * 2], sf[AMX + r0i * 2 + 1]));
        float mnew1 = fmaxf(mold1, fmaxf(sf[AMX + r1i * 2], sf[AMX + r1i * 2 + 1]));
        float f0 = __expf(mold0 - mnew0);
        float f1 = __expf(mold1 - mnew1);
        float sum0 = 0.f, sum1 = 0.f;
#pragma unroll
        for (int nt = 0; nt < 4; nt++) {
            float p00 = __expf(s[nt][0] - mnew0);
            float p01 = __expf(s[nt][1] - mnew0);
            float p10 = __expf(s[nt][2] - mnew1);
            float p11 = __expf(s[nt][3] - mnew1);
            sum0 += p00 + p01; sum1 += p10 + p11;
            uint32_t hw, lw;
            const int pc = warpK * 16 + nt * 4 + tg;
            pack2(p00, p01, hw, lw);
            sa[APH + r0i * 36 + pc] = hw; sa[APL + r0i * 36 + pc] = lw;
            pack2(p10, p11, hw, lw);
            sa[APH + r1i * 36 + pc] = hw; sa[APL + r1i * 36 + pc] = lw;
        }
        sum0 += __shfl_xor_sync(0xffffffffu, sum0, 1);
        sum0 += __shfl_xor_sync(0xffffffffu, sum0, 2);
        sum1 += __shfl_xor_sync(0xffffffffu, sum1, 1);
        sum1 += __shfl_xor_sync(0xffffffffu, sum1, 2);
        if (tg == 0) {
            sf[ASM + r0i * 2 + warpK] = sum0;
            sf[ASM + r1i * 2 + warpK] = sum1;
        }
        __syncthreads();

#pragma unroll
        for (int nt = 0; nt < 4; nt++) {
            O[nt][0] *= f0; O[nt][1] *= f0;
            O[nt][2] *= f1; O[nt][3] *= f1;
        }
#pragma unroll
        for (int kk = 0; kk < 4; kk++) {
            const int pc = kk * 8 + tg;
            uint32_t ahi[4] = {
                sa[APH + r0i * 36 + pc], sa[APH + r1i * 36 + pc],
                sa[APH + r0i * 36 + pc + 4], sa[APH + r1i * 36 + pc + 4]};
            uint32_t alo[4] = {
                sa[APL + r0i * 36 + pc], sa[APL + r1i * 36 + pc],
                sa[APL + r0i * 36 + pc + 4], sa[APL + r1i * 36 + pc + 4]};
#pragma unroll
            for (int nt = 0; nt < 4; nt++) {
                const int d0 = warpK * 32 + nt * 8 + g;
                uint32_t bhi[2] = {sa[AVH + (kk * 8 + tg) * 72 + d0],
                                   sa[AVH + (kk * 8 + 4 + tg) * 72 + d0]};
                uint32_t blo[2] = {sa[AVL + (kk * 8 + tg) * 72 + d0],
                                   sa[AVL + (kk * 8 + 4 + tg) * 72 + d0]};
                MMA_BF16(O[nt], ahi, bhi);
                MMA_BF16(O[nt], ahi, blo);
                MMA_BF16(O[nt], alo, bhi);
            }
        }
        if (warpK == 0 && tg == 0) {
            sf[AMR + r0i] = mnew0;
            sf[AMR + r1i] = mnew1;
            sf[ALR + r0i] = lold0 * f0 + sf[ASM + r0i * 2] + sf[ASM + r0i * 2 + 1];
            sf[ALR + r1i] = lold1 * f1 + sf[ASM + r1i * 2] + sf[ASM + r1i * 2 + 1];
        }
        __syncthreads();
    }

    float inv0 = 1.f / sf[ALR + r0i];
    float inv1 = 1.f / sf[ALR + r1i];
    size_t rowW0 = ((size_t)b * Tq + q0 + r0i) * (kID / 2);
    size_t rowW1 = ((size_t)b * Tq + q0 + r1i) * (kID / 2);
#pragma unroll
    for (int nt = 0; nt < 4; nt++) {
        int col = h * kDH + warpK * 32 + nt * 8 + 2 * tg;
        int w0 = col >> 1;
        uint32_t hw, lw;
        pack2(O[nt][0] * inv0, O[nt][1] * inv0, hw, lw);
        ((uint32_t*)ohi)[rowW0 + permWord(w0)] = hw;
        ((uint32_t*)olo)[rowW0 + permWord(w0)] = lw;
        pack2(O[nt][2] * inv1, O[nt][3] * inv1, hw, lw);
        ((uint32_t*)ohi)[rowW1 + permWord(w0)] = hw;
        ((uint32_t*)olo)[rowW1 + permWord(w0)] = lw;
    }
}

// ---------------- host orchestration ----------------
namespace {
__nv_bfloat16 *h_whi, *h_wlo, *h_ahi, *h_alo;
__nv_bfloat16 *h_qhi, *h_qlo, *h_khi, *h_klo;
uint32_t *h_vph, *h_vpl;
float *h_part;

inline void gemm(size_t aOff, size_t wOff, float* C,
                 __nv_bfloat16* chi, __nv_bfloat16* clo,
                 int M, int N, int Npad, int K,
                 const float* bias, const float* res, int act,
                 int nSplit = 1) {
    dim3 g(Npad / 128, M / 128, nSplit);
    hgemm_kernel<<<g, 256, kGemmSmem>>>(
        h_ahi + aOff, h_alo + aOff, h_whi + wOff, h_wlo + wOff,
        C, chi, clo, M, N, K, bias, res, act, nSplit);
}
}

extern "C" void kernel_launch(void* const* d_in, const int* in_sizes, int n_in,
                              void* d_out, int out_size) {
    const int*   x           = (const int*)d_in[0];
    // d_in[1] = prefix_mask: all-True and padded True => no-op; unused.
    const float* token_emb   = (const float*)d_in[2];
    const float* pos_emb     = (const float*)d_in[3];
    const float* ca_norm_s   = (const float*)d_in[4];
    const float* ca_norm_b   = (const float*)d_in[5];
    const float* ca_ctx_ns   = (const float*)d_in[6];
    const float* ca_ctx_nb   = (const float*)d_in[7];
    const float* ca_wq       = (const float*)d_in[8];
    const float* ca_wkv      = (const float*)d_in[9];
    const float* ca_wo       = (const float*)d_in[10];
    const float* ca_bo       = (const float*)d_in[11];
    const float* ca_ff_ln_s  = (const float*)d_in[12];
    const float* ca_ff_ln_b  = (const float*)d_in[13];
    const float* ca_ff_w1    = (const float*)d_in[14];
    const float* ca_ff_w2    = (const float*)d_in[15];
    const float* l_norm_s    = (const float*)d_in[16];
    const float* l_norm_b    = (const float*)d_in[17];
    const float* l_wqkv      = (const float*)d_in[18];
    const float* l_wo        = (const float*)d_in[19];
    const float* l_ff_ln_s   = (const float*)d_in[20];
    const float* l_ff_ln_b   = (const float*)d_in[21];
    const float* l_ff_w1     = (const float*)d_in[22];
    const float* l_ff_w2     = (const float*)d_in[23];
    const float* w_logits    = (const float*)d_in[24];
    float* out = (float*)d_out;

    float *prefix, *lat, *pkv, *qkv, *ctab, *stab;
    cudaGetSymbolAddress((void**)&prefix, g_prefix);
    cudaGetSymbolAddress((void**)&lat,    g_lat);
    cudaGetSymbolAddress((void**)&pkv,    g_pkv);
    cudaGetSymbolAddress((void**)&qkv,    g_qkv);
    cudaGetSymbolAddress((void**)&ctab,   g_cos);
    cudaGetSymbolAddress((void**)&stab,   g_sin);
    cudaGetSymbolAddress((void**)&h_whi,  g_whi);
    cudaGetSymbolAddress((void**)&h_wlo,  g_wlo);
    cudaGetSymbolAddress((void**)&h_ahi,  g_ahi);
    cudaGetSymbolAddress((void**)&h_alo,  g_alo);
    cudaGetSymbolAddress((void**)&h_qhi,  g_qhi);
    cudaGetSymbolAddress((void**)&h_qlo,  g_qlo);
    cudaGetSymbolAddress((void**)&h_khi,  g_khi);
    cudaGetSymbolAddress((void**)&h_klo,  g_klo);
    cudaGetSymbolAddress((void**)&h_vph,  g_vph);
    cudaGetSymbolAddress((void**)&h_vpl,  g_vpl);
    cudaGetSymbolAddress((void**)&h_part, g_part);

    cudaFuncSetAttribute(hgemm_kernel,
                         cudaFuncAttributeMaxDynamicSharedMemorySize, kGemmSmem);
    cudaFuncSetAttribute(attn_kernel,
                         cudaFuncAttributeMaxDynamicSharedMemorySize, kAttnSmem);

    auto cw = [&](const float* W, size_t off, int K, int N, int Npad,
                  int layers, size_t srcStride, size_t dstStride) {
        dim3 g(K / 64, Npad / 64, layers);
        cvt_wt_kernel<<<g, dim3(32, 8)>>>(W, h_whi + off, h_wlo + off,
                                          K, N, Npad, srcStride, dstStride);
    };

    // weight conversions (batched across layers where possible)
    cw(ca_wq,    OFF_CAWQ,  1024, 1024, 1024, 1, 0, 0);
    cw(ca_wkv,   OFF_CAWKV, 1024, 2048, 2048, 1, 0, 0);
    cw(ca_wo,    OFF_CAWO,  1024, 1024, 1024, 1, 0, 0);
    cw(ca_ff_w1, OFF_CAFF1, 1024, 4096, 4096, 1, 0, 0);
    cw(ca_ff_w2, OFF_CAFF2, 4096, 1024, 1024, 1, 0, 0);
    cw(l_wqkv,   OFF_LQKV,  1024, 3072, 3072, kL, 1024ull * 3072, 3072ull * 1024);
    cw(l_wo,     OFF_LWO,   1024, 1024, 1024, kL, 1024ull * 1024, 1024ull * 1024);
    cw(l_ff_w1,  OFF_LFF1,  1024, 4096, 4096, kL, 1024ull * 4096, 4096ull * 1024);
    cw(l_ff_w2,  OFF_LFF2,  4096, 1024, 1024, kL, 4096ull * 1024, 1024ull * 4096);
    cw(w_logits, OFF_LOGITS, 1024, kV, kVp, 1, 0, 0);

    // embeddings + rope tables
    embed_kernel<<<kB * kS, 256>>>(x, token_emb, pos_emb, prefix, lat);
    rope_table_kernel<<<(kS * 16 + 255) / 256, 256>>>(ctab, stab);

    // 2. cross-attention block
    ln_bf16_kernel<<<kB * kNL, 256>>>(lat,    ca_norm_s, ca_norm_b,
                                      h_ahi + A0,  h_alo + A0);
    ln_bf16_kernel<<<kB * kP,  256>>>(prefix, ca_ctx_ns, ca_ctx_nb,
                                      h_ahi + ACN, h_alo + ACN);
    // combined [q|k|v] projection for latents
    gemm(A0, OFF_CAWQ, qkv, nullptr, nullptr,
         kB * kNL, 3 * kID, 3 * kID, kD, nullptr, nullptr, 0);
    // prefix [k|v] projection, both batches at once
    gemm(ACN, OFF_CAWKV, pkv, nullptr, nullptr,
         kB * kP, 2 * kID, 2 * kID, kD, nullptr, nullptr, 0);

    {
        int warps = kB * kNL * kH;
        qkvprep_kernel<<<(warps + 7) / 8, 256>>>(
            qkv, kB * kNL, 3 * kID, kNL, kP,
            qkv + kID, qkv + 2 * kID, kB * kNL, 3 * kID, kNL, kP, kS, kP,
            ctab, stab, h_qhi, h_qlo, h_khi, h_klo, h_vph, h_vpl);
        warps = kB * kP * kH;
        qkvprep_kernel<<<(warps + 7) / 8, 256>>>(
            nullptr, 0, 0, 1, 0,
            pkv, pkv + kID, kB * kP, 2 * kID, kP, 0, kS, 0,
            ctab, stab, h_qhi, h_qlo, h_khi, h_klo, h_vph, h_vpl);
    }
    attn_kernel<<<dim3(kNL / 64, kH, kB), 256, kAttnSmem>>>(
        h_qhi, h_qlo, h_khi, h_klo, h_vph, h_vpl,
        h_ahi + A0, h_alo + A0, kNL, kS, kP);

    // WO split-K -> fused reduce+bias+residual+LN (FF LN params)
    gemm(A0, OFF_CAWO, h_part, nullptr, nullptr,
         kB * kNL, kD, kD, kID, nullptr, nullptr, 0, 3);
    lnred_bf16_kernel<<<kB * kNL, 256>>>(h_part, ca_bo, lat,
                                         ca_ff_ln_s, ca_ff_ln_b,
                                         lat, h_ahi + A0, h_alo + A0);

    gemm(A0, OFF_CAFF1, nullptr, h_ahi + AFF, h_alo + AFF,
         kB * kNL, kFF, kFF, kD, nullptr, nullptr, 1);
    gemm(AFF, OFF_CAFF2, h_part, nullptr, nullptr,
         kB * kNL, kD, kD, kFF, nullptr, nullptr, 0, 3);
    // FF2 reduce fused with layer-0 attention LN
    lnred_bf16_kernel<<<kB * kNL, 256>>>(h_part, nullptr, lat,
                                         l_norm_s, l_norm_b,
                                         lat, h_ahi + A0, h_alo + A0);

    // 3. latent self-attention layers
    for (int li = 0; li < kL; li++) {
        // (hi/lo already hold LN(lat) for this layer's attention)
        gemm(A0, OFF_LQKV + (size_t)li * 3072 * 1024, qkv, nullptr, nullptr,
             kB * kNL, 3 * kID, 3 * kID, kD, nullptr, nullptr, 0);

        int warps = kB * kNL * kH;
        qkvprep_kernel<<<(warps + 7) / 8, 256>>>(
            qkv, kB * kNL, 3 * kID, kNL, kP,
            qkv + kID, qkv + 2 * kID, kB * kNL, 3 * kID, kNL, kP, kNL, 0,
            ctab, stab, h_qhi, h_qlo, h_khi, h_klo, h_vph, h_vpl);
        attn_kernel<<<dim3(kNL / 64, kH, kB), 256, kAttnSmem>>>(
            h_qhi, h_qlo, h_khi, h_klo, h_vph, h_vpl,
            h_ahi + A0, h_alo + A0, kNL, kNL, 0);

        gemm(A0, OFF_LWO + (size_t)li * 1024 * 1024, h_part, nullptr, nullptr,
             kB * kNL, kD, kD, kID, nullptr, nullptr, 0, 3);
        lnred_bf16_kernel<<<kB * kNL, 256>>>(h_part, nullptr, lat,
                                             l_ff_ln_s + li * kD,
                                             l_ff_ln_b + li * kD,
                                             lat, h_ahi + A0, h_alo + A0);

        gemm(A0, OFF_LFF1 + (size_t)li * 4096 * 1024, nullptr,
             h_ahi + AFF, h_alo + AFF,
             kB * kNL, kFF, kFF, kD, nullptr, nullptr, 1);
        gemm(AFF, OFF_LFF2 + (size_t)li * 1024 * 4096, h_part, nullptr, nullptr,
             kB * kNL, kD, kD, kFF, nullptr, nullptr, 0, 3);
        if (li + 1 < kL) {
            lnred_bf16_kernel<<<kB * kNL, 256>>>(h_part, nullptr, lat,
                                                 l_norm_s + (li + 1) * kD,
                                                 l_norm_b + (li + 1) * kD,
                                                 lat, h_ahi + A0, h_alo + A0);
        } else {
            // last FF2: reduce + residual -> logits GEMM input directly
            redcvt_kernel<<<(kFF2N / 2 + 255) / 256, 256>>>(
                h_part, lat, h_ahi + A0, h_alo + A0);
        }
    }

    // 4. logits head
    gemm(A0, OFF_LOGITS, out, nullptr, nullptr,
         kB * kNL, kV, kVp, kD, nullptr, nullptr, 0);
}